// round 1
// baseline (speedup 1.0000x reference)
#include <cuda_runtime.h>
#include <math.h>

#define DIMN   1024
#define NHEAD  16
#define HDIM   64
#define SEQL   2048
#define BATCH  2
#define TOK    4096          // BATCH*SEQL
#define HIDDEN 2816

// ---------------- scratch (device globals; no runtime allocation) ----------------
__device__ float d_t [BATCH*512];
__device__ float d_gm[BATCH*256];
__device__ float d_gf[BATCH*256];
__device__ float d_xa[TOK*DIMN];
__device__ float d_q [TOK*DIMN];
__device__ float d_k [TOK*DIMN];
__device__ float d_v [TOK*DIMN];
__device__ float d_ao[TOK*DIMN];
__device__ float d_h1[(size_t)TOK*HIDDEN];
__device__ float d_h3[(size_t)TOK*HIDDEN];

// ---------------- helpers ----------------
__device__ __forceinline__ float blockSum256(float v) {
    __shared__ float red[8];
    int lane = threadIdx.x & 31, wid = threadIdx.x >> 5;
    #pragma unroll
    for (int o = 16; o > 0; o >>= 1) v += __shfl_xor_sync(0xffffffffu, v, o);
    __syncthreads();              // protect red[] across repeated calls
    if (lane == 0) red[wid] = v;
    __syncthreads();
    float s = red[0];
    #pragma unroll
    for (int w = 1; w < 8; w++) s += red[w];
    return s;
}

// ---------------- t = silu(adafm_input) @ proj_w + proj_b ----------------
__global__ void proj_t_kernel(const float* __restrict__ ad, const float* __restrict__ pw,
                              const float* __restrict__ pb, float* __restrict__ t) {
    int b = blockIdx.x;
    __shared__ float s[DIMN];
    for (int i = threadIdx.x; i < DIMN; i += blockDim.x) {
        float z = ad[b*DIMN + i];
        s[i] = z / (1.f + expf(-z));
    }
    __syncthreads();
    for (int o = threadIdx.x; o < 512; o += blockDim.x) {
        float acc = pb[o];
        #pragma unroll 4
        for (int i = 0; i < DIMN; i++) acc += s[i] * pw[i*512 + o];
        t[b*512 + o] = acc;
    }
}

// ---------------- g[d] = (1/256) sum_k m[k] cos(2*pi*k*d/256) ----------------
__global__ void make_g_kernel(const float* __restrict__ t,
                              float* __restrict__ gm, float* __restrict__ gf) {
    int b = blockIdx.x >> 1, which = blockIdx.x & 1;
    const float* m = t + b*512 + which*256;
    __shared__ float cs[256], ms[256];
    int d = threadIdx.x;
    cs[d] = cosf((6.283185307179586f / 256.0f) * (float)d);
    ms[d] = m[d];
    __syncthreads();
    float acc = 0.f;
    #pragma unroll 4
    for (int k = 0; k < 256; k++) acc += ms[k] * cs[(k*d) & 255];
    float* out = which ? gf : gm;
    out[b*256 + d] = acc * (1.0f / 256.0f);
}

// ---------------- per-patch 256-tap circular conv (== adafm_modulate) ----------------
__global__ __launch_bounds__(256) void adafm_apply(const float* __restrict__ x,
                                                   const float* __restrict__ g,
                                                   float* __restrict__ y) {
    int j = blockIdx.x, i = blockIdx.y, b = blockIdx.z;
    __shared__ float xs[256], gs[256];
    int t = threadIdx.x;
    const float* xb = x + ((size_t)b*SEQL + i*16) * DIMN + j*16;
    xs[t] = xb[(t >> 4) * DIMN + (t & 15)];
    gs[t] = g[b*256 + t];
    __syncthreads();
    float acc = 0.f;
    #pragma unroll 8
    for (int q0 = 0; q0 < 256; q0 += 4) {
        float4 xv = *(const float4*)&xs[q0];
        acc += xv.x * gs[(t - q0)     & 255];
        acc += xv.y * gs[(t - q0 - 1) & 255];
        acc += xv.z * gs[(t - q0 - 2) & 255];
        acc += xv.w * gs[(t - q0 - 3) & 255];
    }
    y[((size_t)b*SEQL + i*16 + (t >> 4)) * DIMN + j*16 + (t & 15)] = acc;
}

// ---------------- SGEMM: C[M,N] = A[M,K] @ B[K,N], all row-major, dims %128/%8 == 0 ----
__global__ __launch_bounds__(256) void sgemm(const float* __restrict__ A,
                                             const float* __restrict__ B,
                                             float* __restrict__ C,
                                             int M, int N, int K) {
    __shared__ float As[8][128];
    __shared__ float Bs[8][128];
    const int tid = threadIdx.x;
    const int tr = tid >> 4, tc = tid & 15;
    const int bx = blockIdx.x, by = blockIdx.y;
    const float* Ab = A + (size_t)by * 128 * K;
    const float* Bb = B + bx * 128;
    const int arow = tid >> 1, acol = (tid & 1) * 4;
    const int brow = tid >> 5, bcol = (tid & 31) * 4;
    float acc[8][8];
    #pragma unroll
    for (int i = 0; i < 8; i++)
        #pragma unroll
        for (int jj = 0; jj < 8; jj++) acc[i][jj] = 0.f;

    for (int k0 = 0; k0 < K; k0 += 8) {
        float4 av = *(const float4*)(Ab + (size_t)arow * K + k0 + acol);
        As[acol + 0][arow] = av.x; As[acol + 1][arow] = av.y;
        As[acol + 2][arow] = av.z; As[acol + 3][arow] = av.w;
        float4 bv = *(const float4*)(Bb + (size_t)(k0 + brow) * N + bcol);
        *(float4*)&Bs[brow][bcol] = bv;
        __syncthreads();
        #pragma unroll
        for (int kk = 0; kk < 8; kk++) {
            float4 a0 = *(const float4*)&As[kk][tr*8];
            float4 a1 = *(const float4*)&As[kk][tr*8 + 4];
            float4 b0 = *(const float4*)&Bs[kk][tc*8];
            float4 b1 = *(const float4*)&Bs[kk][tc*8 + 4];
            float ra[8] = {a0.x,a0.y,a0.z,a0.w,a1.x,a1.y,a1.z,a1.w};
            float rb[8] = {b0.x,b0.y,b0.z,b0.w,b1.x,b1.y,b1.z,b1.w};
            #pragma unroll
            for (int i = 0; i < 8; i++)
                #pragma unroll
                for (int jj = 0; jj < 8; jj++) acc[i][jj] += ra[i] * rb[jj];
        }
        __syncthreads();
    }
    float* Cb = C + (size_t)(by*128 + tr*8) * N + bx*128 + tc*8;
    #pragma unroll
    for (int i = 0; i < 8; i++) {
        *(float4*)(Cb + (size_t)i*N)     = make_float4(acc[i][0], acc[i][1], acc[i][2], acc[i][3]);
        *(float4*)(Cb + (size_t)i*N + 4) = make_float4(acc[i][4], acc[i][5], acc[i][6], acc[i][7]);
    }
}

// ---------------- rotary + justnorm + sqk_eff on Q,K in-place ----------------
__global__ __launch_bounds__(256) void rope_norm(float* __restrict__ Q, float* __restrict__ K,
                                                 const float* __restrict__ fcos,
                                                 const float* __restrict__ fsin,
                                                 const float* __restrict__ sqk) {
    int w = blockIdx.x * 8 + (threadIdx.x >> 5);
    int lane = threadIdx.x & 31;
    int tok = w >> 4;
    int h = w & 15;
    int s = tok & (SEQL - 1);
    float c  = fcos[s*32 + lane];
    float sn = fsin[s*32 + lane];
    size_t base = (size_t)tok * DIMN + h * HDIM + 2 * lane;
    float se0 = sqk[h*HDIM + 2*lane]     * 32.f;
    float se1 = sqk[h*HDIM + 2*lane + 1] * 32.f;

    {   // Q
        float2 qv = *(float2*)(Q + base);
        float ra = qv.x * c - qv.y * sn;
        float rb = qv.x * sn + qv.y * c;
        float ss = ra*ra + rb*rb;
        #pragma unroll
        for (int o = 16; o > 0; o >>= 1) ss += __shfl_xor_sync(0xffffffffu, ss, o);
        float inv = 1.f / fmaxf(sqrtf(ss), 1e-12f);
        *(float2*)(Q + base) = make_float2(ra * inv * se0, rb * inv * se1);
    }
    {   // K
        float2 kv = *(float2*)(K + base);
        float ra = kv.x * c - kv.y * sn;
        float rb = kv.x * sn + kv.y * c;
        float ss = ra*ra + rb*rb;
        #pragma unroll
        for (int o = 16; o > 0; o >>= 1) ss += __shfl_xor_sync(0xffffffffu, ss, o);
        float inv = 1.f / fmaxf(sqrtf(ss), 1e-12f);
        *(float2*)(K + base) = make_float2(ra * inv * se0, rb * inv * se1);
    }
}

// ---------------- flash attention, fp32, 64x64 tiles, online softmax ----------------
#define FSTRIDE 68
#define FLASH_SMEM (4 * 64 * FSTRIDE * 4)

__global__ __launch_bounds__(256) void flash_attn(const float* __restrict__ Q,
                                                  const float* __restrict__ K,
                                                  const float* __restrict__ V,
                                                  float* __restrict__ O) {
    extern __shared__ float sm[];
    float* Qs = sm;
    float* Ks = sm + 64 * FSTRIDE;
    float* Vs = sm + 2 * 64 * FSTRIDE;
    float* Ps = sm + 3 * 64 * FSTRIDE;

    const int q0 = blockIdx.x * 64;
    const int h  = blockIdx.y;
    const int b  = blockIdx.z;
    const float* Qb = Q + (size_t)b*SEQL*DIMN + h*HDIM;
    const float* Kb = K + (size_t)b*SEQL*DIMN + h*HDIM;
    const float* Vb = V + (size_t)b*SEQL*DIMN + h*HDIM;
    float*       Ob = O + (size_t)b*SEQL*DIMN + h*HDIM;

    const int tid = threadIdx.x;
    const int tx = tid & 15, ty = tid >> 4;
    const int lr = tid >> 2, lc = (tid & 3) * 16;

    #pragma unroll
    for (int u = 0; u < 4; u++) {
        float4 qv = *(const float4*)(Qb + (size_t)(q0 + lr)*DIMN + lc + u*4);
        qv.x *= 8.f; qv.y *= 8.f; qv.z *= 8.f; qv.w *= 8.f;   // score scale = sqrt(HD)
        *(float4*)&Qs[lr*FSTRIDE + lc + u*4] = qv;
    }

    float mrow[4], lsum[4], oacc[4][4];
    #pragma unroll
    for (int i = 0; i < 4; i++) {
        mrow[i] = -1e30f; lsum[i] = 0.f;
        #pragma unroll
        for (int jj = 0; jj < 4; jj++) oacc[i][jj] = 0.f;
    }

    for (int k0 = 0; k0 < SEQL; k0 += 64) {
        __syncthreads();
        #pragma unroll
        for (int u = 0; u < 4; u++) {
            *(float4*)&Ks[lr*FSTRIDE + lc + u*4] = *(const float4*)(Kb + (size_t)(k0+lr)*DIMN + lc + u*4);
            *(float4*)&Vs[lr*FSTRIDE + lc + u*4] = *(const float4*)(Vb + (size_t)(k0+lr)*DIMN + lc + u*4);
        }
        __syncthreads();

        float sacc[4][4];
        #pragma unroll
        for (int i = 0; i < 4; i++)
            #pragma unroll
            for (int jj = 0; jj < 4; jj++) sacc[i][jj] = 0.f;

        #pragma unroll 4
        for (int d = 0; d < HDIM; d++) {
            float qv[4], kv[4];
            #pragma unroll
            for (int i = 0; i < 4; i++)  qv[i] = Qs[(ty*4 + i)*FSTRIDE + d];
            #pragma unroll
            for (int jj = 0; jj < 4; jj++) kv[jj] = Ks[(tx + 16*jj)*FSTRIDE + d];
            #pragma unroll
            for (int i = 0; i < 4; i++)
                #pragma unroll
                for (int jj = 0; jj < 4; jj++) sacc[i][jj] += qv[i] * kv[jj];
        }

        #pragma unroll
        for (int i = 0; i < 4; i++) {
            float tm = fmaxf(fmaxf(sacc[i][0], sacc[i][1]), fmaxf(sacc[i][2], sacc[i][3]));
            #pragma unroll
            for (int o = 8; o > 0; o >>= 1) tm = fmaxf(tm, __shfl_xor_sync(0xffffffffu, tm, o));
            float mn = fmaxf(mrow[i], tm);
            float corr = __expf(mrow[i] - mn);
            float ps = 0.f;
            #pragma unroll
            for (int jj = 0; jj < 4; jj++) {
                float p = __expf(sacc[i][jj] - mn);
                Ps[(ty*4 + i)*FSTRIDE + tx + 16*jj] = p;
                ps += p;
            }
            #pragma unroll
            for (int o = 8; o > 0; o >>= 1) ps += __shfl_xor_sync(0xffffffffu, ps, o);
            lsum[i] = lsum[i] * corr + ps;
            #pragma unroll
            for (int jj = 0; jj < 4; jj++) oacc[i][jj] *= corr;
            mrow[i] = mn;
        }
        __syncthreads();

        #pragma unroll 4
        for (int kk = 0; kk < 64; kk++) {
            float pv[4], vv[4];
            #pragma unroll
            for (int i = 0; i < 4; i++)  pv[i] = Ps[(ty*4 + i)*FSTRIDE + kk];
            #pragma unroll
            for (int jj = 0; jj < 4; jj++) vv[jj] = Vs[kk*FSTRIDE + tx + 16*jj];
            #pragma unroll
            for (int i = 0; i < 4; i++)
                #pragma unroll
                for (int jj = 0; jj < 4; jj++) oacc[i][jj] += pv[i] * vv[jj];
        }
    }

    #pragma unroll
    for (int i = 0; i < 4; i++) {
        float inv = 1.f / lsum[i];
        #pragma unroll
        for (int jj = 0; jj < 4; jj++)
            Ob[(size_t)(q0 + ty*4 + i)*DIMN + tx + 16*jj] = oacc[i][jj] * inv;
    }
}

// ---------------- fused: h=norm(xb); ha=norm(br); out = norm(h + |alpha*1.6|*(ha-h)) ----
__global__ __launch_bounds__(256) void residual_norm(const float* __restrict__ xb,
                                                     const float* __restrict__ br,
                                                     const float* __restrict__ alpha,
                                                     float* __restrict__ out) {
    int t = blockIdx.x;
    int tid = threadIdx.x;
    const float* xr = xb + (size_t)t * DIMN;
    const float* rr = br + (size_t)t * DIMN;
    float xv[4], bv[4];
    float ssx = 0.f, ssb = 0.f;
    #pragma unroll
    for (int u = 0; u < 4; u++) {
        int d = tid + u * 256;
        xv[u] = xr[d]; bv[u] = rr[d];
        ssx += xv[u] * xv[u]; ssb += bv[u] * bv[u];
    }
    ssx = blockSum256(ssx);
    ssb = blockSum256(ssb);
    float rx = 1.f / fmaxf(sqrtf(ssx), 1e-12f);
    float rb = 1.f / fmaxf(sqrtf(ssb), 1e-12f);
    float yv[4]; float ssy = 0.f;
    #pragma unroll
    for (int u = 0; u < 4; u++) {
        int d = tid + u * 256;
        float hh = xv[u] * rx;
        float ha = bv[u] * rb;
        float lr = fabsf(alpha[d] * 1.6f);   // 0.05*sqrt(1024)
        float y = hh + lr * (ha - hh);
        yv[u] = y; ssy += y * y;
    }
    ssy = blockSum256(ssy);
    float ry = 1.f / fmaxf(sqrtf(ssy), 1e-12f);
    #pragma unroll
    for (int u = 0; u < 4; u++)
        out[(size_t)t * DIMN + tid + u * 256] = yv[u] * ry;
}

// ---------------- FFN gate: h1 = silu(h1*sv*sqrt(H)) * (h3*su) ----------------
__global__ void ffn_gate(float* __restrict__ h1, const float* __restrict__ h3,
                         const float* __restrict__ su, const float* __restrict__ sv) {
    const float SC = 53.06599664568481f;   // sqrt(2816)
    size_t n = (size_t)TOK * HIDDEN;
    size_t stride = (size_t)gridDim.x * blockDim.x;
    for (size_t i = (size_t)blockIdx.x * blockDim.x + threadIdx.x; i < n; i += stride) {
        int col = (int)(i % HIDDEN);
        float z = h1[i] * sv[col] * SC;
        float s = z / (1.f + __expf(-z));
        h1[i] = s * (h3[i] * su[col]);
    }
}

// ---------------- launch ----------------
extern "C" void kernel_launch(void* const* d_in, const int* in_sizes, int n_in,
                              void* d_out, int out_size) {
    const float* x      = (const float*)d_in[0];
    const float* fcos   = (const float*)d_in[1];
    const float* fsin   = (const float*)d_in[2];
    const float* adafm  = (const float*)d_in[3];
    const float* wq     = (const float*)d_in[4];
    const float* wk     = (const float*)d_in[5];
    const float* wv     = (const float*)d_in[6];
    const float* wo     = (const float*)d_in[7];
    const float* sqk    = (const float*)d_in[8];
    const float* w1     = (const float*)d_in[9];
    const float* w2     = (const float*)d_in[10];
    const float* w3     = (const float*)d_in[11];
    const float* su     = (const float*)d_in[12];
    const float* sv     = (const float*)d_in[13];
    const float* pw     = (const float*)d_in[14];
    const float* pb     = (const float*)d_in[15];
    const float* aalpha = (const float*)d_in[16];
    const float* malpha = (const float*)d_in[17];
    float* out = (float*)d_out;

    float *pt, *pgm, *pgf, *pxa, *pq, *pk, *pv, *pao, *ph1, *ph3;
    cudaGetSymbolAddress((void**)&pt,  d_t);
    cudaGetSymbolAddress((void**)&pgm, d_gm);
    cudaGetSymbolAddress((void**)&pgf, d_gf);
    cudaGetSymbolAddress((void**)&pxa, d_xa);
    cudaGetSymbolAddress((void**)&pq,  d_q);
    cudaGetSymbolAddress((void**)&pk,  d_k);
    cudaGetSymbolAddress((void**)&pv,  d_v);
    cudaGetSymbolAddress((void**)&pao, d_ao);
    cudaGetSymbolAddress((void**)&ph1, d_h1);
    cudaGetSymbolAddress((void**)&ph3, d_h3);

    cudaFuncSetAttribute(flash_attn, cudaFuncAttributeMaxDynamicSharedMemorySize, FLASH_SMEM);

    // 1) time-modulation coefficients
    proj_t_kernel<<<BATCH, 512>>>(adafm, pw, pb, pt);
    make_g_kernel<<<4, 256>>>(pt, pgm, pgf);

    // 2) attention branch
    adafm_apply<<<dim3(DIMN/16, SEQL/16, BATCH), 256>>>(x, pgm, pxa);
    sgemm<<<dim3(DIMN/128, TOK/128), 256>>>(pxa, wq, pq, TOK, DIMN, DIMN);
    sgemm<<<dim3(DIMN/128, TOK/128), 256>>>(pxa, wk, pk, TOK, DIMN, DIMN);
    sgemm<<<dim3(DIMN/128, TOK/128), 256>>>(pxa, wv, pv, TOK, DIMN, DIMN);
    rope_norm<<<TOK*NHEAD/8, 256>>>(pq, pk, fcos, fsin, sqk);
    flash_attn<<<dim3(SEQL/64, NHEAD, BATCH), 256, FLASH_SMEM>>>(pq, pk, pv, pao);
    sgemm<<<dim3(DIMN/128, TOK/128), 256>>>(pao, wo, pxa, TOK, DIMN, DIMN);
    residual_norm<<<TOK, 256>>>(x, pxa, aalpha, pq);   // pq := x1

    // 3) FFN branch
    adafm_apply<<<dim3(DIMN/16, SEQL/16, BATCH), 256>>>(pq, pgf, pk);   // pk := xm
    sgemm<<<dim3(HIDDEN/128, TOK/128), 256>>>(pk, w1, ph1, TOK, HIDDEN, DIMN);
    sgemm<<<dim3(HIDDEN/128, TOK/128), 256>>>(pk, w3, ph3, TOK, HIDDEN, DIMN);
    ffn_gate<<<4096, 256>>>(ph1, ph3, su, sv);
    sgemm<<<dim3(DIMN/128, TOK/128), 256>>>(ph1, w2, pv, TOK, DIMN, HIDDEN);
    residual_norm<<<TOK, 256>>>(pq, pv, malpha, out);
}

// round 2
// speedup vs baseline: 1.4563x; 1.4563x over previous
#include <cuda_runtime.h>
#include <math.h>

#define DIMN   1024
#define NHEAD  16
#define HDIM   64
#define SEQL   2048
#define BATCH  2
#define TOK    4096          // BATCH*SEQL
#define HIDDEN 2816

// ---------------- scratch (device globals; no runtime allocation) ----------------
__device__ float d_t [BATCH*512];
__device__ float d_gm[BATCH*256];
__device__ float d_gf[BATCH*256];
__device__ float d_xa[TOK*DIMN];
__device__ float d_q [TOK*DIMN];
__device__ float d_k [TOK*DIMN];
__device__ float d_v [TOK*DIMN];
__device__ float d_ao[TOK*DIMN];
__device__ float d_h1[(size_t)TOK*HIDDEN];
__device__ float d_h3[(size_t)TOK*HIDDEN];

// ---------------- helpers ----------------
__device__ __forceinline__ float blockSum256(float v) {
    __shared__ float red[8];
    int lane = threadIdx.x & 31, wid = threadIdx.x >> 5;
    #pragma unroll
    for (int o = 16; o > 0; o >>= 1) v += __shfl_xor_sync(0xffffffffu, v, o);
    __syncthreads();
    if (lane == 0) red[wid] = v;
    __syncthreads();
    float s = red[0];
    #pragma unroll
    for (int w = 1; w < 8; w++) s += red[w];
    return s;
}

__device__ __forceinline__ unsigned f2tf(float x) {
    unsigned u;
    asm("cvt.rna.tf32.f32 %0, %1;" : "=r"(u) : "f"(x));
    return u;
}

// ---------------- t = silu(adafm_input) @ proj_w + proj_b ----------------
__global__ void proj_t_kernel(const float* __restrict__ ad, const float* __restrict__ pw,
                              const float* __restrict__ pb, float* __restrict__ t) {
    int b = blockIdx.x;
    __shared__ float s[DIMN];
    for (int i = threadIdx.x; i < DIMN; i += blockDim.x) {
        float z = ad[b*DIMN + i];
        s[i] = z / (1.f + expf(-z));
    }
    __syncthreads();
    for (int o = threadIdx.x; o < 512; o += blockDim.x) {
        float acc = pb[o];
        #pragma unroll 4
        for (int i = 0; i < DIMN; i++) acc += s[i] * pw[i*512 + o];
        t[b*512 + o] = acc;
    }
}

// ---------------- g[d] = (1/256) sum_k m[k] cos(2*pi*k*d/256) ----------------
__global__ void make_g_kernel(const float* __restrict__ t,
                              float* __restrict__ gm, float* __restrict__ gf) {
    int b = blockIdx.x >> 1, which = blockIdx.x & 1;
    const float* m = t + b*512 + which*256;
    __shared__ float cs[256], ms[256];
    int d = threadIdx.x;
    cs[d] = cosf((6.283185307179586f / 256.0f) * (float)d);
    ms[d] = m[d];
    __syncthreads();
    float acc = 0.f;
    #pragma unroll 4
    for (int k = 0; k < 256; k++) acc += ms[k] * cs[(k*d) & 255];
    float* out = which ? gf : gm;
    out[b*256 + d] = acc * (1.0f / 256.0f);
}

// ---------------- per-patch 256-tap circular conv (== adafm_modulate) ----------------
__global__ __launch_bounds__(256) void adafm_apply(const float* __restrict__ x,
                                                   const float* __restrict__ g,
                                                   float* __restrict__ y) {
    int j = blockIdx.x, i = blockIdx.y, b = blockIdx.z;
    __shared__ float xs[256], gs[256];
    int t = threadIdx.x;
    const float* xb = x + ((size_t)b*SEQL + i*16) * DIMN + j*16;
    xs[t] = xb[(t >> 4) * DIMN + (t & 15)];
    gs[t] = g[b*256 + t];
    __syncthreads();
    float acc = 0.f;
    #pragma unroll 8
    for (int q0 = 0; q0 < 256; q0 += 4) {
        float4 xv = *(const float4*)&xs[q0];
        acc += xv.x * gs[(t - q0)     & 255];
        acc += xv.y * gs[(t - q0 - 1) & 255];
        acc += xv.z * gs[(t - q0 - 2) & 255];
        acc += xv.w * gs[(t - q0 - 3) & 255];
    }
    y[((size_t)b*SEQL + i*16 + (t >> 4)) * DIMN + j*16 + (t & 15)] = acc;
}

// ================= TF32 tensor-core GEMM =================
// C[M,N] = A[M,K] @ B[K,N], row-major, M%128==0, N%128==0, K%32==0.
// Block tile 128x128x32, 8 warps (2x4), warp tile 64x32, mma.m16n8k8.tf32.
// smem: k-major, stride 136 words (conflict-free for frag loads & stores).
#define GSTR 136
#define GEMM_SMEM (2 * 2 * 32 * GSTR * 4)   // 2 stages * (A+B) * 32 rows * 136 words * 4B

__global__ __launch_bounds__(256, 1) void gemm_tf32(const float* __restrict__ A,
                                                    const float* __restrict__ B,
                                                    float* __restrict__ C,
                                                    int M, int N, int K) {
    extern __shared__ unsigned sm4[];
    const int tid  = threadIdx.x;
    const int warp = tid >> 5;
    const int lane = tid & 31;
    const int g    = lane >> 2;       // 0..7
    const int t4   = lane & 3;        // 0..3

    const int bm = blockIdx.y * 128;
    const int bn = blockIdx.x * 128;

    // warp tile origin
    const int wm = (warp >> 2) * 64;  // 0 or 64
    const int wn = (warp & 3) * 32;   // 0,32,64,96

    // A gmem load mapping: row mloc, k-half kh (16 floats via 4 float4)
    const int mloc = (tid & 31) + (tid >> 6) * 32;        // 0..127
    const int kh   = ((tid >> 5) & 1) * 16;               // 0 or 16
    const float* Ag = A + (size_t)(bm + mloc) * K + kh;

    // B gmem load mapping: warp covers rows w*4..w*4+3, lane covers 4 cols
    const int brow = warp * 4;
    const int bcol = (tid & 31) * 4;
    const float* Bg = B + (size_t)brow * N + bn + bcol;

    unsigned* As[2] = { sm4,                sm4 + 2*32*GSTR };
    unsigned* Bs[2] = { sm4 + 32*GSTR,      sm4 + 3*32*GSTR };

    float acc[4][4][4];
    #pragma unroll
    for (int i = 0; i < 4; i++)
        #pragma unroll
        for (int j = 0; j < 4; j++)
            #pragma unroll
            for (int r = 0; r < 4; r++) acc[i][j][r] = 0.f;

    float4 la[4], lb[4];

    // prologue: load k0=0
    #pragma unroll
    for (int u = 0; u < 4; u++) la[u] = *(const float4*)(Ag + 4*u);
    #pragma unroll
    for (int u = 0; u < 4; u++) lb[u] = *(const float4*)(Bg + (size_t)u * N);
    {
        unsigned* At = As[0];
        unsigned* Bt = Bs[0];
        #pragma unroll
        for (int u = 0; u < 4; u++) {
            At[(kh + 4*u + 0)*GSTR + mloc] = f2tf(la[u].x);
            At[(kh + 4*u + 1)*GSTR + mloc] = f2tf(la[u].y);
            At[(kh + 4*u + 2)*GSTR + mloc] = f2tf(la[u].z);
            At[(kh + 4*u + 3)*GSTR + mloc] = f2tf(la[u].w);
        }
        #pragma unroll
        for (int u = 0; u < 4; u++) {
            uint4 bv;
            bv.x = f2tf(lb[u].x); bv.y = f2tf(lb[u].y);
            bv.z = f2tf(lb[u].z); bv.w = f2tf(lb[u].w);
            *(uint4*)&Bt[(brow + u)*GSTR + bcol] = bv;
        }
    }
    __syncthreads();

    int cur = 0;
    for (int k0 = 32; k0 <= K; k0 += 32) {
        const bool more = (k0 < K);
        if (more) {
            #pragma unroll
            for (int u = 0; u < 4; u++) la[u] = *(const float4*)(Ag + k0 + 4*u);
            #pragma unroll
            for (int u = 0; u < 4; u++) lb[u] = *(const float4*)(Bg + (size_t)(k0 + u) * N);
        }

        // compute current stage
        unsigned* At = As[cur];
        unsigned* Bt = Bs[cur];
        #pragma unroll
        for (int kk = 0; kk < 32; kk += 8) {
            unsigned af[4][4], bf[4][2];
            #pragma unroll
            for (int i = 0; i < 4; i++) {
                int m0 = wm + 16*i;
                af[i][0] = At[(kk + t4    )*GSTR + m0 + g    ];
                af[i][1] = At[(kk + t4    )*GSTR + m0 + g + 8];
                af[i][2] = At[(kk + t4 + 4)*GSTR + m0 + g    ];
                af[i][3] = At[(kk + t4 + 4)*GSTR + m0 + g + 8];
            }
            #pragma unroll
            for (int j = 0; j < 4; j++) {
                int n0 = wn + 8*j;
                bf[j][0] = Bt[(kk + t4    )*GSTR + n0 + g];
                bf[j][1] = Bt[(kk + t4 + 4)*GSTR + n0 + g];
            }
            #pragma unroll
            for (int i = 0; i < 4; i++)
                #pragma unroll
                for (int j = 0; j < 4; j++) {
                    asm volatile(
                        "mma.sync.aligned.m16n8k8.row.col.f32.tf32.tf32.f32 "
                        "{%0,%1,%2,%3}, {%4,%5,%6,%7}, {%8,%9}, {%0,%1,%2,%3};"
                        : "+f"(acc[i][j][0]), "+f"(acc[i][j][1]),
                          "+f"(acc[i][j][2]), "+f"(acc[i][j][3])
                        : "r"(af[i][0]), "r"(af[i][1]), "r"(af[i][2]), "r"(af[i][3]),
                          "r"(bf[j][0]), "r"(bf[j][1]));
                }
        }

        if (more) {
            unsigned* At2 = As[cur ^ 1];
            unsigned* Bt2 = Bs[cur ^ 1];
            #pragma unroll
            for (int u = 0; u < 4; u++) {
                At2[(kh + 4*u + 0)*GSTR + mloc] = f2tf(la[u].x);
                At2[(kh + 4*u + 1)*GSTR + mloc] = f2tf(la[u].y);
                At2[(kh + 4*u + 2)*GSTR + mloc] = f2tf(la[u].z);
                At2[(kh + 4*u + 3)*GSTR + mloc] = f2tf(la[u].w);
            }
            #pragma unroll
            for (int u = 0; u < 4; u++) {
                uint4 bv;
                bv.x = f2tf(lb[u].x); bv.y = f2tf(lb[u].y);
                bv.z = f2tf(lb[u].z); bv.w = f2tf(lb[u].w);
                *(uint4*)&Bt2[(brow + u)*GSTR + bcol] = bv;
            }
            __syncthreads();
            cur ^= 1;
        }
    }

    // epilogue: write C
    #pragma unroll
    for (int i = 0; i < 4; i++) {
        int row0 = bm + wm + 16*i + g;
        #pragma unroll
        for (int j = 0; j < 4; j++) {
            int col = bn + wn + 8*j + 2*t4;
            *(float2*)(C + (size_t)row0 * N + col)       = make_float2(acc[i][j][0], acc[i][j][1]);
            *(float2*)(C + (size_t)(row0 + 8) * N + col) = make_float2(acc[i][j][2], acc[i][j][3]);
        }
    }
}

// ---------------- rotary + justnorm + sqk_eff on Q,K in-place ----------------
__global__ __launch_bounds__(256) void rope_norm(float* __restrict__ Q, float* __restrict__ K,
                                                 const float* __restrict__ fcos,
                                                 const float* __restrict__ fsin,
                                                 const float* __restrict__ sqk) {
    int w = blockIdx.x * 8 + (threadIdx.x >> 5);
    int lane = threadIdx.x & 31;
    int tok = w >> 4;
    int h = w & 15;
    int s = tok & (SEQL - 1);
    float c  = fcos[s*32 + lane];
    float sn = fsin[s*32 + lane];
    size_t base = (size_t)tok * DIMN + h * HDIM + 2 * lane;
    float se0 = sqk[h*HDIM + 2*lane]     * 32.f;
    float se1 = sqk[h*HDIM + 2*lane + 1] * 32.f;

    {   // Q
        float2 qv = *(float2*)(Q + base);
        float ra = qv.x * c - qv.y * sn;
        float rb = qv.x * sn + qv.y * c;
        float ss = ra*ra + rb*rb;
        #pragma unroll
        for (int o = 16; o > 0; o >>= 1) ss += __shfl_xor_sync(0xffffffffu, ss, o);
        float inv = 1.f / fmaxf(sqrtf(ss), 1e-12f);
        *(float2*)(Q + base) = make_float2(ra * inv * se0, rb * inv * se1);
    }
    {   // K
        float2 kv = *(float2*)(K + base);
        float ra = kv.x * c - kv.y * sn;
        float rb = kv.x * sn + kv.y * c;
        float ss = ra*ra + rb*rb;
        #pragma unroll
        for (int o = 16; o > 0; o >>= 1) ss += __shfl_xor_sync(0xffffffffu, ss, o);
        float inv = 1.f / fmaxf(sqrtf(ss), 1e-12f);
        *(float2*)(K + base) = make_float2(ra * inv * se0, rb * inv * se1);
    }
}

// ---------------- flash attention, fp32, 64x64 tiles, online softmax ----------------
#define FSTRIDE 68
#define FLASH_SMEM (4 * 64 * FSTRIDE * 4)

__global__ __launch_bounds__(256) void flash_attn(const float* __restrict__ Q,
                                                  const float* __restrict__ K,
                                                  const float* __restrict__ V,
                                                  float* __restrict__ O) {
    extern __shared__ float sm[];
    float* Qs = sm;
    float* Ks = sm + 64 * FSTRIDE;
    float* Vs = sm + 2 * 64 * FSTRIDE;
    float* Ps = sm + 3 * 64 * FSTRIDE;

    const int q0 = blockIdx.x * 64;
    const int h  = blockIdx.y;
    const int b  = blockIdx.z;
    const float* Qb = Q + (size_t)b*SEQL*DIMN + h*HDIM;
    const float* Kb = K + (size_t)b*SEQL*DIMN + h*HDIM;
    const float* Vb = V + (size_t)b*SEQL*DIMN + h*HDIM;
    float*       Ob = O + (size_t)b*SEQL*DIMN + h*HDIM;

    const int tid = threadIdx.x;
    const int tx = tid & 15, ty = tid >> 4;
    const int lr = tid >> 2, lc = (tid & 3) * 16;

    #pragma unroll
    for (int u = 0; u < 4; u++) {
        float4 qv = *(const float4*)(Qb + (size_t)(q0 + lr)*DIMN + lc + u*4);
        qv.x *= 8.f; qv.y *= 8.f; qv.z *= 8.f; qv.w *= 8.f;
        *(float4*)&Qs[lr*FSTRIDE + lc + u*4] = qv;
    }

    float mrow[4], lsum[4], oacc[4][4];
    #pragma unroll
    for (int i = 0; i < 4; i++) {
        mrow[i] = -1e30f; lsum[i] = 0.f;
        #pragma unroll
        for (int jj = 0; jj < 4; jj++) oacc[i][jj] = 0.f;
    }

    for (int k0 = 0; k0 < SEQL; k0 += 64) {
        __syncthreads();
        #pragma unroll
        for (int u = 0; u < 4; u++) {
            *(float4*)&Ks[lr*FSTRIDE + lc + u*4] = *(const float4*)(Kb + (size_t)(k0+lr)*DIMN + lc + u*4);
            *(float4*)&Vs[lr*FSTRIDE + lc + u*4] = *(const float4*)(Vb + (size_t)(k0+lr)*DIMN + lc + u*4);
        }
        __syncthreads();

        float sacc[4][4];
        #pragma unroll
        for (int i = 0; i < 4; i++)
            #pragma unroll
            for (int jj = 0; jj < 4; jj++) sacc[i][jj] = 0.f;

        #pragma unroll 4
        for (int d = 0; d < HDIM; d++) {
            float qv[4], kv[4];
            #pragma unroll
            for (int i = 0; i < 4; i++)  qv[i] = Qs[(ty*4 + i)*FSTRIDE + d];
            #pragma unroll
            for (int jj = 0; jj < 4; jj++) kv[jj] = Ks[(tx + 16*jj)*FSTRIDE + d];
            #pragma unroll
            for (int i = 0; i < 4; i++)
                #pragma unroll
                for (int jj = 0; jj < 4; jj++) sacc[i][jj] += qv[i] * kv[jj];
        }

        #pragma unroll
        for (int i = 0; i < 4; i++) {
            float tm = fmaxf(fmaxf(sacc[i][0], sacc[i][1]), fmaxf(sacc[i][2], sacc[i][3]));
            #pragma unroll
            for (int o = 8; o > 0; o >>= 1) tm = fmaxf(tm, __shfl_xor_sync(0xffffffffu, tm, o));
            float mn = fmaxf(mrow[i], tm);
            float corr = __expf(mrow[i] - mn);
            float ps = 0.f;
            #pragma unroll
            for (int jj = 0; jj < 4; jj++) {
                float p = __expf(sacc[i][jj] - mn);
                Ps[(ty*4 + i)*FSTRIDE + tx + 16*jj] = p;
                ps += p;
            }
            #pragma unroll
            for (int o = 8; o > 0; o >>= 1) ps += __shfl_xor_sync(0xffffffffu, ps, o);
            lsum[i] = lsum[i] * corr + ps;
            #pragma unroll
            for (int jj = 0; jj < 4; jj++) oacc[i][jj] *= corr;
            mrow[i] = mn;
        }
        __syncthreads();

        #pragma unroll 4
        for (int kk = 0; kk < 64; kk++) {
            float pv[4], vv[4];
            #pragma unroll
            for (int i = 0; i < 4; i++)  pv[i] = Ps[(ty*4 + i)*FSTRIDE + kk];
            #pragma unroll
            for (int jj = 0; jj < 4; jj++) vv[jj] = Vs[kk*FSTRIDE + tx + 16*jj];
            #pragma unroll
            for (int i = 0; i < 4; i++)
                #pragma unroll
                for (int jj = 0; jj < 4; jj++) oacc[i][jj] += pv[i] * vv[jj];
        }
    }

    #pragma unroll
    for (int i = 0; i < 4; i++) {
        float inv = 1.f / lsum[i];
        #pragma unroll
        for (int jj = 0; jj < 4; jj++)
            Ob[(size_t)(q0 + ty*4 + i)*DIMN + tx + 16*jj] = oacc[i][jj] * inv;
    }
}

// ---------------- fused: h=norm(xb); ha=norm(br); out = norm(h + |alpha*1.6|*(ha-h)) ----
__global__ __launch_bounds__(256) void residual_norm(const float* __restrict__ xb,
                                                     const float* __restrict__ br,
                                                     const float* __restrict__ alpha,
                                                     float* __restrict__ out) {
    int t = blockIdx.x;
    int tid = threadIdx.x;
    const float* xr = xb + (size_t)t * DIMN;
    const float* rr = br + (size_t)t * DIMN;
    float xv[4], bv[4];
    float ssx = 0.f, ssb = 0.f;
    #pragma unroll
    for (int u = 0; u < 4; u++) {
        int d = tid + u * 256;
        xv[u] = xr[d]; bv[u] = rr[d];
        ssx += xv[u] * xv[u]; ssb += bv[u] * bv[u];
    }
    ssx = blockSum256(ssx);
    ssb = blockSum256(ssb);
    float rx = 1.f / fmaxf(sqrtf(ssx), 1e-12f);
    float rb = 1.f / fmaxf(sqrtf(ssb), 1e-12f);
    float yv[4]; float ssy = 0.f;
    #pragma unroll
    for (int u = 0; u < 4; u++) {
        int d = tid + u * 256;
        float hh = xv[u] * rx;
        float ha = bv[u] * rb;
        float lr = fabsf(alpha[d] * 1.6f);
        float y = hh + lr * (ha - hh);
        yv[u] = y; ssy += y * y;
    }
    ssy = blockSum256(ssy);
    float ry = 1.f / fmaxf(sqrtf(ssy), 1e-12f);
    #pragma unroll
    for (int u = 0; u < 4; u++)
        out[(size_t)t * DIMN + tid + u * 256] = yv[u] * ry;
}

// ---------------- FFN gate: h1 = silu(h1*sv*sqrt(H)) * (h3*su) ----------------
__global__ void ffn_gate(float* __restrict__ h1, const float* __restrict__ h3,
                         const float* __restrict__ su, const float* __restrict__ sv) {
    const float SC = 53.06599664568481f;   // sqrt(2816)
    size_t n = (size_t)TOK * HIDDEN;
    size_t stride = (size_t)gridDim.x * blockDim.x;
    for (size_t i = (size_t)blockIdx.x * blockDim.x + threadIdx.x; i < n; i += stride) {
        int col = (int)(i % HIDDEN);
        float z = h1[i] * sv[col] * SC;
        float s = z / (1.f + __expf(-z));
        h1[i] = s * (h3[i] * su[col]);
    }
}

// ---------------- launch ----------------
extern "C" void kernel_launch(void* const* d_in, const int* in_sizes, int n_in,
                              void* d_out, int out_size) {
    const float* x      = (const float*)d_in[0];
    const float* fcos   = (const float*)d_in[1];
    const float* fsin   = (const float*)d_in[2];
    const float* adafm  = (const float*)d_in[3];
    const float* wq     = (const float*)d_in[4];
    const float* wk     = (const float*)d_in[5];
    const float* wv     = (const float*)d_in[6];
    const float* wo     = (const float*)d_in[7];
    const float* sqk    = (const float*)d_in[8];
    const float* w1     = (const float*)d_in[9];
    const float* w2     = (const float*)d_in[10];
    const float* w3     = (const float*)d_in[11];
    const float* su     = (const float*)d_in[12];
    const float* sv     = (const float*)d_in[13];
    const float* pw     = (const float*)d_in[14];
    const float* pb     = (const float*)d_in[15];
    const float* aalpha = (const float*)d_in[16];
    const float* malpha = (const float*)d_in[17];
    float* out = (float*)d_out;

    float *pt, *pgm, *pgf, *pxa, *pq, *pk, *pv, *pao, *ph1, *ph3;
    cudaGetSymbolAddress((void**)&pt,  d_t);
    cudaGetSymbolAddress((void**)&pgm, d_gm);
    cudaGetSymbolAddress((void**)&pgf, d_gf);
    cudaGetSymbolAddress((void**)&pxa, d_xa);
    cudaGetSymbolAddress((void**)&pq,  d_q);
    cudaGetSymbolAddress((void**)&pk,  d_k);
    cudaGetSymbolAddress((void**)&pv,  d_v);
    cudaGetSymbolAddress((void**)&pao, d_ao);
    cudaGetSymbolAddress((void**)&ph1, d_h1);
    cudaGetSymbolAddress((void**)&ph3, d_h3);

    cudaFuncSetAttribute(flash_attn, cudaFuncAttributeMaxDynamicSharedMemorySize, FLASH_SMEM);
    cudaFuncSetAttribute(gemm_tf32, cudaFuncAttributeMaxDynamicSharedMemorySize, GEMM_SMEM);

    // 1) time-modulation coefficients
    proj_t_kernel<<<BATCH, 512>>>(adafm, pw, pb, pt);
    make_g_kernel<<<4, 256>>>(pt, pgm, pgf);

    // 2) attention branch
    adafm_apply<<<dim3(DIMN/16, SEQL/16, BATCH), 256>>>(x, pgm, pxa);
    gemm_tf32<<<dim3(DIMN/128, TOK/128), 256, GEMM_SMEM>>>(pxa, wq, pq, TOK, DIMN, DIMN);
    gemm_tf32<<<dim3(DIMN/128, TOK/128), 256, GEMM_SMEM>>>(pxa, wk, pk, TOK, DIMN, DIMN);
    gemm_tf32<<<dim3(DIMN/128, TOK/128), 256, GEMM_SMEM>>>(pxa, wv, pv, TOK, DIMN, DIMN);
    rope_norm<<<TOK*NHEAD/8, 256>>>(pq, pk, fcos, fsin, sqk);
    flash_attn<<<dim3(SEQL/64, NHEAD, BATCH), 256, FLASH_SMEM>>>(pq, pk, pv, pao);
    gemm_tf32<<<dim3(DIMN/128, TOK/128), 256, GEMM_SMEM>>>(pao, wo, pxa, TOK, DIMN, DIMN);
    residual_norm<<<TOK, 256>>>(x, pxa, aalpha, pq);   // pq := x1

    // 3) FFN branch
    adafm_apply<<<dim3(DIMN/16, SEQL/16, BATCH), 256>>>(pq, pgf, pk);   // pk := xm
    gemm_tf32<<<dim3(HIDDEN/128, TOK/128), 256, GEMM_SMEM>>>(pk, w1, ph1, TOK, HIDDEN, DIMN);
    gemm_tf32<<<dim3(HIDDEN/128, TOK/128), 256, GEMM_SMEM>>>(pk, w3, ph3, TOK, HIDDEN, DIMN);
    ffn_gate<<<4096, 256>>>(ph1, ph3, su, sv);
    gemm_tf32<<<dim3(DIMN/128, TOK/128), 256, GEMM_SMEM>>>(ph1, w2, pv, TOK, DIMN, HIDDEN);
    residual_norm<<<TOK, 256>>>(pq, pv, malpha, out);
}

// round 3
// speedup vs baseline: 2.4473x; 1.6804x over previous
#include <cuda_runtime.h>
#include <math.h>

#define DIMN   1024
#define NHEAD  16
#define HDIM   64
#define SEQL   2048
#define BATCH  2
#define TOK    4096          // BATCH*SEQL
#define HIDDEN 2816

// ---------------- scratch (device globals; no runtime allocation) ----------------
__device__ float d_t [BATCH*512];
__device__ float d_gm[BATCH*256];
__device__ float d_gf[BATCH*256];
__device__ float d_xa[TOK*DIMN];
__device__ float d_q [TOK*DIMN];
__device__ float d_k [TOK*DIMN];
__device__ float d_v [TOK*DIMN];
__device__ float d_ao[TOK*DIMN];
__device__ float d_h1[(size_t)TOK*HIDDEN];
__device__ float d_h3[(size_t)TOK*HIDDEN];

// ---------------- helpers ----------------
__device__ __forceinline__ float blockSum256(float v) {
    __shared__ float red[8];
    int lane = threadIdx.x & 31, wid = threadIdx.x >> 5;
    #pragma unroll
    for (int o = 16; o > 0; o >>= 1) v += __shfl_xor_sync(0xffffffffu, v, o);
    __syncthreads();
    if (lane == 0) red[wid] = v;
    __syncthreads();
    float s = red[0];
    #pragma unroll
    for (int w = 1; w < 8; w++) s += red[w];
    return s;
}

__device__ __forceinline__ void mma8(float* c, unsigned a0, unsigned a1, unsigned a2, unsigned a3,
                                     unsigned b0, unsigned b1) {
    asm volatile(
        "mma.sync.aligned.m16n8k8.row.col.f32.tf32.tf32.f32 "
        "{%0,%1,%2,%3}, {%4,%5,%6,%7}, {%8,%9}, {%0,%1,%2,%3};"
        : "+f"(c[0]), "+f"(c[1]), "+f"(c[2]), "+f"(c[3])
        : "r"(a0), "r"(a1), "r"(a2), "r"(a3), "r"(b0), "r"(b1));
}

__device__ __forceinline__ void cpa16(unsigned s, const void* g) {
    asm volatile("cp.async.cg.shared.global [%0], [%1], 16;" :: "r"(s), "l"(g));
}

// ---------------- t = silu(adafm_input) @ proj_w + proj_b ----------------
__global__ void proj_t_kernel(const float* __restrict__ ad, const float* __restrict__ pw,
                              const float* __restrict__ pb, float* __restrict__ t) {
    int b = blockIdx.x;
    __shared__ float s[DIMN];
    for (int i = threadIdx.x; i < DIMN; i += blockDim.x) {
        float z = ad[b*DIMN + i];
        s[i] = z / (1.f + expf(-z));
    }
    __syncthreads();
    for (int o = threadIdx.x; o < 512; o += blockDim.x) {
        float acc = pb[o];
        #pragma unroll 4
        for (int i = 0; i < DIMN; i++) acc += s[i] * pw[i*512 + o];
        t[b*512 + o] = acc;
    }
}

// ---------------- g[d] = (1/256) sum_k m[k] cos(2*pi*k*d/256) ----------------
__global__ void make_g_kernel(const float* __restrict__ t,
                              float* __restrict__ gm, float* __restrict__ gf) {
    int b = blockIdx.x >> 1, which = blockIdx.x & 1;
    const float* m = t + b*512 + which*256;
    __shared__ float cs[256], ms[256];
    int d = threadIdx.x;
    cs[d] = cosf((6.283185307179586f / 256.0f) * (float)d);
    ms[d] = m[d];
    __syncthreads();
    float acc = 0.f;
    #pragma unroll 4
    for (int k = 0; k < 256; k++) acc += ms[k] * cs[(k*d) & 255];
    float* out = which ? gf : gm;
    out[b*256 + d] = acc * (1.0f / 256.0f);
}

// ---------------- per-patch 256-tap circular conv (== adafm_modulate) ----------------
__global__ __launch_bounds__(256) void adafm_apply(const float* __restrict__ x,
                                                   const float* __restrict__ g,
                                                   float* __restrict__ y) {
    int j = blockIdx.x, i = blockIdx.y, b = blockIdx.z;
    __shared__ float xs[256], gs[256];
    int t = threadIdx.x;
    const float* xb = x + ((size_t)b*SEQL + i*16) * DIMN + j*16;
    xs[t] = xb[(t >> 4) * DIMN + (t & 15)];
    gs[t] = g[b*256 + t];
    __syncthreads();
    float acc = 0.f;
    #pragma unroll 8
    for (int q0 = 0; q0 < 256; q0 += 4) {
        float4 xv = *(const float4*)&xs[q0];
        acc += xv.x * gs[(t - q0)     & 255];
        acc += xv.y * gs[(t - q0 - 1) & 255];
        acc += xv.z * gs[(t - q0 - 2) & 255];
        acc += xv.w * gs[(t - q0 - 3) & 255];
    }
    y[((size_t)b*SEQL + i*16 + (t >> 4)) * DIMN + j*16 + (t & 15)] = acc;
}

// ================= TF32 tensor-core GEMM, cp.async 3-stage =================
// C[M,N] = A[M,K] @ B[K,N], row-major, M%128==0, N%256==0, K%32==0.
// Block tile 128x256x32, 8 warps (2m x 4n), warp tile 64x64.
#define ASTR 36
#define BSTR 264
#define A_WORDS (128*ASTR)
#define B_WORDS (32*BSTR)
#define STAGE_WORDS (A_WORDS + B_WORDS)
#define GEMM_SMEM (3 * STAGE_WORDS * 4)

__global__ __launch_bounds__(256, 1) void gemm_tf32(const float* __restrict__ A,
                                                    const float* __restrict__ B,
                                                    float* __restrict__ C,
                                                    int M, int N, int K) {
    extern __shared__ float smf[];
    const unsigned sbase = (unsigned)__cvta_generic_to_shared(smf);
    const int tid  = threadIdx.x;
    const int lane = tid & 31;
    const int warp = tid >> 5;
    const int g    = lane >> 2;
    const int t4   = lane & 3;
    const int bm = blockIdx.y * 128;
    const int bn = blockIdx.x * 256;
    const int wm = (warp >> 2) * 64;
    const int wn = (warp & 3) * 64;

    // load-index precompute
    const int am[4] = { (tid + 0*256) >> 3, (tid + 1*256) >> 3, (tid + 2*256) >> 3, (tid + 3*256) >> 3 };
    const int ak = (tid & 7) * 4;
    const int bkr[8] = { (tid+0*256)>>6, (tid+1*256)>>6, (tid+2*256)>>6, (tid+3*256)>>6,
                         (tid+4*256)>>6, (tid+5*256)>>6, (tid+6*256)>>6, (tid+7*256)>>6 };
    const int bnc = (tid & 63) * 4;

    float acc[4][8][4];
    #pragma unroll
    for (int i = 0; i < 4; i++)
        #pragma unroll
        for (int j = 0; j < 8; j++)
            #pragma unroll
            for (int r = 0; r < 4; r++) acc[i][j][r] = 0.f;

    const int ktiles = K >> 5;

    auto load_stage = [&](int st, int k0) {
        unsigned sa = sbase + (unsigned)(st * STAGE_WORDS) * 4u;
        unsigned sb = sa + A_WORDS * 4u;
        #pragma unroll
        for (int u = 0; u < 4; u++)
            cpa16(sa + (unsigned)(am[u]*ASTR + ak)*4u,
                  A + (size_t)(bm + am[u]) * K + k0 + ak);
        #pragma unroll
        for (int u = 0; u < 8; u++)
            cpa16(sb + (unsigned)(bkr[u]*BSTR + bnc)*4u,
                  B + (size_t)(k0 + bkr[u]) * N + bn + bnc);
    };

    load_stage(0, 0);
    asm volatile("cp.async.commit_group;");
    load_stage(1, 32);
    asm volatile("cp.async.commit_group;");

    for (int t = 0; t < ktiles; t++) {
        asm volatile("cp.async.wait_group 1;");
        __syncthreads();
        int nt = t + 2;
        if (nt < ktiles) load_stage(nt % 3, nt * 32);
        asm volatile("cp.async.commit_group;");

        const float* At = smf + (t % 3) * STAGE_WORDS;
        const float* Bt = At + A_WORDS;
        #pragma unroll
        for (int kk = 0; kk < 32; kk += 8) {
            unsigned af[4][4];
            #pragma unroll
            for (int i = 0; i < 4; i++) {
                int m0 = wm + 16*i;
                af[i][0] = __float_as_uint(At[(m0 + g    )*ASTR + kk + t4    ]);
                af[i][1] = __float_as_uint(At[(m0 + g + 8)*ASTR + kk + t4    ]);
                af[i][2] = __float_as_uint(At[(m0 + g    )*ASTR + kk + t4 + 4]);
                af[i][3] = __float_as_uint(At[(m0 + g + 8)*ASTR + kk + t4 + 4]);
            }
            #pragma unroll
            for (int j = 0; j < 8; j++) {
                int n0 = wn + 8*j;
                unsigned b0 = __float_as_uint(Bt[(kk + t4    )*BSTR + n0 + g]);
                unsigned b1 = __float_as_uint(Bt[(kk + t4 + 4)*BSTR + n0 + g]);
                #pragma unroll
                for (int i = 0; i < 4; i++)
                    mma8(acc[i][j], af[i][0], af[i][1], af[i][2], af[i][3], b0, b1);
            }
        }
    }

    #pragma unroll
    for (int i = 0; i < 4; i++) {
        int row0 = bm + wm + 16*i + g;
        #pragma unroll
        for (int j = 0; j < 8; j++) {
            int col = bn + wn + 8*j + 2*t4;
            *(float2*)(C + (size_t)row0 * N + col)       = make_float2(acc[i][j][0], acc[i][j][1]);
            *(float2*)(C + (size_t)(row0 + 8) * N + col) = make_float2(acc[i][j][2], acc[i][j][3]);
        }
    }
}

// ---------------- rotary + justnorm + sqk_eff on Q,K in-place ----------------
__global__ __launch_bounds__(256) void rope_norm(float* __restrict__ Q, float* __restrict__ K,
                                                 const float* __restrict__ fcos,
                                                 const float* __restrict__ fsin,
                                                 const float* __restrict__ sqk) {
    int w = blockIdx.x * 8 + (threadIdx.x >> 5);
    int lane = threadIdx.x & 31;
    int tok = w >> 4;
    int h = w & 15;
    int s = tok & (SEQL - 1);
    float c  = fcos[s*32 + lane];
    float sn = fsin[s*32 + lane];
    size_t base = (size_t)tok * DIMN + h * HDIM + 2 * lane;
    float se0 = sqk[h*HDIM + 2*lane]     * 32.f;
    float se1 = sqk[h*HDIM + 2*lane + 1] * 32.f;

    {
        float2 qv = *(float2*)(Q + base);
        float ra = qv.x * c - qv.y * sn;
        float rb = qv.x * sn + qv.y * c;
        float ss = ra*ra + rb*rb;
        #pragma unroll
        for (int o = 16; o > 0; o >>= 1) ss += __shfl_xor_sync(0xffffffffu, ss, o);
        float inv = 1.f / fmaxf(sqrtf(ss), 1e-12f);
        *(float2*)(Q + base) = make_float2(ra * inv * se0, rb * inv * se1);
    }
    {
        float2 kv = *(float2*)(K + base);
        float ra = kv.x * c - kv.y * sn;
        float rb = kv.x * sn + kv.y * c;
        float ss = ra*ra + rb*rb;
        #pragma unroll
        for (int o = 16; o > 0; o >>= 1) ss += __shfl_xor_sync(0xffffffffu, ss, o);
        float inv = 1.f / fmaxf(sqrtf(ss), 1e-12f);
        *(float2*)(K + base) = make_float2(ra * inv * se0, rb * inv * se1);
    }
}

// ---------------- flash attention: tf32 mma for QK^T and PV ----------------
#define FS 72
#define FLASH_SMEM ((4*64*FS + 128) * 4)

__global__ __launch_bounds__(256) void flash_attn(const float* __restrict__ Q,
                                                  const float* __restrict__ K,
                                                  const float* __restrict__ V,
                                                  float* __restrict__ O) {
    extern __shared__ float sm[];
    float* Qs = sm;
    float* Ks = sm + 64*FS;
    float* Vs = sm + 2*64*FS;
    float* Ps = sm + 3*64*FS;
    float* cr = sm + 4*64*FS;       // corr[64]
    float* li = cr + 64;            // linv[64]

    const int q0 = blockIdx.x * 64;
    const int h  = blockIdx.y;
    const int b  = blockIdx.z;
    const float* Qb = Q + (size_t)b*SEQL*DIMN + h*HDIM;
    const float* Kb = K + (size_t)b*SEQL*DIMN + h*HDIM;
    const float* Vb = V + (size_t)b*SEQL*DIMN + h*HDIM;
    float*       Ob = O + (size_t)b*SEQL*DIMN + h*HDIM;

    const int tid  = threadIdx.x;
    const int lane = tid & 31;
    const int warp = tid >> 5;
    const int g  = lane >> 2;
    const int t4 = lane & 3;
    const int wm = (warp >> 1) * 16;   // 0,16,32,48
    const int wn = (warp & 1) * 32;    // 0,32

    const int lr = tid >> 2, lc = (tid & 3) * 16;

    // Q tile (scaled by sqrt(HD)=8)
    #pragma unroll
    for (int u = 0; u < 4; u++) {
        float4 qv = *(const float4*)(Qb + (size_t)(q0 + lr)*DIMN + lc + 4*u);
        qv.x *= 8.f; qv.y *= 8.f; qv.z *= 8.f; qv.w *= 8.f;
        *(float4*)&Qs[lr*FS + lc + 4*u] = qv;
    }

    float o[4][4];
    #pragma unroll
    for (int j = 0; j < 4; j++)
        #pragma unroll
        for (int r = 0; r < 4; r++) o[j][r] = 0.f;

    // softmax row role: 4 threads per row
    const int srow = tid >> 2;
    float mrow = -1e30f, lsum = 0.f;

    for (int k0 = 0; k0 < SEQL; k0 += 64) {
        __syncthreads();
        #pragma unroll
        for (int u = 0; u < 4; u++) {
            *(float4*)&Ks[lr*FS + lc + 4*u] = *(const float4*)(Kb + (size_t)(k0+lr)*DIMN + lc + 4*u);
            *(float4*)&Vs[lr*FS + lc + 4*u] = *(const float4*)(Vb + (size_t)(k0+lr)*DIMN + lc + 4*u);
        }
        __syncthreads();

        // ---- S = Q @ K^T (warp tile 16x32) ----
        float s[4][4];
        #pragma unroll
        for (int j = 0; j < 4; j++)
            #pragma unroll
            for (int r = 0; r < 4; r++) s[j][r] = 0.f;

        #pragma unroll
        for (int kk = 0; kk < HDIM; kk += 8) {
            unsigned a0 = __float_as_uint(Qs[(wm + g    )*FS + kk + t4    ]);
            unsigned a1 = __float_as_uint(Qs[(wm + g + 8)*FS + kk + t4    ]);
            unsigned a2 = __float_as_uint(Qs[(wm + g    )*FS + kk + t4 + 4]);
            unsigned a3 = __float_as_uint(Qs[(wm + g + 8)*FS + kk + t4 + 4]);
            #pragma unroll
            for (int j = 0; j < 4; j++) {
                int key = wn + 8*j + g;
                unsigned b0 = __float_as_uint(Ks[key*FS + kk + t4    ]);
                unsigned b1 = __float_as_uint(Ks[key*FS + kk + t4 + 4]);
                mma8(s[j], a0, a1, a2, a3, b0, b1);
            }
        }
        // scatter S -> Ps
        #pragma unroll
        for (int j = 0; j < 4; j++) {
            int col = wn + 8*j + 2*t4;
            *(float2*)&Ps[(wm + g    )*FS + col] = make_float2(s[j][0], s[j][1]);
            *(float2*)&Ps[(wm + g + 8)*FS + col] = make_float2(s[j][2], s[j][3]);
        }
        __syncthreads();

        // ---- online softmax on Ps (thread owns 16 cols of row srow) ----
        {
            float p[16];
            #pragma unroll
            for (int u = 0; u < 4; u++)
                *(float4*)&p[4*u] = *(const float4*)&Ps[srow*FS + (tid & 3)*16 + 4*u];
            float tm = p[0];
            #pragma unroll
            for (int u = 1; u < 16; u++) tm = fmaxf(tm, p[u]);
            tm = fmaxf(tm, __shfl_xor_sync(0xffffffffu, tm, 1));
            tm = fmaxf(tm, __shfl_xor_sync(0xffffffffu, tm, 2));
            float mn = fmaxf(mrow, tm);
            float corr = __expf(mrow - mn);
            float ps = 0.f;
            #pragma unroll
            for (int u = 0; u < 16; u++) { p[u] = __expf(p[u] - mn); ps += p[u]; }
            ps += __shfl_xor_sync(0xffffffffu, ps, 1);
            ps += __shfl_xor_sync(0xffffffffu, ps, 2);
            lsum = lsum * corr + ps;
            mrow = mn;
            #pragma unroll
            for (int u = 0; u < 4; u++)
                *(float4*)&Ps[srow*FS + (tid & 3)*16 + 4*u] = *(const float4*)&p[4*u];
            if ((tid & 3) == 0) cr[srow] = corr;
        }
        __syncthreads();

        // ---- O = O*corr + P @ V (warp tile 16x32) ----
        float ca = cr[wm + g], cb = cr[wm + g + 8];
        #pragma unroll
        for (int j = 0; j < 4; j++) {
            o[j][0] *= ca; o[j][1] *= ca; o[j][2] *= cb; o[j][3] *= cb;
        }
        #pragma unroll
        for (int kk = 0; kk < 64; kk += 8) {
            unsigned a0 = __float_as_uint(Ps[(wm + g    )*FS + kk + t4    ]);
            unsigned a1 = __float_as_uint(Ps[(wm + g + 8)*FS + kk + t4    ]);
            unsigned a2 = __float_as_uint(Ps[(wm + g    )*FS + kk + t4 + 4]);
            unsigned a3 = __float_as_uint(Ps[(wm + g + 8)*FS + kk + t4 + 4]);
            #pragma unroll
            for (int j = 0; j < 4; j++) {
                int dcol = wn + 8*j + g;
                unsigned b0 = __float_as_uint(Vs[(kk + t4    )*FS + dcol]);
                unsigned b1 = __float_as_uint(Vs[(kk + t4 + 4)*FS + dcol]);
                mma8(o[j], a0, a1, a2, a3, b0, b1);
            }
        }
    }

    if ((tid & 3) == 0) li[srow] = 1.f / lsum;
    __syncthreads();
    float la = li[wm + g], lb = li[wm + g + 8];
    #pragma unroll
    for (int j = 0; j < 4; j++) {
        int col = wn + 8*j + 2*t4;
        *(float2*)(Ob + (size_t)(q0 + wm + g    )*DIMN + col) = make_float2(o[j][0]*la, o[j][1]*la);
        *(float2*)(Ob + (size_t)(q0 + wm + g + 8)*DIMN + col) = make_float2(o[j][2]*lb, o[j][3]*lb);
    }
}

// ---------------- fused: h=norm(xb); ha=norm(br); out = norm(h + |alpha*1.6|*(ha-h)) ----
__global__ __launch_bounds__(256) void residual_norm(const float* __restrict__ xb,
                                                     const float* __restrict__ br,
                                                     const float* __restrict__ alpha,
                                                     float* __restrict__ out) {
    int t = blockIdx.x;
    int tid = threadIdx.x;
    const float* xr = xb + (size_t)t * DIMN;
    const float* rr = br + (size_t)t * DIMN;
    float xv[4], bv[4];
    float ssx = 0.f, ssb = 0.f;
    #pragma unroll
    for (int u = 0; u < 4; u++) {
        int d = tid + u * 256;
        xv[u] = xr[d]; bv[u] = rr[d];
        ssx += xv[u] * xv[u]; ssb += bv[u] * bv[u];
    }
    ssx = blockSum256(ssx);
    ssb = blockSum256(ssb);
    float rx = 1.f / fmaxf(sqrtf(ssx), 1e-12f);
    float rb = 1.f / fmaxf(sqrtf(ssb), 1e-12f);
    float yv[4]; float ssy = 0.f;
    #pragma unroll
    for (int u = 0; u < 4; u++) {
        int d = tid + u * 256;
        float hh = xv[u] * rx;
        float ha = bv[u] * rb;
        float lr = fabsf(alpha[d] * 1.6f);
        float y = hh + lr * (ha - hh);
        yv[u] = y; ssy += y * y;
    }
    ssy = blockSum256(ssy);
    float ry = 1.f / fmaxf(sqrtf(ssy), 1e-12f);
    #pragma unroll
    for (int u = 0; u < 4; u++)
        out[(size_t)t * DIMN + tid + u * 256] = yv[u] * ry;
}

// ---------------- FFN gate: h1 = silu(h1*sv*sqrt(H)) * (h3*su) ----------------
__global__ void ffn_gate(float* __restrict__ h1, const float* __restrict__ h3,
                         const float* __restrict__ su, const float* __restrict__ sv) {
    const float SC = 53.06599664568481f;   // sqrt(2816)
    size_t n = (size_t)TOK * HIDDEN;
    size_t stride = (size_t)gridDim.x * blockDim.x;
    for (size_t i = (size_t)blockIdx.x * blockDim.x + threadIdx.x; i < n; i += stride) {
        int col = (int)(i % HIDDEN);
        float z = h1[i] * sv[col] * SC;
        float s = z / (1.f + __expf(-z));
        h1[i] = s * (h3[i] * su[col]);
    }
}

// ---------------- launch ----------------
extern "C" void kernel_launch(void* const* d_in, const int* in_sizes, int n_in,
                              void* d_out, int out_size) {
    const float* x      = (const float*)d_in[0];
    const float* fcos   = (const float*)d_in[1];
    const float* fsin   = (const float*)d_in[2];
    const float* adafm  = (const float*)d_in[3];
    const float* wq     = (const float*)d_in[4];
    const float* wk     = (const float*)d_in[5];
    const float* wv     = (const float*)d_in[6];
    const float* wo     = (const float*)d_in[7];
    const float* sqk    = (const float*)d_in[8];
    const float* w1     = (const float*)d_in[9];
    const float* w2     = (const float*)d_in[10];
    const float* w3     = (const float*)d_in[11];
    const float* su     = (const float*)d_in[12];
    const float* sv     = (const float*)d_in[13];
    const float* pw     = (const float*)d_in[14];
    const float* pb     = (const float*)d_in[15];
    const float* aalpha = (const float*)d_in[16];
    const float* malpha = (const float*)d_in[17];
    float* out = (float*)d_out;

    float *pt, *pgm, *pgf, *pxa, *pq, *pk, *pv, *pao, *ph1, *ph3;
    cudaGetSymbolAddress((void**)&pt,  d_t);
    cudaGetSymbolAddress((void**)&pgm, d_gm);
    cudaGetSymbolAddress((void**)&pgf, d_gf);
    cudaGetSymbolAddress((void**)&pxa, d_xa);
    cudaGetSymbolAddress((void**)&pq,  d_q);
    cudaGetSymbolAddress((void**)&pk,  d_k);
    cudaGetSymbolAddress((void**)&pv,  d_v);
    cudaGetSymbolAddress((void**)&pao, d_ao);
    cudaGetSymbolAddress((void**)&ph1, d_h1);
    cudaGetSymbolAddress((void**)&ph3, d_h3);

    cudaFuncSetAttribute(flash_attn, cudaFuncAttributeMaxDynamicSharedMemorySize, FLASH_SMEM);
    cudaFuncSetAttribute(gemm_tf32, cudaFuncAttributeMaxDynamicSharedMemorySize, GEMM_SMEM);

    // 1) time-modulation coefficients
    proj_t_kernel<<<BATCH, 512>>>(adafm, pw, pb, pt);
    make_g_kernel<<<4, 256>>>(pt, pgm, pgf);

    // 2) attention branch
    adafm_apply<<<dim3(DIMN/16, SEQL/16, BATCH), 256>>>(x, pgm, pxa);
    gemm_tf32<<<dim3(DIMN/256, TOK/128), 256, GEMM_SMEM>>>(pxa, wq, pq, TOK, DIMN, DIMN);
    gemm_tf32<<<dim3(DIMN/256, TOK/128), 256, GEMM_SMEM>>>(pxa, wk, pk, TOK, DIMN, DIMN);
    gemm_tf32<<<dim3(DIMN/256, TOK/128), 256, GEMM_SMEM>>>(pxa, wv, pv, TOK, DIMN, DIMN);
    rope_norm<<<TOK*NHEAD/8, 256>>>(pq, pk, fcos, fsin, sqk);
    flash_attn<<<dim3(SEQL/64, NHEAD, BATCH), 256, FLASH_SMEM>>>(pq, pk, pv, pao);
    gemm_tf32<<<dim3(DIMN/256, TOK/128), 256, GEMM_SMEM>>>(pao, wo, pxa, TOK, DIMN, DIMN);
    residual_norm<<<TOK, 256>>>(x, pxa, aalpha, pq);   // pq := x1

    // 3) FFN branch
    adafm_apply<<<dim3(DIMN/16, SEQL/16, BATCH), 256>>>(pq, pgf, pk);   // pk := xm
    gemm_tf32<<<dim3(HIDDEN/256, TOK/128), 256, GEMM_SMEM>>>(pk, w1, ph1, TOK, HIDDEN, DIMN);
    gemm_tf32<<<dim3(HIDDEN/256, TOK/128), 256, GEMM_SMEM>>>(pk, w3, ph3, TOK, HIDDEN, DIMN);
    ffn_gate<<<4096, 256>>>(ph1, ph3, su, sv);
    gemm_tf32<<<dim3(DIMN/256, TOK/128), 256, GEMM_SMEM>>>(ph1, w2, pv, TOK, DIMN, HIDDEN);
    residual_norm<<<TOK, 256>>>(pq, pv, malpha, out);
}

// round 4
// speedup vs baseline: 3.7479x; 1.5315x over previous
#include <cuda_runtime.h>
#include <cuda_bf16.h>
#include <math.h>

typedef __nv_bfloat16 bf16;

#define DIMN   1024
#define NHEAD  16
#define HDIM   64
#define SEQL   2048
#define BATCH  2
#define TOK    4096
#define HIDDEN 2816

// ---------------- scratch ----------------
__device__ float d_t [BATCH*512];
__device__ float d_gm[BATCH*256];
__device__ float d_gf[BATCH*256];
__device__ float d_f0[TOK*DIMN];            // fp32 scratch: q / x1
__device__ float d_f1[TOK*DIMN];            // fp32 scratch: k / mlp-out
__device__ float d_f2[TOK*DIMN];            // fp32 scratch: attn-out
__device__ float d_h1[(size_t)TOK*HIDDEN];
__device__ float d_h3[(size_t)TOK*HIDDEN];

__device__ bf16 b_wq[DIMN*DIMN], b_wk[DIMN*DIMN], b_wv[DIMN*DIMN], b_wo[DIMN*DIMN];
__device__ bf16 b_w1[DIMN*HIDDEN], b_w3[DIMN*HIDDEN], b_w2[HIDDEN*DIMN];
__device__ bf16 b_xa[TOK*DIMN];             // adafm out (attn), reused as xm (ffn)
__device__ bf16 b_q [TOK*DIMN], b_k[TOK*DIMN], b_v[TOK*DIMN], b_ao[TOK*DIMN];
__device__ bf16 b_h1[(size_t)TOK*HIDDEN];

// ---------------- helpers ----------------
__device__ __forceinline__ float blockSum256(float v) {
    __shared__ float red[8];
    int lane = threadIdx.x & 31, wid = threadIdx.x >> 5;
    #pragma unroll
    for (int o = 16; o > 0; o >>= 1) v += __shfl_xor_sync(0xffffffffu, v, o);
    __syncthreads();
    if (lane == 0) red[wid] = v;
    __syncthreads();
    float s = red[0];
    #pragma unroll
    for (int w = 1; w < 8; w++) s += red[w];
    return s;
}

__device__ __forceinline__ void mma16(float* c, unsigned a0, unsigned a1, unsigned a2, unsigned a3,
                                      unsigned b0, unsigned b1) {
    asm volatile(
        "mma.sync.aligned.m16n8k16.row.col.f32.bf16.bf16.f32 "
        "{%0,%1,%2,%3}, {%4,%5,%6,%7}, {%8,%9}, {%0,%1,%2,%3};"
        : "+f"(c[0]), "+f"(c[1]), "+f"(c[2]), "+f"(c[3])
        : "r"(a0), "r"(a1), "r"(a2), "r"(a3), "r"(b0), "r"(b1));
}

__device__ __forceinline__ void ldmx4(unsigned& r0, unsigned& r1, unsigned& r2, unsigned& r3, unsigned addr) {
    asm volatile("ldmatrix.sync.aligned.m8n8.x4.shared.b16 {%0,%1,%2,%3}, [%4];"
                 : "=r"(r0), "=r"(r1), "=r"(r2), "=r"(r3) : "r"(addr));
}
__device__ __forceinline__ void ldmx4t(unsigned& r0, unsigned& r1, unsigned& r2, unsigned& r3, unsigned addr) {
    asm volatile("ldmatrix.sync.aligned.m8n8.x4.trans.shared.b16 {%0,%1,%2,%3}, [%4];"
                 : "=r"(r0), "=r"(r1), "=r"(r2), "=r"(r3) : "r"(addr));
}
__device__ __forceinline__ void cpa16(unsigned s, const void* g) {
    asm volatile("cp.async.cg.shared.global [%0], [%1], 16;" :: "r"(s), "l"(g));
}
__device__ __forceinline__ unsigned pack_bf(float a, float b) {
    __nv_bfloat162 t;
    t.x = __float2bfloat16_rn(a);
    t.y = __float2bfloat16_rn(b);
    return *(unsigned*)&t;
}

// ---------------- fp32 -> bf16 bulk convert (n % 4 == 0) ----------------
__global__ void cvt4(const float* __restrict__ in, bf16* __restrict__ out, int n) {
    int i = (blockIdx.x * blockDim.x + threadIdx.x) * 4;
    if (i < n) {
        float4 v = *(const float4*)(in + i);
        uint2 o;
        o.x = pack_bf(v.x, v.y);
        o.y = pack_bf(v.z, v.w);
        *(uint2*)(out + i) = o;
    }
}

// ---------------- t = silu(adafm_input) @ proj_w + proj_b ----------------
__global__ void proj_t_kernel(const float* __restrict__ ad, const float* __restrict__ pw,
                              const float* __restrict__ pb, float* __restrict__ t) {
    int b = blockIdx.x;
    __shared__ float s[DIMN];
    for (int i = threadIdx.x; i < DIMN; i += blockDim.x) {
        float z = ad[b*DIMN + i];
        s[i] = z / (1.f + expf(-z));
    }
    __syncthreads();
    for (int o = threadIdx.x; o < 512; o += blockDim.x) {
        float acc = pb[o];
        #pragma unroll 4
        for (int i = 0; i < DIMN; i++) acc += s[i] * pw[i*512 + o];
        t[b*512 + o] = acc;
    }
}

// ---------------- g[d] = (1/256) sum_k m[k] cos(2*pi*k*d/256) ----------------
__global__ void make_g_kernel(const float* __restrict__ t,
                              float* __restrict__ gm, float* __restrict__ gf) {
    int b = blockIdx.x >> 1, which = blockIdx.x & 1;
    const float* m = t + b*512 + which*256;
    __shared__ float cs[256], ms[256];
    int d = threadIdx.x;
    cs[d] = cosf((6.283185307179586f / 256.0f) * (float)d);
    ms[d] = m[d];
    __syncthreads();
    float acc = 0.f;
    #pragma unroll 4
    for (int k = 0; k < 256; k++) acc += ms[k] * cs[(k*d) & 255];
    float* out = which ? gf : gm;
    out[b*256 + d] = acc * (1.0f / 256.0f);
}

// ---------------- per-patch 256-tap circular conv -> bf16 ----------------
__global__ __launch_bounds__(256) void adafm_apply(const float* __restrict__ x,
                                                   const float* __restrict__ g,
                                                   bf16* __restrict__ y) {
    int j = blockIdx.x, i = blockIdx.y, b = blockIdx.z;
    __shared__ float xs[256], gs[256];
    int t = threadIdx.x;
    const float* xb = x + ((size_t)b*SEQL + i*16) * DIMN + j*16;
    xs[t] = xb[(t >> 4) * DIMN + (t & 15)];
    gs[t] = g[b*256 + t];
    __syncthreads();
    float acc = 0.f;
    #pragma unroll 8
    for (int q0 = 0; q0 < 256; q0 += 4) {
        float4 xv = *(const float4*)&xs[q0];
        acc += xv.x * gs[(t - q0)     & 255];
        acc += xv.y * gs[(t - q0 - 1) & 255];
        acc += xv.z * gs[(t - q0 - 2) & 255];
        acc += xv.w * gs[(t - q0 - 3) & 255];
    }
    y[((size_t)b*SEQL + i*16 + (t >> 4)) * DIMN + j*16 + (t & 15)] = __float2bfloat16_rn(acc);
}

// ================= BF16 tensor-core GEMM, cp.async 3-stage, ldmatrix =================
// C[M,N] = A[M,K] @ B[K,N]; A,B bf16 row-major; M%128==0, N%256==0, K%32==0.
// Block tile 128x256x32, 8 warps (2m x 4n), warp tile 64x64, mma.m16n8k16.
#define AKE 40
#define BNE 264
#define A_ELT (128*AKE)
#define B_ELT (32*BNE)
#define STG_ELT (A_ELT + B_ELT)
#define GEMM_SMEM (3 * STG_ELT * 2)

__global__ __launch_bounds__(256, 1) void gemm_bf16(const bf16* __restrict__ A,
                                                    const bf16* __restrict__ B,
                                                    float* __restrict__ Cf,
                                                    bf16* __restrict__ Cb,
                                                    int M, int N, int K) {
    extern __shared__ bf16 smb[];
    const unsigned sbase = (unsigned)__cvta_generic_to_shared(smb);
    const int tid  = threadIdx.x;
    const int lane = tid & 31;
    const int warp = tid >> 5;
    const int g    = lane >> 2;
    const int t4   = lane & 3;
    const int lm   = lane & 15;
    const int lh   = lane >> 4;
    const int bm = blockIdx.y * 128;
    const int bn = blockIdx.x * 256;
    const int wm = (warp >> 2) * 64;
    const int wn = (warp & 3) * 64;

    float acc[4][8][4];
    #pragma unroll
    for (int i = 0; i < 4; i++)
        #pragma unroll
        for (int j = 0; j < 8; j++)
            #pragma unroll
            for (int r = 0; r < 4; r++) acc[i][j][r] = 0.f;

    const int ktiles = K >> 5;

    auto load_stage = [&](int st, int k0) {
        unsigned sa = sbase + (unsigned)(st * STG_ELT) * 2u;
        unsigned sb = sa + A_ELT * 2u;
        #pragma unroll
        for (int u = 0; u < 2; u++) {
            int c = tid + 256*u;
            int r = c >> 2, o = (c & 3) * 8;
            cpa16(sa + (unsigned)(r*AKE + o)*2u, A + (size_t)(bm + r) * K + k0 + o);
        }
        #pragma unroll
        for (int u = 0; u < 4; u++) {
            int c = tid + 256*u;
            int r = c >> 5, o = (c & 31) * 8;
            cpa16(sb + (unsigned)(r*BNE + o)*2u, B + (size_t)(k0 + r) * N + bn + o);
        }
    };

    load_stage(0, 0);
    asm volatile("cp.async.commit_group;");
    load_stage(1, 32);
    asm volatile("cp.async.commit_group;");

    for (int t = 0; t < ktiles; t++) {
        asm volatile("cp.async.wait_group 1;");
        __syncthreads();
        int nt = t + 2;
        if (nt < ktiles) load_stage(nt % 3, nt * 32);
        asm volatile("cp.async.commit_group;");

        unsigned sa = sbase + (unsigned)((t % 3) * STG_ELT) * 2u;
        unsigned sb = sa + A_ELT * 2u;

        #pragma unroll
        for (int kk = 0; kk < 32; kk += 16) {
            unsigned af[4][4], bfr[8][2];
            #pragma unroll
            for (int i = 0; i < 4; i++)
                ldmx4(af[i][0], af[i][1], af[i][2], af[i][3],
                      sa + (unsigned)((wm + 16*i + lm)*AKE + kk + lh*8)*2u);
            #pragma unroll
            for (int j2 = 0; j2 < 4; j2++)
                ldmx4t(bfr[2*j2][0], bfr[2*j2][1], bfr[2*j2+1][0], bfr[2*j2+1][1],
                       sb + (unsigned)((kk + lm)*BNE + wn + 16*j2 + lh*8)*2u);
            #pragma unroll
            for (int i = 0; i < 4; i++)
                #pragma unroll
                for (int j = 0; j < 8; j++)
                    mma16(acc[i][j], af[i][0], af[i][1], af[i][2], af[i][3],
                          bfr[j][0], bfr[j][1]);
        }
    }

    #pragma unroll
    for (int i = 0; i < 4; i++) {
        int row0 = bm + wm + 16*i + g;
        #pragma unroll
        for (int j = 0; j < 8; j++) {
            int col = bn + wn + 8*j + 2*t4;
            if (Cf) {
                *(float2*)(Cf + (size_t)row0 * N + col)       = make_float2(acc[i][j][0], acc[i][j][1]);
                *(float2*)(Cf + (size_t)(row0 + 8) * N + col) = make_float2(acc[i][j][2], acc[i][j][3]);
            }
            if (Cb) {
                *(unsigned*)(Cb + (size_t)row0 * N + col)       = pack_bf(acc[i][j][0], acc[i][j][1]);
                *(unsigned*)(Cb + (size_t)(row0 + 8) * N + col) = pack_bf(acc[i][j][2], acc[i][j][3]);
            }
        }
    }
}

// ---------------- rotary + justnorm + sqk_eff; fp32 in -> bf16 out (Q pre-scaled x8) ---
__global__ __launch_bounds__(256) void rope_norm(const float* __restrict__ Q, const float* __restrict__ K,
                                                 bf16* __restrict__ Qo, bf16* __restrict__ Ko,
                                                 const float* __restrict__ fcos,
                                                 const float* __restrict__ fsin,
                                                 const float* __restrict__ sqk) {
    int w = blockIdx.x * 8 + (threadIdx.x >> 5);
    int lane = threadIdx.x & 31;
    int tok = w >> 4;
    int h = w & 15;
    int s = tok & (SEQL - 1);
    float c  = fcos[s*32 + lane];
    float sn = fsin[s*32 + lane];
    size_t base = (size_t)tok * DIMN + h * HDIM + 2 * lane;
    float se0 = sqk[h*HDIM + 2*lane]     * 32.f;
    float se1 = sqk[h*HDIM + 2*lane + 1] * 32.f;

    {
        float2 qv = *(const float2*)(Q + base);
        float ra = qv.x * c - qv.y * sn;
        float rb = qv.x * sn + qv.y * c;
        float ss = ra*ra + rb*rb;
        #pragma unroll
        for (int o = 16; o > 0; o >>= 1) ss += __shfl_xor_sync(0xffffffffu, ss, o);
        float inv = 8.f / fmaxf(sqrtf(ss), 1e-12f);    // x8 score scale folded in
        *(unsigned*)(Qo + base) = pack_bf(ra * inv * se0, rb * inv * se1);
    }
    {
        float2 kv = *(const float2*)(K + base);
        float ra = kv.x * c - kv.y * sn;
        float rb = kv.x * sn + kv.y * c;
        float ss = ra*ra + rb*rb;
        #pragma unroll
        for (int o = 16; o > 0; o >>= 1) ss += __shfl_xor_sync(0xffffffffu, ss, o);
        float inv = 1.f / fmaxf(sqrtf(ss), 1e-12f);
        *(unsigned*)(Ko + base) = pack_bf(ra * inv * se0, rb * inv * se1);
    }
}

// ---------------- flash attention, bf16 mma, fp32 softmax ----------------
#define FSE 72
#define FSS 68
#define FLASH_SMEM (4*64*FSE*2 + 64*FSS*4 + 512)

__global__ __launch_bounds__(256) void flash_attn(const bf16* __restrict__ Q,
                                                  const bf16* __restrict__ K,
                                                  const bf16* __restrict__ V,
                                                  bf16* __restrict__ O) {
    extern __shared__ char fsm[];
    bf16* Qs = (bf16*)fsm;
    bf16* Ks = Qs + 64*FSE;
    bf16* Vs = Ks + 64*FSE;
    bf16* Ps = Vs + 64*FSE;
    float* Ss = (float*)(fsm + 4*64*FSE*2);
    float* cr = Ss + 64*FSS;
    float* li = cr + 64;
    const unsigned sQ = (unsigned)__cvta_generic_to_shared(Qs);
    const unsigned sK = (unsigned)__cvta_generic_to_shared(Ks);
    const unsigned sV = (unsigned)__cvta_generic_to_shared(Vs);
    const unsigned sP = (unsigned)__cvta_generic_to_shared(Ps);

    const int q0 = blockIdx.x * 64;
    const int h  = blockIdx.y;
    const int b  = blockIdx.z;
    const bf16* Qb = Q + (size_t)b*SEQL*DIMN + h*HDIM;
    const bf16* Kb = K + (size_t)b*SEQL*DIMN + h*HDIM;
    const bf16* Vb = V + (size_t)b*SEQL*DIMN + h*HDIM;
    bf16*       Ob = O + (size_t)b*SEQL*DIMN + h*HDIM;

    const int tid  = threadIdx.x;
    const int lane = tid & 31;
    const int warp = tid >> 5;
    const int g  = lane >> 2;
    const int t4 = lane & 3;
    const int lm = lane & 15;
    const int lh = lane >> 4;
    const int wm = (warp >> 1) * 16;
    const int wn = (warp & 1) * 32;

    // Q tile load (2 chunks of 8 bf16 per thread)
    #pragma unroll
    for (int u = 0; u < 2; u++) {
        int c = tid + 256*u;
        int r = c >> 3, o = (c & 7) * 8;
        *(uint4*)&Qs[r*FSE + o] = *(const uint4*)(Qb + (size_t)(q0 + r)*DIMN + o);
    }

    float o[4][4];
    #pragma unroll
    for (int j = 0; j < 4; j++)
        #pragma unroll
        for (int r = 0; r < 4; r++) o[j][r] = 0.f;

    const int srow = tid >> 2;
    float mrow = -1e30f, lsum = 0.f;

    for (int k0 = 0; k0 < SEQL; k0 += 64) {
        __syncthreads();
        #pragma unroll
        for (int u = 0; u < 2; u++) {
            int c = tid + 256*u;
            int r = c >> 3, ofs = (c & 7) * 8;
            *(uint4*)&Ks[r*FSE + ofs] = *(const uint4*)(Kb + (size_t)(k0 + r)*DIMN + ofs);
            *(uint4*)&Vs[r*FSE + ofs] = *(const uint4*)(Vb + (size_t)(k0 + r)*DIMN + ofs);
        }
        __syncthreads();

        // ---- S = Q @ K^T : warp tile 16q x 32key ----
        float s[4][4];
        #pragma unroll
        for (int j = 0; j < 4; j++)
            #pragma unroll
            for (int r = 0; r < 4; r++) s[j][r] = 0.f;

        #pragma unroll
        for (int kk = 0; kk < HDIM; kk += 16) {
            unsigned a0, a1, a2, a3;
            ldmx4(a0, a1, a2, a3, sQ + (unsigned)((wm + lm)*FSE + kk + lh*8)*2u);
            #pragma unroll
            for (int j2 = 0; j2 < 2; j2++) {
                int n0 = wn + 16*j2;
                unsigned r0, r1, r2, r3;
                // non-trans: key rows supply B fragments directly (k contiguous)
                ldmx4(r0, r1, r2, r3,
                      sK + (unsigned)((n0 + (lane & 7) + ((lane >> 4) << 3))*FSE
                                       + kk + (((lane >> 3) & 1) << 3))*2u);
                mma16(s[2*j2],     a0, a1, a2, a3, r0, r1);
                mma16(s[2*j2 + 1], a0, a1, a2, a3, r2, r3);
            }
        }
        // scatter S -> Ss (fp32)
        #pragma unroll
        for (int j = 0; j < 4; j++) {
            int col = wn + 8*j + 2*t4;
            *(float2*)&Ss[(wm + g    )*FSS + col] = make_float2(s[j][0], s[j][1]);
            *(float2*)&Ss[(wm + g + 8)*FSS + col] = make_float2(s[j][2], s[j][3]);
        }
        __syncthreads();

        // ---- online softmax: thread owns 16 cols of row srow ----
        {
            float p[16];
            #pragma unroll
            for (int u = 0; u < 4; u++)
                *(float4*)&p[4*u] = *(const float4*)&Ss[srow*FSS + t4*16 + 4*u];
            float tm = p[0];
            #pragma unroll
            for (int u = 1; u < 16; u++) tm = fmaxf(tm, p[u]);
            tm = fmaxf(tm, __shfl_xor_sync(0xffffffffu, tm, 1));
            tm = fmaxf(tm, __shfl_xor_sync(0xffffffffu, tm, 2));
            float mn = fmaxf(mrow, tm);
            float corr = __expf(mrow - mn);
            float ps = 0.f;
            #pragma unroll
            for (int u = 0; u < 16; u++) { p[u] = __expf(p[u] - mn); ps += p[u]; }
            ps += __shfl_xor_sync(0xffffffffu, ps, 1);
            ps += __shfl_xor_sync(0xffffffffu, ps, 2);
            lsum = lsum * corr + ps;
            mrow = mn;
            #pragma unroll
            for (int u = 0; u < 8; u++)
                *(unsigned*)&Ps[srow*FSE + t4*16 + 2*u] = pack_bf(p[2*u], p[2*u+1]);
            if (t4 == 0) cr[srow] = corr;
        }
        __syncthreads();

        // ---- O = O*corr + P @ V : warp tile 16q x 32d ----
        float ca = cr[wm + g], cb = cr[wm + g + 8];
        #pragma unroll
        for (int j = 0; j < 4; j++) {
            o[j][0] *= ca; o[j][1] *= ca; o[j][2] *= cb; o[j][3] *= cb;
        }
        #pragma unroll
        for (int kk = 0; kk < 64; kk += 16) {
            unsigned a0, a1, a2, a3;
            ldmx4(a0, a1, a2, a3, sP + (unsigned)((wm + lm)*FSE + kk + lh*8)*2u);
            #pragma unroll
            for (int j2 = 0; j2 < 2; j2++) {
                int n0 = wn + 16*j2;
                unsigned r0, r1, r2, r3;
                ldmx4t(r0, r1, r2, r3,
                       sV + (unsigned)((kk + lm)*FSE + n0 + lh*8)*2u);
                mma16(o[2*j2],     a0, a1, a2, a3, r0, r1);
                mma16(o[2*j2 + 1], a0, a1, a2, a3, r2, r3);
            }
        }
    }

    if (t4 == 0) li[srow] = 1.f / lsum;
    __syncthreads();
    float la = li[wm + g], lb = li[wm + g + 8];
    #pragma unroll
    for (int j = 0; j < 4; j++) {
        int col = wn + 8*j + 2*t4;
        *(unsigned*)(Ob + (size_t)(q0 + wm + g    )*DIMN + col) = pack_bf(o[j][0]*la, o[j][1]*la);
        *(unsigned*)(Ob + (size_t)(q0 + wm + g + 8)*DIMN + col) = pack_bf(o[j][2]*lb, o[j][3]*lb);
    }
}

// ---------------- fused residual + norms (fp32) ----------------
__global__ __launch_bounds__(256) void residual_norm(const float* __restrict__ xb,
                                                     const float* __restrict__ br,
                                                     const float* __restrict__ alpha,
                                                     float* __restrict__ out) {
    int t = blockIdx.x;
    int tid = threadIdx.x;
    const float* xr = xb + (size_t)t * DIMN;
    const float* rr = br + (size_t)t * DIMN;
    float xv[4], bv[4];
    float ssx = 0.f, ssb = 0.f;
    #pragma unroll
    for (int u = 0; u < 4; u++) {
        int d = tid + u * 256;
        xv[u] = xr[d]; bv[u] = rr[d];
        ssx += xv[u] * xv[u]; ssb += bv[u] * bv[u];
    }
    ssx = blockSum256(ssx);
    ssb = blockSum256(ssb);
    float rx = 1.f / fmaxf(sqrtf(ssx), 1e-12f);
    float rb = 1.f / fmaxf(sqrtf(ssb), 1e-12f);
    float yv[4]; float ssy = 0.f;
    #pragma unroll
    for (int u = 0; u < 4; u++) {
        int d = tid + u * 256;
        float hh = xv[u] * rx;
        float ha = bv[u] * rb;
        float lr = fabsf(alpha[d] * 1.6f);
        float y = hh + lr * (ha - hh);
        yv[u] = y; ssy += y * y;
    }
    ssy = blockSum256(ssy);
    float ry = 1.f / fmaxf(sqrtf(ssy), 1e-12f);
    #pragma unroll
    for (int u = 0; u < 4; u++)
        out[(size_t)t * DIMN + tid + u * 256] = yv[u] * ry;
}

// ---------------- FFN gate -> bf16 ----------------
__global__ void ffn_gate(const float* __restrict__ h1, const float* __restrict__ h3,
                         bf16* __restrict__ ob,
                         const float* __restrict__ su, const float* __restrict__ sv) {
    const float SC = 53.06599664568481f;   // sqrt(2816)
    size_t np = (size_t)TOK * HIDDEN / 2;
    size_t stride = (size_t)gridDim.x * blockDim.x;
    for (size_t i = (size_t)blockIdx.x * blockDim.x + threadIdx.x; i < np; i += stride) {
        size_t idx = i * 2;
        int col = (int)(idx % HIDDEN);
        float2 a = *(const float2*)(h1 + idx);
        float2 bb = *(const float2*)(h3 + idx);
        float z0 = a.x * sv[col]   * SC;
        float z1 = a.y * sv[col+1] * SC;
        float s0 = z0 / (1.f + __expf(-z0));
        float s1 = z1 / (1.f + __expf(-z1));
        *(unsigned*)(ob + idx) = pack_bf(s0 * (bb.x * su[col]), s1 * (bb.y * su[col+1]));
    }
}

// ---------------- launch ----------------
extern "C" void kernel_launch(void* const* d_in, const int* in_sizes, int n_in,
                              void* d_out, int out_size) {
    const float* x      = (const float*)d_in[0];
    const float* fcos   = (const float*)d_in[1];
    const float* fsin   = (const float*)d_in[2];
    const float* adafm  = (const float*)d_in[3];
    const float* wq     = (const float*)d_in[4];
    const float* wk     = (const float*)d_in[5];
    const float* wv     = (const float*)d_in[6];
    const float* wo     = (const float*)d_in[7];
    const float* sqk    = (const float*)d_in[8];
    const float* w1     = (const float*)d_in[9];
    const float* w2     = (const float*)d_in[10];
    const float* w3     = (const float*)d_in[11];
    const float* su     = (const float*)d_in[12];
    const float* sv     = (const float*)d_in[13];
    const float* pw     = (const float*)d_in[14];
    const float* pb     = (const float*)d_in[15];
    const float* aalpha = (const float*)d_in[16];
    const float* malpha = (const float*)d_in[17];
    float* out = (float*)d_out;

    float *pt, *pgm, *pgf, *pf0, *pf1, *pf2, *ph1, *ph3;
    bf16 *pbwq, *pbwk, *pbwv, *pbwo, *pbw1, *pbw3, *pbw2;
    bf16 *pbxa, *pbq, *pbk, *pbv, *pbao, *pbh1;
    cudaGetSymbolAddress((void**)&pt,  d_t);
    cudaGetSymbolAddress((void**)&pgm, d_gm);
    cudaGetSymbolAddress((void**)&pgf, d_gf);
    cudaGetSymbolAddress((void**)&pf0, d_f0);
    cudaGetSymbolAddress((void**)&pf1, d_f1);
    cudaGetSymbolAddress((void**)&pf2, d_f2);
    cudaGetSymbolAddress((void**)&ph1, d_h1);
    cudaGetSymbolAddress((void**)&ph3, d_h3);
    cudaGetSymbolAddress((void**)&pbwq, b_wq);
    cudaGetSymbolAddress((void**)&pbwk, b_wk);
    cudaGetSymbolAddress((void**)&pbwv, b_wv);
    cudaGetSymbolAddress((void**)&pbwo, b_wo);
    cudaGetSymbolAddress((void**)&pbw1, b_w1);
    cudaGetSymbolAddress((void**)&pbw3, b_w3);
    cudaGetSymbolAddress((void**)&pbw2, b_w2);
    cudaGetSymbolAddress((void**)&pbxa, b_xa);
    cudaGetSymbolAddress((void**)&pbq,  b_q);
    cudaGetSymbolAddress((void**)&pbk,  b_k);
    cudaGetSymbolAddress((void**)&pbv,  b_v);
    cudaGetSymbolAddress((void**)&pbao, b_ao);
    cudaGetSymbolAddress((void**)&pbh1, b_h1);

    cudaFuncSetAttribute(flash_attn, cudaFuncAttributeMaxDynamicSharedMemorySize, FLASH_SMEM);
    cudaFuncSetAttribute(gemm_bf16, cudaFuncAttributeMaxDynamicSharedMemorySize, GEMM_SMEM);

    // 0) weight conversions
    cvt4<<<DIMN*DIMN/1024, 256>>>(wq, pbwq, DIMN*DIMN);
    cvt4<<<DIMN*DIMN/1024, 256>>>(wk, pbwk, DIMN*DIMN);
    cvt4<<<DIMN*DIMN/1024, 256>>>(wv, pbwv, DIMN*DIMN);
    cvt4<<<DIMN*DIMN/1024, 256>>>(wo, pbwo, DIMN*DIMN);
    cvt4<<<DIMN*HIDDEN/1024, 256>>>(w1, pbw1, DIMN*HIDDEN);
    cvt4<<<DIMN*HIDDEN/1024, 256>>>(w3, pbw3, DIMN*HIDDEN);
    cvt4<<<DIMN*HIDDEN/1024, 256>>>(w2, pbw2, HIDDEN*DIMN);

    // 1) time-modulation coefficients
    proj_t_kernel<<<BATCH, 512>>>(adafm, pw, pb, pt);
    make_g_kernel<<<4, 256>>>(pt, pgm, pgf);

    // 2) attention branch
    adafm_apply<<<dim3(DIMN/16, SEQL/16, BATCH), 256>>>(x, pgm, pbxa);
    gemm_bf16<<<dim3(DIMN/256, TOK/128), 256, GEMM_SMEM>>>(pbxa, pbwq, pf0, (bf16*)0, TOK, DIMN, DIMN);
    gemm_bf16<<<dim3(DIMN/256, TOK/128), 256, GEMM_SMEM>>>(pbxa, pbwk, pf1, (bf16*)0, TOK, DIMN, DIMN);
    gemm_bf16<<<dim3(DIMN/256, TOK/128), 256, GEMM_SMEM>>>(pbxa, pbwv, (float*)0, pbv, TOK, DIMN, DIMN);
    rope_norm<<<TOK*NHEAD/8, 256>>>(pf0, pf1, pbq, pbk, fcos, fsin, sqk);
    flash_attn<<<dim3(SEQL/64, NHEAD, BATCH), 256, FLASH_SMEM>>>(pbq, pbk, pbv, pbao);
    gemm_bf16<<<dim3(DIMN/256, TOK/128), 256, GEMM_SMEM>>>(pbao, pbwo, pf2, (bf16*)0, TOK, DIMN, DIMN);
    residual_norm<<<TOK, 256>>>(x, pf2, aalpha, pf0);   // pf0 := x1

    // 3) FFN branch
    adafm_apply<<<dim3(DIMN/16, SEQL/16, BATCH), 256>>>(pf0, pgf, pbxa);   // xm
    gemm_bf16<<<dim3(HIDDEN/256, TOK/128), 256, GEMM_SMEM>>>(pbxa, pbw1, ph1, (bf16*)0, TOK, HIDDEN, DIMN);
    gemm_bf16<<<dim3(HIDDEN/256, TOK/128), 256, GEMM_SMEM>>>(pbxa, pbw3, ph3, (bf16*)0, TOK, HIDDEN, DIMN);
    ffn_gate<<<4096, 256>>>(ph1, ph3, pbh1, su, sv);
    gemm_bf16<<<dim3(DIMN/256, TOK/128), 256, GEMM_SMEM>>>(pbh1, pbw2, pf1, (bf16*)0, TOK, DIMN, HIDDEN);
    residual_norm<<<TOK, 256>>>(pf0, pf1, malpha, out);
}

// round 5
// speedup vs baseline: 5.3182x; 1.4190x over previous
#include <cuda_runtime.h>
#include <cuda_bf16.h>
#include <math.h>

typedef __nv_bfloat16 bf16;

#define DIMN   1024
#define NHEAD  16
#define HDIM   64
#define SEQL   2048
#define BATCH  2
#define TOK    4096
#define HIDDEN 2816

// ---------------- scratch ----------------
__device__ float d_t [BATCH*512];
__device__ float d_f0[TOK*DIMN];            // x1
__device__ float d_f1[TOK*DIMN];            // mlp out
__device__ float d_f2[TOK*DIMN];            // attn out

__device__ bf16 b_wq[DIMN*DIMN], b_wk[DIMN*DIMN], b_wv[DIMN*DIMN], b_wo[DIMN*DIMN];
__device__ bf16 b_w1[DIMN*HIDDEN], b_w3[DIMN*HIDDEN], b_w2[HIDDEN*DIMN];
__device__ bf16 b_xp[BATCH*8192*256];       // patchified input
__device__ bf16 b_gm[BATCH*256*256];        // conv matrix, attn branch
__device__ bf16 b_gf[BATCH*256*256];        // conv matrix, mlp branch
__device__ bf16 b_xa[TOK*DIMN];             // adafm out
__device__ bf16 b_q [TOK*DIMN], b_k[TOK*DIMN], b_v[TOK*DIMN], b_ao[TOK*DIMN];
__device__ bf16 b_h1[(size_t)TOK*HIDDEN];
__device__ bf16 b_h3[(size_t)TOK*HIDDEN];

// ---------------- helpers ----------------
__device__ __forceinline__ float blockSum256(float v) {
    __shared__ float red[8];
    int lane = threadIdx.x & 31, wid = threadIdx.x >> 5;
    #pragma unroll
    for (int o = 16; o > 0; o >>= 1) v += __shfl_xor_sync(0xffffffffu, v, o);
    __syncthreads();
    if (lane == 0) red[wid] = v;
    __syncthreads();
    float s = red[0];
    #pragma unroll
    for (int w = 1; w < 8; w++) s += red[w];
    return s;
}

__device__ __forceinline__ void mma16(float* c, unsigned a0, unsigned a1, unsigned a2, unsigned a3,
                                      unsigned b0, unsigned b1) {
    asm volatile(
        "mma.sync.aligned.m16n8k16.row.col.f32.bf16.bf16.f32 "
        "{%0,%1,%2,%3}, {%4,%5,%6,%7}, {%8,%9}, {%0,%1,%2,%3};"
        : "+f"(c[0]), "+f"(c[1]), "+f"(c[2]), "+f"(c[3])
        : "r"(a0), "r"(a1), "r"(a2), "r"(a3), "r"(b0), "r"(b1));
}
__device__ __forceinline__ void ldmx4(unsigned& r0, unsigned& r1, unsigned& r2, unsigned& r3, unsigned addr) {
    asm volatile("ldmatrix.sync.aligned.m8n8.x4.shared.b16 {%0,%1,%2,%3}, [%4];"
                 : "=r"(r0), "=r"(r1), "=r"(r2), "=r"(r3) : "r"(addr));
}
__device__ __forceinline__ void ldmx4t(unsigned& r0, unsigned& r1, unsigned& r2, unsigned& r3, unsigned addr) {
    asm volatile("ldmatrix.sync.aligned.m8n8.x4.trans.shared.b16 {%0,%1,%2,%3}, [%4];"
                 : "=r"(r0), "=r"(r1), "=r"(r2), "=r"(r3) : "r"(addr));
}
__device__ __forceinline__ void cpa16(unsigned s, const void* g) {
    asm volatile("cp.async.cg.shared.global [%0], [%1], 16;" :: "r"(s), "l"(g));
}
__device__ __forceinline__ unsigned pack_bf(float a, float b) {
    __nv_bfloat162 t;
    t.x = __float2bfloat16_rn(a);
    t.y = __float2bfloat16_rn(b);
    return *(unsigned*)&t;
}
__device__ __forceinline__ float2 unpack_bf(unsigned u) {
    __nv_bfloat162 t = *(__nv_bfloat162*)&u;
    return make_float2(__bfloat162float(t.x), __bfloat162float(t.y));
}

// ---------------- all weight conversions in one kernel ----------------
__global__ void cvt_all(const float* __restrict__ s0, const float* __restrict__ s1,
                        const float* __restrict__ s2, const float* __restrict__ s3,
                        const float* __restrict__ s4, const float* __restrict__ s5,
                        const float* __restrict__ s6) {
    int w = blockIdx.y;
    const float* src; bf16* dst; int n;
    switch (w) {
        case 0: src = s0; dst = b_wq; n = DIMN*DIMN; break;
        case 1: src = s1; dst = b_wk; n = DIMN*DIMN; break;
        case 2: src = s2; dst = b_wv; n = DIMN*DIMN; break;
        case 3: src = s3; dst = b_wo; n = DIMN*DIMN; break;
        case 4: src = s4; dst = b_w1; n = DIMN*HIDDEN; break;
        case 5: src = s5; dst = b_w3; n = DIMN*HIDDEN; break;
        default: src = s6; dst = b_w2; n = HIDDEN*DIMN; break;
    }
    int i = (blockIdx.x * 256 + threadIdx.x) * 8;
    if (i < n) {
        float4 a = *(const float4*)(src + i);
        float4 b = *(const float4*)(src + i + 4);
        uint4 o;
        o.x = pack_bf(a.x, a.y); o.y = pack_bf(a.z, a.w);
        o.z = pack_bf(b.x, b.y); o.w = pack_bf(b.z, b.w);
        *(uint4*)(dst + i) = o;
    }
}

// ---------------- t = silu(adafm_input) @ proj_w + proj_b ----------------
__global__ void proj_t_kernel(const float* __restrict__ ad, const float* __restrict__ pw,
                              const float* __restrict__ pb, float* __restrict__ t) {
    int b = blockIdx.x;
    __shared__ float s[DIMN];
    for (int i = threadIdx.x; i < DIMN; i += blockDim.x) {
        float z = ad[b*DIMN + i];
        s[i] = z / (1.f + expf(-z));
    }
    __syncthreads();
    for (int o = threadIdx.x; o < 512; o += blockDim.x) {
        float acc = pb[o];
        #pragma unroll 4
        for (int i = 0; i < DIMN; i++) acc += s[i] * pw[i*512 + o];
        t[b*512 + o] = acc;
    }
}

// --------- g[d] = (1/256) sum_k m[k] cos(2 pi k d/256); emit Bg[q][t]=g[(t-q)&255] -----
__global__ void make_g_kernel(const float* __restrict__ t) {
    int b = blockIdx.x >> 1, which = blockIdx.x & 1;
    const float* m = t + b*512 + which*256;
    __shared__ float cs[256], ms[256];
    __shared__ bf16 gd[512];
    int d = threadIdx.x;
    cs[d] = cosf((6.283185307179586f / 256.0f) * (float)d);
    ms[d] = m[d];
    __syncthreads();
    float acc = 0.f;
    #pragma unroll 4
    for (int k = 0; k < 256; k++) acc += ms[k] * cs[(k*d) & 255];
    bf16 gv = __float2bfloat16_rn(acc * (1.0f / 256.0f));
    gd[d] = gv; gd[d + 256] = gv;
    __syncthreads();
    bf16* Bg = (which ? b_gf : b_gm) + b * 65536;
    int q = d;
    for (int tt = 0; tt < 256; tt++)
        Bg[q*256 + tt] = gd[tt - q + 256];
}

// ---------------- patchify: x fp32 [B,SEQ,DIM] -> Xp bf16 [B, 8192, 256] ----------------
__global__ void patchify(const float* __restrict__ x) {
    int c = blockIdx.x * 256 + threadIdx.x;           // 8-elem chunk id, total 524288
    int q  = (c & 31) * 8;
    int pi = (c >> 5) & 8191;
    int b  = c >> 18;
    int p = q >> 4, qq = q & 15;
    const float* src = x + ((size_t)(b*2048 + (pi >> 6)*16 + p)) * DIMN + (pi & 63)*16 + qq;
    float4 a = *(const float4*)src;
    float4 v = *(const float4*)(src + 4);
    uint4 o;
    o.x = pack_bf(a.x, a.y); o.y = pack_bf(a.z, a.w);
    o.z = pack_bf(v.x, v.y); o.w = pack_bf(v.z, v.w);
    *(uint4*)(b_xp + (size_t)c * 8) = o;
}

// ================= GEMM core macro pieces (block 128x256x32, 8 warps) =================
#define AKE 40
#define BNE 264
#define A_ELT (128*AKE)
#define B_ELT (32*BNE)
#define STG_ELT (A_ELT + B_ELT)
#define GEMM_SMEM (3 * STG_ELT * 2)

#define GEMM_PROLOG(Aptr, Bptr, Kdim, Ndim, bmv, bnv)                                    \
    extern __shared__ bf16 smb[];                                                        \
    const unsigned sbase = (unsigned)__cvta_generic_to_shared(smb);                      \
    const int tid  = threadIdx.x;                                                        \
    const int lane = tid & 31;                                                           \
    const int warp = tid >> 5;                                                           \
    const int g    = lane >> 2;                                                          \
    const int t4   = lane & 3;                                                           \
    const int lm   = lane & 15;                                                          \
    const int lh   = lane >> 4;                                                          \
    const int wm = (warp >> 2) * 64;                                                     \
    const int wn = (warp & 3) * 64;                                                      \
    float acc[4][8][4];                                                                  \
    _Pragma("unroll") for (int i = 0; i < 4; i++)                                        \
        _Pragma("unroll") for (int j = 0; j < 8; j++)                                    \
            _Pragma("unroll") for (int r = 0; r < 4; r++) acc[i][j][r] = 0.f;            \
    const int ktiles = (Kdim) >> 5;                                                      \
    auto load_stage = [&](int st, int k0) {                                              \
        unsigned sa = sbase + (unsigned)(st * STG_ELT) * 2u;                             \
        unsigned sb = sa + A_ELT * 2u;                                                   \
        _Pragma("unroll") for (int u = 0; u < 2; u++) {                                  \
            int c = tid + 256*u;                                                         \
            int r = c >> 2, o = (c & 3) * 8;                                             \
            cpa16(sa + (unsigned)(r*AKE + o)*2u, (Aptr) + (size_t)((bmv) + r) * (Kdim) + k0 + o); \
        }                                                                                \
        _Pragma("unroll") for (int u = 0; u < 4; u++) {                                  \
            int c = tid + 256*u;                                                         \
            int r = c >> 5, o = (c & 31) * 8;                                            \
            cpa16(sb + (unsigned)(r*BNE + o)*2u, (Bptr) + (size_t)(k0 + r) * (Ndim) + (bnv) + o); \
        }                                                                                \
    };                                                                                   \
    load_stage(0, 0);                                                                    \
    asm volatile("cp.async.commit_group;");                                              \
    load_stage(1, 32);                                                                   \
    asm volatile("cp.async.commit_group;");                                              \
    for (int t = 0; t < ktiles; t++) {                                                   \
        asm volatile("cp.async.wait_group 1;");                                          \
        __syncthreads();                                                                 \
        int nt = t + 2;                                                                  \
        if (nt < ktiles) load_stage(nt % 3, nt * 32);                                    \
        asm volatile("cp.async.commit_group;");                                          \
        unsigned sa = sbase + (unsigned)((t % 3) * STG_ELT) * 2u;                        \
        unsigned sb = sa + A_ELT * 2u;                                                   \
        _Pragma("unroll") for (int kk = 0; kk < 32; kk += 16) {                          \
            unsigned af[4][4], bfr[8][2];                                                \
            _Pragma("unroll") for (int i = 0; i < 4; i++)                                \
                ldmx4(af[i][0], af[i][1], af[i][2], af[i][3],                            \
                      sa + (unsigned)((wm + 16*i + lm)*AKE + kk + lh*8)*2u);             \
            _Pragma("unroll") for (int j2 = 0; j2 < 4; j2++)                             \
                ldmx4t(bfr[2*j2][0], bfr[2*j2][1], bfr[2*j2+1][0], bfr[2*j2+1][1],       \
                       sb + (unsigned)((kk + lm)*BNE + wn + 16*j2 + lh*8)*2u);           \
            _Pragma("unroll") for (int i = 0; i < 4; i++)                                \
                _Pragma("unroll") for (int j = 0; j < 8; j++)                            \
                    mma16(acc[i][j], af[i][0], af[i][1], af[i][2], af[i][3],             \
                          bfr[j][0], bfr[j][1]);                                         \
        }                                                                                \
    }

// ---- generic gemm, fp32 out ----
__global__ __launch_bounds__(256, 1) void gemm_bf16(const bf16* __restrict__ A,
                                                    const bf16* __restrict__ B,
                                                    float* __restrict__ Cf,
                                                    int M, int N, int K) {
    const int bm = blockIdx.y * 128;
    const int bn = blockIdx.x * 256;
    GEMM_PROLOG(A, B, K, N, bm, bn)
    #pragma unroll
    for (int i = 0; i < 4; i++) {
        int row0 = bm + wm + 16*i + g;
        #pragma unroll
        for (int j = 0; j < 8; j++) {
            int col = bn + wn + 8*j + 2*t4;
            *(float2*)(Cf + (size_t)row0 * N + col)       = make_float2(acc[i][j][0], acc[i][j][1]);
            *(float2*)(Cf + (size_t)(row0 + 8) * N + col) = make_float2(acc[i][j][2], acc[i][j][3]);
        }
    }
}

// ---- fused QKV gemm, bf16 outs ----
__global__ __launch_bounds__(256, 1) void gemm_qkv(const bf16* __restrict__ A) {
    const int wsel = blockIdx.x >> 2;
    const int bn = (blockIdx.x & 3) * 256;
    const int bm = blockIdx.y * 128;
    const bf16* B = (wsel == 0) ? b_wq : ((wsel == 1) ? b_wk : b_wv);
    bf16* C = (wsel == 0) ? b_q : ((wsel == 1) ? b_k : b_v);
    GEMM_PROLOG(A, B, DIMN, DIMN, bm, bn)
    #pragma unroll
    for (int i = 0; i < 4; i++) {
        int row0 = bm + wm + 16*i + g;
        #pragma unroll
        for (int j = 0; j < 8; j++) {
            int col = bn + wn + 8*j + 2*t4;
            *(unsigned*)(C + (size_t)row0 * DIMN + col)       = pack_bf(acc[i][j][0], acc[i][j][1]);
            *(unsigned*)(C + (size_t)(row0 + 8) * DIMN + col) = pack_bf(acc[i][j][2], acc[i][j][3]);
        }
    }
}

// ---- fused w1/w3 gemm, bf16 outs ----
__global__ __launch_bounds__(256, 1) void gemm_ffn13(const bf16* __restrict__ A) {
    const int wsel = blockIdx.x / 11;
    const int bn = (blockIdx.x % 11) * 256;
    const int bm = blockIdx.y * 128;
    const bf16* B = wsel ? b_w3 : b_w1;
    bf16* C = wsel ? b_h3 : b_h1;
    GEMM_PROLOG(A, B, DIMN, HIDDEN, bm, bn)
    #pragma unroll
    for (int i = 0; i < 4; i++) {
        int row0 = bm + wm + 16*i + g;
        #pragma unroll
        for (int j = 0; j < 8; j++) {
            int col = bn + wn + 8*j + 2*t4;
            *(unsigned*)(C + (size_t)row0 * HIDDEN + col)       = pack_bf(acc[i][j][0], acc[i][j][1]);
            *(unsigned*)(C + (size_t)(row0 + 8) * HIDDEN + col) = pack_bf(acc[i][j][2], acc[i][j][3]);
        }
    }
}

// ---- adafm gemm: Y[pi][t] = Xp[pi][:] @ Bg[:][t], scatter to token layout ----
__global__ __launch_bounds__(256, 1) void adafm_gemm(const bf16* __restrict__ Bg0,
                                                     bf16* __restrict__ Y) {
    const int z  = blockIdx.z;                     // batch
    const int bm = blockIdx.y * 128;
    const int bn = 0;
    const bf16* A = b_xp + (size_t)z * 8192 * 256;
    const bf16* B = Bg0 + (size_t)z * 65536;
    GEMM_PROLOG(A, B, 256, 256, bm, bn)
    bf16* Yb = Y + (size_t)z * 2048 * DIMN;
    #pragma unroll
    for (int i = 0; i < 4; i++) {
        int pi0 = bm + wm + 16*i + g;
        #pragma unroll
        for (int j = 0; j < 8; j++) {
            int col = wn + 8*j + 2*t4;             // t in 0..255
            int p = col >> 4, qq = col & 15;
            {
                int pi = pi0;
                *(unsigned*)(Yb + (size_t)((pi >> 6)*16 + p) * DIMN + (pi & 63)*16 + qq)
                    = pack_bf(acc[i][j][0], acc[i][j][1]);
            }
            {
                int pi = pi0 + 8;
                *(unsigned*)(Yb + (size_t)((pi >> 6)*16 + p) * DIMN + (pi & 63)*16 + qq)
                    = pack_bf(acc[i][j][2], acc[i][j][3]);
            }
        }
    }
}

// ---------------- rotary + justnorm + sqk_eff; bf16 in-place (Q pre-scaled x8) --------
__global__ __launch_bounds__(256) void rope_norm(bf16* __restrict__ Q, bf16* __restrict__ K,
                                                 const float* __restrict__ fcos,
                                                 const float* __restrict__ fsin,
                                                 const float* __restrict__ sqk) {
    int w = blockIdx.x * 8 + (threadIdx.x >> 5);
    int lane = threadIdx.x & 31;
    int tok = w >> 4;
    int h = w & 15;
    int s = tok & (SEQL - 1);
    float c  = fcos[s*32 + lane];
    float sn = fsin[s*32 + lane];
    size_t base = (size_t)tok * DIMN + h * HDIM + 2 * lane;
    float se0 = sqk[h*HDIM + 2*lane]     * 32.f;
    float se1 = sqk[h*HDIM + 2*lane + 1] * 32.f;

    {
        float2 qv = unpack_bf(*(unsigned*)(Q + base));
        float ra = qv.x * c - qv.y * sn;
        float rb = qv.x * sn + qv.y * c;
        float ss = ra*ra + rb*rb;
        #pragma unroll
        for (int o = 16; o > 0; o >>= 1) ss += __shfl_xor_sync(0xffffffffu, ss, o);
        float inv = 8.f / fmaxf(sqrtf(ss), 1e-12f);
        *(unsigned*)(Q + base) = pack_bf(ra * inv * se0, rb * inv * se1);
    }
    {
        float2 kv = unpack_bf(*(unsigned*)(K + base));
        float ra = kv.x * c - kv.y * sn;
        float rb = kv.x * sn + kv.y * c;
        float ss = ra*ra + rb*rb;
        #pragma unroll
        for (int o = 16; o > 0; o >>= 1) ss += __shfl_xor_sync(0xffffffffu, ss, o);
        float inv = 1.f / fmaxf(sqrtf(ss), 1e-12f);
        *(unsigned*)(K + base) = pack_bf(ra * inv * se0, rb * inv * se1);
    }
}

// ---------------- FA2 flash attention: register softmax, no S/P smem ----------------
#define FAE 72

__global__ __launch_bounds__(256, 2) void flash_attn(const bf16* __restrict__ Q,
                                                     const bf16* __restrict__ K,
                                                     const bf16* __restrict__ V,
                                                     bf16* __restrict__ O) {
    __shared__ bf16 Qs[128*FAE];
    __shared__ bf16 Ks[64*FAE];
    __shared__ bf16 Vs[64*FAE];
    const unsigned sQ = (unsigned)__cvta_generic_to_shared(Qs);
    const unsigned sK = (unsigned)__cvta_generic_to_shared(Ks);
    const unsigned sV = (unsigned)__cvta_generic_to_shared(Vs);

    const int q0 = blockIdx.x * 128;
    const int h  = blockIdx.y;
    const int b  = blockIdx.z;
    const bf16* Qb = Q + (size_t)b*SEQL*DIMN + h*HDIM;
    const bf16* Kb = K + (size_t)b*SEQL*DIMN + h*HDIM;
    const bf16* Vb = V + (size_t)b*SEQL*DIMN + h*HDIM;
    bf16*       Ob = O + (size_t)b*SEQL*DIMN + h*HDIM;

    const int tid  = threadIdx.x;
    const int lane = tid & 31;
    const int warp = tid >> 5;
    const int g  = lane >> 2;
    const int t4 = lane & 3;
    const int lm = lane & 15;
    const int lh = lane >> 4;
    const int wm = warp * 16;

    // load Q tile 128x64
    #pragma unroll
    for (int u = 0; u < 4; u++) {
        int c = tid + 256*u;
        int r = c >> 3, ofs = (c & 7) * 8;
        *(uint4*)&Qs[r*FAE + ofs] = *(const uint4*)(Qb + (size_t)(q0 + r)*DIMN + ofs);
    }

    float o[8][4];
    #pragma unroll
    for (int j = 0; j < 8; j++)
        #pragma unroll
        for (int r = 0; r < 4; r++) o[j][r] = 0.f;
    float m0 = -1e30f, m1 = -1e30f, l0 = 0.f, l1 = 0.f;

    for (int k0 = 0; k0 < SEQL; k0 += 64) {
        __syncthreads();
        #pragma unroll
        for (int u = 0; u < 2; u++) {
            int c = tid + 256*u;
            int r = c >> 3, ofs = (c & 7) * 8;
            *(uint4*)&Ks[r*FAE + ofs] = *(const uint4*)(Kb + (size_t)(k0 + r)*DIMN + ofs);
            *(uint4*)&Vs[r*FAE + ofs] = *(const uint4*)(Vb + (size_t)(k0 + r)*DIMN + ofs);
        }
        __syncthreads();

        // S = Q @ K^T : warp tile 16q x 64key, regs s[8][4]
        float s[8][4];
        #pragma unroll
        for (int j = 0; j < 8; j++)
            #pragma unroll
            for (int r = 0; r < 4; r++) s[j][r] = 0.f;

        #pragma unroll
        for (int kc = 0; kc < 4; kc++) {
            int kk = 16*kc;
            unsigned a0, a1, a2, a3;
            ldmx4(a0, a1, a2, a3, sQ + (unsigned)((wm + lm)*FAE + kk + lh*8)*2u);
            #pragma unroll
            for (int j2 = 0; j2 < 4; j2++) {
                unsigned r0, r1, r2, r3;
                ldmx4(r0, r1, r2, r3,
                      sK + (unsigned)((16*j2 + (lane & 7) + ((lane >> 4) << 3))*FAE
                                       + kk + (((lane >> 3) & 1) << 3))*2u);
                mma16(s[2*j2],     a0, a1, a2, a3, r0, r1);
                mma16(s[2*j2 + 1], a0, a1, a2, a3, r2, r3);
            }
        }

        // register online softmax (rows g and g+8 of this warp's tile)
        float tm0 = -1e30f, tm1 = -1e30f;
        #pragma unroll
        for (int j = 0; j < 8; j++) {
            tm0 = fmaxf(tm0, fmaxf(s[j][0], s[j][1]));
            tm1 = fmaxf(tm1, fmaxf(s[j][2], s[j][3]));
        }
        tm0 = fmaxf(tm0, __shfl_xor_sync(0xffffffffu, tm0, 1));
        tm0 = fmaxf(tm0, __shfl_xor_sync(0xffffffffu, tm0, 2));
        tm1 = fmaxf(tm1, __shfl_xor_sync(0xffffffffu, tm1, 1));
        tm1 = fmaxf(tm1, __shfl_xor_sync(0xffffffffu, tm1, 2));
        float mn0 = fmaxf(m0, tm0), mn1 = fmaxf(m1, tm1);
        float c0 = __expf(m0 - mn0), c1 = __expf(m1 - mn1);
        float ps0 = 0.f, ps1 = 0.f;
        #pragma unroll
        for (int j = 0; j < 8; j++) {
            s[j][0] = __expf(s[j][0] - mn0);
            s[j][1] = __expf(s[j][1] - mn0);
            s[j][2] = __expf(s[j][2] - mn1);
            s[j][3] = __expf(s[j][3] - mn1);
            ps0 += s[j][0] + s[j][1];
            ps1 += s[j][2] + s[j][3];
        }
        ps0 += __shfl_xor_sync(0xffffffffu, ps0, 1);
        ps0 += __shfl_xor_sync(0xffffffffu, ps0, 2);
        ps1 += __shfl_xor_sync(0xffffffffu, ps1, 1);
        ps1 += __shfl_xor_sync(0xffffffffu, ps1, 2);
        l0 = l0 * c0 + ps0;  l1 = l1 * c1 + ps1;
        m0 = mn0;            m1 = mn1;
        #pragma unroll
        for (int j = 0; j < 8; j++) {
            o[j][0] *= c0; o[j][1] *= c0; o[j][2] *= c1; o[j][3] *= c1;
        }

        // O += P @ V; P fragments built from S registers (C-frag == A-frag layout)
        #pragma unroll
        for (int c = 0; c < 4; c++) {
            unsigned pa0 = pack_bf(s[2*c][0],   s[2*c][1]);
            unsigned pa1 = pack_bf(s[2*c][2],   s[2*c][3]);
            unsigned pa2 = pack_bf(s[2*c+1][0], s[2*c+1][1]);
            unsigned pa3 = pack_bf(s[2*c+1][2], s[2*c+1][3]);
            #pragma unroll
            for (int j2 = 0; j2 < 4; j2++) {
                unsigned r0, r1, r2, r3;
                ldmx4t(r0, r1, r2, r3,
                       sV + (unsigned)((16*c + lm)*FAE + 16*j2 + lh*8)*2u);
                mma16(o[2*j2],     pa0, pa1, pa2, pa3, r0, r1);
                mma16(o[2*j2 + 1], pa0, pa1, pa2, pa3, r2, r3);
            }
        }
    }

    float inv0 = 1.f / l0, inv1 = 1.f / l1;
    #pragma unroll
    for (int j = 0; j < 8; j++) {
        int col = 8*j + 2*t4;
        *(unsigned*)(Ob + (size_t)(q0 + wm + g    )*DIMN + col) = pack_bf(o[j][0]*inv0, o[j][1]*inv0);
        *(unsigned*)(Ob + (size_t)(q0 + wm + g + 8)*DIMN + col) = pack_bf(o[j][2]*inv1, o[j][3]*inv1);
    }
}

// ---------------- fused residual + norms (fp32) ----------------
__global__ __launch_bounds__(256) void residual_norm(const float* __restrict__ xb,
                                                     const float* __restrict__ br,
                                                     const float* __restrict__ alpha,
                                                     float* __restrict__ out) {
    int t = blockIdx.x;
    int tid = threadIdx.x;
    const float* xr = xb + (size_t)t * DIMN;
    const float* rr = br + (size_t)t * DIMN;
    float xv[4], bv[4];
    float ssx = 0.f, ssb = 0.f;
    #pragma unroll
    for (int u = 0; u < 4; u++) {
        int d = tid + u * 256;
        xv[u] = xr[d]; bv[u] = rr[d];
        ssx += xv[u] * xv[u]; ssb += bv[u] * bv[u];
    }
    ssx = blockSum256(ssx);
    ssb = blockSum256(ssb);
    float rx = 1.f / fmaxf(sqrtf(ssx), 1e-12f);
    float rb = 1.f / fmaxf(sqrtf(ssb), 1e-12f);
    float yv[4]; float ssy = 0.f;
    #pragma unroll
    for (int u = 0; u < 4; u++) {
        int d = tid + u * 256;
        float hh = xv[u] * rx;
        float ha = bv[u] * rb;
        float lr = fabsf(alpha[d] * 1.6f);
        float y = hh + lr * (ha - hh);
        yv[u] = y; ssy += y * y;
    }
    ssy = blockSum256(ssy);
    float ry = 1.f / fmaxf(sqrtf(ssy), 1e-12f);
    #pragma unroll
    for (int u = 0; u < 4; u++)
        out[(size_t)t * DIMN + tid + u * 256] = yv[u] * ry;
}

// ---------------- FFN gate, bf16 in / bf16 out (in-place on h1) ----------------
__global__ void ffn_gate(bf16* __restrict__ h1, const bf16* __restrict__ h3,
                         const float* __restrict__ su, const float* __restrict__ sv) {
    const float SC = 53.06599664568481f;   // sqrt(2816)
    size_t np = (size_t)TOK * HIDDEN / 2;
    size_t stride = (size_t)gridDim.x * blockDim.x;
    for (size_t i = (size_t)blockIdx.x * blockDim.x + threadIdx.x; i < np; i += stride) {
        size_t idx = i * 2;
        int col = (int)(idx % HIDDEN);
        float2 a  = unpack_bf(*(unsigned*)(h1 + idx));
        float2 bb = unpack_bf(*(unsigned*)(h3 + idx));
        float z0 = a.x * sv[col]   * SC;
        float z1 = a.y * sv[col+1] * SC;
        float s0 = z0 / (1.f + __expf(-z0));
        float s1 = z1 / (1.f + __expf(-z1));
        *(unsigned*)(h1 + idx) = pack_bf(s0 * (bb.x * su[col]), s1 * (bb.y * su[col+1]));
    }
}

// ---------------- launch ----------------
extern "C" void kernel_launch(void* const* d_in, const int* in_sizes, int n_in,
                              void* d_out, int out_size) {
    const float* x      = (const float*)d_in[0];
    const float* fcos   = (const float*)d_in[1];
    const float* fsin   = (const float*)d_in[2];
    const float* adafm  = (const float*)d_in[3];
    const float* wq     = (const float*)d_in[4];
    const float* wk     = (const float*)d_in[5];
    const float* wv     = (const float*)d_in[6];
    const float* wo     = (const float*)d_in[7];
    const float* sqk    = (const float*)d_in[8];
    const float* w1     = (const float*)d_in[9];
    const float* w2     = (const float*)d_in[10];
    const float* w3     = (const float*)d_in[11];
    const float* su     = (const float*)d_in[12];
    const float* sv     = (const float*)d_in[13];
    const float* pw     = (const float*)d_in[14];
    const float* pb     = (const float*)d_in[15];
    const float* aalpha = (const float*)d_in[16];
    const float* malpha = (const float*)d_in[17];
    float* out = (float*)d_out;

    float *pt, *pf0, *pf1, *pf2;
    bf16 *pbgm, *pbgf, *pbxa, *pbq, *pbk, *pbv, *pbao, *pbwo, *pbw2, *pbh1, *pbh3;
    cudaGetSymbolAddress((void**)&pt,  d_t);
    cudaGetSymbolAddress((void**)&pf0, d_f0);
    cudaGetSymbolAddress((void**)&pf1, d_f1);
    cudaGetSymbolAddress((void**)&pf2, d_f2);
    cudaGetSymbolAddress((void**)&pbgm, b_gm);
    cudaGetSymbolAddress((void**)&pbgf, b_gf);
    cudaGetSymbolAddress((void**)&pbxa, b_xa);
    cudaGetSymbolAddress((void**)&pbq,  b_q);
    cudaGetSymbolAddress((void**)&pbk,  b_k);
    cudaGetSymbolAddress((void**)&pbv,  b_v);
    cudaGetSymbolAddress((void**)&pbao, b_ao);
    cudaGetSymbolAddress((void**)&pbwo, b_wo);
    cudaGetSymbolAddress((void**)&pbw2, b_w2);
    cudaGetSymbolAddress((void**)&pbh1, b_h1);
    cudaGetSymbolAddress((void**)&pbh3, b_h3);

    cudaFuncSetAttribute(gemm_bf16, cudaFuncAttributeMaxDynamicSharedMemorySize, GEMM_SMEM);
    cudaFuncSetAttribute(gemm_qkv, cudaFuncAttributeMaxDynamicSharedMemorySize, GEMM_SMEM);
    cudaFuncSetAttribute(gemm_ffn13, cudaFuncAttributeMaxDynamicSharedMemorySize, GEMM_SMEM);
    cudaFuncSetAttribute(adafm_gemm, cudaFuncAttributeMaxDynamicSharedMemorySize, GEMM_SMEM);

    // 0) weight conversions (one kernel)
    cvt_all<<<dim3(1408, 7), 256>>>(wq, wk, wv, wo, w1, w3, w2);

    // 1) time-modulation: t, then conv matrices Bg
    proj_t_kernel<<<BATCH, 512>>>(adafm, pw, pb, pt);
    make_g_kernel<<<4, 256>>>(pt);

    // 2) attention branch
    patchify<<<2048, 256>>>(x);
    adafm_gemm<<<dim3(1, 64, 2), 256, GEMM_SMEM>>>(pbgm, pbxa);
    gemm_qkv<<<dim3(12, 32), 256, GEMM_SMEM>>>(pbxa);
    rope_norm<<<TOK*NHEAD/8, 256>>>(pbq, pbk, fcos, fsin, sqk);
    flash_attn<<<dim3(SEQL/128, NHEAD, BATCH), 256>>>(pbq, pbk, pbv, pbao);
    gemm_bf16<<<dim3(DIMN/256, TOK/128), 256, GEMM_SMEM>>>(pbao, pbwo, pf2, TOK, DIMN, DIMN);
    residual_norm<<<TOK, 256>>>(x, pf2, aalpha, pf0);   // pf0 := x1

    // 3) FFN branch
    patchify<<<2048, 256>>>(pf0);
    adafm_gemm<<<dim3(1, 64, 2), 256, GEMM_SMEM>>>(pbgf, pbxa);
    gemm_ffn13<<<dim3(22, 32), 256, GEMM_SMEM>>>(pbxa);
    ffn_gate<<<4096, 256>>>(pbh1, pbh3, su, sv);
    gemm_bf16<<<dim3(DIMN/256, TOK/128), 256, GEMM_SMEM>>>(pbh1, pbw2, pf1, TOK, DIMN, HIDDEN);
    residual_norm<<<TOK, 256>>>(pf0, pf1, malpha, out);
}

// round 6
// speedup vs baseline: 5.8311x; 1.0964x over previous
#include <cuda_runtime.h>
#include <cuda_bf16.h>
#include <math.h>

typedef __nv_bfloat16 bf16;

#define DIMN   1024
#define NHEAD  16
#define HDIM   64
#define SEQL   2048
#define BATCH  2
#define TOK    4096
#define HIDDEN 2816

// ---------------- scratch ----------------
__device__ float d_t [BATCH*512];
__device__ float d_f0[TOK*DIMN];            // x1
__device__ float d_f1[TOK*DIMN];            // mlp out
__device__ float d_f2[TOK*DIMN];            // attn out

__device__ bf16 b_wq[DIMN*DIMN], b_wk[DIMN*DIMN], b_wv[DIMN*DIMN], b_wo[DIMN*DIMN];
__device__ bf16 b_w1[DIMN*HIDDEN], b_w3[DIMN*HIDDEN], b_w2[HIDDEN*DIMN];
__device__ bf16 b_xp[BATCH*8192*256];       // patchified input
__device__ bf16 b_gm[BATCH*256*256];        // conv matrix, attn branch
__device__ bf16 b_gf[BATCH*256*256];        // conv matrix, mlp branch
__device__ bf16 b_xa[TOK*DIMN];             // adafm out
__device__ bf16 b_q [TOK*DIMN], b_k[TOK*DIMN], b_v[TOK*DIMN], b_ao[TOK*DIMN];
__device__ bf16 b_h1[(size_t)TOK*HIDDEN];
__device__ bf16 b_h3[(size_t)TOK*HIDDEN];

// ---------------- helpers ----------------
__device__ __forceinline__ float blockSum256(float v) {
    __shared__ float red[8];
    int lane = threadIdx.x & 31, wid = threadIdx.x >> 5;
    #pragma unroll
    for (int o = 16; o > 0; o >>= 1) v += __shfl_xor_sync(0xffffffffu, v, o);
    __syncthreads();
    if (lane == 0) red[wid] = v;
    __syncthreads();
    float s = red[0];
    #pragma unroll
    for (int w = 1; w < 8; w++) s += red[w];
    return s;
}

__device__ __forceinline__ void mma16(float* c, unsigned a0, unsigned a1, unsigned a2, unsigned a3,
                                      unsigned b0, unsigned b1) {
    asm volatile(
        "mma.sync.aligned.m16n8k16.row.col.f32.bf16.bf16.f32 "
        "{%0,%1,%2,%3}, {%4,%5,%6,%7}, {%8,%9}, {%0,%1,%2,%3};"
        : "+f"(c[0]), "+f"(c[1]), "+f"(c[2]), "+f"(c[3])
        : "r"(a0), "r"(a1), "r"(a2), "r"(a3), "r"(b0), "r"(b1));
}
__device__ __forceinline__ void ldmx4(unsigned& r0, unsigned& r1, unsigned& r2, unsigned& r3, unsigned addr) {
    asm volatile("ldmatrix.sync.aligned.m8n8.x4.shared.b16 {%0,%1,%2,%3}, [%4];"
                 : "=r"(r0), "=r"(r1), "=r"(r2), "=r"(r3) : "r"(addr));
}
__device__ __forceinline__ void ldmx4t(unsigned& r0, unsigned& r1, unsigned& r2, unsigned& r3, unsigned addr) {
    asm volatile("ldmatrix.sync.aligned.m8n8.x4.trans.shared.b16 {%0,%1,%2,%3}, [%4];"
                 : "=r"(r0), "=r"(r1), "=r"(r2), "=r"(r3) : "r"(addr));
}
__device__ __forceinline__ void cpa16(unsigned s, const void* g) {
    asm volatile("cp.async.cg.shared.global [%0], [%1], 16;" :: "r"(s), "l"(g));
}
__device__ __forceinline__ unsigned pack_bf(float a, float b) {
    __nv_bfloat162 t;
    t.x = __float2bfloat16_rn(a);
    t.y = __float2bfloat16_rn(b);
    return *(unsigned*)&t;
}
__device__ __forceinline__ float2 unpack_bf(unsigned u) {
    __nv_bfloat162 t = *(__nv_bfloat162*)&u;
    return make_float2(__bfloat162float(t.x), __bfloat162float(t.y));
}

// ---------------- all weight conversions in one kernel (16 elems/thread) ----------------
__global__ void cvt_all(const float* __restrict__ s0, const float* __restrict__ s1,
                        const float* __restrict__ s2, const float* __restrict__ s3,
                        const float* __restrict__ s4, const float* __restrict__ s5,
                        const float* __restrict__ s6) {
    int w = blockIdx.y;
    const float* src; bf16* dst; int n;
    switch (w) {
        case 0: src = s0; dst = b_wq; n = DIMN*DIMN; break;
        case 1: src = s1; dst = b_wk; n = DIMN*DIMN; break;
        case 2: src = s2; dst = b_wv; n = DIMN*DIMN; break;
        case 3: src = s3; dst = b_wo; n = DIMN*DIMN; break;
        case 4: src = s4; dst = b_w1; n = DIMN*HIDDEN; break;
        case 5: src = s5; dst = b_w3; n = DIMN*HIDDEN; break;
        default: src = s6; dst = b_w2; n = HIDDEN*DIMN; break;
    }
    int i = (blockIdx.x * 256 + threadIdx.x) * 16;
    if (i < n) {
        float4 a = *(const float4*)(src + i);
        float4 b = *(const float4*)(src + i + 4);
        float4 c = *(const float4*)(src + i + 8);
        float4 d = *(const float4*)(src + i + 12);
        uint4 o1, o2;
        o1.x = pack_bf(a.x, a.y); o1.y = pack_bf(a.z, a.w);
        o1.z = pack_bf(b.x, b.y); o1.w = pack_bf(b.z, b.w);
        o2.x = pack_bf(c.x, c.y); o2.y = pack_bf(c.z, c.w);
        o2.z = pack_bf(d.x, d.y); o2.w = pack_bf(d.z, d.w);
        *(uint4*)(dst + i) = o1;
        *(uint4*)(dst + i + 8) = o2;
    }
}

// ---------------- t = silu(adafm_input) @ proj_w + proj_b ----------------
__global__ void proj_t_kernel(const float* __restrict__ ad, const float* __restrict__ pw,
                              const float* __restrict__ pb, float* __restrict__ t) {
    int b = blockIdx.x;
    __shared__ float s[DIMN];
    for (int i = threadIdx.x; i < DIMN; i += blockDim.x) {
        float z = ad[b*DIMN + i];
        s[i] = z / (1.f + expf(-z));
    }
    __syncthreads();
    for (int o = threadIdx.x; o < 512; o += blockDim.x) {
        float acc = pb[o];
        #pragma unroll 4
        for (int i = 0; i < DIMN; i++) acc += s[i] * pw[i*512 + o];
        t[b*512 + o] = acc;
    }
}

// --------- g[d] = (1/256) sum_k m[k] cos(2 pi k d/256); emit Bg[q][t]=g[(t-q)&255] -----
__global__ void make_g_kernel(const float* __restrict__ t) {
    int b = blockIdx.x >> 1, which = blockIdx.x & 1;
    const float* m = t + b*512 + which*256;
    __shared__ float cs[256], ms[256];
    __shared__ bf16 gd[512];
    int d = threadIdx.x;
    cs[d] = cosf((6.283185307179586f / 256.0f) * (float)d);
    ms[d] = m[d];
    __syncthreads();
    float acc = 0.f;
    #pragma unroll 4
    for (int k = 0; k < 256; k++) acc += ms[k] * cs[(k*d) & 255];
    bf16 gv = __float2bfloat16_rn(acc * (1.0f / 256.0f));
    gd[d] = gv; gd[d + 256] = gv;
    __syncthreads();
    bf16* Bg = (which ? b_gf : b_gm) + b * 65536;
    // thread d owns column d: consecutive lanes -> consecutive addresses
    for (int q = 0; q < 256; q++)
        Bg[q*256 + d] = gd[d - q + 256];
}

// ---------------- patchify: x fp32 [B,SEQ,DIM] -> Xp bf16 [B, 8192, 256] ----------------
__global__ void patchify(const float* __restrict__ x) {
    int c = blockIdx.x * 256 + threadIdx.x;           // 8-elem chunk id, total 524288
    int q  = (c & 31) * 8;
    int pi = (c >> 5) & 8191;
    int b  = c >> 18;
    int p = q >> 4, qq = q & 15;
    const float* src = x + ((size_t)(b*2048 + (pi >> 6)*16 + p)) * DIMN + (pi & 63)*16 + qq;
    float4 a = *(const float4*)src;
    float4 v = *(const float4*)(src + 4);
    uint4 o;
    o.x = pack_bf(a.x, a.y); o.y = pack_bf(a.z, a.w);
    o.z = pack_bf(v.x, v.y); o.w = pack_bf(v.z, v.w);
    *(uint4*)(b_xp + (size_t)c * 8) = o;
}

// ================= GEMM core macro pieces (block 128x256x32, 8 warps) =================
#define AKE 40
#define BNE 264
#define A_ELT (128*AKE)
#define B_ELT (32*BNE)
#define STG_ELT (A_ELT + B_ELT)
#define GEMM_SMEM (3 * STG_ELT * 2)

#define GEMM_PROLOG(Aptr, Bptr, Kdim, Ndim, bmv, bnv)                                    \
    extern __shared__ bf16 smb[];                                                        \
    const unsigned sbase = (unsigned)__cvta_generic_to_shared(smb);                      \
    const int tid  = threadIdx.x;                                                        \
    const int lane = tid & 31;                                                           \
    const int warp = tid >> 5;                                                           \
    const int g    = lane >> 2;                                                          \
    const int t4   = lane & 3;                                                           \
    const int lm   = lane & 15;                                                          \
    const int lh   = lane >> 4;                                                          \
    const int wm = (warp >> 2) * 64;                                                     \
    const int wn = (warp & 3) * 64;                                                      \
    float acc[4][8][4];                                                                  \
    _Pragma("unroll") for (int i = 0; i < 4; i++)                                        \
        _Pragma("unroll") for (int j = 0; j < 8; j++)                                    \
            _Pragma("unroll") for (int r = 0; r < 4; r++) acc[i][j][r] = 0.f;            \
    const int ktiles = (Kdim) >> 5;                                                      \
    auto load_stage = [&](int st, int k0) {                                              \
        unsigned sa = sbase + (unsigned)(st * STG_ELT) * 2u;                             \
        unsigned sb = sa + A_ELT * 2u;                                                   \
        _Pragma("unroll") for (int u = 0; u < 2; u++) {                                  \
            int c = tid + 256*u;                                                         \
            int r = c >> 2, o = (c & 3) * 8;                                             \
            cpa16(sa + (unsigned)(r*AKE + o)*2u, (Aptr) + (size_t)((bmv) + r) * (Kdim) + k0 + o); \
        }                                                                                \
        _Pragma("unroll") for (int u = 0; u < 4; u++) {                                  \
            int c = tid + 256*u;                                                         \
            int r = c >> 5, o = (c & 31) * 8;                                            \
            cpa16(sb + (unsigned)(r*BNE + o)*2u, (Bptr) + (size_t)(k0 + r) * (Ndim) + (bnv) + o); \
        }                                                                                \
    };                                                                                   \
    load_stage(0, 0);                                                                    \
    asm volatile("cp.async.commit_group;");                                              \
    load_stage(1, 32);                                                                   \
    asm volatile("cp.async.commit_group;");                                              \
    for (int t = 0; t < ktiles; t++) {                                                   \
        asm volatile("cp.async.wait_group 1;");                                          \
        __syncthreads();                                                                 \
        int nt = t + 2;                                                                  \
        if (nt < ktiles) load_stage(nt % 3, nt * 32);                                    \
        asm volatile("cp.async.commit_group;");                                          \
        unsigned sa = sbase + (unsigned)((t % 3) * STG_ELT) * 2u;                        \
        unsigned sb = sa + A_ELT * 2u;                                                   \
        _Pragma("unroll") for (int kk = 0; kk < 32; kk += 16) {                          \
            unsigned af[4][4], bfr[8][2];                                                \
            _Pragma("unroll") for (int i = 0; i < 4; i++)                                \
                ldmx4(af[i][0], af[i][1], af[i][2], af[i][3],                            \
                      sa + (unsigned)((wm + 16*i + lm)*AKE + kk + lh*8)*2u);             \
            _Pragma("unroll") for (int j2 = 0; j2 < 4; j2++)                             \
                ldmx4t(bfr[2*j2][0], bfr[2*j2][1], bfr[2*j2+1][0], bfr[2*j2+1][1],       \
                       sb + (unsigned)((kk + lm)*BNE + wn + 16*j2 + lh*8)*2u);           \
            _Pragma("unroll") for (int i = 0; i < 4; i++)                                \
                _Pragma("unroll") for (int j = 0; j < 8; j++)                            \
                    mma16(acc[i][j], af[i][0], af[i][1], af[i][2], af[i][3],             \
                          bfr[j][0], bfr[j][1]);                                         \
        }                                                                                \
    }

// ---- generic gemm, fp32 out ----
__global__ __launch_bounds__(256, 1) void gemm_bf16(const bf16* __restrict__ A,
                                                    const bf16* __restrict__ B,
                                                    float* __restrict__ Cf,
                                                    int M, int N, int K) {
    const int bm = blockIdx.y * 128;
    const int bn = blockIdx.x * 256;
    GEMM_PROLOG(A, B, K, N, bm, bn)
    #pragma unroll
    for (int i = 0; i < 4; i++) {
        int row0 = bm + wm + 16*i + g;
        #pragma unroll
        for (int j = 0; j < 8; j++) {
            int col = bn + wn + 8*j + 2*t4;
            *(float2*)(Cf + (size_t)row0 * N + col)       = make_float2(acc[i][j][0], acc[i][j][1]);
            *(float2*)(Cf + (size_t)(row0 + 8) * N + col) = make_float2(acc[i][j][2], acc[i][j][3]);
        }
    }
}

// ---- fused QKV gemm, bf16 outs ----
__global__ __launch_bounds__(256, 1) void gemm_qkv(const bf16* __restrict__ A) {
    const int wsel = blockIdx.x >> 2;
    const int bn = (blockIdx.x & 3) * 256;
    const int bm = blockIdx.y * 128;
    const bf16* B = (wsel == 0) ? b_wq : ((wsel == 1) ? b_wk : b_wv);
    bf16* C = (wsel == 0) ? b_q : ((wsel == 1) ? b_k : b_v);
    GEMM_PROLOG(A, B, DIMN, DIMN, bm, bn)
    #pragma unroll
    for (int i = 0; i < 4; i++) {
        int row0 = bm + wm + 16*i + g;
        #pragma unroll
        for (int j = 0; j < 8; j++) {
            int col = bn + wn + 8*j + 2*t4;
            *(unsigned*)(C + (size_t)row0 * DIMN + col)       = pack_bf(acc[i][j][0], acc[i][j][1]);
            *(unsigned*)(C + (size_t)(row0 + 8) * DIMN + col) = pack_bf(acc[i][j][2], acc[i][j][3]);
        }
    }
}

// ---- fused w1/w3 gemm, bf16 outs ----
__global__ __launch_bounds__(256, 1) void gemm_ffn13(const bf16* __restrict__ A) {
    const int wsel = blockIdx.x / 11;
    const int bn = (blockIdx.x % 11) * 256;
    const int bm = blockIdx.y * 128;
    const bf16* B = wsel ? b_w3 : b_w1;
    bf16* C = wsel ? b_h3 : b_h1;
    GEMM_PROLOG(A, B, DIMN, HIDDEN, bm, bn)
    #pragma unroll
    for (int i = 0; i < 4; i++) {
        int row0 = bm + wm + 16*i + g;
        #pragma unroll
        for (int j = 0; j < 8; j++) {
            int col = bn + wn + 8*j + 2*t4;
            *(unsigned*)(C + (size_t)row0 * HIDDEN + col)       = pack_bf(acc[i][j][0], acc[i][j][1]);
            *(unsigned*)(C + (size_t)(row0 + 8) * HIDDEN + col) = pack_bf(acc[i][j][2], acc[i][j][3]);
        }
    }
}

// ---- adafm gemm: Y[pi][t] = Xp[pi][:] @ Bg[:][t], scatter to token layout ----
__global__ __launch_bounds__(256, 1) void adafm_gemm(const bf16* __restrict__ Bg0,
                                                     bf16* __restrict__ Y) {
    const int z  = blockIdx.z;                     // batch
    const int bm = blockIdx.y * 128;
    const int bn = 0;
    const bf16* A = b_xp + (size_t)z * 8192 * 256;
    const bf16* B = Bg0 + (size_t)z * 65536;
    GEMM_PROLOG(A, B, 256, 256, bm, bn)
    bf16* Yb = Y + (size_t)z * 2048 * DIMN;
    #pragma unroll
    for (int i = 0; i < 4; i++) {
        int pi0 = bm + wm + 16*i + g;
        #pragma unroll
        for (int j = 0; j < 8; j++) {
            int col = wn + 8*j + 2*t4;             // t in 0..255
            int p = col >> 4, qq = col & 15;
            {
                int pi = pi0;
                *(unsigned*)(Yb + (size_t)((pi >> 6)*16 + p) * DIMN + (pi & 63)*16 + qq)
                    = pack_bf(acc[i][j][0], acc[i][j][1]);
            }
            {
                int pi = pi0 + 8;
                *(unsigned*)(Yb + (size_t)((pi >> 6)*16 + p) * DIMN + (pi & 63)*16 + qq)
                    = pack_bf(acc[i][j][2], acc[i][j][3]);
            }
        }
    }
}

// ---------------- rotary + justnorm + sqk_eff; bf16 in-place (Q pre-scaled x8) --------
__global__ __launch_bounds__(256) void rope_norm(bf16* __restrict__ Q, bf16* __restrict__ K,
                                                 const float* __restrict__ fcos,
                                                 const float* __restrict__ fsin,
                                                 const float* __restrict__ sqk) {
    int w = blockIdx.x * 8 + (threadIdx.x >> 5);
    int lane = threadIdx.x & 31;
    int tok = w >> 4;
    int h = w & 15;
    int s = tok & (SEQL - 1);
    float c  = fcos[s*32 + lane];
    float sn = fsin[s*32 + lane];
    size_t base = (size_t)tok * DIMN + h * HDIM + 2 * lane;
    float se0 = sqk[h*HDIM + 2*lane]     * 32.f;
    float se1 = sqk[h*HDIM + 2*lane + 1] * 32.f;

    {
        float2 qv = unpack_bf(*(unsigned*)(Q + base));
        float ra = qv.x * c - qv.y * sn;
        float rb = qv.x * sn + qv.y * c;
        float ss = ra*ra + rb*rb;
        #pragma unroll
        for (int o = 16; o > 0; o >>= 1) ss += __shfl_xor_sync(0xffffffffu, ss, o);
        float inv = 8.f / fmaxf(sqrtf(ss), 1e-12f);
        *(unsigned*)(Q + base) = pack_bf(ra * inv * se0, rb * inv * se1);
    }
    {
        float2 kv = unpack_bf(*(unsigned*)(K + base));
        float ra = kv.x * c - kv.y * sn;
        float rb = kv.x * sn + kv.y * c;
        float ss = ra*ra + rb*rb;
        #pragma unroll
        for (int o = 16; o > 0; o >>= 1) ss += __shfl_xor_sync(0xffffffffu, ss, o);
        float inv = 1.f / fmaxf(sqrtf(ss), 1e-12f);
        *(unsigned*)(K + base) = pack_bf(ra * inv * se0, rb * inv * se1);
    }
}

// ---------------- FA2 flash attention, cp.async 2-stage K/V pipeline ----------------
#define FAE 72
#define FLASH_SMEM (384 * FAE * 2)   // Q 128 rows + 2*(K 64) + 2*(V 64), bf16

__global__ __launch_bounds__(256, 2) void flash_attn(const bf16* __restrict__ Q,
                                                     const bf16* __restrict__ K,
                                                     const bf16* __restrict__ V,
                                                     bf16* __restrict__ O) {
    extern __shared__ bf16 fsm[];
    bf16* Qs = fsm;
    const unsigned sQ  = (unsigned)__cvta_generic_to_shared(Qs);
    const unsigned sK0 = sQ + 128*FAE*2u;
    const unsigned sV0 = sK0 + 2*64*FAE*2u;

    const int q0 = blockIdx.x * 128;
    const int h  = blockIdx.y;
    const int b  = blockIdx.z;
    const bf16* Qb = Q + (size_t)b*SEQL*DIMN + h*HDIM;
    const bf16* Kb = K + (size_t)b*SEQL*DIMN + h*HDIM;
    const bf16* Vb = V + (size_t)b*SEQL*DIMN + h*HDIM;
    bf16*       Ob = O + (size_t)b*SEQL*DIMN + h*HDIM;

    const int tid  = threadIdx.x;
    const int lane = tid & 31;
    const int warp = tid >> 5;
    const int g  = lane >> 2;
    const int t4 = lane & 3;
    const int lm = lane & 15;
    const int lh = lane >> 4;
    const int wm = warp * 16;

    auto loadKV = [&](int st, int k0) {
        unsigned sk = sK0 + (unsigned)st * 64*FAE*2u;
        unsigned sv = sV0 + (unsigned)st * 64*FAE*2u;
        #pragma unroll
        for (int u = 0; u < 2; u++) {
            int c = tid + 256*u;
            int r = c >> 3, ofs = (c & 7) * 8;
            cpa16(sk + (unsigned)(r*FAE + ofs)*2u, Kb + (size_t)(k0 + r)*DIMN + ofs);
            cpa16(sv + (unsigned)(r*FAE + ofs)*2u, Vb + (size_t)(k0 + r)*DIMN + ofs);
        }
    };

    // Q tile 128x64 (plain loads; covered by first barrier)
    #pragma unroll
    for (int u = 0; u < 4; u++) {
        int c = tid + 256*u;
        int r = c >> 3, ofs = (c & 7) * 8;
        *(uint4*)&Qs[r*FAE + ofs] = *(const uint4*)(Qb + (size_t)(q0 + r)*DIMN + ofs);
    }

    loadKV(0, 0);
    asm volatile("cp.async.commit_group;");

    float o[8][4];
    #pragma unroll
    for (int j = 0; j < 8; j++)
        #pragma unroll
        for (int r = 0; r < 4; r++) o[j][r] = 0.f;
    float m0 = -1e30f, m1 = -1e30f, l0 = 0.f, l1 = 0.f;

    const int NT = SEQL / 64;
    for (int t = 0; t < NT; t++) {
        if (t + 1 < NT) {
            loadKV((t + 1) & 1, (t + 1) * 64);
            asm volatile("cp.async.commit_group;");
            asm volatile("cp.async.wait_group 1;");
        } else {
            asm volatile("cp.async.wait_group 0;");
        }
        __syncthreads();

        const unsigned sK = sK0 + (unsigned)(t & 1) * 64*FAE*2u;
        const unsigned sV = sV0 + (unsigned)(t & 1) * 64*FAE*2u;

        // S = Q @ K^T : warp tile 16q x 64key
        float s[8][4];
        #pragma unroll
        for (int j = 0; j < 8; j++)
            #pragma unroll
            for (int r = 0; r < 4; r++) s[j][r] = 0.f;

        #pragma unroll
        for (int kc = 0; kc < 4; kc++) {
            int kk = 16*kc;
            unsigned a0, a1, a2, a3;
            ldmx4(a0, a1, a2, a3, sQ + (unsigned)((wm + lm)*FAE + kk + lh*8)*2u);
            #pragma unroll
            for (int j2 = 0; j2 < 4; j2++) {
                unsigned r0, r1, r2, r3;
                ldmx4(r0, r1, r2, r3,
                      sK + (unsigned)((16*j2 + (lane & 7) + ((lane >> 4) << 3))*FAE
                                       + kk + (((lane >> 3) & 1) << 3))*2u);
                mma16(s[2*j2],     a0, a1, a2, a3, r0, r1);
                mma16(s[2*j2 + 1], a0, a1, a2, a3, r2, r3);
            }
        }

        // register online softmax
        float tm0 = -1e30f, tm1 = -1e30f;
        #pragma unroll
        for (int j = 0; j < 8; j++) {
            tm0 = fmaxf(tm0, fmaxf(s[j][0], s[j][1]));
            tm1 = fmaxf(tm1, fmaxf(s[j][2], s[j][3]));
        }
        tm0 = fmaxf(tm0, __shfl_xor_sync(0xffffffffu, tm0, 1));
        tm0 = fmaxf(tm0, __shfl_xor_sync(0xffffffffu, tm0, 2));
        tm1 = fmaxf(tm1, __shfl_xor_sync(0xffffffffu, tm1, 1));
        tm1 = fmaxf(tm1, __shfl_xor_sync(0xffffffffu, tm1, 2));
        float mn0 = fmaxf(m0, tm0), mn1 = fmaxf(m1, tm1);
        float c0 = __expf(m0 - mn0), c1 = __expf(m1 - mn1);
        float ps0 = 0.f, ps1 = 0.f;
        #pragma unroll
        for (int j = 0; j < 8; j++) {
            s[j][0] = __expf(s[j][0] - mn0);
            s[j][1] = __expf(s[j][1] - mn0);
            s[j][2] = __expf(s[j][2] - mn1);
            s[j][3] = __expf(s[j][3] - mn1);
            ps0 += s[j][0] + s[j][1];
            ps1 += s[j][2] + s[j][3];
        }
        ps0 += __shfl_xor_sync(0xffffffffu, ps0, 1);
        ps0 += __shfl_xor_sync(0xffffffffu, ps0, 2);
        ps1 += __shfl_xor_sync(0xffffffffu, ps1, 1);
        ps1 += __shfl_xor_sync(0xffffffffu, ps1, 2);
        l0 = l0 * c0 + ps0;  l1 = l1 * c1 + ps1;
        m0 = mn0;            m1 = mn1;
        #pragma unroll
        for (int j = 0; j < 8; j++) {
            o[j][0] *= c0; o[j][1] *= c0; o[j][2] *= c1; o[j][3] *= c1;
        }

        // O += P @ V (P fragments from S registers)
        #pragma unroll
        for (int c = 0; c < 4; c++) {
            unsigned pa0 = pack_bf(s[2*c][0],   s[2*c][1]);
            unsigned pa1 = pack_bf(s[2*c][2],   s[2*c][3]);
            unsigned pa2 = pack_bf(s[2*c+1][0], s[2*c+1][1]);
            unsigned pa3 = pack_bf(s[2*c+1][2], s[2*c+1][3]);
            #pragma unroll
            for (int j2 = 0; j2 < 4; j2++) {
                unsigned r0, r1, r2, r3;
                ldmx4t(r0, r1, r2, r3,
                       sV + (unsigned)((16*c + lm)*FAE + 16*j2 + lh*8)*2u);
                mma16(o[2*j2],     pa0, pa1, pa2, pa3, r0, r1);
                mma16(o[2*j2 + 1], pa0, pa1, pa2, pa3, r2, r3);
            }
        }
        __syncthreads();   // stage (t+1)&1 may be overwritten next iteration
    }

    float inv0 = 1.f / l0, inv1 = 1.f / l1;
    #pragma unroll
    for (int j = 0; j < 8; j++) {
        int col = 8*j + 2*t4;
        *(unsigned*)(Ob + (size_t)(q0 + wm + g    )*DIMN + col) = pack_bf(o[j][0]*inv0, o[j][1]*inv0);
        *(unsigned*)(Ob + (size_t)(q0 + wm + g + 8)*DIMN + col) = pack_bf(o[j][2]*inv1, o[j][3]*inv1);
    }
}

// ---------------- fused residual + norms (fp32) ----------------
__global__ __launch_bounds__(256) void residual_norm(const float* __restrict__ xb,
                                                     const float* __restrict__ br,
                                                     const float* __restrict__ alpha,
                                                     float* __restrict__ out) {
    int t = blockIdx.x;
    int tid = threadIdx.x;
    const float* xr = xb + (size_t)t * DIMN;
    const float* rr = br + (size_t)t * DIMN;
    float xv[4], bv[4];
    float ssx = 0.f, ssb = 0.f;
    #pragma unroll
    for (int u = 0; u < 4; u++) {
        int d = tid + u * 256;
        xv[u] = xr[d]; bv[u] = rr[d];
        ssx += xv[u] * xv[u]; ssb += bv[u] * bv[u];
    }
    ssx = blockSum256(ssx);
    ssb = blockSum256(ssb);
    float rx = 1.f / fmaxf(sqrtf(ssx), 1e-12f);
    float rb = 1.f / fmaxf(sqrtf(ssb), 1e-12f);
    float yv[4]; float ssy = 0.f;
    #pragma unroll
    for (int u = 0; u < 4; u++) {
        int d = tid + u * 256;
        float hh = xv[u] * rx;
        float ha = bv[u] * rb;
        float lr = fabsf(alpha[d] * 1.6f);
        float y = hh + lr * (ha - hh);
        yv[u] = y; ssy += y * y;
    }
    ssy = blockSum256(ssy);
    float ry = 1.f / fmaxf(sqrtf(ssy), 1e-12f);
    #pragma unroll
    for (int u = 0; u < 4; u++)
        out[(size_t)t * DIMN + tid + u * 256] = yv[u] * ry;
}

// ---------------- FFN gate, no modulo: grid (6, TOK), pair index = threads ----------------
__global__ void ffn_gate(bf16* __restrict__ h1, const bf16* __restrict__ h3,
                         const float* __restrict__ su, const float* __restrict__ sv) {
    const float SC = 53.06599664568481f;   // sqrt(2816)
    int t = blockIdx.x * 256 + threadIdx.x;          // pair index in row
    if (t >= HIDDEN/2) return;
    int row = blockIdx.y;
    int col = 2 * t;
    size_t idx = (size_t)row * HIDDEN + col;
    float2 a  = unpack_bf(*(unsigned*)(h1 + idx));
    float2 bb = unpack_bf(*(unsigned*)(h3 + idx));
    float z0 = a.x * sv[col]   * SC;
    float z1 = a.y * sv[col+1] * SC;
    float s0 = z0 / (1.f + __expf(-z0));
    float s1 = z1 / (1.f + __expf(-z1));
    *(unsigned*)(h1 + idx) = pack_bf(s0 * (bb.x * su[col]), s1 * (bb.y * su[col+1]));
}

// ---------------- launch ----------------
extern "C" void kernel_launch(void* const* d_in, const int* in_sizes, int n_in,
                              void* d_out, int out_size) {
    const float* x      = (const float*)d_in[0];
    const float* fcos   = (const float*)d_in[1];
    const float* fsin   = (const float*)d_in[2];
    const float* adafm  = (const float*)d_in[3];
    const float* wq     = (const float*)d_in[4];
    const float* wk     = (const float*)d_in[5];
    const float* wv     = (const float*)d_in[6];
    const float* wo     = (const float*)d_in[7];
    const float* sqk    = (const float*)d_in[8];
    const float* w1     = (const float*)d_in[9];
    const float* w2     = (const float*)d_in[10];
    const float* w3     = (const float*)d_in[11];
    const float* su     = (const float*)d_in[12];
    const float* sv     = (const float*)d_in[13];
    const float* pw     = (const float*)d_in[14];
    const float* pb     = (const float*)d_in[15];
    const float* aalpha = (const float*)d_in[16];
    const float* malpha = (const float*)d_in[17];
    float* out = (float*)d_out;

    float *pt, *pf0, *pf1, *pf2;
    bf16 *pbgm, *pbgf, *pbxa, *pbq, *pbk, *pbv, *pbao, *pbwo, *pbw2, *pbh1, *pbh3;
    cudaGetSymbolAddress((void**)&pt,  d_t);
    cudaGetSymbolAddress((void**)&pf0, d_f0);
    cudaGetSymbolAddress((void**)&pf1, d_f1);
    cudaGetSymbolAddress((void**)&pf2, d_f2);
    cudaGetSymbolAddress((void**)&pbgm, b_gm);
    cudaGetSymbolAddress((void**)&pbgf, b_gf);
    cudaGetSymbolAddress((void**)&pbxa, b_xa);
    cudaGetSymbolAddress((void**)&pbq,  b_q);
    cudaGetSymbolAddress((void**)&pbk,  b_k);
    cudaGetSymbolAddress((void**)&pbv,  b_v);
    cudaGetSymbolAddress((void**)&pbao, b_ao);
    cudaGetSymbolAddress((void**)&pbwo, b_wo);
    cudaGetSymbolAddress((void**)&pbw2, b_w2);
    cudaGetSymbolAddress((void**)&pbh1, b_h1);
    cudaGetSymbolAddress((void**)&pbh3, b_h3);

    cudaFuncSetAttribute(gemm_bf16, cudaFuncAttributeMaxDynamicSharedMemorySize, GEMM_SMEM);
    cudaFuncSetAttribute(gemm_qkv, cudaFuncAttributeMaxDynamicSharedMemorySize, GEMM_SMEM);
    cudaFuncSetAttribute(gemm_ffn13, cudaFuncAttributeMaxDynamicSharedMemorySize, GEMM_SMEM);
    cudaFuncSetAttribute(adafm_gemm, cudaFuncAttributeMaxDynamicSharedMemorySize, GEMM_SMEM);
    cudaFuncSetAttribute(flash_attn, cudaFuncAttributeMaxDynamicSharedMemorySize, FLASH_SMEM);

    // 0) weight conversions (one kernel)
    cvt_all<<<dim3(704, 7), 256>>>(wq, wk, wv, wo, w1, w3, w2);

    // 1) time-modulation: t, then conv matrices Bg
    proj_t_kernel<<<BATCH, 512>>>(adafm, pw, pb, pt);
    make_g_kernel<<<4, 256>>>(pt);

    // 2) attention branch
    patchify<<<2048, 256>>>(x);
    adafm_gemm<<<dim3(1, 64, 2), 256, GEMM_SMEM>>>(pbgm, pbxa);
    gemm_qkv<<<dim3(12, 32), 256, GEMM_SMEM>>>(pbxa);
    rope_norm<<<TOK*NHEAD/8, 256>>>(pbq, pbk, fcos, fsin, sqk);
    flash_attn<<<dim3(SEQL/128, NHEAD, BATCH), 256, FLASH_SMEM>>>(pbq, pbk, pbv, pbao);
    gemm_bf16<<<dim3(DIMN/256, TOK/128), 256, GEMM_SMEM>>>(pbao, pbwo, pf2, TOK, DIMN, DIMN);
    residual_norm<<<TOK, 256>>>(x, pf2, aalpha, pf0);   // pf0 := x1

    // 3) FFN branch
    patchify<<<2048, 256>>>(pf0);
    adafm_gemm<<<dim3(1, 64, 2), 256, GEMM_SMEM>>>(pbgf, pbxa);
    gemm_ffn13<<<dim3(22, 32), 256, GEMM_SMEM>>>(pbxa);
    ffn_gate<<<dim3(6, TOK), 256>>>(pbh1, pbh3, su, sv);
    gemm_bf16<<<dim3(DIMN/256, TOK/128), 256, GEMM_SMEM>>>(pbh1, pbw2, pf1, TOK, DIMN, HIDDEN);
    residual_norm<<<TOK, 256>>>(pf0, pf1, malpha, out);
}

// round 8
// speedup vs baseline: 5.9406x; 1.0188x over previous
#include <cuda_runtime.h>
#include <cuda_bf16.h>
#include <math.h>

typedef __nv_bfloat16 bf16;

#define DIMN   1024
#define NHEAD  16
#define HDIM   64
#define SEQL   2048
#define BATCH  2
#define TOK    4096
#define HIDDEN 2816

// ---------------- scratch ----------------
__device__ float d_t [BATCH*512];
__device__ float d_f0[TOK*DIMN];            // x1
__device__ float d_f1[TOK*DIMN];            // mlp out
__device__ float d_f2[TOK*DIMN];            // attn out

__device__ bf16 b_wq[DIMN*DIMN], b_wk[DIMN*DIMN], b_wv[DIMN*DIMN], b_wo[DIMN*DIMN];
__device__ bf16 b_w1[DIMN*HIDDEN], b_w3[DIMN*HIDDEN], b_w2[HIDDEN*DIMN];
__device__ bf16 b_xp[BATCH*8192*256];       // patchified input
__device__ bf16 b_gm[BATCH*256*256];        // conv matrix, attn branch
__device__ bf16 b_gf[BATCH*256*256];        // conv matrix, mlp branch
__device__ bf16 b_xa[TOK*DIMN];             // adafm out
__device__ bf16 b_q [TOK*DIMN], b_k[TOK*DIMN], b_v[TOK*DIMN], b_ao[TOK*DIMN];
__device__ bf16 b_h1[(size_t)TOK*HIDDEN];

// ---------------- helpers ----------------
__device__ __forceinline__ float blockSum256(float v) {
    __shared__ float red[8];
    int lane = threadIdx.x & 31, wid = threadIdx.x >> 5;
    #pragma unroll
    for (int o = 16; o > 0; o >>= 1) v += __shfl_xor_sync(0xffffffffu, v, o);
    __syncthreads();
    if (lane == 0) red[wid] = v;
    __syncthreads();
    float s = red[0];
    #pragma unroll
    for (int w = 1; w < 8; w++) s += red[w];
    return s;
}

__device__ __forceinline__ void mma16(float* c, unsigned a0, unsigned a1, unsigned a2, unsigned a3,
                                      unsigned b0, unsigned b1) {
    asm volatile(
        "mma.sync.aligned.m16n8k16.row.col.f32.bf16.bf16.f32 "
        "{%0,%1,%2,%3}, {%4,%5,%6,%7}, {%8,%9}, {%0,%1,%2,%3};"
        : "+f"(c[0]), "+f"(c[1]), "+f"(c[2]), "+f"(c[3])
        : "r"(a0), "r"(a1), "r"(a2), "r"(a3), "r"(b0), "r"(b1));
}
__device__ __forceinline__ void ldmx4(unsigned& r0, unsigned& r1, unsigned& r2, unsigned& r3, unsigned addr) {
    asm volatile("ldmatrix.sync.aligned.m8n8.x4.shared.b16 {%0,%1,%2,%3}, [%4];"
                 : "=r"(r0), "=r"(r1), "=r"(r2), "=r"(r3) : "r"(addr));
}
__device__ __forceinline__ void ldmx4t(unsigned& r0, unsigned& r1, unsigned& r2, unsigned& r3, unsigned addr) {
    asm volatile("ldmatrix.sync.aligned.m8n8.x4.trans.shared.b16 {%0,%1,%2,%3}, [%4];"
                 : "=r"(r0), "=r"(r1), "=r"(r2), "=r"(r3) : "r"(addr));
}
__device__ __forceinline__ void cpa16(unsigned s, const void* g) {
    asm volatile("cp.async.cg.shared.global [%0], [%1], 16;" :: "r"(s), "l"(g));
}
__device__ __forceinline__ unsigned pack_bf(float a, float b) {
    __nv_bfloat162 t;
    t.x = __float2bfloat16_rn(a);
    t.y = __float2bfloat16_rn(b);
    return *(unsigned*)&t;
}
__device__ __forceinline__ float2 unpack_bf(unsigned u) {
    __nv_bfloat162 t = *(__nv_bfloat162*)&u;
    return make_float2(__bfloat162float(t.x), __bfloat162float(t.y));
}

// ---------------- all weight conversions in one kernel (16 elems/thread) ----------------
__global__ void cvt_all(const float* __restrict__ s0, const float* __restrict__ s1,
                        const float* __restrict__ s2, const float* __restrict__ s3,
                        const float* __restrict__ s4, const float* __restrict__ s5,
                        const float* __restrict__ s6) {
    int w = blockIdx.y;
    const float* src; bf16* dst; int n;
    switch (w) {
        case 0: src = s0; dst = b_wq; n = DIMN*DIMN; break;
        case 1: src = s1; dst = b_wk; n = DIMN*DIMN; break;
        case 2: src = s2; dst = b_wv; n = DIMN*DIMN; break;
        case 3: src = s3; dst = b_wo; n = DIMN*DIMN; break;
        case 4: src = s4; dst = b_w1; n = DIMN*HIDDEN; break;
        case 5: src = s5; dst = b_w3; n = DIMN*HIDDEN; break;
        default: src = s6; dst = b_w2; n = HIDDEN*DIMN; break;
    }
    int i = (blockIdx.x * 256 + threadIdx.x) * 16;
    if (i < n) {
        float4 a = *(const float4*)(src + i);
        float4 b = *(const float4*)(src + i + 4);
        float4 c = *(const float4*)(src + i + 8);
        float4 d = *(const float4*)(src + i + 12);
        uint4 o1, o2;
        o1.x = pack_bf(a.x, a.y); o1.y = pack_bf(a.z, a.w);
        o1.z = pack_bf(b.x, b.y); o1.w = pack_bf(b.z, b.w);
        o2.x = pack_bf(c.x, c.y); o2.y = pack_bf(c.z, c.w);
        o2.z = pack_bf(d.x, d.y); o2.w = pack_bf(d.z, d.w);
        *(uint4*)(dst + i) = o1;
        *(uint4*)(dst + i + 8) = o2;
    }
}

// ---------------- t = silu(adafm_input) @ proj_w + proj_b ----------------
__global__ void proj_t_kernel(const float* __restrict__ ad, const float* __restrict__ pw,
                              const float* __restrict__ pb, float* __restrict__ t) {
    int b = blockIdx.x;
    __shared__ float s[DIMN];
    for (int i = threadIdx.x; i < DIMN; i += blockDim.x) {
        float z = ad[b*DIMN + i];
        s[i] = z / (1.f + expf(-z));
    }
    __syncthreads();
    for (int o = threadIdx.x; o < 512; o += blockDim.x) {
        float acc = pb[o];
        #pragma unroll 4
        for (int i = 0; i < DIMN; i++) acc += s[i] * pw[i*512 + o];
        t[b*512 + o] = acc;
    }
}

// --------- g[d] = (1/256) sum_k m[k] cos(2 pi k d/256); emit Bg[q][t]=g[(t-q)&255] -----
__global__ void make_g_kernel(const float* __restrict__ t) {
    int b = blockIdx.x >> 1, which = blockIdx.x & 1;
    const float* m = t + b*512 + which*256;
    __shared__ float cs[256], ms[256];
    __shared__ bf16 gd[512];
    int d = threadIdx.x;
    cs[d] = cosf((6.283185307179586f / 256.0f) * (float)d);
    ms[d] = m[d];
    __syncthreads();
    float acc = 0.f;
    #pragma unroll 4
    for (int k = 0; k < 256; k++) acc += ms[k] * cs[(k*d) & 255];
    bf16 gv = __float2bfloat16_rn(acc * (1.0f / 256.0f));
    gd[d] = gv; gd[d + 256] = gv;
    __syncthreads();
    bf16* Bg = (which ? b_gf : b_gm) + b * 65536;
    for (int q = 0; q < 256; q++)
        Bg[q*256 + d] = gd[d - q + 256];
}

// ---------------- patchify: x fp32 [B,SEQ,DIM] -> Xp bf16 [B, 8192, 256] ----------------
__global__ void patchify(const float* __restrict__ x) {
    int c = blockIdx.x * 256 + threadIdx.x;
    int q  = (c & 31) * 8;
    int pi = (c >> 5) & 8191;
    int b  = c >> 18;
    int p = q >> 4, qq = q & 15;
    const float* src = x + ((size_t)(b*2048 + (pi >> 6)*16 + p)) * DIMN + (pi & 63)*16 + qq;
    float4 a = *(const float4*)src;
    float4 v = *(const float4*)(src + 4);
    uint4 o;
    o.x = pack_bf(a.x, a.y); o.y = pack_bf(a.z, a.w);
    o.z = pack_bf(v.x, v.y); o.w = pack_bf(v.z, v.w);
    *(uint4*)(b_xp + (size_t)c * 8) = o;
}

// ================= GEMM core macro pieces (block 128x256x32, 8 warps) =================
#define AKE 40
#define BNE 264
#define A_ELT (128*AKE)
#define B_ELT (32*BNE)
#define STG_ELT (A_ELT + B_ELT)
#define GEMM_SMEM (3 * STG_ELT * 2)

#define GEMM_PROLOG(Aptr, Bptr, Kdim, Ndim, bmv, bnv)                                    \
    extern __shared__ bf16 smb[];                                                        \
    const unsigned sbase = (unsigned)__cvta_generic_to_shared(smb);                      \
    const int tid  = threadIdx.x;                                                        \
    const int lane = tid & 31;                                                           \
    const int warp = tid >> 5;                                                           \
    const int g    = lane >> 2;                                                          \
    const int t4   = lane & 3;                                                           \
    const int lm   = lane & 15;                                                          \
    const int lh   = lane >> 4;                                                          \
    const int wm = (warp >> 2) * 64;                                                     \
    const int wn = (warp & 3) * 64;                                                      \
    float acc[4][8][4];                                                                  \
    _Pragma("unroll") for (int i = 0; i < 4; i++)                                        \
        _Pragma("unroll") for (int j = 0; j < 8; j++)                                    \
            _Pragma("unroll") for (int r = 0; r < 4; r++) acc[i][j][r] = 0.f;            \
    const int ktiles = (Kdim) >> 5;                                                      \
    auto load_stage = [&](int st, int k0) {                                              \
        unsigned sa = sbase + (unsigned)(st * STG_ELT) * 2u;                             \
        unsigned sb = sa + A_ELT * 2u;                                                   \
        _Pragma("unroll") for (int u = 0; u < 2; u++) {                                  \
            int c = tid + 256*u;                                                         \
            int r = c >> 2, o = (c & 3) * 8;                                             \
            cpa16(sa + (unsigned)(r*AKE + o)*2u, (Aptr) + (size_t)((bmv) + r) * (Kdim) + k0 + o); \
        }                                                                                \
        _Pragma("unroll") for (int u = 0; u < 4; u++) {                                  \
            int c = tid + 256*u;                                                         \
            int r = c >> 5, o = (c & 31) * 8;                                            \
            cpa16(sb + (unsigned)(r*BNE + o)*2u, (Bptr) + (size_t)(k0 + r) * (Ndim) + (bnv) + o); \
        }                                                                                \
    };                                                                                   \
    load_stage(0, 0);                                                                    \
    asm volatile("cp.async.commit_group;");                                              \
    load_stage(1, 32);                                                                   \
    asm volatile("cp.async.commit_group;");                                              \
    for (int t = 0; t < ktiles; t++) {                                                   \
        asm volatile("cp.async.wait_group 1;");                                          \
        __syncthreads();                                                                 \
        int nt = t + 2;                                                                  \
        if (nt < ktiles) load_stage(nt % 3, nt * 32);                                    \
        asm volatile("cp.async.commit_group;");                                          \
        unsigned sa = sbase + (unsigned)((t % 3) * STG_ELT) * 2u;                        \
        unsigned sb = sa + A_ELT * 2u;                                                   \
        _Pragma("unroll") for (int kk = 0; kk < 32; kk += 16) {                          \
            unsigned af[4][4], bfr[8][2];                                                \
            _Pragma("unroll") for (int i = 0; i < 4; i++)                                \
                ldmx4(af[i][0], af[i][1], af[i][2], af[i][3],                            \
                      sa + (unsigned)((wm + 16*i + lm)*AKE + kk + lh*8)*2u);             \
            _Pragma("unroll") for (int j2 = 0; j2 < 4; j2++)                             \
                ldmx4t(bfr[2*j2][0], bfr[2*j2][1], bfr[2*j2+1][0], bfr[2*j2+1][1],       \
                       sb + (unsigned)((kk + lm)*BNE + wn + 16*j2 + lh*8)*2u);           \
            _Pragma("unroll") for (int i = 0; i < 4; i++)                                \
                _Pragma("unroll") for (int j = 0; j < 8; j++)                            \
                    mma16(acc[i][j], af[i][0], af[i][1], af[i][2], af[i][3],             \
                          bfr[j][0], bfr[j][1]);                                         \
        }                                                                                \
    }

// ---- generic gemm, fp32 out ----
__global__ __launch_bounds__(256, 1) void gemm_bf16(const bf16* __restrict__ A,
                                                    const bf16* __restrict__ B,
                                                    float* __restrict__ Cf,
                                                    int M, int N, int K) {
    const int bm = blockIdx.y * 128;
    const int bn = blockIdx.x * 256;
    GEMM_PROLOG(A, B, K, N, bm, bn)
    #pragma unroll
    for (int i = 0; i < 4; i++) {
        int row0 = bm + wm + 16*i + g;
        #pragma unroll
        for (int j = 0; j < 8; j++) {
            int col = bn + wn + 8*j + 2*t4;
            *(float2*)(Cf + (size_t)row0 * N + col)       = make_float2(acc[i][j][0], acc[i][j][1]);
            *(float2*)(Cf + (size_t)(row0 + 8) * N + col) = make_float2(acc[i][j][2], acc[i][j][3]);
        }
    }
}

// ---- fused QKV gemm + RoPE + head-norm + sqk_eff epilogue ----
// Q additionally scaled by 8*log2(e) so flash can use exp2.
__global__ __launch_bounds__(256, 1) void gemm_qkv(const bf16* __restrict__ A,
                                                   const float* __restrict__ fcos,
                                                   const float* __restrict__ fsin,
                                                   const float* __restrict__ sqk) {
    const int wsel = blockIdx.x >> 2;
    const int bn = (blockIdx.x & 3) * 256;
    const int bm = blockIdx.y * 128;
    const bf16* B = (wsel == 0) ? b_wq : ((wsel == 1) ? b_wk : b_wv);
    bf16* C = (wsel == 0) ? b_q : ((wsel == 1) ? b_k : b_v);
    GEMM_PROLOG(A, B, DIMN, DIMN, bm, bn)
    if (wsel == 2) {
        #pragma unroll
        for (int i = 0; i < 4; i++) {
            int row0 = bm + wm + 16*i + g;
            #pragma unroll
            for (int j = 0; j < 8; j++) {
                int col = bn + wn + 8*j + 2*t4;
                *(unsigned*)(C + (size_t)row0 * DIMN + col)       = pack_bf(acc[i][j][0], acc[i][j][1]);
                *(unsigned*)(C + (size_t)(row0 + 8) * DIMN + col) = pack_bf(acc[i][j][2], acc[i][j][3]);
            }
        }
    } else {
        const int h = (bn + wn) >> 6;          // this warp's 64-col tile == one head
        const float qscale = (wsel == 0) ? 8.f * 1.4426950408889634f : 1.f;
        #pragma unroll
        for (int i = 0; i < 4; i++) {
            int row0 = bm + wm + 16*i + g;
            int row1 = row0 + 8;
            float ss0 = 0.f, ss1 = 0.f;
            #pragma unroll
            for (int j = 0; j < 8; j++) {
                ss0 += acc[i][j][0]*acc[i][j][0] + acc[i][j][1]*acc[i][j][1];
                ss1 += acc[i][j][2]*acc[i][j][2] + acc[i][j][3]*acc[i][j][3];
            }
            // rotation preserves per-pair sum of squares -> norm from pre-rotation accs
            ss0 += __shfl_xor_sync(0xffffffffu, ss0, 1);
            ss0 += __shfl_xor_sync(0xffffffffu, ss0, 2);
            ss1 += __shfl_xor_sync(0xffffffffu, ss1, 1);
            ss1 += __shfl_xor_sync(0xffffffffu, ss1, 2);
            float inv0 = qscale / fmaxf(sqrtf(ss0), 1e-12f);
            float inv1 = qscale / fmaxf(sqrtf(ss1), 1e-12f);
            int s0 = row0 & (SEQL - 1), s1 = row1 & (SEQL - 1);
            #pragma unroll
            for (int j = 0; j < 8; j++) {
                int pidx = 4*j + t4;
                int d = 8*j + 2*t4;
                float se0 = sqk[h*HDIM + d]     * 32.f;
                float se1 = sqk[h*HDIM + d + 1] * 32.f;
                float c0 = fcos[s0*32 + pidx], sn0 = fsin[s0*32 + pidx];
                float c1 = fcos[s1*32 + pidx], sn1 = fsin[s1*32 + pidx];
                float a0 = acc[i][j][0], a1 = acc[i][j][1];
                float b0 = acc[i][j][2], b1 = acc[i][j][3];
                int col = bn + wn + d;
                *(unsigned*)(C + (size_t)row0 * DIMN + col) =
                    pack_bf((a0*c0 - a1*sn0) * inv0 * se0, (a0*sn0 + a1*c0) * inv0 * se1);
                *(unsigned*)(C + (size_t)row1 * DIMN + col) =
                    pack_bf((b0*c1 - b1*sn1) * inv1 * se0, (b0*sn1 + b1*c1) * inv1 * se1);
            }
        }
    }
}

// ---- fused w1/w3 GEMM + silu gate: writes gated h (bf16) only ----
// block 128M x 128N against BOTH w1 and w3; warp tile 64x32 per weight.
__global__ __launch_bounds__(256, 1) void gemm_ffn13g(const bf16* __restrict__ A,
                                                      const float* __restrict__ su,
                                                      const float* __restrict__ sv) {
    const int bnb = blockIdx.x * 128;
    const int bm  = blockIdx.y * 128;
    extern __shared__ bf16 smb[];
    const unsigned sbase = (unsigned)__cvta_generic_to_shared(smb);
    const int tid  = threadIdx.x;
    const int lane = tid & 31;
    const int warp = tid >> 5;
    const int g    = lane >> 2;
    const int t4   = lane & 3;
    const int lm   = lane & 15;
    const int lh   = lane >> 4;
    const int wm = (warp >> 2) * 64;
    const int wn = (warp & 3) * 32;

    float acc1[4][4][4], acc3[4][4][4];
    #pragma unroll
    for (int i = 0; i < 4; i++)
        #pragma unroll
        for (int j = 0; j < 4; j++)
            #pragma unroll
            for (int r = 0; r < 4; r++) { acc1[i][j][r] = 0.f; acc3[i][j][r] = 0.f; }

    const int ktiles = DIMN >> 5;
    auto load_stage = [&](int st, int k0) {
        unsigned sa = sbase + (unsigned)(st * STG_ELT) * 2u;
        unsigned sb = sa + A_ELT * 2u;
        #pragma unroll
        for (int u = 0; u < 2; u++) {
            int c = tid + 256*u;
            int r = c >> 2, o = (c & 3) * 8;
            cpa16(sa + (unsigned)(r*AKE + o)*2u, A + (size_t)(bm + r) * DIMN + k0 + o);
        }
        #pragma unroll
        for (int u = 0; u < 4; u++) {
            int c = tid + 256*u;
            int r = c >> 5, o = (c & 31) * 8;
            const bf16* src = (o < 128)
                ? (b_w1 + (size_t)(k0 + r) * HIDDEN + bnb + o)
                : (b_w3 + (size_t)(k0 + r) * HIDDEN + bnb + o - 128);
            cpa16(sb + (unsigned)(r*BNE + o)*2u, src);
        }
    };
    load_stage(0, 0);
    asm volatile("cp.async.commit_group;");
    load_stage(1, 32);
    asm volatile("cp.async.commit_group;");

    for (int t = 0; t < ktiles; t++) {
        asm volatile("cp.async.wait_group 1;");
        __syncthreads();
        int nt = t + 2;
        if (nt < ktiles) load_stage(nt % 3, nt * 32);
        asm volatile("cp.async.commit_group;");
        unsigned sa = sbase + (unsigned)((t % 3) * STG_ELT) * 2u;
        unsigned sb = sa + A_ELT * 2u;
        #pragma unroll
        for (int kk = 0; kk < 32; kk += 16) {
            unsigned af[4][4], b1f[4][2], b3f[4][2];
            #pragma unroll
            for (int i = 0; i < 4; i++)
                ldmx4(af[i][0], af[i][1], af[i][2], af[i][3],
                      sa + (unsigned)((wm + 16*i + lm)*AKE + kk + lh*8)*2u);
            #pragma unroll
            for (int j2 = 0; j2 < 2; j2++) {
                ldmx4t(b1f[2*j2][0], b1f[2*j2][1], b1f[2*j2+1][0], b1f[2*j2+1][1],
                       sb + (unsigned)((kk + lm)*BNE + wn + 16*j2 + lh*8)*2u);
                ldmx4t(b3f[2*j2][0], b3f[2*j2][1], b3f[2*j2+1][0], b3f[2*j2+1][1],
                       sb + (unsigned)((kk + lm)*BNE + 128 + wn + 16*j2 + lh*8)*2u);
            }
            #pragma unroll
            for (int i = 0; i < 4; i++)
                #pragma unroll
                for (int j = 0; j < 4; j++) {
                    mma16(acc1[i][j], af[i][0], af[i][1], af[i][2], af[i][3], b1f[j][0], b1f[j][1]);
                    mma16(acc3[i][j], af[i][0], af[i][1], af[i][2], af[i][3], b3f[j][0], b3f[j][1]);
                }
        }
    }

    const float SC = 53.06599664568481f;   // sqrt(2816)
    #pragma unroll
    for (int i = 0; i < 4; i++) {
        int row0 = bm + wm + 16*i + g;
        #pragma unroll
        for (int j = 0; j < 4; j++) {
            int col = bnb + wn + 8*j + 2*t4;
            float sv0 = sv[col] * SC, sv1 = sv[col+1] * SC;
            float su0 = su[col],      su1 = su[col+1];
            float z, sgl;
            float outv[4];
            z = acc1[i][j][0] * sv0; sgl = z / (1.f + __expf(-z)); outv[0] = sgl * (acc3[i][j][0] * su0);
            z = acc1[i][j][1] * sv1; sgl = z / (1.f + __expf(-z)); outv[1] = sgl * (acc3[i][j][1] * su1);
            z = acc1[i][j][2] * sv0; sgl = z / (1.f + __expf(-z)); outv[2] = sgl * (acc3[i][j][2] * su0);
            z = acc1[i][j][3] * sv1; sgl = z / (1.f + __expf(-z)); outv[3] = sgl * (acc3[i][j][3] * su1);
            *(unsigned*)(b_h1 + (size_t)row0 * HIDDEN + col)       = pack_bf(outv[0], outv[1]);
            *(unsigned*)(b_h1 + (size_t)(row0 + 8) * HIDDEN + col) = pack_bf(outv[2], outv[3]);
        }
    }
}

// ---- adafm gemm: Y[pi][t] = Xp[pi][:] @ Bg[:][t], scatter to token layout ----
__global__ __launch_bounds__(256, 1) void adafm_gemm(const bf16* __restrict__ Bg0,
                                                     bf16* __restrict__ Y) {
    const int z  = blockIdx.z;
    const int bm = blockIdx.y * 128;
    const int bn = 0;
    const bf16* A = b_xp + (size_t)z * 8192 * 256;
    const bf16* B = Bg0 + (size_t)z * 65536;
    GEMM_PROLOG(A, B, 256, 256, bm, bn)
    bf16* Yb = Y + (size_t)z * 2048 * DIMN;
    #pragma unroll
    for (int i = 0; i < 4; i++) {
        int pi0 = bm + wm + 16*i + g;
        #pragma unroll
        for (int j = 0; j < 8; j++) {
            int col = wn + 8*j + 2*t4;
            int p = col >> 4, qq = col & 15;
            {
                int pi = pi0;
                *(unsigned*)(Yb + (size_t)((pi >> 6)*16 + p) * DIMN + (pi & 63)*16 + qq)
                    = pack_bf(acc[i][j][0], acc[i][j][1]);
            }
            {
                int pi = pi0 + 8;
                *(unsigned*)(Yb + (size_t)((pi >> 6)*16 + p) * DIMN + (pi & 63)*16 + qq)
                    = pack_bf(acc[i][j][2], acc[i][j][3]);
            }
        }
    }
}

// ---------------- FA2 flash attention, cp.async 2-stage K/V pipeline, exp2 ----------------
#define FAE 72
#define FLASH_SMEM (384 * FAE * 2)

__global__ __launch_bounds__(256, 2) void flash_attn(const bf16* __restrict__ Q,
                                                     const bf16* __restrict__ K,
                                                     const bf16* __restrict__ V,
                                                     bf16* __restrict__ O) {
    extern __shared__ bf16 fsm[];
    bf16* Qs = fsm;
    const unsigned sQ  = (unsigned)__cvta_generic_to_shared(Qs);
    const unsigned sK0 = sQ + 128*FAE*2u;
    const unsigned sV0 = sK0 + 2*64*FAE*2u;

    const int q0 = blockIdx.x * 128;
    const int h  = blockIdx.y;
    const int b  = blockIdx.z;
    const bf16* Qb = Q + (size_t)b*SEQL*DIMN + h*HDIM;
    const bf16* Kb = K + (size_t)b*SEQL*DIMN + h*HDIM;
    const bf16* Vb = V + (size_t)b*SEQL*DIMN + h*HDIM;
    bf16*       Ob = O + (size_t)b*SEQL*DIMN + h*HDIM;

    const int tid  = threadIdx.x;
    const int lane = tid & 31;
    const int warp = tid >> 5;
    const int g  = lane >> 2;
    const int t4 = lane & 3;
    const int lm = lane & 15;
    const int lh = lane >> 4;
    const int wm = warp * 16;

    auto loadKV = [&](int st, int k0) {
        unsigned sk = sK0 + (unsigned)st * 64*FAE*2u;
        unsigned sv = sV0 + (unsigned)st * 64*FAE*2u;
        #pragma unroll
        for (int u = 0; u < 2; u++) {
            int c = tid + 256*u;
            int r = c >> 3, ofs = (c & 7) * 8;
            cpa16(sk + (unsigned)(r*FAE + ofs)*2u, Kb + (size_t)(k0 + r)*DIMN + ofs);
            cpa16(sv + (unsigned)(r*FAE + ofs)*2u, Vb + (size_t)(k0 + r)*DIMN + ofs);
        }
    };

    #pragma unroll
    for (int u = 0; u < 4; u++) {
        int c = tid + 256*u;
        int r = c >> 3, ofs = (c & 7) * 8;
        *(uint4*)&Qs[r*FAE + ofs] = *(const uint4*)(Qb + (size_t)(q0 + r)*DIMN + ofs);
    }

    loadKV(0, 0);
    asm volatile("cp.async.commit_group;");

    float o[8][4];
    #pragma unroll
    for (int j = 0; j < 8; j++)
        #pragma unroll
        for (int r = 0; r < 4; r++) o[j][r] = 0.f;
    float m0 = -1e30f, m1 = -1e30f, l0 = 0.f, l1 = 0.f;

    const int NT = SEQL / 64;
    for (int t = 0; t < NT; t++) {
        if (t + 1 < NT) {
            loadKV((t + 1) & 1, (t + 1) * 64);
            asm volatile("cp.async.commit_group;");
            asm volatile("cp.async.wait_group 1;");
        } else {
            asm volatile("cp.async.wait_group 0;");
        }
        __syncthreads();

        const unsigned sK = sK0 + (unsigned)(t & 1) * 64*FAE*2u;
        const unsigned sV = sV0 + (unsigned)(t & 1) * 64*FAE*2u;

        float s[8][4];
        #pragma unroll
        for (int j = 0; j < 8; j++)
            #pragma unroll
            for (int r = 0; r < 4; r++) s[j][r] = 0.f;

        #pragma unroll
        for (int kc = 0; kc < 4; kc++) {
            int kk = 16*kc;
            unsigned a0, a1, a2, a3;
            ldmx4(a0, a1, a2, a3, sQ + (unsigned)((wm + lm)*FAE + kk + lh*8)*2u);
            #pragma unroll
            for (int j2 = 0; j2 < 4; j2++) {
                unsigned r0, r1, r2, r3;
                ldmx4(r0, r1, r2, r3,
                      sK + (unsigned)((16*j2 + (lane & 7) + ((lane >> 4) << 3))*FAE
                                       + kk + (((lane >> 3) & 1) << 3))*2u);
                mma16(s[2*j2],     a0, a1, a2, a3, r0, r1);
                mma16(s[2*j2 + 1], a0, a1, a2, a3, r2, r3);
            }
        }

        float tm0 = -1e30f, tm1 = -1e30f;
        #pragma unroll
        for (int j = 0; j < 8; j++) {
            tm0 = fmaxf(tm0, fmaxf(s[j][0], s[j][1]));
            tm1 = fmaxf(tm1, fmaxf(s[j][2], s[j][3]));
        }
        tm0 = fmaxf(tm0, __shfl_xor_sync(0xffffffffu, tm0, 1));
        tm0 = fmaxf(tm0, __shfl_xor_sync(0xffffffffu, tm0, 2));
        tm1 = fmaxf(tm1, __shfl_xor_sync(0xffffffffu, tm1, 1));
        tm1 = fmaxf(tm1, __shfl_xor_sync(0xffffffffu, tm1, 2));
        float mn0 = fmaxf(m0, tm0), mn1 = fmaxf(m1, tm1);
        float c0 = exp2f(m0 - mn0), c1 = exp2f(m1 - mn1);
        float ps0 = 0.f, ps1 = 0.f;
        #pragma unroll
        for (int j = 0; j < 8; j++) {
            s[j][0] = exp2f(s[j][0] - mn0);
            s[j][1] = exp2f(s[j][1] - mn0);
            s[j][2] = exp2f(s[j][2] - mn1);
            s[j][3] = exp2f(s[j][3] - mn1);
            ps0 += s[j][0] + s[j][1];
            ps1 += s[j][2] + s[j][3];
        }
        ps0 += __shfl_xor_sync(0xffffffffu, ps0, 1);
        ps0 += __shfl_xor_sync(0xffffffffu, ps0, 2);
        ps1 += __shfl_xor_sync(0xffffffffu, ps1, 1);
        ps1 += __shfl_xor_sync(0xffffffffu, ps1, 2);
        l0 = l0 * c0 + ps0;  l1 = l1 * c1 + ps1;
        m0 = mn0;            m1 = mn1;
        #pragma unroll
        for (int j = 0; j < 8; j++) {
            o[j][0] *= c0; o[j][1] *= c0; o[j][2] *= c1; o[j][3] *= c1;
        }

        #pragma unroll
        for (int c = 0; c < 4; c++) {
            unsigned pa0 = pack_bf(s[2*c][0],   s[2*c][1]);
            unsigned pa1 = pack_bf(s[2*c][2],   s[2*c][3]);
            unsigned pa2 = pack_bf(s[2*c+1][0], s[2*c+1][1]);
            unsigned pa3 = pack_bf(s[2*c+1][2], s[2*c+1][3]);
            #pragma unroll
            for (int j2 = 0; j2 < 4; j2++) {
                unsigned r0, r1, r2, r3;
                ldmx4t(r0, r1, r2, r3,
                       sV + (unsigned)((16*c + lm)*FAE + 16*j2 + lh*8)*2u);
                mma16(o[2*j2],     pa0, pa1, pa2, pa3, r0, r1);
                mma16(o[2*j2 + 1], pa0, pa1, pa2, pa3, r2, r3);
            }
        }
        __syncthreads();
    }

    float inv0 = 1.f / l0, inv1 = 1.f / l1;
    #pragma unroll
    for (int j = 0; j < 8; j++) {
        int col = 8*j + 2*t4;
        *(unsigned*)(Ob + (size_t)(q0 + wm + g    )*DIMN + col) = pack_bf(o[j][0]*inv0, o[j][1]*inv0);
        *(unsigned*)(Ob + (size_t)(q0 + wm + g + 8)*DIMN + col) = pack_bf(o[j][2]*inv1, o[j][3]*inv1);
    }
}

// ------- fused residual + norms (fp32); optional bf16 patchified output -------
__global__ __launch_bounds__(256) void residual_norm(const float* __restrict__ xb,
                                                     const float* __restrict__ br,
                                                     const float* __restrict__ alpha,
                                                     float* __restrict__ out,
                                                     bf16* __restrict__ xp) {
    int t = blockIdx.x;
    int tid = threadIdx.x;
    const float* xr = xb + (size_t)t * DIMN;
    const float* rr = br + (size_t)t * DIMN;
    float xv[4], bv[4];
    float ssx = 0.f, ssb = 0.f;
    #pragma unroll
    for (int u = 0; u < 4; u++) {
        int d = tid + u * 256;
        xv[u] = xr[d]; bv[u] = rr[d];
        ssx += xv[u] * xv[u]; ssb += bv[u] * bv[u];
    }
    ssx = blockSum256(ssx);
    ssb = blockSum256(ssb);
    float rx = 1.f / fmaxf(sqrtf(ssx), 1e-12f);
    float rb = 1.f / fmaxf(sqrtf(ssb), 1e-12f);
    float yv[4]; float ssy = 0.f;
    #pragma unroll
    for (int u = 0; u < 4; u++) {
        int d = tid + u * 256;
        float hh = xv[u] * rx;
        float ha = bv[u] * rb;
        float lr = fabsf(alpha[d] * 1.6f);
        float y = hh + lr * (ha - hh);
        yv[u] = y; ssy += y * y;
    }
    ssy = blockSum256(ssy);
    float ry = 1.f / fmaxf(sqrtf(ssy), 1e-12f);
    int b = t >> 11, se = t & 2047;
    int ip = se >> 4, p = se & 15;
    #pragma unroll
    for (int u = 0; u < 4; u++) {
        int d = tid + u * 256;
        float y = yv[u] * ry;
        out[(size_t)t * DIMN + d] = y;
        if (xp) {
            int jj = d >> 4, qq = d & 15;
            xp[((size_t)b*8192 + ip*64 + jj)*256 + p*16 + qq] = __float2bfloat16_rn(y);
        }
    }
}

// ---------------- launch ----------------
extern "C" void kernel_launch(void* const* d_in, const int* in_sizes, int n_in,
                              void* d_out, int out_size) {
    const float* x      = (const float*)d_in[0];
    const float* fcos   = (const float*)d_in[1];
    const float* fsin   = (const float*)d_in[2];
    const float* adafm  = (const float*)d_in[3];
    const float* wq     = (const float*)d_in[4];
    const float* wk     = (const float*)d_in[5];
    const float* wv     = (const float*)d_in[6];
    const float* wo     = (const float*)d_in[7];
    const float* sqk    = (const float*)d_in[8];
    const float* w1     = (const float*)d_in[9];
    const float* w2     = (const float*)d_in[10];
    const float* w3     = (const float*)d_in[11];
    const float* su     = (const float*)d_in[12];
    const float* sv     = (const float*)d_in[13];
    const float* pw     = (const float*)d_in[14];
    const float* pb     = (const float*)d_in[15];
    const float* aalpha = (const float*)d_in[16];
    const float* malpha = (const float*)d_in[17];
    float* out = (float*)d_out;

    float *pt, *pf0, *pf1, *pf2;
    bf16 *pbgm, *pbgf, *pbxa, *pbq, *pbk, *pbv, *pbao, *pbwo, *pbw2, *pbh1, *pbxp;
    cudaGetSymbolAddress((void**)&pt,  d_t);
    cudaGetSymbolAddress((void**)&pf0, d_f0);
    cudaGetSymbolAddress((void**)&pf1, d_f1);
    cudaGetSymbolAddress((void**)&pf2, d_f2);
    cudaGetSymbolAddress((void**)&pbgm, b_gm);
    cudaGetSymbolAddress((void**)&pbgf, b_gf);
    cudaGetSymbolAddress((void**)&pbxa, b_xa);
    cudaGetSymbolAddress((void**)&pbq,  b_q);
    cudaGetSymbolAddress((void**)&pbk,  b_k);
    cudaGetSymbolAddress((void**)&pbv,  b_v);
    cudaGetSymbolAddress((void**)&pbao, b_ao);
    cudaGetSymbolAddress((void**)&pbwo, b_wo);
    cudaGetSymbolAddress((void**)&pbw2, b_w2);
    cudaGetSymbolAddress((void**)&pbh1, b_h1);
    cudaGetSymbolAddress((void**)&pbxp, b_xp);

    cudaFuncSetAttribute(gemm_bf16, cudaFuncAttributeMaxDynamicSharedMemorySize, GEMM_SMEM);
    cudaFuncSetAttribute(gemm_qkv, cudaFuncAttributeMaxDynamicSharedMemorySize, GEMM_SMEM);
    cudaFuncSetAttribute(gemm_ffn13g, cudaFuncAttributeMaxDynamicSharedMemorySize, GEMM_SMEM);
    cudaFuncSetAttribute(adafm_gemm, cudaFuncAttributeMaxDynamicSharedMemorySize, GEMM_SMEM);
    cudaFuncSetAttribute(flash_attn, cudaFuncAttributeMaxDynamicSharedMemorySize, FLASH_SMEM);

    // 0) weight conversions
    cvt_all<<<dim3(704, 7), 256>>>(wq, wk, wv, wo, w1, w3, w2);

    // 1) time-modulation: t, then conv matrices Bg
    proj_t_kernel<<<BATCH, 512>>>(adafm, pw, pb, pt);
    make_g_kernel<<<4, 256>>>(pt);

    // 2) attention branch
    patchify<<<2048, 256>>>(x);
    adafm_gemm<<<dim3(1, 64, 2), 256, GEMM_SMEM>>>(pbgm, pbxa);
    gemm_qkv<<<dim3(12, 32), 256, GEMM_SMEM>>>(pbxa, fcos, fsin, sqk);
    flash_attn<<<dim3(SEQL/128, NHEAD, BATCH), 256, FLASH_SMEM>>>(pbq, pbk, pbv, pbao);
    gemm_bf16<<<dim3(DIMN/256, TOK/128), 256, GEMM_SMEM>>>(pbao, pbwo, pf2, TOK, DIMN, DIMN);
    residual_norm<<<TOK, 256>>>(x, pf2, aalpha, pf0, pbxp);   // x1 + patchified

    // 3) FFN branch
    adafm_gemm<<<dim3(1, 64, 2), 256, GEMM_SMEM>>>(pbgf, pbxa);
    gemm_ffn13g<<<dim3(HIDDEN/128, TOK/128), 256, GEMM_SMEM>>>(pbxa, su, sv);
    gemm_bf16<<<dim3(DIMN/256, TOK/128), 256, GEMM_SMEM>>>(pbh1, pbw2, pf1, TOK, DIMN, HIDDEN);
    residual_norm<<<TOK, 256>>>(pf0, pf1, malpha, out, (bf16*)0);
}

// round 9
// speedup vs baseline: 5.9700x; 1.0050x over previous
#include <cuda_runtime.h>
#include <cuda_bf16.h>
#include <math.h>

typedef __nv_bfloat16 bf16;

#define DIMN   1024
#define NHEAD  16
#define HDIM   64
#define SEQL   2048
#define BATCH  2
#define TOK    4096
#define HIDDEN 2816

// ---------------- scratch ----------------
__device__ float d_t [BATCH*512];
__device__ float d_f0[TOK*DIMN];            // x1
__device__ float d_f1[TOK*DIMN];            // mlp out
__device__ float d_f2[TOK*DIMN];            // attn out

__device__ bf16 b_wq[DIMN*DIMN], b_wk[DIMN*DIMN], b_wv[DIMN*DIMN], b_wo[DIMN*DIMN];
__device__ bf16 b_w1[DIMN*HIDDEN], b_w3[DIMN*HIDDEN], b_w2[HIDDEN*DIMN];
__device__ bf16 b_xp[BATCH*8192*256];       // patchified input
__device__ bf16 b_gm[BATCH*256*256];        // conv matrix, attn branch
__device__ bf16 b_gf[BATCH*256*256];        // conv matrix, mlp branch
__device__ bf16 b_xa[TOK*DIMN];             // adafm out
__device__ bf16 b_q [TOK*DIMN], b_k[TOK*DIMN], b_v[TOK*DIMN], b_ao[TOK*DIMN];
__device__ bf16 b_h1[(size_t)TOK*HIDDEN];

// ---------------- helpers ----------------
__device__ __forceinline__ float blockSum256(float v) {
    __shared__ float red[8];
    int lane = threadIdx.x & 31, wid = threadIdx.x >> 5;
    #pragma unroll
    for (int o = 16; o > 0; o >>= 1) v += __shfl_xor_sync(0xffffffffu, v, o);
    __syncthreads();
    if (lane == 0) red[wid] = v;
    __syncthreads();
    float s = red[0];
    #pragma unroll
    for (int w = 1; w < 8; w++) s += red[w];
    return s;
}

__device__ __forceinline__ void mma16(float* c, unsigned a0, unsigned a1, unsigned a2, unsigned a3,
                                      unsigned b0, unsigned b1) {
    asm volatile(
        "mma.sync.aligned.m16n8k16.row.col.f32.bf16.bf16.f32 "
        "{%0,%1,%2,%3}, {%4,%5,%6,%7}, {%8,%9}, {%0,%1,%2,%3};"
        : "+f"(c[0]), "+f"(c[1]), "+f"(c[2]), "+f"(c[3])
        : "r"(a0), "r"(a1), "r"(a2), "r"(a3), "r"(b0), "r"(b1));
}
__device__ __forceinline__ void ldmx4(unsigned& r0, unsigned& r1, unsigned& r2, unsigned& r3, unsigned addr) {
    asm volatile("ldmatrix.sync.aligned.m8n8.x4.shared.b16 {%0,%1,%2,%3}, [%4];"
                 : "=r"(r0), "=r"(r1), "=r"(r2), "=r"(r3) : "r"(addr));
}
__device__ __forceinline__ void ldmx4t(unsigned& r0, unsigned& r1, unsigned& r2, unsigned& r3, unsigned addr) {
    asm volatile("ldmatrix.sync.aligned.m8n8.x4.trans.shared.b16 {%0,%1,%2,%3}, [%4];"
                 : "=r"(r0), "=r"(r1), "=r"(r2), "=r"(r3) : "r"(addr));
}
__device__ __forceinline__ void cpa16(unsigned s, const void* g) {
    asm volatile("cp.async.cg.shared.global [%0], [%1], 16;" :: "r"(s), "l"(g));
}
__device__ __forceinline__ unsigned pack_bf(float a, float b) {
    __nv_bfloat162 t;
    t.x = __float2bfloat16_rn(a);
    t.y = __float2bfloat16_rn(b);
    return *(unsigned*)&t;
}
__device__ __forceinline__ float2 unpack_bf(unsigned u) {
    __nv_bfloat162 t = *(__nv_bfloat162*)&u;
    return make_float2(__bfloat162float(t.x), __bfloat162float(t.y));
}

// ---------------- all weight conversions in one kernel (16 elems/thread) ----------------
__global__ void cvt_all(const float* __restrict__ s0, const float* __restrict__ s1,
                        const float* __restrict__ s2, const float* __restrict__ s3,
                        const float* __restrict__ s4, const float* __restrict__ s5,
                        const float* __restrict__ s6) {
    int w = blockIdx.y;
    const float* src; bf16* dst; int n;
    switch (w) {
        case 0: src = s0; dst = b_wq; n = DIMN*DIMN; break;
        case 1: src = s1; dst = b_wk; n = DIMN*DIMN; break;
        case 2: src = s2; dst = b_wv; n = DIMN*DIMN; break;
        case 3: src = s3; dst = b_wo; n = DIMN*DIMN; break;
        case 4: src = s4; dst = b_w1; n = DIMN*HIDDEN; break;
        case 5: src = s5; dst = b_w3; n = DIMN*HIDDEN; break;
        default: src = s6; dst = b_w2; n = HIDDEN*DIMN; break;
    }
    int i = (blockIdx.x * 256 + threadIdx.x) * 16;
    if (i < n) {
        float4 a = *(const float4*)(src + i);
        float4 b = *(const float4*)(src + i + 4);
        float4 c = *(const float4*)(src + i + 8);
        float4 d = *(const float4*)(src + i + 12);
        uint4 o1, o2;
        o1.x = pack_bf(a.x, a.y); o1.y = pack_bf(a.z, a.w);
        o1.z = pack_bf(b.x, b.y); o1.w = pack_bf(b.z, b.w);
        o2.x = pack_bf(c.x, c.y); o2.y = pack_bf(c.z, c.w);
        o2.z = pack_bf(d.x, d.y); o2.w = pack_bf(d.z, d.w);
        *(uint4*)(dst + i) = o1;
        *(uint4*)(dst + i + 8) = o2;
    }
}

// ---------------- t = silu(adafm_input) @ proj_w + proj_b ----------------
__global__ void proj_t_kernel(const float* __restrict__ ad, const float* __restrict__ pw,
                              const float* __restrict__ pb, float* __restrict__ t) {
    int b = blockIdx.x;
    __shared__ float s[DIMN];
    for (int i = threadIdx.x; i < DIMN; i += blockDim.x) {
        float z = ad[b*DIMN + i];
        s[i] = z / (1.f + expf(-z));
    }
    __syncthreads();
    for (int o = threadIdx.x; o < 512; o += blockDim.x) {
        float acc = pb[o];
        #pragma unroll 4
        for (int i = 0; i < DIMN; i++) acc += s[i] * pw[i*512 + o];
        t[b*512 + o] = acc;
    }
}

// --------- g[d] = (1/256) sum_k m[k] cos(2 pi k d/256); emit Bg[q][t]=g[(t-q)&255] -----
__global__ void make_g_kernel(const float* __restrict__ t) {
    int b = blockIdx.x >> 1, which = blockIdx.x & 1;
    const float* m = t + b*512 + which*256;
    __shared__ float cs[256], ms[256];
    __shared__ bf16 gd[512];
    int d = threadIdx.x;
    cs[d] = cosf((6.283185307179586f / 256.0f) * (float)d);
    ms[d] = m[d];
    __syncthreads();
    float acc = 0.f;
    #pragma unroll 4
    for (int k = 0; k < 256; k++) acc += ms[k] * cs[(k*d) & 255];
    bf16 gv = __float2bfloat16_rn(acc * (1.0f / 256.0f));
    gd[d] = gv; gd[d + 256] = gv;
    __syncthreads();
    bf16* Bg = (which ? b_gf : b_gm) + b * 65536;
    for (int q = 0; q < 256; q++)
        Bg[q*256 + d] = gd[d - q + 256];
}

// ---------------- patchify: x fp32 [B,SEQ,DIM] -> Xp bf16 [B, 8192, 256] ----------------
__global__ void patchify(const float* __restrict__ x) {
    int c = blockIdx.x * 256 + threadIdx.x;
    int q  = (c & 31) * 8;
    int pi = (c >> 5) & 8191;
    int b  = c >> 18;
    int p = q >> 4, qq = q & 15;
    const float* src = x + ((size_t)(b*2048 + (pi >> 6)*16 + p)) * DIMN + (pi & 63)*16 + qq;
    float4 a = *(const float4*)src;
    float4 v = *(const float4*)(src + 4);
    uint4 o;
    o.x = pack_bf(a.x, a.y); o.y = pack_bf(a.z, a.w);
    o.z = pack_bf(v.x, v.y); o.w = pack_bf(v.z, v.w);
    *(uint4*)(b_xp + (size_t)c * 8) = o;
}

// ================= GEMM core macro pieces (block 128x256x32, 8 warps) =================
#define AKE 40
#define BNE 264
#define A_ELT (128*AKE)
#define B_ELT (32*BNE)
#define STG_ELT (A_ELT + B_ELT)
#define GEMM_SMEM (3 * STG_ELT * 2)

#define GEMM_PROLOG(Aptr, Bptr, Kdim, Ndim, bmv, bnv)                                    \
    extern __shared__ bf16 smb[];                                                        \
    const unsigned sbase = (unsigned)__cvta_generic_to_shared(smb);                      \
    const int tid  = threadIdx.x;                                                        \
    const int lane = tid & 31;                                                           \
    const int warp = tid >> 5;                                                           \
    const int g    = lane >> 2;                                                          \
    const int t4   = lane & 3;                                                           \
    const int lm   = lane & 15;                                                          \
    const int lh   = lane >> 4;                                                          \
    const int wm = (warp >> 2) * 64;                                                     \
    const int wn = (warp & 3) * 64;                                                      \
    float acc[4][8][4];                                                                  \
    _Pragma("unroll") for (int i = 0; i < 4; i++)                                        \
        _Pragma("unroll") for (int j = 0; j < 8; j++)                                    \
            _Pragma("unroll") for (int r = 0; r < 4; r++) acc[i][j][r] = 0.f;            \
    const int ktiles = (Kdim) >> 5;                                                      \
    auto load_stage = [&](int st, int k0) {                                              \
        unsigned sa = sbase + (unsigned)(st * STG_ELT) * 2u;                             \
        unsigned sb = sa + A_ELT * 2u;                                                   \
        _Pragma("unroll") for (int u = 0; u < 2; u++) {                                  \
            int c = tid + 256*u;                                                         \
            int r = c >> 2, o = (c & 3) * 8;                                             \
            cpa16(sa + (unsigned)(r*AKE + o)*2u, (Aptr) + (size_t)((bmv) + r) * (Kdim) + k0 + o); \
        }                                                                                \
        _Pragma("unroll") for (int u = 0; u < 4; u++) {                                  \
            int c = tid + 256*u;                                                         \
            int r = c >> 5, o = (c & 31) * 8;                                            \
            cpa16(sb + (unsigned)(r*BNE + o)*2u, (Bptr) + (size_t)(k0 + r) * (Ndim) + (bnv) + o); \
        }                                                                                \
    };                                                                                   \
    load_stage(0, 0);                                                                    \
    asm volatile("cp.async.commit_group;");                                              \
    load_stage(1, 32);                                                                   \
    asm volatile("cp.async.commit_group;");                                              \
    for (int t = 0; t < ktiles; t++) {                                                   \
        asm volatile("cp.async.wait_group 1;");                                          \
        __syncthreads();                                                                 \
        int nt = t + 2;                                                                  \
        if (nt < ktiles) load_stage(nt % 3, nt * 32);                                    \
        asm volatile("cp.async.commit_group;");                                          \
        unsigned sa = sbase + (unsigned)((t % 3) * STG_ELT) * 2u;                        \
        unsigned sb = sa + A_ELT * 2u;                                                   \
        _Pragma("unroll") for (int kk = 0; kk < 32; kk += 16) {                          \
            unsigned af[4][4], bfr[8][2];                                                \
            _Pragma("unroll") for (int i = 0; i < 4; i++)                                \
                ldmx4(af[i][0], af[i][1], af[i][2], af[i][3],                            \
                      sa + (unsigned)((wm + 16*i + lm)*AKE + kk + lh*8)*2u);             \
            _Pragma("unroll") for (int j2 = 0; j2 < 4; j2++)                             \
                ldmx4t(bfr[2*j2][0], bfr[2*j2][1], bfr[2*j2+1][0], bfr[2*j2+1][1],       \
                       sb + (unsigned)((kk + lm)*BNE + wn + 16*j2 + lh*8)*2u);           \
            _Pragma("unroll") for (int i = 0; i < 4; i++)                                \
                _Pragma("unroll") for (int j = 0; j < 8; j++)                            \
                    mma16(acc[i][j], af[i][0], af[i][1], af[i][2], af[i][3],             \
                          bfr[j][0], bfr[j][1]);                                         \
        }                                                                                \
    }

// ---- generic gemm, fp32 out ----
__global__ __launch_bounds__(256, 1) void gemm_bf16(const bf16* __restrict__ A,
                                                    const bf16* __restrict__ B,
                                                    float* __restrict__ Cf,
                                                    int M, int N, int K) {
    const int bm = blockIdx.y * 128;
    const int bn = blockIdx.x * 256;
    GEMM_PROLOG(A, B, K, N, bm, bn)
    #pragma unroll
    for (int i = 0; i < 4; i++) {
        int row0 = bm + wm + 16*i + g;
        #pragma unroll
        for (int j = 0; j < 8; j++) {
            int col = bn + wn + 8*j + 2*t4;
            *(float2*)(Cf + (size_t)row0 * N + col)       = make_float2(acc[i][j][0], acc[i][j][1]);
            *(float2*)(Cf + (size_t)(row0 + 8) * N + col) = make_float2(acc[i][j][2], acc[i][j][3]);
        }
    }
}

// ---- fused QKV gemm + RoPE + head-norm + sqk_eff epilogue ----
// Q additionally scaled by 8*log2(e) so flash can use exp2.
__global__ __launch_bounds__(256, 1) void gemm_qkv(const bf16* __restrict__ A,
                                                   const float* __restrict__ fcos,
                                                   const float* __restrict__ fsin,
                                                   const float* __restrict__ sqk) {
    const int wsel = blockIdx.x >> 2;
    const int bn = (blockIdx.x & 3) * 256;
    const int bm = blockIdx.y * 128;
    const bf16* B = (wsel == 0) ? b_wq : ((wsel == 1) ? b_wk : b_wv);
    bf16* C = (wsel == 0) ? b_q : ((wsel == 1) ? b_k : b_v);
    GEMM_PROLOG(A, B, DIMN, DIMN, bm, bn)
    if (wsel == 2) {
        #pragma unroll
        for (int i = 0; i < 4; i++) {
            int row0 = bm + wm + 16*i + g;
            #pragma unroll
            for (int j = 0; j < 8; j++) {
                int col = bn + wn + 8*j + 2*t4;
                *(unsigned*)(C + (size_t)row0 * DIMN + col)       = pack_bf(acc[i][j][0], acc[i][j][1]);
                *(unsigned*)(C + (size_t)(row0 + 8) * DIMN + col) = pack_bf(acc[i][j][2], acc[i][j][3]);
            }
        }
    } else {
        const int h = (bn + wn) >> 6;          // this warp's 64-col tile == one head
        const float qscale = (wsel == 0) ? 8.f * 1.4426950408889634f : 1.f;
        #pragma unroll
        for (int i = 0; i < 4; i++) {
            int row0 = bm + wm + 16*i + g;
            int row1 = row0 + 8;
            float ss0 = 0.f, ss1 = 0.f;
            #pragma unroll
            for (int j = 0; j < 8; j++) {
                ss0 += acc[i][j][0]*acc[i][j][0] + acc[i][j][1]*acc[i][j][1];
                ss1 += acc[i][j][2]*acc[i][j][2] + acc[i][j][3]*acc[i][j][3];
            }
            // rotation preserves per-pair sum of squares -> norm from pre-rotation accs
            ss0 += __shfl_xor_sync(0xffffffffu, ss0, 1);
            ss0 += __shfl_xor_sync(0xffffffffu, ss0, 2);
            ss1 += __shfl_xor_sync(0xffffffffu, ss1, 1);
            ss1 += __shfl_xor_sync(0xffffffffu, ss1, 2);
            float inv0 = qscale / fmaxf(sqrtf(ss0), 1e-12f);
            float inv1 = qscale / fmaxf(sqrtf(ss1), 1e-12f);
            int s0 = row0 & (SEQL - 1), s1 = row1 & (SEQL - 1);
            #pragma unroll
            for (int j = 0; j < 8; j++) {
                int pidx = 4*j + t4;
                int d = 8*j + 2*t4;
                float se0 = sqk[h*HDIM + d]     * 32.f;
                float se1 = sqk[h*HDIM + d + 1] * 32.f;
                float c0 = fcos[s0*32 + pidx], sn0 = fsin[s0*32 + pidx];
                float c1 = fcos[s1*32 + pidx], sn1 = fsin[s1*32 + pidx];
                float a0 = acc[i][j][0], a1 = acc[i][j][1];
                float b0 = acc[i][j][2], b1 = acc[i][j][3];
                int col = bn + wn + d;
                *(unsigned*)(C + (size_t)row0 * DIMN + col) =
                    pack_bf((a0*c0 - a1*sn0) * inv0 * se0, (a0*sn0 + a1*c0) * inv0 * se1);
                *(unsigned*)(C + (size_t)row1 * DIMN + col) =
                    pack_bf((b0*c1 - b1*sn1) * inv1 * se0, (b0*sn1 + b1*c1) * inv1 * se1);
            }
        }
    }
}

// ---- fused w1/w3 GEMM + silu gate: writes gated h (bf16) only ----
// block 128M x 128N against BOTH w1 and w3; warp tile 64x32 per weight.
__global__ __launch_bounds__(256, 1) void gemm_ffn13g(const bf16* __restrict__ A,
                                                      const float* __restrict__ su,
                                                      const float* __restrict__ sv) {
    const int bnb = blockIdx.x * 128;
    const int bm  = blockIdx.y * 128;
    extern __shared__ bf16 smb[];
    const unsigned sbase = (unsigned)__cvta_generic_to_shared(smb);
    const int tid  = threadIdx.x;
    const int lane = tid & 31;
    const int warp = tid >> 5;
    const int g    = lane >> 2;
    const int t4   = lane & 3;
    const int lm   = lane & 15;
    const int lh   = lane >> 4;
    const int wm = (warp >> 2) * 64;
    const int wn = (warp & 3) * 32;

    float acc1[4][4][4], acc3[4][4][4];
    #pragma unroll
    for (int i = 0; i < 4; i++)
        #pragma unroll
        for (int j = 0; j < 4; j++)
            #pragma unroll
            for (int r = 0; r < 4; r++) { acc1[i][j][r] = 0.f; acc3[i][j][r] = 0.f; }

    const int ktiles = DIMN >> 5;
    auto load_stage = [&](int st, int k0) {
        unsigned sa = sbase + (unsigned)(st * STG_ELT) * 2u;
        unsigned sb = sa + A_ELT * 2u;
        #pragma unroll
        for (int u = 0; u < 2; u++) {
            int c = tid + 256*u;
            int r = c >> 2, o = (c & 3) * 8;
            cpa16(sa + (unsigned)(r*AKE + o)*2u, A + (size_t)(bm + r) * DIMN + k0 + o);
        }
        #pragma unroll
        for (int u = 0; u < 4; u++) {
            int c = tid + 256*u;
            int r = c >> 5, o = (c & 31) * 8;
            const bf16* src = (o < 128)
                ? (b_w1 + (size_t)(k0 + r) * HIDDEN + bnb + o)
                : (b_w3 + (size_t)(k0 + r) * HIDDEN + bnb + o - 128);
            cpa16(sb + (unsigned)(r*BNE + o)*2u, src);
        }
    };
    load_stage(0, 0);
    asm volatile("cp.async.commit_group;");
    load_stage(1, 32);
    asm volatile("cp.async.commit_group;");

    for (int t = 0; t < ktiles; t++) {
        asm volatile("cp.async.wait_group 1;");
        __syncthreads();
        int nt = t + 2;
        if (nt < ktiles) load_stage(nt % 3, nt * 32);
        asm volatile("cp.async.commit_group;");
        unsigned sa = sbase + (unsigned)((t % 3) * STG_ELT) * 2u;
        unsigned sb = sa + A_ELT * 2u;
        #pragma unroll
        for (int kk = 0; kk < 32; kk += 16) {
            unsigned af[4][4], b1f[4][2], b3f[4][2];
            #pragma unroll
            for (int i = 0; i < 4; i++)
                ldmx4(af[i][0], af[i][1], af[i][2], af[i][3],
                      sa + (unsigned)((wm + 16*i + lm)*AKE + kk + lh*8)*2u);
            #pragma unroll
            for (int j2 = 0; j2 < 2; j2++) {
                ldmx4t(b1f[2*j2][0], b1f[2*j2][1], b1f[2*j2+1][0], b1f[2*j2+1][1],
                       sb + (unsigned)((kk + lm)*BNE + wn + 16*j2 + lh*8)*2u);
                ldmx4t(b3f[2*j2][0], b3f[2*j2][1], b3f[2*j2+1][0], b3f[2*j2+1][1],
                       sb + (unsigned)((kk + lm)*BNE + 128 + wn + 16*j2 + lh*8)*2u);
            }
            #pragma unroll
            for (int i = 0; i < 4; i++)
                #pragma unroll
                for (int j = 0; j < 4; j++) {
                    mma16(acc1[i][j], af[i][0], af[i][1], af[i][2], af[i][3], b1f[j][0], b1f[j][1]);
                    mma16(acc3[i][j], af[i][0], af[i][1], af[i][2], af[i][3], b3f[j][0], b3f[j][1]);
                }
        }
    }

    const float SC = 53.06599664568481f;   // sqrt(2816)
    #pragma unroll
    for (int i = 0; i < 4; i++) {
        int row0 = bm + wm + 16*i + g;
        #pragma unroll
        for (int j = 0; j < 4; j++) {
            int col = bnb + wn + 8*j + 2*t4;
            float sv0 = sv[col] * SC, sv1 = sv[col+1] * SC;
            float su0 = su[col],      su1 = su[col+1];
            float z, sgl;
            float outv[4];
            z = acc1[i][j][0] * sv0; sgl = z / (1.f + __expf(-z)); outv[0] = sgl * (acc3[i][j][0] * su0);
            z = acc1[i][j][1] * sv1; sgl = z / (1.f + __expf(-z)); outv[1] = sgl * (acc3[i][j][1] * su1);
            z = acc1[i][j][2] * sv0; sgl = z / (1.f + __expf(-z)); outv[2] = sgl * (acc3[i][j][2] * su0);
            z = acc1[i][j][3] * sv1; sgl = z / (1.f + __expf(-z)); outv[3] = sgl * (acc3[i][j][3] * su1);
            *(unsigned*)(b_h1 + (size_t)row0 * HIDDEN + col)       = pack_bf(outv[0], outv[1]);
            *(unsigned*)(b_h1 + (size_t)(row0 + 8) * HIDDEN + col) = pack_bf(outv[2], outv[3]);
        }
    }
}

// ---- adafm gemm: Y[pi][t] = Xp[pi][:] @ Bg[:][t], scatter to token layout ----
__global__ __launch_bounds__(256, 1) void adafm_gemm(const bf16* __restrict__ Bg0,
                                                     bf16* __restrict__ Y) {
    const int z  = blockIdx.z;
    const int bm = blockIdx.y * 128;
    const int bn = 0;
    const bf16* A = b_xp + (size_t)z * 8192 * 256;
    const bf16* B = Bg0 + (size_t)z * 65536;
    GEMM_PROLOG(A, B, 256, 256, bm, bn)
    bf16* Yb = Y + (size_t)z * 2048 * DIMN;
    #pragma unroll
    for (int i = 0; i < 4; i++) {
        int pi0 = bm + wm + 16*i + g;
        #pragma unroll
        for (int j = 0; j < 8; j++) {
            int col = wn + 8*j + 2*t4;
            int p = col >> 4, qq = col & 15;
            {
                int pi = pi0;
                *(unsigned*)(Yb + (size_t)((pi >> 6)*16 + p) * DIMN + (pi & 63)*16 + qq)
                    = pack_bf(acc[i][j][0], acc[i][j][1]);
            }
            {
                int pi = pi0 + 8;
                *(unsigned*)(Yb + (size_t)((pi >> 6)*16 + p) * DIMN + (pi & 63)*16 + qq)
                    = pack_bf(acc[i][j][2], acc[i][j][3]);
            }
        }
    }
}

// ---------------- FA2 flash attention, cp.async 2-stage K/V pipeline, exp2 ----------------
#define FAE 72
#define FLASH_SMEM (384 * FAE * 2)

__global__ __launch_bounds__(256, 2) void flash_attn(const bf16* __restrict__ Q,
                                                     const bf16* __restrict__ K,
                                                     const bf16* __restrict__ V,
                                                     bf16* __restrict__ O) {
    extern __shared__ bf16 fsm[];
    bf16* Qs = fsm;
    const unsigned sQ  = (unsigned)__cvta_generic_to_shared(Qs);
    const unsigned sK0 = sQ + 128*FAE*2u;
    const unsigned sV0 = sK0 + 2*64*FAE*2u;

    const int q0 = blockIdx.x * 128;
    const int h  = blockIdx.y;
    const int b  = blockIdx.z;
    const bf16* Qb = Q + (size_t)b*SEQL*DIMN + h*HDIM;
    const bf16* Kb = K + (size_t)b*SEQL*DIMN + h*HDIM;
    const bf16* Vb = V + (size_t)b*SEQL*DIMN + h*HDIM;
    bf16*       Ob = O + (size_t)b*SEQL*DIMN + h*HDIM;

    const int tid  = threadIdx.x;
    const int lane = tid & 31;
    const int warp = tid >> 5;
    const int g  = lane >> 2;
    const int t4 = lane & 3;
    const int lm = lane & 15;
    const int lh = lane >> 4;
    const int wm = warp * 16;

    auto loadKV = [&](int st, int k0) {
        unsigned sk = sK0 + (unsigned)st * 64*FAE*2u;
        unsigned sv = sV0 + (unsigned)st * 64*FAE*2u;
        #pragma unroll
        for (int u = 0; u < 2; u++) {
            int c = tid + 256*u;
            int r = c >> 3, ofs = (c & 7) * 8;
            cpa16(sk + (unsigned)(r*FAE + ofs)*2u, Kb + (size_t)(k0 + r)*DIMN + ofs);
            cpa16(sv + (unsigned)(r*FAE + ofs)*2u, Vb + (size_t)(k0 + r)*DIMN + ofs);
        }
    };

    #pragma unroll
    for (int u = 0; u < 4; u++) {
        int c = tid + 256*u;
        int r = c >> 3, ofs = (c & 7) * 8;
        *(uint4*)&Qs[r*FAE + ofs] = *(const uint4*)(Qb + (size_t)(q0 + r)*DIMN + ofs);
    }

    loadKV(0, 0);
    asm volatile("cp.async.commit_group;");

    float o[8][4];
    #pragma unroll
    for (int j = 0; j < 8; j++)
        #pragma unroll
        for (int r = 0; r < 4; r++) o[j][r] = 0.f;
    float m0 = -1e30f, m1 = -1e30f, l0 = 0.f, l1 = 0.f;

    const int NT = SEQL / 64;
    for (int t = 0; t < NT; t++) {
        if (t + 1 < NT) {
            loadKV((t + 1) & 1, (t + 1) * 64);
            asm volatile("cp.async.commit_group;");
            asm volatile("cp.async.wait_group 1;");
        } else {
            asm volatile("cp.async.wait_group 0;");
        }
        __syncthreads();

        const unsigned sK = sK0 + (unsigned)(t & 1) * 64*FAE*2u;
        const unsigned sV = sV0 + (unsigned)(t & 1) * 64*FAE*2u;

        float s[8][4];
        #pragma unroll
        for (int j = 0; j < 8; j++)
            #pragma unroll
            for (int r = 0; r < 4; r++) s[j][r] = 0.f;

        #pragma unroll
        for (int kc = 0; kc < 4; kc++) {
            int kk = 16*kc;
            unsigned a0, a1, a2, a3;
            ldmx4(a0, a1, a2, a3, sQ + (unsigned)((wm + lm)*FAE + kk + lh*8)*2u);
            #pragma unroll
            for (int j2 = 0; j2 < 4; j2++) {
                unsigned r0, r1, r2, r3;
                ldmx4(r0, r1, r2, r3,
                      sK + (unsigned)((16*j2 + (lane & 7) + ((lane >> 4) << 3))*FAE
                                       + kk + (((lane >> 3) & 1) << 3))*2u);
                mma16(s[2*j2],     a0, a1, a2, a3, r0, r1);
                mma16(s[2*j2 + 1], a0, a1, a2, a3, r2, r3);
            }
        }

        float tm0 = -1e30f, tm1 = -1e30f;
        #pragma unroll
        for (int j = 0; j < 8; j++) {
            tm0 = fmaxf(tm0, fmaxf(s[j][0], s[j][1]));
            tm1 = fmaxf(tm1, fmaxf(s[j][2], s[j][3]));
        }
        tm0 = fmaxf(tm0, __shfl_xor_sync(0xffffffffu, tm0, 1));
        tm0 = fmaxf(tm0, __shfl_xor_sync(0xffffffffu, tm0, 2));
        tm1 = fmaxf(tm1, __shfl_xor_sync(0xffffffffu, tm1, 1));
        tm1 = fmaxf(tm1, __shfl_xor_sync(0xffffffffu, tm1, 2));
        float mn0 = fmaxf(m0, tm0), mn1 = fmaxf(m1, tm1);
        float c0 = exp2f(m0 - mn0), c1 = exp2f(m1 - mn1);
        float ps0 = 0.f, ps1 = 0.f;
        #pragma unroll
        for (int j = 0; j < 8; j++) {
            s[j][0] = exp2f(s[j][0] - mn0);
            s[j][1] = exp2f(s[j][1] - mn0);
            s[j][2] = exp2f(s[j][2] - mn1);
            s[j][3] = exp2f(s[j][3] - mn1);
            ps0 += s[j][0] + s[j][1];
            ps1 += s[j][2] + s[j][3];
        }
        ps0 += __shfl_xor_sync(0xffffffffu, ps0, 1);
        ps0 += __shfl_xor_sync(0xffffffffu, ps0, 2);
        ps1 += __shfl_xor_sync(0xffffffffu, ps1, 1);
        ps1 += __shfl_xor_sync(0xffffffffu, ps1, 2);
        l0 = l0 * c0 + ps0;  l1 = l1 * c1 + ps1;
        m0 = mn0;            m1 = mn1;
        #pragma unroll
        for (int j = 0; j < 8; j++) {
            o[j][0] *= c0; o[j][1] *= c0; o[j][2] *= c1; o[j][3] *= c1;
        }

        #pragma unroll
        for (int c = 0; c < 4; c++) {
            unsigned pa0 = pack_bf(s[2*c][0],   s[2*c][1]);
            unsigned pa1 = pack_bf(s[2*c][2],   s[2*c][3]);
            unsigned pa2 = pack_bf(s[2*c+1][0], s[2*c+1][1]);
            unsigned pa3 = pack_bf(s[2*c+1][2], s[2*c+1][3]);
            #pragma unroll
            for (int j2 = 0; j2 < 4; j2++) {
                unsigned r0, r1, r2, r3;
                ldmx4t(r0, r1, r2, r3,
                       sV + (unsigned)((16*c + lm)*FAE + 16*j2 + lh*8)*2u);
                mma16(o[2*j2],     pa0, pa1, pa2, pa3, r0, r1);
                mma16(o[2*j2 + 1], pa0, pa1, pa2, pa3, r2, r3);
            }
        }
        __syncthreads();
    }

    float inv0 = 1.f / l0, inv1 = 1.f / l1;
    #pragma unroll
    for (int j = 0; j < 8; j++) {
        int col = 8*j + 2*t4;
        *(unsigned*)(Ob + (size_t)(q0 + wm + g    )*DIMN + col) = pack_bf(o[j][0]*inv0, o[j][1]*inv0);
        *(unsigned*)(Ob + (size_t)(q0 + wm + g + 8)*DIMN + col) = pack_bf(o[j][2]*inv1, o[j][3]*inv1);
    }
}

// ------- fused residual + norms (fp32); optional bf16 patchified output -------
__global__ __launch_bounds__(256) void residual_norm(const float* __restrict__ xb,
                                                     const float* __restrict__ br,
                                                     const float* __restrict__ alpha,
                                                     float* __restrict__ out,
                                                     bf16* __restrict__ xp) {
    int t = blockIdx.x;
    int tid = threadIdx.x;
    const float* xr = xb + (size_t)t * DIMN;
    const float* rr = br + (size_t)t * DIMN;
    float xv[4], bv[4];
    float ssx = 0.f, ssb = 0.f;
    #pragma unroll
    for (int u = 0; u < 4; u++) {
        int d = tid + u * 256;
        xv[u] = xr[d]; bv[u] = rr[d];
        ssx += xv[u] * xv[u]; ssb += bv[u] * bv[u];
    }
    ssx = blockSum256(ssx);
    ssb = blockSum256(ssb);
    float rx = 1.f / fmaxf(sqrtf(ssx), 1e-12f);
    float rb = 1.f / fmaxf(sqrtf(ssb), 1e-12f);
    float yv[4]; float ssy = 0.f;
    #pragma unroll
    for (int u = 0; u < 4; u++) {
        int d = tid + u * 256;
        float hh = xv[u] * rx;
        float ha = bv[u] * rb;
        float lr = fabsf(alpha[d] * 1.6f);
        float y = hh + lr * (ha - hh);
        yv[u] = y; ssy += y * y;
    }
    ssy = blockSum256(ssy);
    float ry = 1.f / fmaxf(sqrtf(ssy), 1e-12f);
    int b = t >> 11, se = t & 2047;
    int ip = se >> 4, p = se & 15;
    #pragma unroll
    for (int u = 0; u < 4; u++) {
        int d = tid + u * 256;
        float y = yv[u] * ry;
        out[(size_t)t * DIMN + d] = y;
        if (xp) {
            int jj = d >> 4, qq = d & 15;
            xp[((size_t)b*8192 + ip*64 + jj)*256 + p*16 + qq] = __float2bfloat16_rn(y);
        }
    }
}

// ---------------- launch ----------------
extern "C" void kernel_launch(void* const* d_in, const int* in_sizes, int n_in,
                              void* d_out, int out_size) {
    const float* x      = (const float*)d_in[0];
    const float* fcos   = (const float*)d_in[1];
    const float* fsin   = (const float*)d_in[2];
    const float* adafm  = (const float*)d_in[3];
    const float* wq     = (const float*)d_in[4];
    const float* wk     = (const float*)d_in[5];
    const float* wv     = (const float*)d_in[6];
    const float* wo     = (const float*)d_in[7];
    const float* sqk    = (const float*)d_in[8];
    const float* w1     = (const float*)d_in[9];
    const float* w2     = (const float*)d_in[10];
    const float* w3     = (const float*)d_in[11];
    const float* su     = (const float*)d_in[12];
    const float* sv     = (const float*)d_in[13];
    const float* pw     = (const float*)d_in[14];
    const float* pb     = (const float*)d_in[15];
    const float* aalpha = (const float*)d_in[16];
    const float* malpha = (const float*)d_in[17];
    float* out = (float*)d_out;

    float *pt, *pf0, *pf1, *pf2;
    bf16 *pbgm, *pbgf, *pbxa, *pbq, *pbk, *pbv, *pbao, *pbwo, *pbw2, *pbh1, *pbxp;
    cudaGetSymbolAddress((void**)&pt,  d_t);
    cudaGetSymbolAddress((void**)&pf0, d_f0);
    cudaGetSymbolAddress((void**)&pf1, d_f1);
    cudaGetSymbolAddress((void**)&pf2, d_f2);
    cudaGetSymbolAddress((void**)&pbgm, b_gm);
    cudaGetSymbolAddress((void**)&pbgf, b_gf);
    cudaGetSymbolAddress((void**)&pbxa, b_xa);
    cudaGetSymbolAddress((void**)&pbq,  b_q);
    cudaGetSymbolAddress((void**)&pbk,  b_k);
    cudaGetSymbolAddress((void**)&pbv,  b_v);
    cudaGetSymbolAddress((void**)&pbao, b_ao);
    cudaGetSymbolAddress((void**)&pbwo, b_wo);
    cudaGetSymbolAddress((void**)&pbw2, b_w2);
    cudaGetSymbolAddress((void**)&pbh1, b_h1);
    cudaGetSymbolAddress((void**)&pbxp, b_xp);

    cudaFuncSetAttribute(gemm_bf16, cudaFuncAttributeMaxDynamicSharedMemorySize, GEMM_SMEM);
    cudaFuncSetAttribute(gemm_qkv, cudaFuncAttributeMaxDynamicSharedMemorySize, GEMM_SMEM);
    cudaFuncSetAttribute(gemm_ffn13g, cudaFuncAttributeMaxDynamicSharedMemorySize, GEMM_SMEM);
    cudaFuncSetAttribute(adafm_gemm, cudaFuncAttributeMaxDynamicSharedMemorySize, GEMM_SMEM);
    cudaFuncSetAttribute(flash_attn, cudaFuncAttributeMaxDynamicSharedMemorySize, FLASH_SMEM);

    // 0) weight conversions
    cvt_all<<<dim3(704, 7), 256>>>(wq, wk, wv, wo, w1, w3, w2);

    // 1) time-modulation: t, then conv matrices Bg
    proj_t_kernel<<<BATCH, 512>>>(adafm, pw, pb, pt);
    make_g_kernel<<<4, 256>>>(pt);

    // 2) attention branch
    patchify<<<2048, 256>>>(x);
    adafm_gemm<<<dim3(1, 64, 2), 256, GEMM_SMEM>>>(pbgm, pbxa);
    gemm_qkv<<<dim3(12, 32), 256, GEMM_SMEM>>>(pbxa, fcos, fsin, sqk);
    flash_attn<<<dim3(SEQL/128, NHEAD, BATCH), 256, FLASH_SMEM>>>(pbq, pbk, pbv, pbao);
    gemm_bf16<<<dim3(DIMN/256, TOK/128), 256, GEMM_SMEM>>>(pbao, pbwo, pf2, TOK, DIMN, DIMN);
    residual_norm<<<TOK, 256>>>(x, pf2, aalpha, pf0, pbxp);   // x1 + patchified

    // 3) FFN branch
    adafm_gemm<<<dim3(1, 64, 2), 256, GEMM_SMEM>>>(pbgf, pbxa);
    gemm_ffn13g<<<dim3(HIDDEN/128, TOK/128), 256, GEMM_SMEM>>>(pbxa, su, sv);
    gemm_bf16<<<dim3(DIMN/256, TOK/128), 256, GEMM_SMEM>>>(pbh1, pbw2, pf1, TOK, DIMN, HIDDEN);
    residual_norm<<<TOK, 256>>>(pf0, pf1, malpha, out, (bf16*)0);
}

// round 11
// speedup vs baseline: 6.9411x; 1.1627x over previous
#include <cuda_runtime.h>
#include <cuda_bf16.h>
#include <math.h>

typedef __nv_bfloat16 bf16;

#define DIMN   1024
#define NHEAD  16
#define HDIM   64
#define SEQL   2048
#define BATCH  2
#define TOK    4096
#define HIDDEN 2816

// ---------------- scratch ----------------
__device__ float d_t [BATCH*512];
__device__ float d_f0[TOK*DIMN];            // x1
__device__ float d_f1[TOK*DIMN];            // mlp out
__device__ float d_f2[TOK*DIMN];            // attn out

__device__ bf16 b_wq[DIMN*DIMN], b_wk[DIMN*DIMN], b_wv[DIMN*DIMN], b_wo[DIMN*DIMN];
__device__ bf16 b_w1[DIMN*HIDDEN], b_w3[DIMN*HIDDEN], b_w2[HIDDEN*DIMN];
__device__ bf16 b_xp[BATCH*8192*256];       // patchified input
__device__ bf16 b_gm[BATCH*256*256];        // conv matrix, attn branch
__device__ bf16 b_gf[BATCH*256*256];        // conv matrix, mlp branch
__device__ bf16 b_xa[TOK*DIMN];             // adafm out
__device__ bf16 b_q [TOK*DIMN], b_k[TOK*DIMN], b_v[TOK*DIMN], b_ao[TOK*DIMN];
__device__ bf16 b_h1[(size_t)TOK*HIDDEN];

// ---------------- helpers ----------------
__device__ __forceinline__ float blockSum256(float v) {
    __shared__ float red[8];
    int lane = threadIdx.x & 31, wid = threadIdx.x >> 5;
    #pragma unroll
    for (int o = 16; o > 0; o >>= 1) v += __shfl_xor_sync(0xffffffffu, v, o);
    __syncthreads();
    if (lane == 0) red[wid] = v;
    __syncthreads();
    float s = red[0];
    #pragma unroll
    for (int w = 1; w < 8; w++) s += red[w];
    return s;
}

__device__ __forceinline__ void mma16(float* c, unsigned a0, unsigned a1, unsigned a2, unsigned a3,
                                      unsigned b0, unsigned b1) {
    asm volatile(
        "mma.sync.aligned.m16n8k16.row.col.f32.bf16.bf16.f32 "
        "{%0,%1,%2,%3}, {%4,%5,%6,%7}, {%8,%9}, {%0,%1,%2,%3};"
        : "+f"(c[0]), "+f"(c[1]), "+f"(c[2]), "+f"(c[3])
        : "r"(a0), "r"(a1), "r"(a2), "r"(a3), "r"(b0), "r"(b1));
}
__device__ __forceinline__ void ldmx4(unsigned& r0, unsigned& r1, unsigned& r2, unsigned& r3, unsigned addr) {
    asm volatile("ldmatrix.sync.aligned.m8n8.x4.shared.b16 {%0,%1,%2,%3}, [%4];"
                 : "=r"(r0), "=r"(r1), "=r"(r2), "=r"(r3) : "r"(addr));
}
__device__ __forceinline__ void ldmx4t(unsigned& r0, unsigned& r1, unsigned& r2, unsigned& r3, unsigned addr) {
    asm volatile("ldmatrix.sync.aligned.m8n8.x4.trans.shared.b16 {%0,%1,%2,%3}, [%4];"
                 : "=r"(r0), "=r"(r1), "=r"(r2), "=r"(r3) : "r"(addr));
}
__device__ __forceinline__ void cpa16(unsigned s, const void* g) {
    asm volatile("cp.async.cg.shared.global [%0], [%1], 16;" :: "r"(s), "l"(g));
}
__device__ __forceinline__ unsigned pack_bf(float a, float b) {
    __nv_bfloat162 t;
    t.x = __float2bfloat16_rn(a);
    t.y = __float2bfloat16_rn(b);
    return *(unsigned*)&t;
}

// ---------------- all weight conversions in one kernel (16 elems/thread) ----------------
__global__ void cvt_all(const float* __restrict__ s0, const float* __restrict__ s1,
                        const float* __restrict__ s2, const float* __restrict__ s3,
                        const float* __restrict__ s4, const float* __restrict__ s5,
                        const float* __restrict__ s6) {
    int w = blockIdx.y;
    const float* src; bf16* dst; int n;
    switch (w) {
        case 0: src = s0; dst = b_wq; n = DIMN*DIMN; break;
        case 1: src = s1; dst = b_wk; n = DIMN*DIMN; break;
        case 2: src = s2; dst = b_wv; n = DIMN*DIMN; break;
        case 3: src = s3; dst = b_wo; n = DIMN*DIMN; break;
        case 4: src = s4; dst = b_w1; n = DIMN*HIDDEN; break;
        case 5: src = s5; dst = b_w3; n = DIMN*HIDDEN; break;
        default: src = s6; dst = b_w2; n = HIDDEN*DIMN; break;
    }
    int i = (blockIdx.x * 256 + threadIdx.x) * 16;
    if (i < n) {
        float4 a = *(const float4*)(src + i);
        float4 b = *(const float4*)(src + i + 4);
        float4 c = *(const float4*)(src + i + 8);
        float4 d = *(const float4*)(src + i + 12);
        uint4 o1, o2;
        o1.x = pack_bf(a.x, a.y); o1.y = pack_bf(a.z, a.w);
        o1.z = pack_bf(b.x, b.y); o1.w = pack_bf(b.z, b.w);
        o2.x = pack_bf(c.x, c.y); o2.y = pack_bf(c.z, c.w);
        o2.z = pack_bf(d.x, d.y); o2.w = pack_bf(d.z, d.w);
        *(uint4*)(dst + i) = o1;
        *(uint4*)(dst + i + 8) = o2;
    }
}

// -------- t = silu(adafm_input) @ proj_w + proj_b, grid (BATCH, 8) --------
__global__ void proj_t_kernel(const float* __restrict__ ad, const float* __restrict__ pw,
                              const float* __restrict__ pb, float* __restrict__ t) {
    int b = blockIdx.x, o0 = blockIdx.y * 64;
    __shared__ float s[DIMN];
    __shared__ float red[4][64];
    int tid = threadIdx.x;
    for (int i = tid; i < DIMN; i += 256) {
        float z = ad[b*DIMN + i];
        s[i] = z / (1.f + expf(-z));
    }
    __syncthreads();
    int o = o0 + (tid & 63), seg = tid >> 6;
    float acc = 0.f;
    #pragma unroll 4
    for (int i = seg*256; i < seg*256 + 256; i++) acc += s[i] * pw[i*512 + o];
    red[seg][tid & 63] = acc;
    __syncthreads();
    if (tid < 64)
        t[b*512 + o0 + tid] = red[0][tid] + red[1][tid] + red[2][tid] + red[3][tid] + pb[o0 + tid];
}

// --- g[d] = (1/256) sum m[k] cos(2 pi k d/256); Bg[q][t]=g[(t-q)&255]; grid (4, 8) ---
__global__ void make_g_kernel(const float* __restrict__ t) {
    int b = blockIdx.x >> 1, which = blockIdx.x & 1;
    int q0 = blockIdx.y * 32;
    const float* m = t + b*512 + which*256;
    __shared__ float cs[256], ms[256];
    __shared__ bf16 gd[512];
    int d = threadIdx.x;
    cs[d] = cosf((6.283185307179586f / 256.0f) * (float)d);
    ms[d] = m[d];
    __syncthreads();
    float acc = 0.f;
    #pragma unroll 4
    for (int k = 0; k < 256; k++) acc += ms[k] * cs[(k*d) & 255];
    bf16 gv = __float2bfloat16_rn(acc * (1.0f / 256.0f));
    gd[d] = gv; gd[d + 256] = gv;
    __syncthreads();
    bf16* Bg = (which ? b_gf : b_gm) + b * 65536;
    for (int q = q0; q < q0 + 32; q++)
        Bg[q*256 + d] = gd[d - q + 256];
}

// ---------------- patchify: x fp32 [B,SEQ,DIM] -> Xp bf16 [B, 8192, 256] ----------------
__global__ void patchify(const float* __restrict__ x) {
    int c = blockIdx.x * 256 + threadIdx.x;
    int q  = (c & 31) * 8;
    int pi = (c >> 5) & 8191;
    int b  = c >> 18;
    int p = q >> 4, qq = q & 15;
    const float* src = x + ((size_t)(b*2048 + (pi >> 6)*16 + p)) * DIMN + (pi & 63)*16 + qq;
    float4 a = *(const float4*)src;
    float4 v = *(const float4*)(src + 4);
    uint4 o;
    o.x = pack_bf(a.x, a.y); o.y = pack_bf(a.z, a.w);
    o.z = pack_bf(v.x, v.y); o.w = pack_bf(v.z, v.w);
    *(uint4*)(b_xp + (size_t)c * 8) = o;
}

// ================= GEMM core macro pieces (block 128x256x32, 8 warps) =================
#define AKE 40
#define BNE 264
#define A_ELT (128*AKE)
#define B_ELT (32*BNE)
#define STG_ELT (A_ELT + B_ELT)
#define GEMM_SMEM (3 * STG_ELT * 2)

#define GEMM_PROLOG(Aptr, Bptr, Kdim, Ndim, bmv, bnv)                                    \
    extern __shared__ bf16 smb[];                                                        \
    const unsigned sbase = (unsigned)__cvta_generic_to_shared(smb);                      \
    const int tid  = threadIdx.x;                                                        \
    const int lane = tid & 31;                                                           \
    const int warp = tid >> 5;                                                           \
    const int g    = lane >> 2;                                                          \
    const int t4   = lane & 3;                                                           \
    const int lm   = lane & 15;                                                          \
    const int lh   = lane >> 4;                                                          \
    const int wm = (warp >> 2) * 64;                                                     \
    const int wn = (warp & 3) * 64;                                                      \
    float acc[4][8][4];                                                                  \
    _Pragma("unroll") for (int i = 0; i < 4; i++)                                        \
        _Pragma("unroll") for (int j = 0; j < 8; j++)                                    \
            _Pragma("unroll") for (int r = 0; r < 4; r++) acc[i][j][r] = 0.f;            \
    const int ktiles = (Kdim) >> 5;                                                      \
    auto load_stage = [&](int st, int k0) {                                              \
        unsigned sa = sbase + (unsigned)(st * STG_ELT) * 2u;                             \
        unsigned sb = sa + A_ELT * 2u;                                                   \
        _Pragma("unroll") for (int u = 0; u < 2; u++) {                                  \
            int c = tid + 256*u;                                                         \
            int r = c >> 2, o = (c & 3) * 8;                                             \
            cpa16(sa + (unsigned)(r*AKE + o)*2u, (Aptr) + (size_t)((bmv) + r) * (Kdim) + k0 + o); \
        }                                                                                \
        _Pragma("unroll") for (int u = 0; u < 4; u++) {                                  \
            int c = tid + 256*u;                                                         \
            int r = c >> 5, o = (c & 31) * 8;                                            \
            cpa16(sb + (unsigned)(r*BNE + o)*2u, (Bptr) + (size_t)(k0 + r) * (Ndim) + (bnv) + o); \
        }                                                                                \
    };                                                                                   \
    load_stage(0, 0);                                                                    \
    asm volatile("cp.async.commit_group;");                                              \
    load_stage(1, 32);                                                                   \
    asm volatile("cp.async.commit_group;");                                              \
    for (int t = 0; t < ktiles; t++) {                                                   \
        asm volatile("cp.async.wait_group 1;");                                          \
        __syncthreads();                                                                 \
        int nt = t + 2;                                                                  \
        if (nt < ktiles) load_stage(nt % 3, nt * 32);                                    \
        asm volatile("cp.async.commit_group;");                                          \
        unsigned sa = sbase + (unsigned)((t % 3) * STG_ELT) * 2u;                        \
        unsigned sb = sa + A_ELT * 2u;                                                   \
        _Pragma("unroll") for (int kk = 0; kk < 32; kk += 16) {                          \
            unsigned af[4][4], bfr[8][2];                                                \
            _Pragma("unroll") for (int i = 0; i < 4; i++)                                \
                ldmx4(af[i][0], af[i][1], af[i][2], af[i][3],                            \
                      sa + (unsigned)((wm + 16*i + lm)*AKE + kk + lh*8)*2u);             \
            _Pragma("unroll") for (int j2 = 0; j2 < 4; j2++)                             \
                ldmx4t(bfr[2*j2][0], bfr[2*j2][1], bfr[2*j2+1][0], bfr[2*j2+1][1],       \
                       sb + (unsigned)((kk + lm)*BNE + wn + 16*j2 + lh*8)*2u);           \
            _Pragma("unroll") for (int i = 0; i < 4; i++)                                \
                _Pragma("unroll") for (int j = 0; j < 8; j++)                            \
                    mma16(acc[i][j], af[i][0], af[i][1], af[i][2], af[i][3],             \
                          bfr[j][0], bfr[j][1]);                                         \
        }                                                                                \
    }

// ---- generic gemm, fp32 out ----
__global__ __launch_bounds__(256, 1) void gemm_bf16(const bf16* __restrict__ A,
                                                    const bf16* __restrict__ B,
                                                    float* __restrict__ Cf,
                                                    int M, int N, int K) {
    const int bm = blockIdx.y * 128;
    const int bn = blockIdx.x * 256;
    GEMM_PROLOG(A, B, K, N, bm, bn)
    #pragma unroll
    for (int i = 0; i < 4; i++) {
        int row0 = bm + wm + 16*i + g;
        #pragma unroll
        for (int j = 0; j < 8; j++) {
            int col = bn + wn + 8*j + 2*t4;
            *(float2*)(Cf + (size_t)row0 * N + col)       = make_float2(acc[i][j][0], acc[i][j][1]);
            *(float2*)(Cf + (size_t)(row0 + 8) * N + col) = make_float2(acc[i][j][2], acc[i][j][3]);
        }
    }
}

// ---- fused QKV gemm + RoPE + head-norm + sqk_eff epilogue ----
__global__ __launch_bounds__(256, 1) void gemm_qkv(const bf16* __restrict__ A,
                                                   const float* __restrict__ fcos,
                                                   const float* __restrict__ fsin,
                                                   const float* __restrict__ sqk) {
    const int wsel = blockIdx.x >> 2;
    const int bn = (blockIdx.x & 3) * 256;
    const int bm = blockIdx.y * 128;
    const bf16* B = (wsel == 0) ? b_wq : ((wsel == 1) ? b_wk : b_wv);
    bf16* C = (wsel == 0) ? b_q : ((wsel == 1) ? b_k : b_v);
    GEMM_PROLOG(A, B, DIMN, DIMN, bm, bn)
    if (wsel == 2) {
        #pragma unroll
        for (int i = 0; i < 4; i++) {
            int row0 = bm + wm + 16*i + g;
            #pragma unroll
            for (int j = 0; j < 8; j++) {
                int col = bn + wn + 8*j + 2*t4;
                *(unsigned*)(C + (size_t)row0 * DIMN + col)       = pack_bf(acc[i][j][0], acc[i][j][1]);
                *(unsigned*)(C + (size_t)(row0 + 8) * DIMN + col) = pack_bf(acc[i][j][2], acc[i][j][3]);
            }
        }
    } else {
        const int h = (bn + wn) >> 6;
        const float qscale = (wsel == 0) ? 8.f * 1.4426950408889634f : 1.f;
        #pragma unroll
        for (int i = 0; i < 4; i++) {
            int row0 = bm + wm + 16*i + g;
            int row1 = row0 + 8;
            float ss0 = 0.f, ss1 = 0.f;
            #pragma unroll
            for (int j = 0; j < 8; j++) {
                ss0 += acc[i][j][0]*acc[i][j][0] + acc[i][j][1]*acc[i][j][1];
                ss1 += acc[i][j][2]*acc[i][j][2] + acc[i][j][3]*acc[i][j][3];
            }
            ss0 += __shfl_xor_sync(0xffffffffu, ss0, 1);
            ss0 += __shfl_xor_sync(0xffffffffu, ss0, 2);
            ss1 += __shfl_xor_sync(0xffffffffu, ss1, 1);
            ss1 += __shfl_xor_sync(0xffffffffu, ss1, 2);
            float inv0 = qscale / fmaxf(sqrtf(ss0), 1e-12f);
            float inv1 = qscale / fmaxf(sqrtf(ss1), 1e-12f);
            int s0 = row0 & (SEQL - 1), s1 = row1 & (SEQL - 1);
            #pragma unroll
            for (int j = 0; j < 8; j++) {
                int pidx = 4*j + t4;
                int d = 8*j + 2*t4;
                float se0 = sqk[h*HDIM + d]     * 32.f;
                float se1 = sqk[h*HDIM + d + 1] * 32.f;
                float c0 = fcos[s0*32 + pidx], sn0 = fsin[s0*32 + pidx];
                float c1 = fcos[s1*32 + pidx], sn1 = fsin[s1*32 + pidx];
                float a0 = acc[i][j][0], a1 = acc[i][j][1];
                float b0 = acc[i][j][2], b1 = acc[i][j][3];
                int col = bn + wn + d;
                *(unsigned*)(C + (size_t)row0 * DIMN + col) =
                    pack_bf((a0*c0 - a1*sn0) * inv0 * se0, (a0*sn0 + a1*c0) * inv0 * se1);
                *(unsigned*)(C + (size_t)row1 * DIMN + col) =
                    pack_bf((b0*c1 - b1*sn1) * inv1 * se0, (b0*sn1 + b1*c1) * inv1 * se1);
            }
        }
    }
}

// ---- fused w1/w3 GEMM + silu gate: writes gated h (bf16) only ----
__global__ __launch_bounds__(256, 1) void gemm_ffn13g(const bf16* __restrict__ A,
                                                      const float* __restrict__ su,
                                                      const float* __restrict__ sv) {
    const int bnb = blockIdx.x * 128;
    const int bm  = blockIdx.y * 128;
    extern __shared__ bf16 smb[];
    const unsigned sbase = (unsigned)__cvta_generic_to_shared(smb);
    const int tid  = threadIdx.x;
    const int lane = tid & 31;
    const int warp = tid >> 5;
    const int g    = lane >> 2;
    const int t4   = lane & 3;
    const int lm   = lane & 15;
    const int lh   = lane >> 4;
    const int wm = (warp >> 2) * 64;
    const int wn = (warp & 3) * 32;

    float acc1[4][4][4], acc3[4][4][4];
    #pragma unroll
    for (int i = 0; i < 4; i++)
        #pragma unroll
        for (int j = 0; j < 4; j++)
            #pragma unroll
            for (int r = 0; r < 4; r++) { acc1[i][j][r] = 0.f; acc3[i][j][r] = 0.f; }

    const int ktiles = DIMN >> 5;
    auto load_stage = [&](int st, int k0) {
        unsigned sa = sbase + (unsigned)(st * STG_ELT) * 2u;
        unsigned sb = sa + A_ELT * 2u;
        #pragma unroll
        for (int u = 0; u < 2; u++) {
            int c = tid + 256*u;
            int r = c >> 2, o = (c & 3) * 8;
            cpa16(sa + (unsigned)(r*AKE + o)*2u, A + (size_t)(bm + r) * DIMN + k0 + o);
        }
        #pragma unroll
        for (int u = 0; u < 4; u++) {
            int c = tid + 256*u;
            int r = c >> 5, o = (c & 31) * 8;
            const bf16* src = (o < 128)
                ? (b_w1 + (size_t)(k0 + r) * HIDDEN + bnb + o)
                : (b_w3 + (size_t)(k0 + r) * HIDDEN + bnb + o - 128);
            cpa16(sb + (unsigned)(r*BNE + o)*2u, src);
        }
    };
    load_stage(0, 0);
    asm volatile("cp.async.commit_group;");
    load_stage(1, 32);
    asm volatile("cp.async.commit_group;");

    for (int t = 0; t < ktiles; t++) {
        asm volatile("cp.async.wait_group 1;");
        __syncthreads();
        int nt = t + 2;
        if (nt < ktiles) load_stage(nt % 3, nt * 32);
        asm volatile("cp.async.commit_group;");
        unsigned sa = sbase + (unsigned)((t % 3) * STG_ELT) * 2u;
        unsigned sb = sa + A_ELT * 2u;
        #pragma unroll
        for (int kk = 0; kk < 32; kk += 16) {
            unsigned af[4][4], b1f[4][2], b3f[4][2];
            #pragma unroll
            for (int i = 0; i < 4; i++)
                ldmx4(af[i][0], af[i][1], af[i][2], af[i][3],
                      sa + (unsigned)((wm + 16*i + lm)*AKE + kk + lh*8)*2u);
            #pragma unroll
            for (int j2 = 0; j2 < 2; j2++) {
                ldmx4t(b1f[2*j2][0], b1f[2*j2][1], b1f[2*j2+1][0], b1f[2*j2+1][1],
                       sb + (unsigned)((kk + lm)*BNE + wn + 16*j2 + lh*8)*2u);
                ldmx4t(b3f[2*j2][0], b3f[2*j2][1], b3f[2*j2+1][0], b3f[2*j2+1][1],
                       sb + (unsigned)((kk + lm)*BNE + 128 + wn + 16*j2 + lh*8)*2u);
            }
            #pragma unroll
            for (int i = 0; i < 4; i++)
                #pragma unroll
                for (int j = 0; j < 4; j++) {
                    mma16(acc1[i][j], af[i][0], af[i][1], af[i][2], af[i][3], b1f[j][0], b1f[j][1]);
                    mma16(acc3[i][j], af[i][0], af[i][1], af[i][2], af[i][3], b3f[j][0], b3f[j][1]);
                }
        }
    }

    const float SC = 53.06599664568481f;
    #pragma unroll
    for (int i = 0; i < 4; i++) {
        int row0 = bm + wm + 16*i + g;
        #pragma unroll
        for (int j = 0; j < 4; j++) {
            int col = bnb + wn + 8*j + 2*t4;
            float sv0 = sv[col] * SC, sv1 = sv[col+1] * SC;
            float su0 = su[col],      su1 = su[col+1];
            float z, sgl;
            float outv[4];
            z = acc1[i][j][0] * sv0; sgl = z / (1.f + __expf(-z)); outv[0] = sgl * (acc3[i][j][0] * su0);
            z = acc1[i][j][1] * sv1; sgl = z / (1.f + __expf(-z)); outv[1] = sgl * (acc3[i][j][1] * su1);
            z = acc1[i][j][2] * sv0; sgl = z / (1.f + __expf(-z)); outv[2] = sgl * (acc3[i][j][2] * su0);
            z = acc1[i][j][3] * sv1; sgl = z / (1.f + __expf(-z)); outv[3] = sgl * (acc3[i][j][3] * su1);
            *(unsigned*)(b_h1 + (size_t)row0 * HIDDEN + col)       = pack_bf(outv[0], outv[1]);
            *(unsigned*)(b_h1 + (size_t)(row0 + 8) * HIDDEN + col) = pack_bf(outv[2], outv[3]);
        }
    }
}

// ---- adafm gemm: Y[pi][t] = Xp[pi][:] @ Bg[:][t], scatter to token layout ----
__global__ __launch_bounds__(256, 1) void adafm_gemm(const bf16* __restrict__ Bg0,
                                                     bf16* __restrict__ Y) {
    const int z  = blockIdx.z;
    const int bm = blockIdx.y * 128;
    const int bn = 0;
    const bf16* A = b_xp + (size_t)z * 8192 * 256;
    const bf16* B = Bg0 + (size_t)z * 65536;
    GEMM_PROLOG(A, B, 256, 256, bm, bn)
    bf16* Yb = Y + (size_t)z * 2048 * DIMN;
    #pragma unroll
    for (int i = 0; i < 4; i++) {
        int pi0 = bm + wm + 16*i + g;
        #pragma unroll
        for (int j = 0; j < 8; j++) {
            int col = wn + 8*j + 2*t4;
            int p = col >> 4, qq = col & 15;
            *(unsigned*)(Yb + (size_t)((pi0 >> 6)*16 + p) * DIMN + (pi0 & 63)*16 + qq)
                = pack_bf(acc[i][j][0], acc[i][j][1]);
            int pi = pi0 + 8;
            *(unsigned*)(Yb + (size_t)((pi >> 6)*16 + p) * DIMN + (pi & 63)*16 + qq)
                = pack_bf(acc[i][j][2], acc[i][j][3]);
        }
    }
}

// ---------------- FA2 flash attention, cp.async 2-stage K/V pipeline, exp2 ----------------
#define FAE 72
#define FLASH_SMEM (384 * FAE * 2)

__global__ __launch_bounds__(256, 2) void flash_attn(const bf16* __restrict__ Q,
                                                     const bf16* __restrict__ K,
                                                     const bf16* __restrict__ V,
                                                     bf16* __restrict__ O) {
    extern __shared__ bf16 fsm[];
    bf16* Qs = fsm;
    const unsigned sQ  = (unsigned)__cvta_generic_to_shared(Qs);
    const unsigned sK0 = sQ + 128*FAE*2u;
    const unsigned sV0 = sK0 + 2*64*FAE*2u;

    const int q0 = blockIdx.x * 128;
    const int h  = blockIdx.y;
    const int b  = blockIdx.z;
    const bf16* Qb = Q + (size_t)b*SEQL*DIMN + h*HDIM;
    const bf16* Kb = K + (size_t)b*SEQL*DIMN + h*HDIM;
    const bf16* Vb = V + (size_t)b*SEQL*DIMN + h*HDIM;
    bf16*       Ob = O + (size_t)b*SEQL*DIMN + h*HDIM;

    const int tid  = threadIdx.x;
    const int lane = tid & 31;
    const int warp = tid >> 5;
    const int g  = lane >> 2;
    const int t4 = lane & 3;
    const int lm = lane & 15;
    const int lh = lane >> 4;
    const int wm = warp * 16;

    auto loadKV = [&](int st, int k0) {
        unsigned sk = sK0 + (unsigned)st * 64*FAE*2u;
        unsigned sv = sV0 + (unsigned)st * 64*FAE*2u;
        #pragma unroll
        for (int u = 0; u < 2; u++) {
            int c = tid + 256*u;
            int r = c >> 3, ofs = (c & 7) * 8;
            cpa16(sk + (unsigned)(r*FAE + ofs)*2u, Kb + (size_t)(k0 + r)*DIMN + ofs);
            cpa16(sv + (unsigned)(r*FAE + ofs)*2u, Vb + (size_t)(k0 + r)*DIMN + ofs);
        }
    };

    #pragma unroll
    for (int u = 0; u < 4; u++) {
        int c = tid + 256*u;
        int r = c >> 3, ofs = (c & 7) * 8;
        *(uint4*)&Qs[r*FAE + ofs] = *(const uint4*)(Qb + (size_t)(q0 + r)*DIMN + ofs);
    }

    loadKV(0, 0);
    asm volatile("cp.async.commit_group;");

    float o[8][4];
    #pragma unroll
    for (int j = 0; j < 8; j++)
        #pragma unroll
        for (int r = 0; r < 4; r++) o[j][r] = 0.f;
    float m0 = -1e30f, m1 = -1e30f, l0 = 0.f, l1 = 0.f;

    const int NT = SEQL / 64;
    for (int t = 0; t < NT; t++) {
        if (t + 1 < NT) {
            loadKV((t + 1) & 1, (t + 1) * 64);
            asm volatile("cp.async.commit_group;");
            asm volatile("cp.async.wait_group 1;");
        } else {
            asm volatile("cp.async.wait_group 0;");
        }
        __syncthreads();

        const unsigned sK = sK0 + (unsigned)(t & 1) * 64*FAE*2u;
        const unsigned sV = sV0 + (unsigned)(t & 1) * 64*FAE*2u;

        float s[8][4];
        #pragma unroll
        for (int j = 0; j < 8; j++)
            #pragma unroll
            for (int r = 0; r < 4; r++) s[j][r] = 0.f;

        #pragma unroll
        for (int kc = 0; kc < 4; kc++) {
            int kk = 16*kc;
            unsigned a0, a1, a2, a3;
            ldmx4(a0, a1, a2, a3, sQ + (unsigned)((wm + lm)*FAE + kk + lh*8)*2u);
            #pragma unroll
            for (int j2 = 0; j2 < 4; j2++) {
                unsigned r0, r1, r2, r3;
                ldmx4(r0, r1, r2, r3,
                      sK + (unsigned)((16*j2 + (lane & 7) + ((lane >> 4) << 3))*FAE
                                       + kk + (((lane >> 3) & 1) << 3))*2u);
                mma16(s[2*j2],     a0, a1, a2, a3, r0, r1);
                mma16(s[2*j2 + 1], a0, a1, a2, a3, r2, r3);
            }
        }

        float tm0 = -1e30f, tm1 = -1e30f;
        #pragma unroll
        for (int j = 0; j < 8; j++) {
            tm0 = fmaxf(tm0, fmaxf(s[j][0], s[j][1]));
            tm1 = fmaxf(tm1, fmaxf(s[j][2], s[j][3]));
        }
        tm0 = fmaxf(tm0, __shfl_xor_sync(0xffffffffu, tm0, 1));
        tm0 = fmaxf(tm0, __shfl_xor_sync(0xffffffffu, tm0, 2));
        tm1 = fmaxf(tm1, __shfl_xor_sync(0xffffffffu, tm1, 1));
        tm1 = fmaxf(tm1, __shfl_xor_sync(0xffffffffu, tm1, 2));
        float mn0 = fmaxf(m0, tm0), mn1 = fmaxf(m1, tm1);
        float c0 = exp2f(m0 - mn0), c1 = exp2f(m1 - mn1);
        float ps0 = 0.f, ps1 = 0.f;
        #pragma unroll
        for (int j = 0; j < 8; j++) {
            s[j][0] = exp2f(s[j][0] - mn0);
            s[j][1] = exp2f(s[j][1] - mn0);
            s[j][2] = exp2f(s[j][2] - mn1);
            s[j][3] = exp2f(s[j][3] - mn1);
            ps0 += s[j][0] + s[j][1];
            ps1 += s[j][2] + s[j][3];
        }
        ps0 += __shfl_xor_sync(0xffffffffu, ps0, 1);
        ps0 += __shfl_xor_sync(0xffffffffu, ps0, 2);
        ps1 += __shfl_xor_sync(0xffffffffu, ps1, 1);
        ps1 += __shfl_xor_sync(0xffffffffu, ps1, 2);
        l0 = l0 * c0 + ps0;  l1 = l1 * c1 + ps1;
        m0 = mn0;            m1 = mn1;
        #pragma unroll
        for (int j = 0; j < 8; j++) {
            o[j][0] *= c0; o[j][1] *= c0; o[j][2] *= c1; o[j][3] *= c1;
        }

        #pragma unroll
        for (int c = 0; c < 4; c++) {
            unsigned pa0 = pack_bf(s[2*c][0],   s[2*c][1]);
            unsigned pa1 = pack_bf(s[2*c][2],   s[2*c][3]);
            unsigned pa2 = pack_bf(s[2*c+1][0], s[2*c+1][1]);
            unsigned pa3 = pack_bf(s[2*c+1][2], s[2*c+1][3]);
            #pragma unroll
            for (int j2 = 0; j2 < 4; j2++) {
                unsigned r0, r1, r2, r3;
                ldmx4t(r0, r1, r2, r3,
                       sV + (unsigned)((16*c + lm)*FAE + 16*j2 + lh*8)*2u);
                mma16(o[2*j2],     pa0, pa1, pa2, pa3, r0, r1);
                mma16(o[2*j2 + 1], pa0, pa1, pa2, pa3, r2, r3);
            }
        }
        __syncthreads();
    }

    float inv0 = 1.f / l0, inv1 = 1.f / l1;
    #pragma unroll
    for (int j = 0; j < 8; j++) {
        int col = 8*j + 2*t4;
        *(unsigned*)(Ob + (size_t)(q0 + wm + g    )*DIMN + col) = pack_bf(o[j][0]*inv0, o[j][1]*inv0);
        *(unsigned*)(Ob + (size_t)(q0 + wm + g + 8)*DIMN + col) = pack_bf(o[j][2]*inv1, o[j][3]*inv1);
    }
}

// ------- fused residual + norms (fp32); optional bf16 patchified output -------
__global__ __launch_bounds__(256) void residual_norm(const float* __restrict__ xb,
                                                     const float* __restrict__ br,
                                                     const float* __restrict__ alpha,
                                                     float* __restrict__ out,
                                                     bf16* __restrict__ xp) {
    int t = blockIdx.x;
    int tid = threadIdx.x;
    const float* xr = xb + (size_t)t * DIMN;
    const float* rr = br + (size_t)t * DIMN;
    float xv[4], bv[4];
    float ssx = 0.f, ssb = 0.f;
    #pragma unroll
    for (int u = 0; u < 4; u++) {
        int d = tid + u * 256;
        xv[u] = xr[d]; bv[u] = rr[d];
        ssx += xv[u] * xv[u]; ssb += bv[u] * bv[u];
    }
    ssx = blockSum256(ssx);
    ssb = blockSum256(ssb);
    float rx = 1.f / fmaxf(sqrtf(ssx), 1e-12f);
    float rb = 1.f / fmaxf(sqrtf(ssb), 1e-12f);
    float yv[4]; float ssy = 0.f;
    #pragma unroll
    for (int u = 0; u < 4; u++) {
        int d = tid + u * 256;
        float hh = xv[u] * rx;
        float ha = bv[u] * rb;
        float lr = fabsf(alpha[d] * 1.6f);
        float y = hh + lr * (ha - hh);
        yv[u] = y; ssy += y * y;
    }
    ssy = blockSum256(ssy);
    float ry = 1.f / fmaxf(sqrtf(ssy), 1e-12f);
    int b = t >> 11, se = t & 2047;
    int ip = se >> 4, p = se & 15;
    #pragma unroll
    for (int u = 0; u < 4; u++) {
        int d = tid + u * 256;
        float y = yv[u] * ry;
        out[(size_t)t * DIMN + d] = y;
        if (xp) {
            int jj = d >> 4, qq = d & 15;
            xp[((size_t)b*8192 + ip*64 + jj)*256 + p*16 + qq] = __float2bfloat16_rn(y);
        }
    }
}

// ---------------- launch ----------------
extern "C" void kernel_launch(void* const* d_in, const int* in_sizes, int n_in,
                              void* d_out, int out_size) {
    const float* x      = (const float*)d_in[0];
    const float* fcos   = (const float*)d_in[1];
    const float* fsin   = (const float*)d_in[2];
    const float* adafm  = (const float*)d_in[3];
    const float* wq     = (const float*)d_in[4];
    const float* wk     = (const float*)d_in[5];
    const float* wv     = (const float*)d_in[6];
    const float* wo     = (const float*)d_in[7];
    const float* sqk    = (const float*)d_in[8];
    const float* w1     = (const float*)d_in[9];
    const float* w2     = (const float*)d_in[10];
    const float* w3     = (const float*)d_in[11];
    const float* su     = (const float*)d_in[12];
    const float* sv     = (const float*)d_in[13];
    const float* pw     = (const float*)d_in[14];
    const float* pb     = (const float*)d_in[15];
    const float* aalpha = (const float*)d_in[16];
    const float* malpha = (const float*)d_in[17];
    float* out = (float*)d_out;

    float *pt, *pf0, *pf1, *pf2;
    bf16 *pbgm, *pbgf, *pbxa, *pbq, *pbk, *pbv, *pbao, *pbwo, *pbw2, *pbh1, *pbxp;
    cudaGetSymbolAddress((void**)&pt,  d_t);
    cudaGetSymbolAddress((void**)&pf0, d_f0);
    cudaGetSymbolAddress((void**)&pf1, d_f1);
    cudaGetSymbolAddress((void**)&pf2, d_f2);
    cudaGetSymbolAddress((void**)&pbgm, b_gm);
    cudaGetSymbolAddress((void**)&pbgf, b_gf);
    cudaGetSymbolAddress((void**)&pbxa, b_xa);
    cudaGetSymbolAddress((void**)&pbq,  b_q);
    cudaGetSymbolAddress((void**)&pbk,  b_k);
    cudaGetSymbolAddress((void**)&pbv,  b_v);
    cudaGetSymbolAddress((void**)&pbao, b_ao);
    cudaGetSymbolAddress((void**)&pbwo, b_wo);
    cudaGetSymbolAddress((void**)&pbw2, b_w2);
    cudaGetSymbolAddress((void**)&pbh1, b_h1);
    cudaGetSymbolAddress((void**)&pbxp, b_xp);

    cudaFuncSetAttribute(gemm_bf16, cudaFuncAttributeMaxDynamicSharedMemorySize, GEMM_SMEM);
    cudaFuncSetAttribute(gemm_qkv, cudaFuncAttributeMaxDynamicSharedMemorySize, GEMM_SMEM);
    cudaFuncSetAttribute(gemm_ffn13g, cudaFuncAttributeMaxDynamicSharedMemorySize, GEMM_SMEM);
    cudaFuncSetAttribute(adafm_gemm, cudaFuncAttributeMaxDynamicSharedMemorySize, GEMM_SMEM);
    cudaFuncSetAttribute(flash_attn, cudaFuncAttributeMaxDynamicSharedMemorySize, FLASH_SMEM);

    // 0) weight conversions
    cvt_all<<<dim3(704, 7), 256>>>(wq, wk, wv, wo, w1, w3, w2);

    // 1) time-modulation: t, then conv matrices Bg (both parallelized)
    proj_t_kernel<<<dim3(BATCH, 8), 256>>>(adafm, pw, pb, pt);
    make_g_kernel<<<dim3(4, 8), 256>>>(pt);

    // 2) attention branch
    patchify<<<2048, 256>>>(x);
    adafm_gemm<<<dim3(1, 64, 2), 256, GEMM_SMEM>>>(pbgm, pbxa);
    gemm_qkv<<<dim3(12, 32), 256, GEMM_SMEM>>>(pbxa, fcos, fsin, sqk);
    flash_attn<<<dim3(SEQL/128, NHEAD, BATCH), 256, FLASH_SMEM>>>(pbq, pbk, pbv, pbao);
    gemm_bf16<<<dim3(DIMN/256, TOK/128), 256, GEMM_SMEM>>>(pbao, pbwo, pf2, TOK, DIMN, DIMN);
    residual_norm<<<TOK, 256>>>(x, pf2, aalpha, pf0, pbxp);

    // 3) FFN branch
    adafm_gemm<<<dim3(1, 64, 2), 256, GEMM_SMEM>>>(pbgf, pbxa);
    gemm_ffn13g<<<dim3(HIDDEN/128, TOK/128), 256, GEMM_SMEM>>>(pbxa, su, sv);
    gemm_bf16<<<dim3(DIMN/256, TOK/128), 256, GEMM_SMEM>>>(pbh1, pbw2, pf1, TOK, DIMN, HIDDEN);
    residual_norm<<<TOK, 256>>>(pf0, pf1, malpha, out, (bf16*)0);
}

// round 12
// speedup vs baseline: 6.9465x; 1.0008x over previous
#include <cuda_runtime.h>
#include <cuda_bf16.h>
#include <math.h>

typedef __nv_bfloat16 bf16;

#define DIMN   1024
#define NHEAD  16
#define HDIM   64
#define SEQL   2048
#define BATCH  2
#define TOK    4096
#define HIDDEN 2816

// ---------------- scratch ----------------
__device__ float d_t [BATCH*512];
__device__ float d_f0[TOK*DIMN];            // x1 (fp32)

__device__ bf16 b_wq[DIMN*DIMN], b_wk[DIMN*DIMN], b_wv[DIMN*DIMN], b_wo[DIMN*DIMN];
__device__ bf16 b_w1[DIMN*HIDDEN], b_w3[DIMN*HIDDEN], b_w2[HIDDEN*DIMN];
__device__ bf16 b_xp[BATCH*8192*256];       // patchified input
__device__ bf16 b_gm[BATCH*256*256];        // conv matrix, attn branch
__device__ bf16 b_gf[BATCH*256*256];        // conv matrix, mlp branch
__device__ bf16 b_xa[TOK*DIMN];             // adafm out
__device__ bf16 b_q [TOK*DIMN], b_k[TOK*DIMN], b_v[TOK*DIMN], b_ao[TOK*DIMN];
__device__ bf16 b_h1[(size_t)TOK*HIDDEN];

// ---------------- helpers ----------------
__device__ __forceinline__ float blockSum256(float v) {
    __shared__ float red[8];
    int lane = threadIdx.x & 31, wid = threadIdx.x >> 5;
    #pragma unroll
    for (int o = 16; o > 0; o >>= 1) v += __shfl_xor_sync(0xffffffffu, v, o);
    __syncthreads();
    if (lane == 0) red[wid] = v;
    __syncthreads();
    float s = red[0];
    #pragma unroll
    for (int w = 1; w < 8; w++) s += red[w];
    return s;
}

__device__ __forceinline__ void mma16(float* c, unsigned a0, unsigned a1, unsigned a2, unsigned a3,
                                      unsigned b0, unsigned b1) {
    asm volatile(
        "mma.sync.aligned.m16n8k16.row.col.f32.bf16.bf16.f32 "
        "{%0,%1,%2,%3}, {%4,%5,%6,%7}, {%8,%9}, {%0,%1,%2,%3};"
        : "+f"(c[0]), "+f"(c[1]), "+f"(c[2]), "+f"(c[3])
        : "r"(a0), "r"(a1), "r"(a2), "r"(a3), "r"(b0), "r"(b1));
}
__device__ __forceinline__ void ldmx4(unsigned& r0, unsigned& r1, unsigned& r2, unsigned& r3, unsigned addr) {
    asm volatile("ldmatrix.sync.aligned.m8n8.x4.shared.b16 {%0,%1,%2,%3}, [%4];"
                 : "=r"(r0), "=r"(r1), "=r"(r2), "=r"(r3) : "r"(addr));
}
__device__ __forceinline__ void ldmx4t(unsigned& r0, unsigned& r1, unsigned& r2, unsigned& r3, unsigned addr) {
    asm volatile("ldmatrix.sync.aligned.m8n8.x4.trans.shared.b16 {%0,%1,%2,%3}, [%4];"
                 : "=r"(r0), "=r"(r1), "=r"(r2), "=r"(r3) : "r"(addr));
}
__device__ __forceinline__ void cpa16(unsigned s, const void* g) {
    asm volatile("cp.async.cg.shared.global [%0], [%1], 16;" :: "r"(s), "l"(g));
}
__device__ __forceinline__ unsigned pack_bf(float a, float b) {
    __nv_bfloat162 t;
    t.x = __float2bfloat16_rn(a);
    t.y = __float2bfloat16_rn(b);
    return *(unsigned*)&t;
}
__device__ __forceinline__ float2 unpack_bf(unsigned u) {
    __nv_bfloat162 t = *(__nv_bfloat162*)&u;
    return make_float2(__bfloat162float(t.x), __bfloat162float(t.y));
}

// ---------------- all weight conversions in one kernel (16 elems/thread) ----------------
__global__ void cvt_all(const float* __restrict__ s0, const float* __restrict__ s1,
                        const float* __restrict__ s2, const float* __restrict__ s3,
                        const float* __restrict__ s4, const float* __restrict__ s5,
                        const float* __restrict__ s6) {
    int w = blockIdx.y;
    const float* src; bf16* dst; int n;
    switch (w) {
        case 0: src = s0; dst = b_wq; n = DIMN*DIMN; break;
        case 1: src = s1; dst = b_wk; n = DIMN*DIMN; break;
        case 2: src = s2; dst = b_wv; n = DIMN*DIMN; break;
        case 3: src = s3; dst = b_wo; n = DIMN*DIMN; break;
        case 4: src = s4; dst = b_w1; n = DIMN*HIDDEN; break;
        case 5: src = s5; dst = b_w3; n = DIMN*HIDDEN; break;
        default: src = s6; dst = b_w2; n = HIDDEN*DIMN; break;
    }
    int i = (blockIdx.x * 256 + threadIdx.x) * 16;
    if (i < n) {
        float4 a = *(const float4*)(src + i);
        float4 b = *(const float4*)(src + i + 4);
        float4 c = *(const float4*)(src + i + 8);
        float4 d = *(const float4*)(src + i + 12);
        uint4 o1, o2;
        o1.x = pack_bf(a.x, a.y); o1.y = pack_bf(a.z, a.w);
        o1.z = pack_bf(b.x, b.y); o1.w = pack_bf(b.z, b.w);
        o2.x = pack_bf(c.x, c.y); o2.y = pack_bf(c.z, c.w);
        o2.z = pack_bf(d.x, d.y); o2.w = pack_bf(d.z, d.w);
        *(uint4*)(dst + i) = o1;
        *(uint4*)(dst + i + 8) = o2;
    }
}

// -------- t = silu(adafm_input) @ proj_w + proj_b, grid (BATCH, 8) --------
__global__ void proj_t_kernel(const float* __restrict__ ad, const float* __restrict__ pw,
                              const float* __restrict__ pb, float* __restrict__ t) {
    int b = blockIdx.x, o0 = blockIdx.y * 64;
    __shared__ float s[DIMN];
    __shared__ float red[4][64];
    int tid = threadIdx.x;
    for (int i = tid; i < DIMN; i += 256) {
        float z = ad[b*DIMN + i];
        s[i] = z / (1.f + expf(-z));
    }
    __syncthreads();
    int o = o0 + (tid & 63), seg = tid >> 6;
    float acc = 0.f;
    #pragma unroll 4
    for (int i = seg*256; i < seg*256 + 256; i++) acc += s[i] * pw[i*512 + o];
    red[seg][tid & 63] = acc;
    __syncthreads();
    if (tid < 64)
        t[b*512 + o0 + tid] = red[0][tid] + red[1][tid] + red[2][tid] + red[3][tid] + pb[o0 + tid];
}

// --- g[d] = (1/256) sum m[k] cos(2 pi k d/256); Bg[q][t]=g[(t-q)&255]; grid (4, 8) ---
__global__ void make_g_kernel(const float* __restrict__ t) {
    int b = blockIdx.x >> 1, which = blockIdx.x & 1;
    int q0 = blockIdx.y * 32;
    const float* m = t + b*512 + which*256;
    __shared__ float cs[256], ms[256];
    __shared__ bf16 gd[512];
    int d = threadIdx.x;
    cs[d] = cosf((6.283185307179586f / 256.0f) * (float)d);
    ms[d] = m[d];
    __syncthreads();
    float acc = 0.f;
    #pragma unroll 4
    for (int k = 0; k < 256; k++) acc += ms[k] * cs[(k*d) & 255];
    bf16 gv = __float2bfloat16_rn(acc * (1.0f / 256.0f));
    gd[d] = gv; gd[d + 256] = gv;
    __syncthreads();
    bf16* Bg = (which ? b_gf : b_gm) + b * 65536;
    for (int q = q0; q < q0 + 32; q++)
        Bg[q*256 + d] = gd[d - q + 256];
}

// ---------------- patchify: x fp32 [B,SEQ,DIM] -> Xp bf16 [B, 8192, 256] ----------------
__global__ void patchify(const float* __restrict__ x) {
    int c = blockIdx.x * 256 + threadIdx.x;
    int q  = (c & 31) * 8;
    int pi = (c >> 5) & 8191;
    int b  = c >> 18;
    int p = q >> 4, qq = q & 15;
    const float* src = x + ((size_t)(b*2048 + (pi >> 6)*16 + p)) * DIMN + (pi & 63)*16 + qq;
    float4 a = *(const float4*)src;
    float4 v = *(const float4*)(src + 4);
    uint4 o;
    o.x = pack_bf(a.x, a.y); o.y = pack_bf(a.z, a.w);
    o.z = pack_bf(v.x, v.y); o.w = pack_bf(v.z, v.w);
    *(uint4*)(b_xp + (size_t)c * 8) = o;
}

// ================= GEMM core macro pieces (block 128x256x32, 8 warps) =================
#define AKE 40
#define BNE 264
#define A_ELT (128*AKE)
#define B_ELT (32*BNE)
#define STG_ELT (A_ELT + B_ELT)
#define GEMM_SMEM (3 * STG_ELT * 2)

#define GEMM_PROLOG(Aptr, Bptr, Kdim, Ndim, bmv, bnv)                                    \
    extern __shared__ bf16 smb[];                                                        \
    const unsigned sbase = (unsigned)__cvta_generic_to_shared(smb);                      \
    const int tid  = threadIdx.x;                                                        \
    const int lane = tid & 31;                                                           \
    const int warp = tid >> 5;                                                           \
    const int g    = lane >> 2;                                                          \
    const int t4   = lane & 3;                                                           \
    const int lm   = lane & 15;                                                          \
    const int lh   = lane >> 4;                                                          \
    const int wm = (warp >> 2) * 64;                                                     \
    const int wn = (warp & 3) * 64;                                                      \
    float acc[4][8][4];                                                                  \
    _Pragma("unroll") for (int i = 0; i < 4; i++)                                        \
        _Pragma("unroll") for (int j = 0; j < 8; j++)                                    \
            _Pragma("unroll") for (int r = 0; r < 4; r++) acc[i][j][r] = 0.f;            \
    const int ktiles = (Kdim) >> 5;                                                      \
    auto load_stage = [&](int st, int k0) {                                              \
        unsigned sa = sbase + (unsigned)(st * STG_ELT) * 2u;                             \
        unsigned sb = sa + A_ELT * 2u;                                                   \
        _Pragma("unroll") for (int u = 0; u < 2; u++) {                                  \
            int c = tid + 256*u;                                                         \
            int r = c >> 2, o = (c & 3) * 8;                                             \
            cpa16(sa + (unsigned)(r*AKE + o)*2u, (Aptr) + (size_t)((bmv) + r) * (Kdim) + k0 + o); \
        }                                                                                \
        _Pragma("unroll") for (int u = 0; u < 4; u++) {                                  \
            int c = tid + 256*u;                                                         \
            int r = c >> 5, o = (c & 31) * 8;                                            \
            cpa16(sb + (unsigned)(r*BNE + o)*2u, (Bptr) + (size_t)(k0 + r) * (Ndim) + (bnv) + o); \
        }                                                                                \
    };                                                                                   \
    load_stage(0, 0);                                                                    \
    asm volatile("cp.async.commit_group;");                                              \
    load_stage(1, 32);                                                                   \
    asm volatile("cp.async.commit_group;");                                              \
    for (int t = 0; t < ktiles; t++) {                                                   \
        asm volatile("cp.async.wait_group 1;");                                          \
        __syncthreads();                                                                 \
        int nt = t + 2;                                                                  \
        if (nt < ktiles) load_stage(nt % 3, nt * 32);                                    \
        asm volatile("cp.async.commit_group;");                                          \
        unsigned sa = sbase + (unsigned)((t % 3) * STG_ELT) * 2u;                        \
        unsigned sb = sa + A_ELT * 2u;                                                   \
        _Pragma("unroll") for (int kk = 0; kk < 32; kk += 16) {                          \
            unsigned af[4][4], bfr[8][2];                                                \
            _Pragma("unroll") for (int i = 0; i < 4; i++)                                \
                ldmx4(af[i][0], af[i][1], af[i][2], af[i][3],                            \
                      sa + (unsigned)((wm + 16*i + lm)*AKE + kk + lh*8)*2u);             \
            _Pragma("unroll") for (int j2 = 0; j2 < 4; j2++)                             \
                ldmx4t(bfr[2*j2][0], bfr[2*j2][1], bfr[2*j2+1][0], bfr[2*j2+1][1],       \
                       sb + (unsigned)((kk + lm)*BNE + wn + 16*j2 + lh*8)*2u);           \
            _Pragma("unroll") for (int i = 0; i < 4; i++)                                \
                _Pragma("unroll") for (int j = 0; j < 8; j++)                            \
                    mma16(acc[i][j], af[i][0], af[i][1], af[i][2], af[i][3],             \
                          bfr[j][0], bfr[j][1]);                                         \
        }                                                                                \
    }

// ---- generic gemm, bf16 out ----
__global__ __launch_bounds__(256, 1) void gemm_bf16o(const bf16* __restrict__ A,
                                                     const bf16* __restrict__ B,
                                                     bf16* __restrict__ Cb,
                                                     int M, int N, int K) {
    const int bm = blockIdx.y * 128;
    const int bn = blockIdx.x * 256;
    GEMM_PROLOG(A, B, K, N, bm, bn)
    #pragma unroll
    for (int i = 0; i < 4; i++) {
        int row0 = bm + wm + 16*i + g;
        #pragma unroll
        for (int j = 0; j < 8; j++) {
            int col = bn + wn + 8*j + 2*t4;
            *(unsigned*)(Cb + (size_t)row0 * N + col)       = pack_bf(acc[i][j][0], acc[i][j][1]);
            *(unsigned*)(Cb + (size_t)(row0 + 8) * N + col) = pack_bf(acc[i][j][2], acc[i][j][3]);
        }
    }
}

// ---- fused QKV gemm + RoPE + head-norm + sqk_eff epilogue ----
__global__ __launch_bounds__(256, 1) void gemm_qkv(const bf16* __restrict__ A,
                                                   const float* __restrict__ fcos,
                                                   const float* __restrict__ fsin,
                                                   const float* __restrict__ sqk) {
    const int wsel = blockIdx.x >> 2;
    const int bn = (blockIdx.x & 3) * 256;
    const int bm = blockIdx.y * 128;
    const bf16* B = (wsel == 0) ? b_wq : ((wsel == 1) ? b_wk : b_wv);
    bf16* C = (wsel == 0) ? b_q : ((wsel == 1) ? b_k : b_v);
    GEMM_PROLOG(A, B, DIMN, DIMN, bm, bn)
    if (wsel == 2) {
        #pragma unroll
        for (int i = 0; i < 4; i++) {
            int row0 = bm + wm + 16*i + g;
            #pragma unroll
            for (int j = 0; j < 8; j++) {
                int col = bn + wn + 8*j + 2*t4;
                *(unsigned*)(C + (size_t)row0 * DIMN + col)       = pack_bf(acc[i][j][0], acc[i][j][1]);
                *(unsigned*)(C + (size_t)(row0 + 8) * DIMN + col) = pack_bf(acc[i][j][2], acc[i][j][3]);
            }
        }
    } else {
        const int h = (bn + wn) >> 6;
        const float qscale = (wsel == 0) ? 8.f * 1.4426950408889634f : 1.f;
        #pragma unroll
        for (int i = 0; i < 4; i++) {
            int row0 = bm + wm + 16*i + g;
            int row1 = row0 + 8;
            float ss0 = 0.f, ss1 = 0.f;
            #pragma unroll
            for (int j = 0; j < 8; j++) {
                ss0 += acc[i][j][0]*acc[i][j][0] + acc[i][j][1]*acc[i][j][1];
                ss1 += acc[i][j][2]*acc[i][j][2] + acc[i][j][3]*acc[i][j][3];
            }
            ss0 += __shfl_xor_sync(0xffffffffu, ss0, 1);
            ss0 += __shfl_xor_sync(0xffffffffu, ss0, 2);
            ss1 += __shfl_xor_sync(0xffffffffu, ss1, 1);
            ss1 += __shfl_xor_sync(0xffffffffu, ss1, 2);
            float inv0 = qscale / fmaxf(sqrtf(ss0), 1e-12f);
            float inv1 = qscale / fmaxf(sqrtf(ss1), 1e-12f);
            int s0 = row0 & (SEQL - 1), s1 = row1 & (SEQL - 1);
            #pragma unroll
            for (int j = 0; j < 8; j++) {
                int pidx = 4*j + t4;
                int d = 8*j + 2*t4;
                float se0 = sqk[h*HDIM + d]     * 32.f;
                float se1 = sqk[h*HDIM + d + 1] * 32.f;
                float c0 = fcos[s0*32 + pidx], sn0 = fsin[s0*32 + pidx];
                float c1 = fcos[s1*32 + pidx], sn1 = fsin[s1*32 + pidx];
                float a0 = acc[i][j][0], a1 = acc[i][j][1];
                float b0 = acc[i][j][2], b1 = acc[i][j][3];
                int col = bn + wn + d;
                *(unsigned*)(C + (size_t)row0 * DIMN + col) =
                    pack_bf((a0*c0 - a1*sn0) * inv0 * se0, (a0*sn0 + a1*c0) * inv0 * se1);
                *(unsigned*)(C + (size_t)row1 * DIMN + col) =
                    pack_bf((b0*c1 - b1*sn1) * inv1 * se0, (b0*sn1 + b1*c1) * inv1 * se1);
            }
        }
    }
}

// ---- fused w1/w3 GEMM + silu gate: writes gated h (bf16) only ----
__global__ __launch_bounds__(256, 1) void gemm_ffn13g(const bf16* __restrict__ A,
                                                      const float* __restrict__ su,
                                                      const float* __restrict__ sv) {
    const int bnb = blockIdx.x * 128;
    const int bm  = blockIdx.y * 128;
    extern __shared__ bf16 smb[];
    const unsigned sbase = (unsigned)__cvta_generic_to_shared(smb);
    const int tid  = threadIdx.x;
    const int lane = tid & 31;
    const int warp = tid >> 5;
    const int g    = lane >> 2;
    const int t4   = lane & 3;
    const int lm   = lane & 15;
    const int lh   = lane >> 4;
    const int wm = (warp >> 2) * 64;
    const int wn = (warp & 3) * 32;

    float acc1[4][4][4], acc3[4][4][4];
    #pragma unroll
    for (int i = 0; i < 4; i++)
        #pragma unroll
        for (int j = 0; j < 4; j++)
            #pragma unroll
            for (int r = 0; r < 4; r++) { acc1[i][j][r] = 0.f; acc3[i][j][r] = 0.f; }

    const int ktiles = DIMN >> 5;
    auto load_stage = [&](int st, int k0) {
        unsigned sa = sbase + (unsigned)(st * STG_ELT) * 2u;
        unsigned sb = sa + A_ELT * 2u;
        #pragma unroll
        for (int u = 0; u < 2; u++) {
            int c = tid + 256*u;
            int r = c >> 2, o = (c & 3) * 8;
            cpa16(sa + (unsigned)(r*AKE + o)*2u, A + (size_t)(bm + r) * DIMN + k0 + o);
        }
        #pragma unroll
        for (int u = 0; u < 4; u++) {
            int c = tid + 256*u;
            int r = c >> 5, o = (c & 31) * 8;
            const bf16* src = (o < 128)
                ? (b_w1 + (size_t)(k0 + r) * HIDDEN + bnb + o)
                : (b_w3 + (size_t)(k0 + r) * HIDDEN + bnb + o - 128);
            cpa16(sb + (unsigned)(r*BNE + o)*2u, src);
        }
    };
    load_stage(0, 0);
    asm volatile("cp.async.commit_group;");
    load_stage(1, 32);
    asm volatile("cp.async.commit_group;");

    for (int t = 0; t < ktiles; t++) {
        asm volatile("cp.async.wait_group 1;");
        __syncthreads();
        int nt = t + 2;
        if (nt < ktiles) load_stage(nt % 3, nt * 32);
        asm volatile("cp.async.commit_group;");
        unsigned sa = sbase + (unsigned)((t % 3) * STG_ELT) * 2u;
        unsigned sb = sa + A_ELT * 2u;
        #pragma unroll
        for (int kk = 0; kk < 32; kk += 16) {
            unsigned af[4][4], b1f[4][2], b3f[4][2];
            #pragma unroll
            for (int i = 0; i < 4; i++)
                ldmx4(af[i][0], af[i][1], af[i][2], af[i][3],
                      sa + (unsigned)((wm + 16*i + lm)*AKE + kk + lh*8)*2u);
            #pragma unroll
            for (int j2 = 0; j2 < 2; j2++) {
                ldmx4t(b1f[2*j2][0], b1f[2*j2][1], b1f[2*j2+1][0], b1f[2*j2+1][1],
                       sb + (unsigned)((kk + lm)*BNE + wn + 16*j2 + lh*8)*2u);
                ldmx4t(b3f[2*j2][0], b3f[2*j2][1], b3f[2*j2+1][0], b3f[2*j2+1][1],
                       sb + (unsigned)((kk + lm)*BNE + 128 + wn + 16*j2 + lh*8)*2u);
            }
            #pragma unroll
            for (int i = 0; i < 4; i++)
                #pragma unroll
                for (int j = 0; j < 4; j++) {
                    mma16(acc1[i][j], af[i][0], af[i][1], af[i][2], af[i][3], b1f[j][0], b1f[j][1]);
                    mma16(acc3[i][j], af[i][0], af[i][1], af[i][2], af[i][3], b3f[j][0], b3f[j][1]);
                }
        }
    }

    const float SC = 53.06599664568481f;
    #pragma unroll
    for (int i = 0; i < 4; i++) {
        int row0 = bm + wm + 16*i + g;
        #pragma unroll
        for (int j = 0; j < 4; j++) {
            int col = bnb + wn + 8*j + 2*t4;
            float sv0 = sv[col] * SC, sv1 = sv[col+1] * SC;
            float su0 = su[col],      su1 = su[col+1];
            float z, sgl;
            float outv[4];
            z = acc1[i][j][0] * sv0; sgl = z / (1.f + __expf(-z)); outv[0] = sgl * (acc3[i][j][0] * su0);
            z = acc1[i][j][1] * sv1; sgl = z / (1.f + __expf(-z)); outv[1] = sgl * (acc3[i][j][1] * su1);
            z = acc1[i][j][2] * sv0; sgl = z / (1.f + __expf(-z)); outv[2] = sgl * (acc3[i][j][2] * su0);
            z = acc1[i][j][3] * sv1; sgl = z / (1.f + __expf(-z)); outv[3] = sgl * (acc3[i][j][3] * su1);
            *(unsigned*)(b_h1 + (size_t)row0 * HIDDEN + col)       = pack_bf(outv[0], outv[1]);
            *(unsigned*)(b_h1 + (size_t)(row0 + 8) * HIDDEN + col) = pack_bf(outv[2], outv[3]);
        }
    }
}

// ---- adafm gemm: Y[pi][t] = Xp[pi][:] @ Bg[:][t], scatter to token layout ----
__global__ __launch_bounds__(256, 1) void adafm_gemm(const bf16* __restrict__ Bg0,
                                                     bf16* __restrict__ Y) {
    const int z  = blockIdx.z;
    const int bm = blockIdx.y * 128;
    const int bn = 0;
    const bf16* A = b_xp + (size_t)z * 8192 * 256;
    const bf16* B = Bg0 + (size_t)z * 65536;
    GEMM_PROLOG(A, B, 256, 256, bm, bn)
    bf16* Yb = Y + (size_t)z * 2048 * DIMN;
    #pragma unroll
    for (int i = 0; i < 4; i++) {
        int pi0 = bm + wm + 16*i + g;
        #pragma unroll
        for (int j = 0; j < 8; j++) {
            int col = wn + 8*j + 2*t4;
            int p = col >> 4, qq = col & 15;
            *(unsigned*)(Yb + (size_t)((pi0 >> 6)*16 + p) * DIMN + (pi0 & 63)*16 + qq)
                = pack_bf(acc[i][j][0], acc[i][j][1]);
            int pi = pi0 + 8;
            *(unsigned*)(Yb + (size_t)((pi >> 6)*16 + p) * DIMN + (pi & 63)*16 + qq)
                = pack_bf(acc[i][j][2], acc[i][j][3]);
        }
    }
}

// --------- FA2 flash attention, cp.async 3-stage K/V ring, ONE barrier/iter ---------
#define FAE 72
#define FLASH_SMEM ((128 + 6*64) * FAE * 2)

__global__ __launch_bounds__(256, 2) void flash_attn(const bf16* __restrict__ Q,
                                                     const bf16* __restrict__ K,
                                                     const bf16* __restrict__ V,
                                                     bf16* __restrict__ O) {
    extern __shared__ bf16 fsm[];
    bf16* Qs = fsm;
    const unsigned sQ  = (unsigned)__cvta_generic_to_shared(Qs);
    const unsigned sK0 = sQ + 128*FAE*2u;
    const unsigned sV0 = sK0 + 3*64*FAE*2u;

    const int q0 = blockIdx.x * 128;
    const int h  = blockIdx.y;
    const int b  = blockIdx.z;
    const bf16* Qb = Q + (size_t)b*SEQL*DIMN + h*HDIM;
    const bf16* Kb = K + (size_t)b*SEQL*DIMN + h*HDIM;
    const bf16* Vb = V + (size_t)b*SEQL*DIMN + h*HDIM;
    bf16*       Ob = O + (size_t)b*SEQL*DIMN + h*HDIM;

    const int tid  = threadIdx.x;
    const int lane = tid & 31;
    const int warp = tid >> 5;
    const int g  = lane >> 2;
    const int t4 = lane & 3;
    const int lm = lane & 15;
    const int lh = lane >> 4;
    const int wm = warp * 16;

    auto loadKV = [&](int st, int k0) {
        unsigned sk = sK0 + (unsigned)st * 64*FAE*2u;
        unsigned sv = sV0 + (unsigned)st * 64*FAE*2u;
        #pragma unroll
        for (int u = 0; u < 2; u++) {
            int c = tid + 256*u;
            int r = c >> 3, ofs = (c & 7) * 8;
            cpa16(sk + (unsigned)(r*FAE + ofs)*2u, Kb + (size_t)(k0 + r)*DIMN + ofs);
            cpa16(sv + (unsigned)(r*FAE + ofs)*2u, Vb + (size_t)(k0 + r)*DIMN + ofs);
        }
    };

    #pragma unroll
    for (int u = 0; u < 4; u++) {
        int c = tid + 256*u;
        int r = c >> 3, ofs = (c & 7) * 8;
        *(uint4*)&Qs[r*FAE + ofs] = *(const uint4*)(Qb + (size_t)(q0 + r)*DIMN + ofs);
    }

    loadKV(0, 0);
    asm volatile("cp.async.commit_group;");
    loadKV(1, 64);
    asm volatile("cp.async.commit_group;");

    float o[8][4];
    #pragma unroll
    for (int j = 0; j < 8; j++)
        #pragma unroll
        for (int r = 0; r < 4; r++) o[j][r] = 0.f;
    float m0 = -1e30f, m1 = -1e30f, l0 = 0.f, l1 = 0.f;

    const int NT = SEQL / 64;
    for (int t = 0; t < NT; t++) {
        // wait for stage t (keep at most 1 newer group pending)
        if (t + 1 < NT) asm volatile("cp.async.wait_group 1;");
        else            asm volatile("cp.async.wait_group 0;");
        __syncthreads();   // all smem (incl. other threads' copies + prior reads of this stage) settled
        if (t + 2 < NT) {
            loadKV((t + 2) % 3, (t + 2) * 64);
            asm volatile("cp.async.commit_group;");
        }

        const unsigned sK = sK0 + (unsigned)(t % 3) * 64*FAE*2u;
        const unsigned sV = sV0 + (unsigned)(t % 3) * 64*FAE*2u;

        float s[8][4];
        #pragma unroll
        for (int j = 0; j < 8; j++)
            #pragma unroll
            for (int r = 0; r < 4; r++) s[j][r] = 0.f;

        #pragma unroll
        for (int kc = 0; kc < 4; kc++) {
            int kk = 16*kc;
            unsigned a0, a1, a2, a3;
            ldmx4(a0, a1, a2, a3, sQ + (unsigned)((wm + lm)*FAE + kk + lh*8)*2u);
            #pragma unroll
            for (int j2 = 0; j2 < 4; j2++) {
                unsigned r0, r1, r2, r3;
                ldmx4(r0, r1, r2, r3,
                      sK + (unsigned)((16*j2 + (lane & 7) + ((lane >> 4) << 3))*FAE
                                       + kk + (((lane >> 3) & 1) << 3))*2u);
                mma16(s[2*j2],     a0, a1, a2, a3, r0, r1);
                mma16(s[2*j2 + 1], a0, a1, a2, a3, r2, r3);
            }
        }

        float tm0 = -1e30f, tm1 = -1e30f;
        #pragma unroll
        for (int j = 0; j < 8; j++) {
            tm0 = fmaxf(tm0, fmaxf(s[j][0], s[j][1]));
            tm1 = fmaxf(tm1, fmaxf(s[j][2], s[j][3]));
        }
        tm0 = fmaxf(tm0, __shfl_xor_sync(0xffffffffu, tm0, 1));
        tm0 = fmaxf(tm0, __shfl_xor_sync(0xffffffffu, tm0, 2));
        tm1 = fmaxf(tm1, __shfl_xor_sync(0xffffffffu, tm1, 1));
        tm1 = fmaxf(tm1, __shfl_xor_sync(0xffffffffu, tm1, 2));
        float mn0 = fmaxf(m0, tm0), mn1 = fmaxf(m1, tm1);
        float c0 = exp2f(m0 - mn0), c1 = exp2f(m1 - mn1);
        float ps0 = 0.f, ps1 = 0.f;
        #pragma unroll
        for (int j = 0; j < 8; j++) {
            s[j][0] = exp2f(s[j][0] - mn0);
            s[j][1] = exp2f(s[j][1] - mn0);
            s[j][2] = exp2f(s[j][2] - mn1);
            s[j][3] = exp2f(s[j][3] - mn1);
            ps0 += s[j][0] + s[j][1];
            ps1 += s[j][2] + s[j][3];
        }
        ps0 += __shfl_xor_sync(0xffffffffu, ps0, 1);
        ps0 += __shfl_xor_sync(0xffffffffu, ps0, 2);
        ps1 += __shfl_xor_sync(0xffffffffu, ps1, 1);
        ps1 += __shfl_xor_sync(0xffffffffu, ps1, 2);
        l0 = l0 * c0 + ps0;  l1 = l1 * c1 + ps1;
        m0 = mn0;            m1 = mn1;
        #pragma unroll
        for (int j = 0; j < 8; j++) {
            o[j][0] *= c0; o[j][1] *= c0; o[j][2] *= c1; o[j][3] *= c1;
        }

        #pragma unroll
        for (int c = 0; c < 4; c++) {
            unsigned pa0 = pack_bf(s[2*c][0],   s[2*c][1]);
            unsigned pa1 = pack_bf(s[2*c][2],   s[2*c][3]);
            unsigned pa2 = pack_bf(s[2*c+1][0], s[2*c+1][1]);
            unsigned pa3 = pack_bf(s[2*c+1][2], s[2*c+1][3]);
            #pragma unroll
            for (int j2 = 0; j2 < 4; j2++) {
                unsigned r0, r1, r2, r3;
                ldmx4t(r0, r1, r2, r3,
                       sV + (unsigned)((16*c + lm)*FAE + 16*j2 + lh*8)*2u);
                mma16(o[2*j2],     pa0, pa1, pa2, pa3, r0, r1);
                mma16(o[2*j2 + 1], pa0, pa1, pa2, pa3, r2, r3);
            }
        }
        // no trailing barrier: stage (t%3) is not rewritten until iteration t+1's
        // loadKV((t+3)%3) == stage t%3, which is issued after the next start-of-iter barrier
    }

    float inv0 = 1.f / l0, inv1 = 1.f / l1;
    #pragma unroll
    for (int j = 0; j < 8; j++) {
        int col = 8*j + 2*t4;
        *(unsigned*)(Ob + (size_t)(q0 + wm + g    )*DIMN + col) = pack_bf(o[j][0]*inv0, o[j][1]*inv0);
        *(unsigned*)(Ob + (size_t)(q0 + wm + g + 8)*DIMN + col) = pack_bf(o[j][2]*inv1, o[j][3]*inv1);
    }
}

// ------- fused residual + norms; branch input bf16; optional bf16 patchified output -------
__global__ __launch_bounds__(256) void residual_norm(const float* __restrict__ xb,
                                                     const bf16* __restrict__ br,
                                                     const float* __restrict__ alpha,
                                                     float* __restrict__ out,
                                                     bf16* __restrict__ xp) {
    int t = blockIdx.x;
    int tid = threadIdx.x;
    const float* xr = xb + (size_t)t * DIMN;
    const bf16*  rr = br + (size_t)t * DIMN;
    float xv[4], bv[4];
    float ssx = 0.f, ssb = 0.f;
    #pragma unroll
    for (int u = 0; u < 2; u++) {
        int d = tid*2 + u * 512;
        float2 xx = *(const float2*)(xr + d);
        float2 bb = unpack_bf(*(const unsigned*)(rr + d));
        xv[2*u] = xx.x; xv[2*u+1] = xx.y;
        bv[2*u] = bb.x; bv[2*u+1] = bb.y;
        ssx += xx.x*xx.x + xx.y*xx.y;
        ssb += bb.x*bb.x + bb.y*bb.y;
    }
    ssx = blockSum256(ssx);
    ssb = blockSum256(ssb);
    float rx = 1.f / fmaxf(sqrtf(ssx), 1e-12f);
    float rb = 1.f / fmaxf(sqrtf(ssb), 1e-12f);
    float yv[4]; float ssy = 0.f;
    #pragma unroll
    for (int u = 0; u < 4; u++) {
        int d = tid*2 + (u >> 1) * 512 + (u & 1);
        float hh = xv[u] * rx;
        float ha = bv[u] * rb;
        float lr = fabsf(alpha[d] * 1.6f);
        float y = hh + lr * (ha - hh);
        yv[u] = y; ssy += y * y;
    }
    ssy = blockSum256(ssy);
    float ry = 1.f / fmaxf(sqrtf(ssy), 1e-12f);
    int b = t >> 11, se = t & 2047;
    int ip = se >> 4, p = se & 15;
    #pragma unroll
    for (int u = 0; u < 4; u++) {
        int d = tid*2 + (u >> 1) * 512 + (u & 1);
        float y = yv[u] * ry;
        out[(size_t)t * DIMN + d] = y;
        if (xp) {
            int jj = d >> 4, qq = d & 15;
            xp[((size_t)b*8192 + ip*64 + jj)*256 + p*16 + qq] = __float2bfloat16_rn(y);
        }
    }
}

// ---------------- launch ----------------
extern "C" void kernel_launch(void* const* d_in, const int* in_sizes, int n_in,
                              void* d_out, int out_size) {
    const float* x      = (const float*)d_in[0];
    const float* fcos   = (const float*)d_in[1];
    const float* fsin   = (const float*)d_in[2];
    const float* adafm  = (const float*)d_in[3];
    const float* wq     = (const float*)d_in[4];
    const float* wk     = (const float*)d_in[5];
    const float* wv     = (const float*)d_in[6];
    const float* wo     = (const float*)d_in[7];
    const float* sqk    = (const float*)d_in[8];
    const float* w1     = (const float*)d_in[9];
    const float* w2     = (const float*)d_in[10];
    const float* w3     = (const float*)d_in[11];
    const float* su     = (const float*)d_in[12];
    const float* sv     = (const float*)d_in[13];
    const float* pw     = (const float*)d_in[14];
    const float* pb     = (const float*)d_in[15];
    const float* aalpha = (const float*)d_in[16];
    const float* malpha = (const float*)d_in[17];
    float* out = (float*)d_out;

    float *pt, *pf0;
    bf16 *pbgm, *pbgf, *pbxa, *pbq, *pbk, *pbv, *pbao, *pbwo, *pbw2, *pbh1, *pbxp;
    cudaGetSymbolAddress((void**)&pt,  d_t);
    cudaGetSymbolAddress((void**)&pf0, d_f0);
    cudaGetSymbolAddress((void**)&pbgm, b_gm);
    cudaGetSymbolAddress((void**)&pbgf, b_gf);
    cudaGetSymbolAddress((void**)&pbxa, b_xa);
    cudaGetSymbolAddress((void**)&pbq,  b_q);
    cudaGetSymbolAddress((void**)&pbk,  b_k);
    cudaGetSymbolAddress((void**)&pbv,  b_v);
    cudaGetSymbolAddress((void**)&pbao, b_ao);
    cudaGetSymbolAddress((void**)&pbwo, b_wo);
    cudaGetSymbolAddress((void**)&pbw2, b_w2);
    cudaGetSymbolAddress((void**)&pbh1, b_h1);
    cudaGetSymbolAddress((void**)&pbxp, b_xp);

    cudaFuncSetAttribute(gemm_bf16o, cudaFuncAttributeMaxDynamicSharedMemorySize, GEMM_SMEM);
    cudaFuncSetAttribute(gemm_qkv, cudaFuncAttributeMaxDynamicSharedMemorySize, GEMM_SMEM);
    cudaFuncSetAttribute(gemm_ffn13g, cudaFuncAttributeMaxDynamicSharedMemorySize, GEMM_SMEM);
    cudaFuncSetAttribute(adafm_gemm, cudaFuncAttributeMaxDynamicSharedMemorySize, GEMM_SMEM);
    cudaFuncSetAttribute(flash_attn, cudaFuncAttributeMaxDynamicSharedMemorySize, FLASH_SMEM);

    // 0) weight conversions
    cvt_all<<<dim3(704, 7), 256>>>(wq, wk, wv, wo, w1, w3, w2);

    // 1) time-modulation: t, then conv matrices Bg
    proj_t_kernel<<<dim3(BATCH, 8), 256>>>(adafm, pw, pb, pt);
    make_g_kernel<<<dim3(4, 8), 256>>>(pt);

    // 2) attention branch
    patchify<<<2048, 256>>>(x);
    adafm_gemm<<<dim3(1, 64, 2), 256, GEMM_SMEM>>>(pbgm, pbxa);
    gemm_qkv<<<dim3(12, 32), 256, GEMM_SMEM>>>(pbxa, fcos, fsin, sqk);
    flash_attn<<<dim3(SEQL/128, NHEAD, BATCH), 256, FLASH_SMEM>>>(pbq, pbk, pbv, pbao);
    gemm_bf16o<<<dim3(DIMN/256, TOK/128), 256, GEMM_SMEM>>>(pbao, pbwo, pbq, TOK, DIMN, DIMN);  // b_q := attn out
    residual_norm<<<TOK, 256>>>(x, pbq, aalpha, pf0, pbxp);

    // 3) FFN branch
    adafm_gemm<<<dim3(1, 64, 2), 256, GEMM_SMEM>>>(pbgf, pbxa);
    gemm_ffn13g<<<dim3(HIDDEN/128, TOK/128), 256, GEMM_SMEM>>>(pbxa, su, sv);
    gemm_bf16o<<<dim3(DIMN/256, TOK/128), 256, GEMM_SMEM>>>(pbh1, pbw2, pbk, TOK, DIMN, HIDDEN); // b_k := mlp out
    residual_norm<<<TOK, 256>>>(pf0, pbk, malpha, out, (bf16*)0);
}

// round 13
// speedup vs baseline: 7.2091x; 1.0378x over previous
#include <cuda_runtime.h>
#include <cuda_bf16.h>
#include <cuda_fp8.h>
#include <math.h>

typedef __nv_bfloat16 bf16;

#define DIMN   1024
#define NHEAD  16
#define HDIM   64
#define SEQL   2048
#define BATCH  2
#define TOK    4096
#define HIDDEN 2816

// ---------------- scratch ----------------
__device__ float d_t [BATCH*512];
__device__ float d_f0[TOK*DIMN];

__device__ bf16 b_wq[DIMN*DIMN], b_wk[DIMN*DIMN], b_wv[DIMN*DIMN], b_wo[DIMN*DIMN];
__device__ bf16 b_w1[DIMN*HIDDEN], b_w3[DIMN*HIDDEN];
__device__ unsigned char b_w2t[(size_t)DIMN*HIDDEN];      // fp8 [N][K], x64
__device__ bf16 b_xp[BATCH*8192*256];
__device__ bf16 b_gm[BATCH*256*256];
__device__ bf16 b_gf[BATCH*256*256];
__device__ bf16 b_xa[TOK*DIMN];
__device__ bf16 b_q [TOK*DIMN], b_k[TOK*DIMN], b_v[TOK*DIMN], b_ao[TOK*DIMN];
__device__ unsigned char b_h8[(size_t)TOK*HIDDEN];        // fp8 gated h, x256

// ---------------- helpers ----------------
__device__ __forceinline__ float blockSum256(float v) {
    __shared__ float red[8];
    int lane = threadIdx.x & 31, wid = threadIdx.x >> 5;
    #pragma unroll
    for (int o = 16; o > 0; o >>= 1) v += __shfl_xor_sync(0xffffffffu, v, o);
    __syncthreads();
    if (lane == 0) red[wid] = v;
    __syncthreads();
    float s = red[0];
    #pragma unroll
    for (int w = 1; w < 8; w++) s += red[w];
    return s;
}
__device__ __forceinline__ void mma16(float* c, unsigned a0, unsigned a1, unsigned a2, unsigned a3,
                                      unsigned b0, unsigned b1) {
    asm volatile("mma.sync.aligned.m16n8k16.row.col.f32.bf16.bf16.f32 "
        "{%0,%1,%2,%3}, {%4,%5,%6,%7}, {%8,%9}, {%0,%1,%2,%3};"
        : "+f"(c[0]), "+f"(c[1]), "+f"(c[2]), "+f"(c[3])
        : "r"(a0), "r"(a1), "r"(a2), "r"(a3), "r"(b0), "r"(b1));
}
__device__ __forceinline__ void mma8f8(float* c, unsigned a0, unsigned a1, unsigned a2, unsigned a3,
                                       unsigned b0, unsigned b1) {
    asm volatile("mma.sync.aligned.m16n8k32.row.col.f32.e4m3.e4m3.f32 "
        "{%0,%1,%2,%3}, {%4,%5,%6,%7}, {%8,%9}, {%0,%1,%2,%3};"
        : "+f"(c[0]), "+f"(c[1]), "+f"(c[2]), "+f"(c[3])
        : "r"(a0), "r"(a1), "r"(a2), "r"(a3), "r"(b0), "r"(b1));
}
__device__ __forceinline__ void ldmx4(unsigned& r0, unsigned& r1, unsigned& r2, unsigned& r3, unsigned a) {
    asm volatile("ldmatrix.sync.aligned.m8n8.x4.shared.b16 {%0,%1,%2,%3}, [%4];"
                 : "=r"(r0), "=r"(r1), "=r"(r2), "=r"(r3) : "r"(a));
}
__device__ __forceinline__ void ldmx4t(unsigned& r0, unsigned& r1, unsigned& r2, unsigned& r3, unsigned a) {
    asm volatile("ldmatrix.sync.aligned.m8n8.x4.trans.shared.b16 {%0,%1,%2,%3}, [%4];"
                 : "=r"(r0), "=r"(r1), "=r"(r2), "=r"(r3) : "r"(a));
}
__device__ __forceinline__ void cpa16(unsigned s, const void* g) {
    asm volatile("cp.async.cg.shared.global [%0], [%1], 16;" :: "r"(s), "l"(g));
}
__device__ __forceinline__ unsigned pack_bf(float a, float b) {
    __nv_bfloat162 t; t.x = __float2bfloat16_rn(a); t.y = __float2bfloat16_rn(b);
    return *(unsigned*)&t;
}
__device__ __forceinline__ float2 unpack_bf(unsigned u) {
    __nv_bfloat162 t = *(__nv_bfloat162*)&u;
    return make_float2(__bfloat162float(t.x), __bfloat162float(t.y));
}
__device__ __forceinline__ unsigned short pack_f8(float lo, float hi) {
    unsigned short r;
    asm("cvt.rn.satfinite.e4m3x2.f32 %0, %1, %2;" : "=h"(r) : "f"(hi), "f"(lo));
    return r;
}

// ---------------- weight conversions (6 bf16 weights) ----------------
__global__ void cvt_all(const float* __restrict__ s0, const float* __restrict__ s1,
                        const float* __restrict__ s2, const float* __restrict__ s3,
                        const float* __restrict__ s4, const float* __restrict__ s5) {
    int w = blockIdx.y;
    const float* src; bf16* dst; int n;
    switch (w) {
        case 0: src = s0; dst = b_wq; n = DIMN*DIMN; break;
        case 1: src = s1; dst = b_wk; n = DIMN*DIMN; break;
        case 2: src = s2; dst = b_wv; n = DIMN*DIMN; break;
        case 3: src = s3; dst = b_wo; n = DIMN*DIMN; break;
        case 4: src = s4; dst = b_w1; n = DIMN*HIDDEN; break;
        default: src = s5; dst = b_w3; n = DIMN*HIDDEN; break;
    }
    int i = (blockIdx.x * 256 + threadIdx.x) * 16;
    if (i < n) {
        float4 a = *(const float4*)(src + i);
        float4 b = *(const float4*)(src + i + 4);
        float4 c = *(const float4*)(src + i + 8);
        float4 d = *(const float4*)(src + i + 12);
        uint4 o1, o2;
        o1.x = pack_bf(a.x, a.y); o1.y = pack_bf(a.z, a.w);
        o1.z = pack_bf(b.x, b.y); o1.w = pack_bf(b.z, b.w);
        o2.x = pack_bf(c.x, c.y); o2.y = pack_bf(c.z, c.w);
        o2.z = pack_bf(d.x, d.y); o2.w = pack_bf(d.z, d.w);
        *(uint4*)(dst + i) = o1;
        *(uint4*)(dst + i + 8) = o2;
    }
}

// ---- w2 [K=2816][N=1024] fp32 -> w2t [N][K] e4m3 x64 ----
__global__ void cvt_w2t(const float* __restrict__ src) {
    int kt = blockIdx.x >> 5, nt = blockIdx.x & 31;
    __shared__ float sT[32][33];
    int tx = threadIdx.x & 31, ty0 = threadIdx.x >> 5;
    #pragma unroll
    for (int it = 0; it < 4; it++)
        sT[ty0 + 8*it][tx] = src[(size_t)(kt*32 + ty0 + 8*it) * DIMN + nt*32 + tx];
    __syncthreads();
    #pragma unroll
    for (int it = 0; it < 4; it++) {
        int row = ty0 + 8*it;
        __nv_fp8_e4m3 v(sT[tx][row] * 64.f);
        b_w2t[(size_t)(nt*32 + row) * HIDDEN + kt*32 + tx] = *(unsigned char*)&v;
    }
}

// -------- t = silu(adafm_input) @ proj_w + proj_b --------
__global__ void proj_t_kernel(const float* __restrict__ ad, const float* __restrict__ pw,
                              const float* __restrict__ pb, float* __restrict__ t) {
    int b = blockIdx.x, o0 = blockIdx.y * 64;
    __shared__ float s[DIMN];
    __shared__ float red[4][64];
    int tid = threadIdx.x;
    for (int i = tid; i < DIMN; i += 256) {
        float z = ad[b*DIMN + i];
        s[i] = z / (1.f + expf(-z));
    }
    __syncthreads();
    int o = o0 + (tid & 63), seg = tid >> 6;
    float acc = 0.f;
    #pragma unroll 4
    for (int i = seg*256; i < seg*256 + 256; i++) acc += s[i] * pw[i*512 + o];
    red[seg][tid & 63] = acc;
    __syncthreads();
    if (tid < 64)
        t[b*512 + o0 + tid] = red[0][tid] + red[1][tid] + red[2][tid] + red[3][tid] + pb[o0 + tid];
}

__global__ void make_g_kernel(const float* __restrict__ t) {
    int b = blockIdx.x >> 1, which = blockIdx.x & 1;
    int q0 = blockIdx.y * 32;
    const float* m = t + b*512 + which*256;
    __shared__ float cs[256], ms[256];
    __shared__ bf16 gd[512];
    int d = threadIdx.x;
    cs[d] = cosf((6.283185307179586f / 256.0f) * (float)d);
    ms[d] = m[d];
    __syncthreads();
    float acc = 0.f;
    #pragma unroll 4
    for (int k = 0; k < 256; k++) acc += ms[k] * cs[(k*d) & 255];
    bf16 gv = __float2bfloat16_rn(acc * (1.0f / 256.0f));
    gd[d] = gv; gd[d + 256] = gv;
    __syncthreads();
    bf16* Bg = (which ? b_gf : b_gm) + b * 65536;
    for (int q = q0; q < q0 + 32; q++)
        Bg[q*256 + d] = gd[d - q + 256];
}

__global__ void patchify(const float* __restrict__ x) {
    int c = blockIdx.x * 256 + threadIdx.x;
    int q  = (c & 31) * 8;
    int pi = (c >> 5) & 8191;
    int b  = c >> 18;
    int p = q >> 4, qq = q & 15;
    const float* src = x + ((size_t)(b*2048 + (pi >> 6)*16 + p)) * DIMN + (pi & 63)*16 + qq;
    float4 a = *(const float4*)src;
    float4 v = *(const float4*)(src + 4);
    uint4 o;
    o.x = pack_bf(a.x, a.y); o.y = pack_bf(a.z, a.w);
    o.z = pack_bf(v.x, v.y); o.w = pack_bf(v.z, v.w);
    *(uint4*)(b_xp + (size_t)c * 8) = o;
}

// ================= bf16 GEMM core (4-stage cp.async) =================
#define AKE 40
#define BNE 264
#define A_ELT (128*AKE)
#define B_ELT (32*BNE)
#define STG_ELT (A_ELT + B_ELT)
#define GEMM_SMEM (4 * STG_ELT * 2)

#define GEMM_PROLOG(Aptr, Bptr, Kdim, Ndim, bmv, bnv)                                    \
    extern __shared__ bf16 smb[];                                                        \
    const unsigned sbase = (unsigned)__cvta_generic_to_shared(smb);                      \
    const int tid  = threadIdx.x;                                                        \
    const int lane = tid & 31;                                                           \
    const int warp = tid >> 5;                                                           \
    const int g    = lane >> 2;                                                          \
    const int t4   = lane & 3;                                                           \
    const int lm   = lane & 15;                                                          \
    const int lh   = lane >> 4;                                                          \
    const int wm = (warp >> 2) * 64;                                                     \
    const int wn = (warp & 3) * 64;                                                      \
    float acc[4][8][4];                                                                  \
    _Pragma("unroll") for (int i = 0; i < 4; i++)                                        \
        _Pragma("unroll") for (int j = 0; j < 8; j++)                                    \
            _Pragma("unroll") for (int r = 0; r < 4; r++) acc[i][j][r] = 0.f;            \
    const int ktiles = (Kdim) >> 5;                                                      \
    auto load_stage = [&](int st, int k0) {                                              \
        unsigned sa = sbase + (unsigned)(st * STG_ELT) * 2u;                             \
        unsigned sb = sa + A_ELT * 2u;                                                   \
        _Pragma("unroll") for (int u = 0; u < 2; u++) {                                  \
            int c = tid + 256*u;                                                         \
            int r = c >> 2, o = (c & 3) * 8;                                             \
            cpa16(sa + (unsigned)(r*AKE + o)*2u, (Aptr) + (size_t)((bmv) + r) * (Kdim) + k0 + o); \
        }                                                                                \
        _Pragma("unroll") for (int u = 0; u < 4; u++) {                                  \
            int c = tid + 256*u;                                                         \
            int r = c >> 5, o = (c & 31) * 8;                                            \
            cpa16(sb + (unsigned)(r*BNE + o)*2u, (Bptr) + (size_t)(k0 + r) * (Ndim) + (bnv) + o); \
        }                                                                                \
    };                                                                                   \
    load_stage(0, 0);                                                                    \
    asm volatile("cp.async.commit_group;");                                              \
    load_stage(1, 32);                                                                   \
    asm volatile("cp.async.commit_group;");                                              \
    load_stage(2, 64);                                                                   \
    asm volatile("cp.async.commit_group;");                                              \
    for (int t = 0; t < ktiles; t++) {                                                   \
        asm volatile("cp.async.wait_group 2;");                                          \
        __syncthreads();                                                                 \
        int nt = t + 3;                                                                  \
        if (nt < ktiles) load_stage(nt & 3, nt * 32);                                    \
        asm volatile("cp.async.commit_group;");                                          \
        unsigned sa = sbase + (unsigned)((t & 3) * STG_ELT) * 2u;                        \
        unsigned sb = sa + A_ELT * 2u;                                                   \
        _Pragma("unroll") for (int kk = 0; kk < 32; kk += 16) {                          \
            unsigned af[4][4], bfr[8][2];                                                \
            _Pragma("unroll") for (int i = 0; i < 4; i++)                                \
                ldmx4(af[i][0], af[i][1], af[i][2], af[i][3],                            \
                      sa + (unsigned)((wm + 16*i + lm)*AKE + kk + lh*8)*2u);             \
            _Pragma("unroll") for (int j2 = 0; j2 < 4; j2++)                             \
                ldmx4t(bfr[2*j2][0], bfr[2*j2][1], bfr[2*j2+1][0], bfr[2*j2+1][1],       \
                       sb + (unsigned)((kk + lm)*BNE + wn + 16*j2 + lh*8)*2u);           \
            _Pragma("unroll") for (int i = 0; i < 4; i++)                                \
                _Pragma("unroll") for (int j = 0; j < 8; j++)                            \
                    mma16(acc[i][j], af[i][0], af[i][1], af[i][2], af[i][3],             \
                          bfr[j][0], bfr[j][1]);                                         \
        }                                                                                \
    }

// ---- generic gemm, bf16 out ----
__global__ __launch_bounds__(256, 1) void gemm_bf16o(const bf16* __restrict__ A,
                                                     const bf16* __restrict__ B,
                                                     bf16* __restrict__ Cb,
                                                     int M, int N, int K) {
    const int bm = blockIdx.y * 128;
    const int bn = blockIdx.x * 256;
    GEMM_PROLOG(A, B, K, N, bm, bn)
    #pragma unroll
    for (int i = 0; i < 4; i++) {
        int row0 = bm + wm + 16*i + g;
        #pragma unroll
        for (int j = 0; j < 8; j++) {
            int col = bn + wn + 8*j + 2*t4;
            *(unsigned*)(Cb + (size_t)row0 * N + col)       = pack_bf(acc[i][j][0], acc[i][j][1]);
            *(unsigned*)(Cb + (size_t)(row0 + 8) * N + col) = pack_bf(acc[i][j][2], acc[i][j][3]);
        }
    }
}

// ---- fused QKV gemm + RoPE + head-norm + sqk_eff ----
__global__ __launch_bounds__(256, 1) void gemm_qkv(const bf16* __restrict__ A,
                                                   const float* __restrict__ fcos,
                                                   const float* __restrict__ fsin,
                                                   const float* __restrict__ sqk) {
    const int wsel = blockIdx.x >> 2;
    const int bn = (blockIdx.x & 3) * 256;
    const int bm = blockIdx.y * 128;
    const bf16* B = (wsel == 0) ? b_wq : ((wsel == 1) ? b_wk : b_wv);
    bf16* C = (wsel == 0) ? b_q : ((wsel == 1) ? b_k : b_v);
    GEMM_PROLOG(A, B, DIMN, DIMN, bm, bn)
    if (wsel == 2) {
        #pragma unroll
        for (int i = 0; i < 4; i++) {
            int row0 = bm + wm + 16*i + g;
            #pragma unroll
            for (int j = 0; j < 8; j++) {
                int col = bn + wn + 8*j + 2*t4;
                *(unsigned*)(C + (size_t)row0 * DIMN + col)       = pack_bf(acc[i][j][0], acc[i][j][1]);
                *(unsigned*)(C + (size_t)(row0 + 8) * DIMN + col) = pack_bf(acc[i][j][2], acc[i][j][3]);
            }
        }
    } else {
        const int h = (bn + wn) >> 6;
        const float qscale = (wsel == 0) ? 8.f * 1.4426950408889634f : 1.f;
        #pragma unroll
        for (int i = 0; i < 4; i++) {
            int row0 = bm + wm + 16*i + g;
            int row1 = row0 + 8;
            float ss0 = 0.f, ss1 = 0.f;
            #pragma unroll
            for (int j = 0; j < 8; j++) {
                ss0 += acc[i][j][0]*acc[i][j][0] + acc[i][j][1]*acc[i][j][1];
                ss1 += acc[i][j][2]*acc[i][j][2] + acc[i][j][3]*acc[i][j][3];
            }
            ss0 += __shfl_xor_sync(0xffffffffu, ss0, 1);
            ss0 += __shfl_xor_sync(0xffffffffu, ss0, 2);
            ss1 += __shfl_xor_sync(0xffffffffu, ss1, 1);
            ss1 += __shfl_xor_sync(0xffffffffu, ss1, 2);
            float inv0 = qscale / fmaxf(sqrtf(ss0), 1e-12f);
            float inv1 = qscale / fmaxf(sqrtf(ss1), 1e-12f);
            int s0 = row0 & (SEQL - 1), s1 = row1 & (SEQL - 1);
            #pragma unroll
            for (int j = 0; j < 8; j++) {
                int pidx = 4*j + t4;
                int d = 8*j + 2*t4;
                float se0 = sqk[h*HDIM + d]     * 32.f;
                float se1 = sqk[h*HDIM + d + 1] * 32.f;
                float c0 = fcos[s0*32 + pidx], sn0 = fsin[s0*32 + pidx];
                float c1 = fcos[s1*32 + pidx], sn1 = fsin[s1*32 + pidx];
                float a0 = acc[i][j][0], a1 = acc[i][j][1];
                float b0 = acc[i][j][2], b1 = acc[i][j][3];
                int col = bn + wn + d;
                *(unsigned*)(C + (size_t)row0 * DIMN + col) =
                    pack_bf((a0*c0 - a1*sn0) * inv0 * se0, (a0*sn0 + a1*c0) * inv0 * se1);
                *(unsigned*)(C + (size_t)row1 * DIMN + col) =
                    pack_bf((b0*c1 - b1*sn1) * inv1 * se0, (b0*sn1 + b1*c1) * inv1 * se1);
            }
        }
    }
}

// ---- fused w1/w3 GEMM + silu gate -> fp8 h (x256) ----
__global__ __launch_bounds__(256, 1) void gemm_ffn13g(const bf16* __restrict__ A,
                                                      const float* __restrict__ su,
                                                      const float* __restrict__ sv) {
    const int bnb = blockIdx.x * 128;
    const int bm  = blockIdx.y * 128;
    extern __shared__ bf16 smb[];
    const unsigned sbase = (unsigned)__cvta_generic_to_shared(smb);
    const int tid  = threadIdx.x;
    const int lane = tid & 31;
    const int warp = tid >> 5;
    const int g    = lane >> 2;
    const int t4   = lane & 3;
    const int lm   = lane & 15;
    const int lh   = lane >> 4;
    const int wm = (warp >> 2) * 64;
    const int wn = (warp & 3) * 32;

    float acc1[4][4][4], acc3[4][4][4];
    #pragma unroll
    for (int i = 0; i < 4; i++)
        #pragma unroll
        for (int j = 0; j < 4; j++)
            #pragma unroll
            for (int r = 0; r < 4; r++) { acc1[i][j][r] = 0.f; acc3[i][j][r] = 0.f; }

    const int ktiles = DIMN >> 5;
    auto load_stage = [&](int st, int k0) {
        unsigned sa = sbase + (unsigned)(st * STG_ELT) * 2u;
        unsigned sb = sa + A_ELT * 2u;
        #pragma unroll
        for (int u = 0; u < 2; u++) {
            int c = tid + 256*u;
            int r = c >> 2, o = (c & 3) * 8;
            cpa16(sa + (unsigned)(r*AKE + o)*2u, A + (size_t)(bm + r) * DIMN + k0 + o);
        }
        #pragma unroll
        for (int u = 0; u < 4; u++) {
            int c = tid + 256*u;
            int r = c >> 5, o = (c & 31) * 8;
            const bf16* src = (o < 128)
                ? (b_w1 + (size_t)(k0 + r) * HIDDEN + bnb + o)
                : (b_w3 + (size_t)(k0 + r) * HIDDEN + bnb + o - 128);
            cpa16(sb + (unsigned)(r*BNE + o)*2u, src);
        }
    };
    load_stage(0, 0);
    asm volatile("cp.async.commit_group;");
    load_stage(1, 32);
    asm volatile("cp.async.commit_group;");
    load_stage(2, 64);
    asm volatile("cp.async.commit_group;");

    for (int t = 0; t < ktiles; t++) {
        asm volatile("cp.async.wait_group 2;");
        __syncthreads();
        int nt = t + 3;
        if (nt < ktiles) load_stage(nt & 3, nt * 32);
        asm volatile("cp.async.commit_group;");
        unsigned sa = sbase + (unsigned)((t & 3) * STG_ELT) * 2u;
        unsigned sb = sa + A_ELT * 2u;
        #pragma unroll
        for (int kk = 0; kk < 32; kk += 16) {
            unsigned af[4][4], b1f[4][2], b3f[4][2];
            #pragma unroll
            for (int i = 0; i < 4; i++)
                ldmx4(af[i][0], af[i][1], af[i][2], af[i][3],
                      sa + (unsigned)((wm + 16*i + lm)*AKE + kk + lh*8)*2u);
            #pragma unroll
            for (int j2 = 0; j2 < 2; j2++) {
                ldmx4t(b1f[2*j2][0], b1f[2*j2][1], b1f[2*j2+1][0], b1f[2*j2+1][1],
                       sb + (unsigned)((kk + lm)*BNE + wn + 16*j2 + lh*8)*2u);
                ldmx4t(b3f[2*j2][0], b3f[2*j2][1], b3f[2*j2+1][0], b3f[2*j2+1][1],
                       sb + (unsigned)((kk + lm)*BNE + 128 + wn + 16*j2 + lh*8)*2u);
            }
            #pragma unroll
            for (int i = 0; i < 4; i++)
                #pragma unroll
                for (int j = 0; j < 4; j++) {
                    mma16(acc1[i][j], af[i][0], af[i][1], af[i][2], af[i][3], b1f[j][0], b1f[j][1]);
                    mma16(acc3[i][j], af[i][0], af[i][1], af[i][2], af[i][3], b3f[j][0], b3f[j][1]);
                }
        }
    }

    const float SC = 53.06599664568481f;
    #pragma unroll
    for (int i = 0; i < 4; i++) {
        int row0 = bm + wm + 16*i + g;
        #pragma unroll
        for (int j = 0; j < 4; j++) {
            int col = bnb + wn + 8*j + 2*t4;
            float sv0 = sv[col] * SC, sv1 = sv[col+1] * SC;
            float su0 = su[col],      su1 = su[col+1];
            float z, sgl, outv[4];
            z = acc1[i][j][0] * sv0; sgl = z / (1.f + __expf(-z)); outv[0] = sgl * (acc3[i][j][0] * su0);
            z = acc1[i][j][1] * sv1; sgl = z / (1.f + __expf(-z)); outv[1] = sgl * (acc3[i][j][1] * su1);
            z = acc1[i][j][2] * sv0; sgl = z / (1.f + __expf(-z)); outv[2] = sgl * (acc3[i][j][2] * su0);
            z = acc1[i][j][3] * sv1; sgl = z / (1.f + __expf(-z)); outv[3] = sgl * (acc3[i][j][3] * su1);
            *(unsigned short*)(b_h8 + (size_t)row0 * HIDDEN + col)
                = pack_f8(outv[0]*256.f, outv[1]*256.f);
            *(unsigned short*)(b_h8 + (size_t)(row0 + 8) * HIDDEN + col)
                = pack_f8(outv[2]*256.f, outv[3]*256.f);
        }
    }
}

// ---- w2 fp8 GEMM: Cb[4096,1024] bf16 = (h8/256) @ (w2t/64)^T ----
#define A8S 80
#define B8S 80
#define STG8 (128*A8S + 256*B8S)
#define W2F8_SMEM (4 * STG8)

__global__ __launch_bounds__(256, 1) void gemm_w2f8(bf16* __restrict__ Cb) {
    const int bm = blockIdx.y * 128;
    const int bn = blockIdx.x * 256;
    extern __shared__ __align__(16) unsigned char sm8[];
    const unsigned sbase = (unsigned)__cvta_generic_to_shared(sm8);
    const int tid  = threadIdx.x;
    const int lane = tid & 31;
    const int warp = tid >> 5;
    const int g    = lane >> 2;
    const int t4   = lane & 3;
    const int lm   = lane & 15;
    const int lh   = lane >> 4;
    const int wm = (warp >> 2) * 64;
    const int wn = (warp & 3) * 64;
    const int q8 = lane >> 3, r8 = lane & 7;

    float acc[4][8][4];
    #pragma unroll
    for (int i = 0; i < 4; i++)
        #pragma unroll
        for (int j = 0; j < 8; j++)
            #pragma unroll
            for (int r = 0; r < 4; r++) acc[i][j][r] = 0.f;

    const int ktiles = HIDDEN >> 6;   // 44
    auto load_stage = [&](int st, int k0) {
        unsigned sa = sbase + (unsigned)(st * STG8);
        unsigned sb = sa + 128*A8S;
        #pragma unroll
        for (int u = 0; u < 2; u++) {
            int c = tid + 256*u;
            int r = c >> 2, o = (c & 3) * 16;
            cpa16(sa + (unsigned)(r*A8S + o), b_h8 + (size_t)(bm + r) * HIDDEN + k0 + o);
        }
        #pragma unroll
        for (int u = 0; u < 4; u++) {
            int c = tid + 256*u;
            int r = c >> 2, o = (c & 3) * 16;
            cpa16(sb + (unsigned)(r*B8S + o), b_w2t + (size_t)(bn + r) * HIDDEN + k0 + o);
        }
    };
    load_stage(0, 0);
    asm volatile("cp.async.commit_group;");
    load_stage(1, 64);
    asm volatile("cp.async.commit_group;");
    load_stage(2, 128);
    asm volatile("cp.async.commit_group;");

    for (int t = 0; t < ktiles; t++) {
        asm volatile("cp.async.wait_group 2;");
        __syncthreads();
        int nt = t + 3;
        if (nt < ktiles) load_stage(nt & 3, nt * 64);
        asm volatile("cp.async.commit_group;");
        unsigned sa = sbase + (unsigned)((t & 3) * STG8);
        unsigned sb = sa + 128*A8S;
        #pragma unroll
        for (int ks = 0; ks < 2; ks++) {
            int k0 = ks * 32;
            unsigned af[4][4], bfr[8][2];
            #pragma unroll
            for (int i = 0; i < 4; i++)
                ldmx4(af[i][0], af[i][1], af[i][2], af[i][3],
                      sa + (unsigned)((wm + 16*i + lm)*A8S + k0 + lh*16));
            #pragma unroll
            for (int jp = 0; jp < 4; jp++) {
                // x4: m0=j b0, m1=j b1, m2=j+1 b0, m3=j+1 b1 (per-lane addresses)
                int n0 = wn + 16*jp;
                unsigned addr = sb + (unsigned)((n0 + ((q8 >> 1) << 3) + r8)*B8S + k0 + ((q8 & 1) << 4));
                ldmx4(bfr[2*jp][0], bfr[2*jp][1], bfr[2*jp+1][0], bfr[2*jp+1][1], addr);
            }
            #pragma unroll
            for (int i = 0; i < 4; i++)
                #pragma unroll
                for (int j = 0; j < 8; j++)
                    mma8f8(acc[i][j], af[i][0], af[i][1], af[i][2], af[i][3],
                           bfr[j][0], bfr[j][1]);
        }
    }

    const float OS = 1.f / 16384.f;
    #pragma unroll
    for (int i = 0; i < 4; i++) {
        int row0 = bm + wm + 16*i + g;
        #pragma unroll
        for (int j = 0; j < 8; j++) {
            int col = bn + wn + 8*j + 2*t4;
            *(unsigned*)(Cb + (size_t)row0 * DIMN + col)       = pack_bf(acc[i][j][0]*OS, acc[i][j][1]*OS);
            *(unsigned*)(Cb + (size_t)(row0 + 8) * DIMN + col) = pack_bf(acc[i][j][2]*OS, acc[i][j][3]*OS);
        }
    }
}

// ---- adafm gemm: Y[pi][t] = Xp @ Bg, scatter to token layout ----
__global__ __launch_bounds__(256, 1) void adafm_gemm(const bf16* __restrict__ Bg0,
                                                     bf16* __restrict__ Y) {
    const int z  = blockIdx.z;
    const int bm = blockIdx.y * 128;
    const int bn = 0;
    const bf16* A = b_xp + (size_t)z * 8192 * 256;
    const bf16* B = Bg0 + (size_t)z * 65536;
    GEMM_PROLOG(A, B, 256, 256, bm, bn)
    bf16* Yb = Y + (size_t)z * 2048 * DIMN;
    #pragma unroll
    for (int i = 0; i < 4; i++) {
        int pi0 = bm + wm + 16*i + g;
        #pragma unroll
        for (int j = 0; j < 8; j++) {
            int col = wn + 8*j + 2*t4;
            int p = col >> 4, qq = col & 15;
            *(unsigned*)(Yb + (size_t)((pi0 >> 6)*16 + p) * DIMN + (pi0 & 63)*16 + qq)
                = pack_bf(acc[i][j][0], acc[i][j][1]);
            int pi = pi0 + 8;
            *(unsigned*)(Yb + (size_t)((pi >> 6)*16 + p) * DIMN + (pi & 63)*16 + qq)
                = pack_bf(acc[i][j][2], acc[i][j][3]);
        }
    }
}

// --------- FA2 flash attention, cp.async 3-stage ring ---------
#define FAE 72
#define FLASH_SMEM ((128 + 6*64) * FAE * 2)

__global__ __launch_bounds__(256, 2) void flash_attn(const bf16* __restrict__ Q,
                                                     const bf16* __restrict__ K,
                                                     const bf16* __restrict__ V,
                                                     bf16* __restrict__ O) {
    extern __shared__ bf16 fsm[];
    bf16* Qs = fsm;
    const unsigned sQ  = (unsigned)__cvta_generic_to_shared(Qs);
    const unsigned sK0 = sQ + 128*FAE*2u;
    const unsigned sV0 = sK0 + 3*64*FAE*2u;

    const int q0 = blockIdx.x * 128;
    const int h  = blockIdx.y;
    const int b  = blockIdx.z;
    const bf16* Qb = Q + (size_t)b*SEQL*DIMN + h*HDIM;
    const bf16* Kb = K + (size_t)b*SEQL*DIMN + h*HDIM;
    const bf16* Vb = V + (size_t)b*SEQL*DIMN + h*HDIM;
    bf16*       Ob = O + (size_t)b*SEQL*DIMN + h*HDIM;

    const int tid  = threadIdx.x;
    const int lane = tid & 31;
    const int warp = tid >> 5;
    const int g  = lane >> 2;
    const int t4 = lane & 3;
    const int lm = lane & 15;
    const int lh = lane >> 4;
    const int wm = warp * 16;

    auto loadKV = [&](int st, int k0) {
        unsigned sk = sK0 + (unsigned)st * 64*FAE*2u;
        unsigned sv = sV0 + (unsigned)st * 64*FAE*2u;
        #pragma unroll
        for (int u = 0; u < 2; u++) {
            int c = tid + 256*u;
            int r = c >> 3, ofs = (c & 7) * 8;
            cpa16(sk + (unsigned)(r*FAE + ofs)*2u, Kb + (size_t)(k0 + r)*DIMN + ofs);
            cpa16(sv + (unsigned)(r*FAE + ofs)*2u, Vb + (size_t)(k0 + r)*DIMN + ofs);
        }
    };

    #pragma unroll
    for (int u = 0; u < 4; u++) {
        int c = tid + 256*u;
        int r = c >> 3, ofs = (c & 7) * 8;
        *(uint4*)&Qs[r*FAE + ofs] = *(const uint4*)(Qb + (size_t)(q0 + r)*DIMN + ofs);
    }

    loadKV(0, 0);
    asm volatile("cp.async.commit_group;");
    loadKV(1, 64);
    asm volatile("cp.async.commit_group;");

    float o[8][4];
    #pragma unroll
    for (int j = 0; j < 8; j++)
        #pragma unroll
        for (int r = 0; r < 4; r++) o[j][r] = 0.f;
    float m0 = -1e30f, m1 = -1e30f, l0 = 0.f, l1 = 0.f;

    const int NT = SEQL / 64;
    for (int t = 0; t < NT; t++) {
        if (t + 1 < NT) asm volatile("cp.async.wait_group 1;");
        else            asm volatile("cp.async.wait_group 0;");
        __syncthreads();
        if (t + 2 < NT) {
            loadKV((t + 2) % 3, (t + 2) * 64);
            asm volatile("cp.async.commit_group;");
        }

        const unsigned sK = sK0 + (unsigned)(t % 3) * 64*FAE*2u;
        const unsigned sV = sV0 + (unsigned)(t % 3) * 64*FAE*2u;

        float s[8][4];
        #pragma unroll
        for (int j = 0; j < 8; j++)
            #pragma unroll
            for (int r = 0; r < 4; r++) s[j][r] = 0.f;

        #pragma unroll
        for (int kc = 0; kc < 4; kc++) {
            int kk = 16*kc;
            unsigned a0, a1, a2, a3;
            ldmx4(a0, a1, a2, a3, sQ + (unsigned)((wm + lm)*FAE + kk + lh*8)*2u);
            #pragma unroll
            for (int j2 = 0; j2 < 4; j2++) {
                unsigned r0, r1, r2, r3;
                ldmx4(r0, r1, r2, r3,
                      sK + (unsigned)((16*j2 + (lane & 7) + ((lane >> 4) << 3))*FAE
                                       + kk + (((lane >> 3) & 1) << 3))*2u);
                mma16(s[2*j2],     a0, a1, a2, a3, r0, r1);
                mma16(s[2*j2 + 1], a0, a1, a2, a3, r2, r3);
            }
        }

        float tm0 = -1e30f, tm1 = -1e30f;
        #pragma unroll
        for (int j = 0; j < 8; j++) {
            tm0 = fmaxf(tm0, fmaxf(s[j][0], s[j][1]));
            tm1 = fmaxf(tm1, fmaxf(s[j][2], s[j][3]));
        }
        tm0 = fmaxf(tm0, __shfl_xor_sync(0xffffffffu, tm0, 1));
        tm0 = fmaxf(tm0, __shfl_xor_sync(0xffffffffu, tm0, 2));
        tm1 = fmaxf(tm1, __shfl_xor_sync(0xffffffffu, tm1, 1));
        tm1 = fmaxf(tm1, __shfl_xor_sync(0xffffffffu, tm1, 2));
        float mn0 = fmaxf(m0, tm0), mn1 = fmaxf(m1, tm1);
        float c0 = exp2f(m0 - mn0), c1 = exp2f(m1 - mn1);
        float ps0 = 0.f, ps1 = 0.f;
        #pragma unroll
        for (int j = 0; j < 8; j++) {
            s[j][0] = exp2f(s[j][0] - mn0);
            s[j][1] = exp2f(s[j][1] - mn0);
            s[j][2] = exp2f(s[j][2] - mn1);
            s[j][3] = exp2f(s[j][3] - mn1);
            ps0 += s[j][0] + s[j][1];
            ps1 += s[j][2] + s[j][3];
        }
        ps0 += __shfl_xor_sync(0xffffffffu, ps0, 1);
        ps0 += __shfl_xor_sync(0xffffffffu, ps0, 2);
        ps1 += __shfl_xor_sync(0xffffffffu, ps1, 1);
        ps1 += __shfl_xor_sync(0xffffffffu, ps1, 2);
        l0 = l0 * c0 + ps0;  l1 = l1 * c1 + ps1;
        m0 = mn0;            m1 = mn1;
        #pragma unroll
        for (int j = 0; j < 8; j++) {
            o[j][0] *= c0; o[j][1] *= c0; o[j][2] *= c1; o[j][3] *= c1;
        }

        #pragma unroll
        for (int c = 0; c < 4; c++) {
            unsigned pa0 = pack_bf(s[2*c][0],   s[2*c][1]);
            unsigned pa1 = pack_bf(s[2*c][2],   s[2*c][3]);
            unsigned pa2 = pack_bf(s[2*c+1][0], s[2*c+1][1]);
            unsigned pa3 = pack_bf(s[2*c+1][2], s[2*c+1][3]);
            #pragma unroll
            for (int j2 = 0; j2 < 4; j2++) {
                unsigned r0, r1, r2, r3;
                ldmx4t(r0, r1, r2, r3,
                       sV + (unsigned)((16*c + lm)*FAE + 16*j2 + lh*8)*2u);
                mma16(o[2*j2],     pa0, pa1, pa2, pa3, r0, r1);
                mma16(o[2*j2 + 1], pa0, pa1, pa2, pa3, r2, r3);
            }
        }
    }

    float inv0 = 1.f / l0, inv1 = 1.f / l1;
    #pragma unroll
    for (int j = 0; j < 8; j++) {
        int col = 8*j + 2*t4;
        *(unsigned*)(Ob + (size_t)(q0 + wm + g    )*DIMN + col) = pack_bf(o[j][0]*inv0, o[j][1]*inv0);
        *(unsigned*)(Ob + (size_t)(q0 + wm + g + 8)*DIMN + col) = pack_bf(o[j][2]*inv1, o[j][3]*inv1);
    }
}

// ------- fused residual + norms; branch input bf16; optional patchified output -------
__global__ __launch_bounds__(256) void residual_norm(const float* __restrict__ xb,
                                                     const bf16* __restrict__ br,
                                                     const float* __restrict__ alpha,
                                                     float* __restrict__ out,
                                                     bf16* __restrict__ xp) {
    int t = blockIdx.x;
    int tid = threadIdx.x;
    const float* xr = xb + (size_t)t * DIMN;
    const bf16*  rr = br + (size_t)t * DIMN;
    float xv[4], bv[4];
    float ssx = 0.f, ssb = 0.f;
    #pragma unroll
    for (int u = 0; u < 2; u++) {
        int d = tid*2 + u * 512;
        float2 xx = *(const float2*)(xr + d);
        float2 bb = unpack_bf(*(const unsigned*)(rr + d));
        xv[2*u] = xx.x; xv[2*u+1] = xx.y;
        bv[2*u] = bb.x; bv[2*u+1] = bb.y;
        ssx += xx.x*xx.x + xx.y*xx.y;
        ssb += bb.x*bb.x + bb.y*bb.y;
    }
    ssx = blockSum256(ssx);
    ssb = blockSum256(ssb);
    float rx = 1.f / fmaxf(sqrtf(ssx), 1e-12f);
    float rb = 1.f / fmaxf(sqrtf(ssb), 1e-12f);
    float yv[4]; float ssy = 0.f;
    #pragma unroll
    for (int u = 0; u < 4; u++) {
        int d = tid*2 + (u >> 1) * 512 + (u & 1);
        float hh = xv[u] * rx;
        float ha = bv[u] * rb;
        float lr = fabsf(alpha[d] * 1.6f);
        float y = hh + lr * (ha - hh);
        yv[u] = y; ssy += y * y;
    }
    ssy = blockSum256(ssy);
    float ry = 1.f / fmaxf(sqrtf(ssy), 1e-12f);
    int b = t >> 11, se = t & 2047;
    int ip = se >> 4, p = se & 15;
    #pragma unroll
    for (int u = 0; u < 4; u++) {
        int d = tid*2 + (u >> 1) * 512 + (u & 1);
        float y = yv[u] * ry;
        out[(size_t)t * DIMN + d] = y;
        if (xp) {
            int jj = d >> 4, qq = d & 15;
            xp[((size_t)b*8192 + ip*64 + jj)*256 + p*16 + qq] = __float2bfloat16_rn(y);
        }
    }
}

// ---------------- launch ----------------
extern "C" void kernel_launch(void* const* d_in, const int* in_sizes, int n_in,
                              void* d_out, int out_size) {
    const float* x      = (const float*)d_in[0];
    const float* fcos   = (const float*)d_in[1];
    const float* fsin   = (const float*)d_in[2];
    const float* adafm  = (const float*)d_in[3];
    const float* wq     = (const float*)d_in[4];
    const float* wk     = (const float*)d_in[5];
    const float* wv     = (const float*)d_in[6];
    const float* wo     = (const float*)d_in[7];
    const float* sqk    = (const float*)d_in[8];
    const float* w1     = (const float*)d_in[9];
    const float* w2     = (const float*)d_in[10];
    const float* w3     = (const float*)d_in[11];
    const float* su     = (const float*)d_in[12];
    const float* sv     = (const float*)d_in[13];
    const float* pw     = (const float*)d_in[14];
    const float* pb     = (const float*)d_in[15];
    const float* aalpha = (const float*)d_in[16];
    const float* malpha = (const float*)d_in[17];
    float* out = (float*)d_out;

    float *pt, *pf0;
    bf16 *pbgm, *pbgf, *pbxa, *pbq, *pbk, *pbv, *pbao, *pbwo, *pbxp;
    cudaGetSymbolAddress((void**)&pt,  d_t);
    cudaGetSymbolAddress((void**)&pf0, d_f0);
    cudaGetSymbolAddress((void**)&pbgm, b_gm);
    cudaGetSymbolAddress((void**)&pbgf, b_gf);
    cudaGetSymbolAddress((void**)&pbxa, b_xa);
    cudaGetSymbolAddress((void**)&pbq,  b_q);
    cudaGetSymbolAddress((void**)&pbk,  b_k);
    cudaGetSymbolAddress((void**)&pbv,  b_v);
    cudaGetSymbolAddress((void**)&pbao, b_ao);
    cudaGetSymbolAddress((void**)&pbwo, b_wo);
    cudaGetSymbolAddress((void**)&pbxp, b_xp);

    cudaFuncSetAttribute(gemm_bf16o, cudaFuncAttributeMaxDynamicSharedMemorySize, GEMM_SMEM);
    cudaFuncSetAttribute(gemm_qkv, cudaFuncAttributeMaxDynamicSharedMemorySize, GEMM_SMEM);
    cudaFuncSetAttribute(gemm_ffn13g, cudaFuncAttributeMaxDynamicSharedMemorySize, GEMM_SMEM);
    cudaFuncSetAttribute(adafm_gemm, cudaFuncAttributeMaxDynamicSharedMemorySize, GEMM_SMEM);
    cudaFuncSetAttribute(gemm_w2f8, cudaFuncAttributeMaxDynamicSharedMemorySize, W2F8_SMEM);
    cudaFuncSetAttribute(flash_attn, cudaFuncAttributeMaxDynamicSharedMemorySize, FLASH_SMEM);

    // 0) weight conversions
    cvt_all<<<dim3(704, 6), 256>>>(wq, wk, wv, wo, w1, w3);
    cvt_w2t<<<2816, 256>>>(w2);

    // 1) time-modulation
    proj_t_kernel<<<dim3(BATCH, 8), 256>>>(adafm, pw, pb, pt);
    make_g_kernel<<<dim3(4, 8), 256>>>(pt);

    // 2) attention branch
    patchify<<<2048, 256>>>(x);
    adafm_gemm<<<dim3(1, 64, 2), 256, GEMM_SMEM>>>(pbgm, pbxa);
    gemm_qkv<<<dim3(12, 32), 256, GEMM_SMEM>>>(pbxa, fcos, fsin, sqk);
    flash_attn<<<dim3(SEQL/128, NHEAD, BATCH), 256, FLASH_SMEM>>>(pbq, pbk, pbv, pbao);
    gemm_bf16o<<<dim3(DIMN/256, TOK/128), 256, GEMM_SMEM>>>(pbao, pbwo, pbq, TOK, DIMN, DIMN);
    residual_norm<<<TOK, 256>>>(x, pbq, aalpha, pf0, pbxp);

    // 3) FFN branch
    adafm_gemm<<<dim3(1, 64, 2), 256, GEMM_SMEM>>>(pbgf, pbxa);
    gemm_ffn13g<<<dim3(HIDDEN/128, TOK/128), 256, GEMM_SMEM>>>(pbxa, su, sv);
    gemm_w2f8<<<dim3(DIMN/256, TOK/128), 256, W2F8_SMEM>>>(pbk);
    residual_norm<<<TOK, 256>>>(pf0, pbk, malpha, out, (bf16*)0);
}

// round 14
// speedup vs baseline: 7.2326x; 1.0033x over previous
#include <cuda_runtime.h>
#include <cuda_bf16.h>
#include <cuda_fp8.h>
#include <math.h>

typedef __nv_bfloat16 bf16;

#define DIMN   1024
#define NHEAD  16
#define HDIM   64
#define SEQL   2048
#define BATCH  2
#define TOK    4096
#define HIDDEN 2816

// ---------------- scratch ----------------
__device__ float d_t [BATCH*512];
__device__ float d_f0[TOK*DIMN];

__device__ bf16 b_wq[DIMN*DIMN], b_wk[DIMN*DIMN], b_wv[DIMN*DIMN], b_wo[DIMN*DIMN];
__device__ unsigned char b_w13t[(size_t)2*HIDDEN*DIMN];   // fp8 [N][K] w1|w3, x256
__device__ unsigned char b_w2t[(size_t)DIMN*HIDDEN];      // fp8 [N][K], x64
__device__ bf16 b_xp[BATCH*8192*256];
__device__ bf16 b_gm[BATCH*256*256];
__device__ bf16 b_gf[BATCH*256*256];
__device__ bf16 b_xa[TOK*DIMN];
__device__ unsigned char b_xm8[TOK*DIMN];                 // fp8 xm, x16
__device__ bf16 b_q [TOK*DIMN], b_k[TOK*DIMN], b_v[TOK*DIMN], b_ao[TOK*DIMN];
__device__ unsigned char b_h8[(size_t)TOK*HIDDEN];        // fp8 gated h, x256

// ---------------- helpers ----------------
__device__ __forceinline__ float blockSum256(float v) {
    __shared__ float red[8];
    int lane = threadIdx.x & 31, wid = threadIdx.x >> 5;
    #pragma unroll
    for (int o = 16; o > 0; o >>= 1) v += __shfl_xor_sync(0xffffffffu, v, o);
    __syncthreads();
    if (lane == 0) red[wid] = v;
    __syncthreads();
    float s = red[0];
    #pragma unroll
    for (int w = 1; w < 8; w++) s += red[w];
    return s;
}
__device__ __forceinline__ void mma16(float* c, unsigned a0, unsigned a1, unsigned a2, unsigned a3,
                                      unsigned b0, unsigned b1) {
    asm volatile("mma.sync.aligned.m16n8k16.row.col.f32.bf16.bf16.f32 "
        "{%0,%1,%2,%3}, {%4,%5,%6,%7}, {%8,%9}, {%0,%1,%2,%3};"
        : "+f"(c[0]), "+f"(c[1]), "+f"(c[2]), "+f"(c[3])
        : "r"(a0), "r"(a1), "r"(a2), "r"(a3), "r"(b0), "r"(b1));
}
__device__ __forceinline__ void mma8f8(float* c, unsigned a0, unsigned a1, unsigned a2, unsigned a3,
                                       unsigned b0, unsigned b1) {
    asm volatile("mma.sync.aligned.m16n8k32.row.col.f32.e4m3.e4m3.f32 "
        "{%0,%1,%2,%3}, {%4,%5,%6,%7}, {%8,%9}, {%0,%1,%2,%3};"
        : "+f"(c[0]), "+f"(c[1]), "+f"(c[2]), "+f"(c[3])
        : "r"(a0), "r"(a1), "r"(a2), "r"(a3), "r"(b0), "r"(b1));
}
__device__ __forceinline__ void ldmx4(unsigned& r0, unsigned& r1, unsigned& r2, unsigned& r3, unsigned a) {
    asm volatile("ldmatrix.sync.aligned.m8n8.x4.shared.b16 {%0,%1,%2,%3}, [%4];"
                 : "=r"(r0), "=r"(r1), "=r"(r2), "=r"(r3) : "r"(a));
}
__device__ __forceinline__ void ldmx4t(unsigned& r0, unsigned& r1, unsigned& r2, unsigned& r3, unsigned a) {
    asm volatile("ldmatrix.sync.aligned.m8n8.x4.trans.shared.b16 {%0,%1,%2,%3}, [%4];"
                 : "=r"(r0), "=r"(r1), "=r"(r2), "=r"(r3) : "r"(a));
}
__device__ __forceinline__ void cpa16(unsigned s, const void* g) {
    asm volatile("cp.async.cg.shared.global [%0], [%1], 16;" :: "r"(s), "l"(g));
}
__device__ __forceinline__ unsigned pack_bf(float a, float b) {
    __nv_bfloat162 t; t.x = __float2bfloat16_rn(a); t.y = __float2bfloat16_rn(b);
    return *(unsigned*)&t;
}
__device__ __forceinline__ float2 unpack_bf(unsigned u) {
    __nv_bfloat162 t = *(__nv_bfloat162*)&u;
    return make_float2(__bfloat162float(t.x), __bfloat162float(t.y));
}
__device__ __forceinline__ unsigned short pack_f8(float lo, float hi) {
    unsigned short r;
    asm("cvt.rn.satfinite.e4m3x2.f32 %0, %1, %2;" : "=h"(r) : "f"(hi), "f"(lo));
    return r;
}

// ---------------- weight conversions (4 bf16 weights) ----------------
__global__ void cvt_all(const float* __restrict__ s0, const float* __restrict__ s1,
                        const float* __restrict__ s2, const float* __restrict__ s3) {
    int w = blockIdx.y;
    const float* src = (w == 0) ? s0 : (w == 1 ? s1 : (w == 2 ? s2 : s3));
    bf16* dst = (w == 0) ? b_wq : (w == 1 ? b_wk : (w == 2 ? b_wv : b_wo));
    int i = (blockIdx.x * 256 + threadIdx.x) * 16;
    float4 a = *(const float4*)(src + i);
    float4 b = *(const float4*)(src + i + 4);
    float4 c = *(const float4*)(src + i + 8);
    float4 d = *(const float4*)(src + i + 12);
    uint4 o1, o2;
    o1.x = pack_bf(a.x, a.y); o1.y = pack_bf(a.z, a.w);
    o1.z = pack_bf(b.x, b.y); o1.w = pack_bf(b.z, b.w);
    o2.x = pack_bf(c.x, c.y); o2.y = pack_bf(c.z, c.w);
    o2.z = pack_bf(d.x, d.y); o2.w = pack_bf(d.z, d.w);
    *(uint4*)(dst + i) = o1;
    *(uint4*)(dst + i + 8) = o2;
}

// ---- w1/w3 [K=1024][N=2816] fp32 -> w13t [N][K] e4m3 x256 ----
__global__ void cvt_w13t(const float* __restrict__ s1, const float* __restrict__ s3) {
    const float* src = blockIdx.y ? s3 : s1;
    unsigned char* dst = b_w13t + (blockIdx.y ? (size_t)HIDDEN*DIMN : 0);
    const int ntN = HIDDEN / 32;   // 88
    int kt = blockIdx.x / ntN, nt = blockIdx.x % ntN;
    __shared__ float sT[32][33];
    int tx = threadIdx.x & 31, ty0 = threadIdx.x >> 5;
    #pragma unroll
    for (int it = 0; it < 4; it++)
        sT[ty0 + 8*it][tx] = src[(size_t)(kt*32 + ty0 + 8*it) * HIDDEN + nt*32 + tx];
    __syncthreads();
    #pragma unroll
    for (int it = 0; it < 4; it++) {
        int row = ty0 + 8*it;
        __nv_fp8_e4m3 v(sT[tx][row] * 256.f);
        dst[(size_t)(nt*32 + row) * DIMN + kt*32 + tx] = *(unsigned char*)&v;
    }
}

// ---- w2 [K=2816][N=1024] fp32 -> w2t [N][K] e4m3 x64 ----
__global__ void cvt_w2t(const float* __restrict__ src) {
    int kt = blockIdx.x >> 5, nt = blockIdx.x & 31;
    __shared__ float sT[32][33];
    int tx = threadIdx.x & 31, ty0 = threadIdx.x >> 5;
    #pragma unroll
    for (int it = 0; it < 4; it++)
        sT[ty0 + 8*it][tx] = src[(size_t)(kt*32 + ty0 + 8*it) * DIMN + nt*32 + tx];
    __syncthreads();
    #pragma unroll
    for (int it = 0; it < 4; it++) {
        int row = ty0 + 8*it;
        __nv_fp8_e4m3 v(sT[tx][row] * 64.f);
        b_w2t[(size_t)(nt*32 + row) * HIDDEN + kt*32 + tx] = *(unsigned char*)&v;
    }
}

// -------- t = silu(adafm_input) @ proj_w + proj_b --------
__global__ void proj_t_kernel(const float* __restrict__ ad, const float* __restrict__ pw,
                              const float* __restrict__ pb, float* __restrict__ t) {
    int b = blockIdx.x, o0 = blockIdx.y * 64;
    __shared__ float s[DIMN];
    __shared__ float red[4][64];
    int tid = threadIdx.x;
    for (int i = tid; i < DIMN; i += 256) {
        float z = ad[b*DIMN + i];
        s[i] = z / (1.f + expf(-z));
    }
    __syncthreads();
    int o = o0 + (tid & 63), seg = tid >> 6;
    float acc = 0.f;
    #pragma unroll 4
    for (int i = seg*256; i < seg*256 + 256; i++) acc += s[i] * pw[i*512 + o];
    red[seg][tid & 63] = acc;
    __syncthreads();
    if (tid < 64)
        t[b*512 + o0 + tid] = red[0][tid] + red[1][tid] + red[2][tid] + red[3][tid] + pb[o0 + tid];
}

__global__ void make_g_kernel(const float* __restrict__ t) {
    int b = blockIdx.x >> 1, which = blockIdx.x & 1;
    int q0 = blockIdx.y * 32;
    const float* m = t + b*512 + which*256;
    __shared__ float cs[256], ms[256];
    __shared__ bf16 gd[512];
    int d = threadIdx.x;
    cs[d] = cosf((6.283185307179586f / 256.0f) * (float)d);
    ms[d] = m[d];
    __syncthreads();
    float acc = 0.f;
    #pragma unroll 4
    for (int k = 0; k < 256; k++) acc += ms[k] * cs[(k*d) & 255];
    bf16 gv = __float2bfloat16_rn(acc * (1.0f / 256.0f));
    gd[d] = gv; gd[d + 256] = gv;
    __syncthreads();
    bf16* Bg = (which ? b_gf : b_gm) + b * 65536;
    for (int q = q0; q < q0 + 32; q++)
        Bg[q*256 + d] = gd[d - q + 256];
}

__global__ void patchify(const float* __restrict__ x) {
    int c = blockIdx.x * 256 + threadIdx.x;
    int q  = (c & 31) * 8;
    int pi = (c >> 5) & 8191;
    int b  = c >> 18;
    int p = q >> 4, qq = q & 15;
    const float* src = x + ((size_t)(b*2048 + (pi >> 6)*16 + p)) * DIMN + (pi & 63)*16 + qq;
    float4 a = *(const float4*)src;
    float4 v = *(const float4*)(src + 4);
    uint4 o;
    o.x = pack_bf(a.x, a.y); o.y = pack_bf(a.z, a.w);
    o.z = pack_bf(v.x, v.y); o.w = pack_bf(v.z, v.w);
    *(uint4*)(b_xp + (size_t)c * 8) = o;
}

// ================= bf16 GEMM core (4-stage cp.async) =================
#define AKE 40
#define BNE 264
#define A_ELT (128*AKE)
#define B_ELT (32*BNE)
#define STG_ELT (A_ELT + B_ELT)
#define GEMM_SMEM (4 * STG_ELT * 2)

#define GEMM_PROLOG(Aptr, Bptr, Kdim, Ndim, bmv, bnv)                                    \
    extern __shared__ bf16 smb[];                                                        \
    const unsigned sbase = (unsigned)__cvta_generic_to_shared(smb);                      \
    const int tid  = threadIdx.x;                                                        \
    const int lane = tid & 31;                                                           \
    const int warp = tid >> 5;                                                           \
    const int g    = lane >> 2;                                                          \
    const int t4   = lane & 3;                                                           \
    const int lm   = lane & 15;                                                          \
    const int lh   = lane >> 4;                                                          \
    const int wm = (warp >> 2) * 64;                                                     \
    const int wn = (warp & 3) * 64;                                                      \
    float acc[4][8][4];                                                                  \
    _Pragma("unroll") for (int i = 0; i < 4; i++)                                        \
        _Pragma("unroll") for (int j = 0; j < 8; j++)                                    \
            _Pragma("unroll") for (int r = 0; r < 4; r++) acc[i][j][r] = 0.f;            \
    const int ktiles = (Kdim) >> 5;                                                      \
    auto load_stage = [&](int st, int k0) {                                              \
        unsigned sa = sbase + (unsigned)(st * STG_ELT) * 2u;                             \
        unsigned sb = sa + A_ELT * 2u;                                                   \
        _Pragma("unroll") for (int u = 0; u < 2; u++) {                                  \
            int c = tid + 256*u;                                                         \
            int r = c >> 2, o = (c & 3) * 8;                                             \
            cpa16(sa + (unsigned)(r*AKE + o)*2u, (Aptr) + (size_t)((bmv) + r) * (Kdim) + k0 + o); \
        }                                                                                \
        _Pragma("unroll") for (int u = 0; u < 4; u++) {                                  \
            int c = tid + 256*u;                                                         \
            int r = c >> 5, o = (c & 31) * 8;                                            \
            cpa16(sb + (unsigned)(r*BNE + o)*2u, (Bptr) + (size_t)(k0 + r) * (Ndim) + (bnv) + o); \
        }                                                                                \
    };                                                                                   \
    load_stage(0, 0);                                                                    \
    asm volatile("cp.async.commit_group;");                                              \
    load_stage(1, 32);                                                                   \
    asm volatile("cp.async.commit_group;");                                              \
    load_stage(2, 64);                                                                   \
    asm volatile("cp.async.commit_group;");                                              \
    for (int t = 0; t < ktiles; t++) {                                                   \
        asm volatile("cp.async.wait_group 2;");                                          \
        __syncthreads();                                                                 \
        int nt = t + 3;                                                                  \
        if (nt < ktiles) load_stage(nt & 3, nt * 32);                                    \
        asm volatile("cp.async.commit_group;");                                          \
        unsigned sa = sbase + (unsigned)((t & 3) * STG_ELT) * 2u;                        \
        unsigned sb = sa + A_ELT * 2u;                                                   \
        _Pragma("unroll") for (int kk = 0; kk < 32; kk += 16) {                          \
            unsigned af[4][4], bfr[8][2];                                                \
            _Pragma("unroll") for (int i = 0; i < 4; i++)                                \
                ldmx4(af[i][0], af[i][1], af[i][2], af[i][3],                            \
                      sa + (unsigned)((wm + 16*i + lm)*AKE + kk + lh*8)*2u);             \
            _Pragma("unroll") for (int j2 = 0; j2 < 4; j2++)                             \
                ldmx4t(bfr[2*j2][0], bfr[2*j2][1], bfr[2*j2+1][0], bfr[2*j2+1][1],       \
                       sb + (unsigned)((kk + lm)*BNE + wn + 16*j2 + lh*8)*2u);           \
            _Pragma("unroll") for (int i = 0; i < 4; i++)                                \
                _Pragma("unroll") for (int j = 0; j < 8; j++)                            \
                    mma16(acc[i][j], af[i][0], af[i][1], af[i][2], af[i][3],             \
                          bfr[j][0], bfr[j][1]);                                         \
        }                                                                                \
    }

// ---- generic gemm, bf16 out ----
__global__ __launch_bounds__(256, 1) void gemm_bf16o(const bf16* __restrict__ A,
                                                     const bf16* __restrict__ B,
                                                     bf16* __restrict__ Cb,
                                                     int M, int N, int K) {
    const int bm = blockIdx.y * 128;
    const int bn = blockIdx.x * 256;
    GEMM_PROLOG(A, B, K, N, bm, bn)
    #pragma unroll
    for (int i = 0; i < 4; i++) {
        int row0 = bm + wm + 16*i + g;
        #pragma unroll
        for (int j = 0; j < 8; j++) {
            int col = bn + wn + 8*j + 2*t4;
            *(unsigned*)(Cb + (size_t)row0 * N + col)       = pack_bf(acc[i][j][0], acc[i][j][1]);
            *(unsigned*)(Cb + (size_t)(row0 + 8) * N + col) = pack_bf(acc[i][j][2], acc[i][j][3]);
        }
    }
}

// ---- fused QKV gemm + RoPE + head-norm + sqk_eff ----
__global__ __launch_bounds__(256, 1) void gemm_qkv(const bf16* __restrict__ A,
                                                   const float* __restrict__ fcos,
                                                   const float* __restrict__ fsin,
                                                   const float* __restrict__ sqk) {
    const int wsel = blockIdx.x >> 2;
    const int bn = (blockIdx.x & 3) * 256;
    const int bm = blockIdx.y * 128;
    const bf16* B = (wsel == 0) ? b_wq : ((wsel == 1) ? b_wk : b_wv);
    bf16* C = (wsel == 0) ? b_q : ((wsel == 1) ? b_k : b_v);
    GEMM_PROLOG(A, B, DIMN, DIMN, bm, bn)
    if (wsel == 2) {
        #pragma unroll
        for (int i = 0; i < 4; i++) {
            int row0 = bm + wm + 16*i + g;
            #pragma unroll
            for (int j = 0; j < 8; j++) {
                int col = bn + wn + 8*j + 2*t4;
                *(unsigned*)(C + (size_t)row0 * DIMN + col)       = pack_bf(acc[i][j][0], acc[i][j][1]);
                *(unsigned*)(C + (size_t)(row0 + 8) * DIMN + col) = pack_bf(acc[i][j][2], acc[i][j][3]);
            }
        }
    } else {
        const int h = (bn + wn) >> 6;
        const float qscale = (wsel == 0) ? 8.f * 1.4426950408889634f : 1.f;
        #pragma unroll
        for (int i = 0; i < 4; i++) {
            int row0 = bm + wm + 16*i + g;
            int row1 = row0 + 8;
            float ss0 = 0.f, ss1 = 0.f;
            #pragma unroll
            for (int j = 0; j < 8; j++) {
                ss0 += acc[i][j][0]*acc[i][j][0] + acc[i][j][1]*acc[i][j][1];
                ss1 += acc[i][j][2]*acc[i][j][2] + acc[i][j][3]*acc[i][j][3];
            }
            ss0 += __shfl_xor_sync(0xffffffffu, ss0, 1);
            ss0 += __shfl_xor_sync(0xffffffffu, ss0, 2);
            ss1 += __shfl_xor_sync(0xffffffffu, ss1, 1);
            ss1 += __shfl_xor_sync(0xffffffffu, ss1, 2);
            float inv0 = qscale / fmaxf(sqrtf(ss0), 1e-12f);
            float inv1 = qscale / fmaxf(sqrtf(ss1), 1e-12f);
            int s0 = row0 & (SEQL - 1), s1 = row1 & (SEQL - 1);
            #pragma unroll
            for (int j = 0; j < 8; j++) {
                int pidx = 4*j + t4;
                int d = 8*j + 2*t4;
                float se0 = sqk[h*HDIM + d]     * 32.f;
                float se1 = sqk[h*HDIM + d + 1] * 32.f;
                float c0 = fcos[s0*32 + pidx], sn0 = fsin[s0*32 + pidx];
                float c1 = fcos[s1*32 + pidx], sn1 = fsin[s1*32 + pidx];
                float a0 = acc[i][j][0], a1 = acc[i][j][1];
                float b0 = acc[i][j][2], b1 = acc[i][j][3];
                int col = bn + wn + d;
                *(unsigned*)(C + (size_t)row0 * DIMN + col) =
                    pack_bf((a0*c0 - a1*sn0) * inv0 * se0, (a0*sn0 + a1*c0) * inv0 * se1);
                *(unsigned*)(C + (size_t)row1 * DIMN + col) =
                    pack_bf((b0*c1 - b1*sn1) * inv1 * se0, (b0*sn1 + b1*c1) * inv1 * se1);
            }
        }
    }
}

// ---- adafm gemm: Y = Xp @ Bg, scatter; bf16 out (attn) or fp8 x16 out (ffn) ----
__global__ __launch_bounds__(256, 1) void adafm_gemm(const bf16* __restrict__ Bg0,
                                                     bf16* __restrict__ Y,
                                                     unsigned char* __restrict__ Y8) {
    const int z  = blockIdx.z;
    const int bm = blockIdx.y * 128;
    const int bn = 0;
    const bf16* A = b_xp + (size_t)z * 8192 * 256;
    const bf16* B = Bg0 + (size_t)z * 65536;
    GEMM_PROLOG(A, B, 256, 256, bm, bn)
    #pragma unroll
    for (int i = 0; i < 4; i++) {
        int pi0 = bm + wm + 16*i + g;
        #pragma unroll
        for (int j = 0; j < 8; j++) {
            int col = wn + 8*j + 2*t4;
            int p = col >> 4, qq = col & 15;
            int pi1 = pi0 + 8;
            size_t off0 = (size_t)(z*2048 + (pi0 >> 6)*16 + p) * DIMN + (pi0 & 63)*16 + qq;
            size_t off1 = (size_t)(z*2048 + (pi1 >> 6)*16 + p) * DIMN + (pi1 & 63)*16 + qq;
            if (Y8) {
                *(unsigned short*)(Y8 + off0) = pack_f8(acc[i][j][0]*16.f, acc[i][j][1]*16.f);
                *(unsigned short*)(Y8 + off1) = pack_f8(acc[i][j][2]*16.f, acc[i][j][3]*16.f);
            } else {
                *(unsigned*)(Y + off0) = pack_bf(acc[i][j][0], acc[i][j][1]);
                *(unsigned*)(Y + off1) = pack_bf(acc[i][j][2], acc[i][j][3]);
            }
        }
    }
}

// ================= fp8 FFN w1/w3 GEMM + silu gate =================
#define F8AS 80
#define F8STG (128*F8AS + 256*F8AS)
#define FFN8_SMEM (4 * F8STG)

__global__ __launch_bounds__(256, 1) void gemm_ffn13f8(const float* __restrict__ su,
                                                       const float* __restrict__ sv) {
    const int bnb = blockIdx.x * 128;
    const int bm  = blockIdx.y * 128;
    extern __shared__ __align__(16) unsigned char sm8[];
    const unsigned sbase = (unsigned)__cvta_generic_to_shared(sm8);
    const int tid  = threadIdx.x;
    const int lane = tid & 31;
    const int warp = tid >> 5;
    const int g    = lane >> 2;
    const int t4   = lane & 3;
    const int lm   = lane & 15;
    const int lh   = lane >> 4;
    const int wm = (warp >> 2) * 64;
    const int wn = (warp & 3) * 32;
    const int q8 = lane >> 3, r8 = lane & 7;

    float acc1[4][4][4], acc3[4][4][4];
    #pragma unroll
    for (int i = 0; i < 4; i++)
        #pragma unroll
        for (int j = 0; j < 4; j++)
            #pragma unroll
            for (int r = 0; r < 4; r++) { acc1[i][j][r] = 0.f; acc3[i][j][r] = 0.f; }

    const int ktiles = DIMN >> 6;   // 16 tiles of 64 fp8
    auto load_stage = [&](int st, int k0) {
        unsigned sa = sbase + (unsigned)(st * F8STG);
        unsigned sb = sa + 128*F8AS;
        #pragma unroll
        for (int u = 0; u < 2; u++) {
            int c = tid + 256*u;
            int r = c >> 2, o = (c & 3) * 16;
            cpa16(sa + (unsigned)(r*F8AS + o), b_xm8 + (size_t)(bm + r) * DIMN + k0 + o);
        }
        #pragma unroll
        for (int u = 0; u < 4; u++) {
            int c = tid + 256*u;
            int r = c >> 2, o = (c & 3) * 16;
            const unsigned char* src = (r < 128)
                ? (b_w13t + (size_t)(bnb + r) * DIMN)
                : (b_w13t + (size_t)HIDDEN*DIMN + (size_t)(bnb + r - 128) * DIMN);
            cpa16(sb + (unsigned)(r*F8AS + o), src + k0 + o);
        }
    };
    load_stage(0, 0);
    asm volatile("cp.async.commit_group;");
    load_stage(1, 64);
    asm volatile("cp.async.commit_group;");
    load_stage(2, 128);
    asm volatile("cp.async.commit_group;");

    for (int t = 0; t < ktiles; t++) {
        asm volatile("cp.async.wait_group 2;");
        __syncthreads();
        int nt = t + 3;
        if (nt < ktiles) load_stage(nt & 3, nt * 64);
        asm volatile("cp.async.commit_group;");
        unsigned sa = sbase + (unsigned)((t & 3) * F8STG);
        unsigned sb = sa + 128*F8AS;
        #pragma unroll
        for (int ks = 0; ks < 2; ks++) {
            int k0 = ks * 32;
            unsigned af[4][4], b1f[4][2], b3f[4][2];
            #pragma unroll
            for (int i = 0; i < 4; i++)
                ldmx4(af[i][0], af[i][1], af[i][2], af[i][3],
                      sa + (unsigned)((wm + 16*i + lm)*F8AS + k0 + lh*16));
            #pragma unroll
            for (int jp = 0; jp < 2; jp++) {
                int n0 = wn + 16*jp;
                unsigned ra = (unsigned)((n0 + ((q8 >> 1) << 3) + r8)*F8AS + k0 + ((q8 & 1) << 4));
                ldmx4(b1f[2*jp][0], b1f[2*jp][1], b1f[2*jp+1][0], b1f[2*jp+1][1], sb + ra);
                ldmx4(b3f[2*jp][0], b3f[2*jp][1], b3f[2*jp+1][0], b3f[2*jp+1][1],
                      sb + 128u*F8AS + ra);
            }
            #pragma unroll
            for (int i = 0; i < 4; i++)
                #pragma unroll
                for (int j = 0; j < 4; j++) {
                    mma8f8(acc1[i][j], af[i][0], af[i][1], af[i][2], af[i][3], b1f[j][0], b1f[j][1]);
                    mma8f8(acc3[i][j], af[i][0], af[i][1], af[i][2], af[i][3], b3f[j][0], b3f[j][1]);
                }
        }
    }

    const float SC = 53.06599664568481f;
    const float OS13 = 1.f / 4096.f;   // 1/(16*256)
    #pragma unroll
    for (int i = 0; i < 4; i++) {
        int row0 = bm + wm + 16*i + g;
        #pragma unroll
        for (int j = 0; j < 4; j++) {
            int col = bnb + wn + 8*j + 2*t4;
            float sv0 = sv[col] * SC * OS13, sv1 = sv[col+1] * SC * OS13;
            float su0 = su[col] * OS13,      su1 = su[col+1] * OS13;
            float z, sgl, outv[4];
            z = acc1[i][j][0] * sv0; sgl = z / (1.f + __expf(-z)); outv[0] = sgl * (acc3[i][j][0] * su0);
            z = acc1[i][j][1] * sv1; sgl = z / (1.f + __expf(-z)); outv[1] = sgl * (acc3[i][j][1] * su1);
            z = acc1[i][j][2] * sv0; sgl = z / (1.f + __expf(-z)); outv[2] = sgl * (acc3[i][j][2] * su0);
            z = acc1[i][j][3] * sv1; sgl = z / (1.f + __expf(-z)); outv[3] = sgl * (acc3[i][j][3] * su1);
            *(unsigned short*)(b_h8 + (size_t)row0 * HIDDEN + col)
                = pack_f8(outv[0]*256.f, outv[1]*256.f);
            *(unsigned short*)(b_h8 + (size_t)(row0 + 8) * HIDDEN + col)
                = pack_f8(outv[2]*256.f, outv[3]*256.f);
        }
    }
}

// ---- w2 fp8 GEMM: Cb bf16 = (h8/256) @ (w2t/64)^T ----
#define A8S 80
#define STG8 (128*A8S + 256*A8S)
#define W2F8_SMEM (4 * STG8)

__global__ __launch_bounds__(256, 1) void gemm_w2f8(bf16* __restrict__ Cb) {
    const int bm = blockIdx.y * 128;
    const int bn = blockIdx.x * 256;
    extern __shared__ __align__(16) unsigned char sm8[];
    const unsigned sbase = (unsigned)__cvta_generic_to_shared(sm8);
    const int tid  = threadIdx.x;
    const int lane = tid & 31;
    const int warp = tid >> 5;
    const int g    = lane >> 2;
    const int t4   = lane & 3;
    const int lm   = lane & 15;
    const int lh   = lane >> 4;
    const int wm = (warp >> 2) * 64;
    const int wn = (warp & 3) * 64;
    const int q8 = lane >> 3, r8 = lane & 7;

    float acc[4][8][4];
    #pragma unroll
    for (int i = 0; i < 4; i++)
        #pragma unroll
        for (int j = 0; j < 8; j++)
            #pragma unroll
            for (int r = 0; r < 4; r++) acc[i][j][r] = 0.f;

    const int ktiles = HIDDEN >> 6;
    auto load_stage = [&](int st, int k0) {
        unsigned sa = sbase + (unsigned)(st * STG8);
        unsigned sb = sa + 128*A8S;
        #pragma unroll
        for (int u = 0; u < 2; u++) {
            int c = tid + 256*u;
            int r = c >> 2, o = (c & 3) * 16;
            cpa16(sa + (unsigned)(r*A8S + o), b_h8 + (size_t)(bm + r) * HIDDEN + k0 + o);
        }
        #pragma unroll
        for (int u = 0; u < 4; u++) {
            int c = tid + 256*u;
            int r = c >> 2, o = (c & 3) * 16;
            cpa16(sb + (unsigned)(r*A8S + o), b_w2t + (size_t)(bn + r) * HIDDEN + k0 + o);
        }
    };
    load_stage(0, 0);
    asm volatile("cp.async.commit_group;");
    load_stage(1, 64);
    asm volatile("cp.async.commit_group;");
    load_stage(2, 128);
    asm volatile("cp.async.commit_group;");

    for (int t = 0; t < ktiles; t++) {
        asm volatile("cp.async.wait_group 2;");
        __syncthreads();
        int nt = t + 3;
        if (nt < ktiles) load_stage(nt & 3, nt * 64);
        asm volatile("cp.async.commit_group;");
        unsigned sa = sbase + (unsigned)((t & 3) * STG8);
        unsigned sb = sa + 128*A8S;
        #pragma unroll
        for (int ks = 0; ks < 2; ks++) {
            int k0 = ks * 32;
            unsigned af[4][4], bfr[8][2];
            #pragma unroll
            for (int i = 0; i < 4; i++)
                ldmx4(af[i][0], af[i][1], af[i][2], af[i][3],
                      sa + (unsigned)((wm + 16*i + lm)*A8S + k0 + lh*16));
            #pragma unroll
            for (int jp = 0; jp < 4; jp++) {
                int n0 = wn + 16*jp;
                unsigned addr = sb + (unsigned)((n0 + ((q8 >> 1) << 3) + r8)*A8S + k0 + ((q8 & 1) << 4));
                ldmx4(bfr[2*jp][0], bfr[2*jp][1], bfr[2*jp+1][0], bfr[2*jp+1][1], addr);
            }
            #pragma unroll
            for (int i = 0; i < 4; i++)
                #pragma unroll
                for (int j = 0; j < 8; j++)
                    mma8f8(acc[i][j], af[i][0], af[i][1], af[i][2], af[i][3],
                           bfr[j][0], bfr[j][1]);
        }
    }

    const float OS = 1.f / 16384.f;
    #pragma unroll
    for (int i = 0; i < 4; i++) {
        int row0 = bm + wm + 16*i + g;
        #pragma unroll
        for (int j = 0; j < 8; j++) {
            int col = bn + wn + 8*j + 2*t4;
            *(unsigned*)(Cb + (size_t)row0 * DIMN + col)       = pack_bf(acc[i][j][0]*OS, acc[i][j][1]*OS);
            *(unsigned*)(Cb + (size_t)(row0 + 8) * DIMN + col) = pack_bf(acc[i][j][2]*OS, acc[i][j][3]*OS);
        }
    }
}

// --------- FA2 flash attention, cp.async 3-stage ring ---------
#define FAE 72
#define FLASH_SMEM ((128 + 6*64) * FAE * 2)

__global__ __launch_bounds__(256, 2) void flash_attn(const bf16* __restrict__ Q,
                                                     const bf16* __restrict__ K,
                                                     const bf16* __restrict__ V,
                                                     bf16* __restrict__ O) {
    extern __shared__ bf16 fsm[];
    bf16* Qs = fsm;
    const unsigned sQ  = (unsigned)__cvta_generic_to_shared(Qs);
    const unsigned sK0 = sQ + 128*FAE*2u;
    const unsigned sV0 = sK0 + 3*64*FAE*2u;

    const int q0 = blockIdx.x * 128;
    const int h  = blockIdx.y;
    const int b  = blockIdx.z;
    const bf16* Qb = Q + (size_t)b*SEQL*DIMN + h*HDIM;
    const bf16* Kb = K + (size_t)b*SEQL*DIMN + h*HDIM;
    const bf16* Vb = V + (size_t)b*SEQL*DIMN + h*HDIM;
    bf16*       Ob = O + (size_t)b*SEQL*DIMN + h*HDIM;

    const int tid  = threadIdx.x;
    const int lane = tid & 31;
    const int warp = tid >> 5;
    const int g  = lane >> 2;
    const int t4 = lane & 3;
    const int lm = lane & 15;
    const int lh = lane >> 4;
    const int wm = warp * 16;

    auto loadKV = [&](int st, int k0) {
        unsigned sk = sK0 + (unsigned)st * 64*FAE*2u;
        unsigned sv = sV0 + (unsigned)st * 64*FAE*2u;
        #pragma unroll
        for (int u = 0; u < 2; u++) {
            int c = tid + 256*u;
            int r = c >> 3, ofs = (c & 7) * 8;
            cpa16(sk + (unsigned)(r*FAE + ofs)*2u, Kb + (size_t)(k0 + r)*DIMN + ofs);
            cpa16(sv + (unsigned)(r*FAE + ofs)*2u, Vb + (size_t)(k0 + r)*DIMN + ofs);
        }
    };

    #pragma unroll
    for (int u = 0; u < 4; u++) {
        int c = tid + 256*u;
        int r = c >> 3, ofs = (c & 7) * 8;
        *(uint4*)&Qs[r*FAE + ofs] = *(const uint4*)(Qb + (size_t)(q0 + r)*DIMN + ofs);
    }

    loadKV(0, 0);
    asm volatile("cp.async.commit_group;");
    loadKV(1, 64);
    asm volatile("cp.async.commit_group;");

    float o[8][4];
    #pragma unroll
    for (int j = 0; j < 8; j++)
        #pragma unroll
        for (int r = 0; r < 4; r++) o[j][r] = 0.f;
    float m0 = -1e30f, m1 = -1e30f, l0 = 0.f, l1 = 0.f;

    const int NT = SEQL / 64;
    for (int t = 0; t < NT; t++) {
        if (t + 1 < NT) asm volatile("cp.async.wait_group 1;");
        else            asm volatile("cp.async.wait_group 0;");
        __syncthreads();
        if (t + 2 < NT) {
            loadKV((t + 2) % 3, (t + 2) * 64);
            asm volatile("cp.async.commit_group;");
        }

        const unsigned sK = sK0 + (unsigned)(t % 3) * 64*FAE*2u;
        const unsigned sV = sV0 + (unsigned)(t % 3) * 64*FAE*2u;

        float s[8][4];
        #pragma unroll
        for (int j = 0; j < 8; j++)
            #pragma unroll
            for (int r = 0; r < 4; r++) s[j][r] = 0.f;

        #pragma unroll
        for (int kc = 0; kc < 4; kc++) {
            int kk = 16*kc;
            unsigned a0, a1, a2, a3;
            ldmx4(a0, a1, a2, a3, sQ + (unsigned)((wm + lm)*FAE + kk + lh*8)*2u);
            #pragma unroll
            for (int j2 = 0; j2 < 4; j2++) {
                unsigned r0, r1, r2, r3;
                ldmx4(r0, r1, r2, r3,
                      sK + (unsigned)((16*j2 + (lane & 7) + ((lane >> 4) << 3))*FAE
                                       + kk + (((lane >> 3) & 1) << 3))*2u);
                mma16(s[2*j2],     a0, a1, a2, a3, r0, r1);
                mma16(s[2*j2 + 1], a0, a1, a2, a3, r2, r3);
            }
        }

        float tm0 = -1e30f, tm1 = -1e30f;
        #pragma unroll
        for (int j = 0; j < 8; j++) {
            tm0 = fmaxf(tm0, fmaxf(s[j][0], s[j][1]));
            tm1 = fmaxf(tm1, fmaxf(s[j][2], s[j][3]));
        }
        tm0 = fmaxf(tm0, __shfl_xor_sync(0xffffffffu, tm0, 1));
        tm0 = fmaxf(tm0, __shfl_xor_sync(0xffffffffu, tm0, 2));
        tm1 = fmaxf(tm1, __shfl_xor_sync(0xffffffffu, tm1, 1));
        tm1 = fmaxf(tm1, __shfl_xor_sync(0xffffffffu, tm1, 2));
        float mn0 = fmaxf(m0, tm0), mn1 = fmaxf(m1, tm1);
        float c0 = exp2f(m0 - mn0), c1 = exp2f(m1 - mn1);
        float ps0 = 0.f, ps1 = 0.f;
        #pragma unroll
        for (int j = 0; j < 8; j++) {
            s[j][0] = exp2f(s[j][0] - mn0);
            s[j][1] = exp2f(s[j][1] - mn0);
            s[j][2] = exp2f(s[j][2] - mn1);
            s[j][3] = exp2f(s[j][3] - mn1);
            ps0 += s[j][0] + s[j][1];
            ps1 += s[j][2] + s[j][3];
        }
        ps0 += __shfl_xor_sync(0xffffffffu, ps0, 1);
        ps0 += __shfl_xor_sync(0xffffffffu, ps0, 2);
        ps1 += __shfl_xor_sync(0xffffffffu, ps1, 1);
        ps1 += __shfl_xor_sync(0xffffffffu, ps1, 2);
        l0 = l0 * c0 + ps0;  l1 = l1 * c1 + ps1;
        m0 = mn0;            m1 = mn1;
        #pragma unroll
        for (int j = 0; j < 8; j++) {
            o[j][0] *= c0; o[j][1] *= c0; o[j][2] *= c1; o[j][3] *= c1;
        }

        #pragma unroll
        for (int c = 0; c < 4; c++) {
            unsigned pa0 = pack_bf(s[2*c][0],   s[2*c][1]);
            unsigned pa1 = pack_bf(s[2*c][2],   s[2*c][3]);
            unsigned pa2 = pack_bf(s[2*c+1][0], s[2*c+1][1]);
            unsigned pa3 = pack_bf(s[2*c+1][2], s[2*c+1][3]);
            #pragma unroll
            for (int j2 = 0; j2 < 4; j2++) {
                unsigned r0, r1, r2, r3;
                ldmx4t(r0, r1, r2, r3,
                       sV + (unsigned)((16*c + lm)*FAE + 16*j2 + lh*8)*2u);
                mma16(o[2*j2],     pa0, pa1, pa2, pa3, r0, r1);
                mma16(o[2*j2 + 1], pa0, pa1, pa2, pa3, r2, r3);
            }
        }
    }

    float inv0 = 1.f / l0, inv1 = 1.f / l1;
    #pragma unroll
    for (int j = 0; j < 8; j++) {
        int col = 8*j + 2*t4;
        *(unsigned*)(Ob + (size_t)(q0 + wm + g    )*DIMN + col) = pack_bf(o[j][0]*inv0, o[j][1]*inv0);
        *(unsigned*)(Ob + (size_t)(q0 + wm + g + 8)*DIMN + col) = pack_bf(o[j][2]*inv1, o[j][3]*inv1);
    }
}

// ------- fused residual + norms; branch input bf16; optional patchified output -------
__global__ __launch_bounds__(256) void residual_norm(const float* __restrict__ xb,
                                                     const bf16* __restrict__ br,
                                                     const float* __restrict__ alpha,
                                                     float* __restrict__ out,
                                                     bf16* __restrict__ xp) {
    int t = blockIdx.x;
    int tid = threadIdx.x;
    const float* xr = xb + (size_t)t * DIMN;
    const bf16*  rr = br + (size_t)t * DIMN;
    float xv[4], bv[4];
    float ssx = 0.f, ssb = 0.f;
    #pragma unroll
    for (int u = 0; u < 2; u++) {
        int d = tid*2 + u * 512;
        float2 xx = *(const float2*)(xr + d);
        float2 bb = unpack_bf(*(const unsigned*)(rr + d));
        xv[2*u] = xx.x; xv[2*u+1] = xx.y;
        bv[2*u] = bb.x; bv[2*u+1] = bb.y;
        ssx += xx.x*xx.x + xx.y*xx.y;
        ssb += bb.x*bb.x + bb.y*bb.y;
    }
    ssx = blockSum256(ssx);
    ssb = blockSum256(ssb);
    float rx = 1.f / fmaxf(sqrtf(ssx), 1e-12f);
    float rb = 1.f / fmaxf(sqrtf(ssb), 1e-12f);
    float yv[4]; float ssy = 0.f;
    #pragma unroll
    for (int u = 0; u < 4; u++) {
        int d = tid*2 + (u >> 1) * 512 + (u & 1);
        float hh = xv[u] * rx;
        float ha = bv[u] * rb;
        float lr = fabsf(alpha[d] * 1.6f);
        float y = hh + lr * (ha - hh);
        yv[u] = y; ssy += y * y;
    }
    ssy = blockSum256(ssy);
    float ry = 1.f / fmaxf(sqrtf(ssy), 1e-12f);
    int b = t >> 11, se = t & 2047;
    int ip = se >> 4, p = se & 15;
    #pragma unroll
    for (int u = 0; u < 4; u++) {
        int d = tid*2 + (u >> 1) * 512 + (u & 1);
        float y = yv[u] * ry;
        out[(size_t)t * DIMN + d] = y;
        if (xp) {
            int jj = d >> 4, qq = d & 15;
            xp[((size_t)b*8192 + ip*64 + jj)*256 + p*16 + qq] = __float2bfloat16_rn(y);
        }
    }
}

// ---------------- launch ----------------
extern "C" void kernel_launch(void* const* d_in, const int* in_sizes, int n_in,
                              void* d_out, int out_size) {
    const float* x      = (const float*)d_in[0];
    const float* fcos   = (const float*)d_in[1];
    const float* fsin   = (const float*)d_in[2];
    const float* adafm  = (const float*)d_in[3];
    const float* wq     = (const float*)d_in[4];
    const float* wk     = (const float*)d_in[5];
    const float* wv     = (const float*)d_in[6];
    const float* wo     = (const float*)d_in[7];
    const float* sqk    = (const float*)d_in[8];
    const float* w1     = (const float*)d_in[9];
    const float* w2     = (const float*)d_in[10];
    const float* w3     = (const float*)d_in[11];
    const float* su     = (const float*)d_in[12];
    const float* sv     = (const float*)d_in[13];
    const float* pw     = (const float*)d_in[14];
    const float* pb     = (const float*)d_in[15];
    const float* aalpha = (const float*)d_in[16];
    const float* malpha = (const float*)d_in[17];
    float* out = (float*)d_out;

    float *pt, *pf0;
    bf16 *pbgm, *pbgf, *pbxa, *pbq, *pbk, *pbv, *pbao, *pbwo, *pbxp;
    unsigned char *pxm8;
    cudaGetSymbolAddress((void**)&pt,  d_t);
    cudaGetSymbolAddress((void**)&pf0, d_f0);
    cudaGetSymbolAddress((void**)&pbgm, b_gm);
    cudaGetSymbolAddress((void**)&pbgf, b_gf);
    cudaGetSymbolAddress((void**)&pbxa, b_xa);
    cudaGetSymbolAddress((void**)&pbq,  b_q);
    cudaGetSymbolAddress((void**)&pbk,  b_k);
    cudaGetSymbolAddress((void**)&pbv,  b_v);
    cudaGetSymbolAddress((void**)&pbao, b_ao);
    cudaGetSymbolAddress((void**)&pbwo, b_wo);
    cudaGetSymbolAddress((void**)&pbxp, b_xp);
    cudaGetSymbolAddress((void**)&pxm8, b_xm8);

    cudaFuncSetAttribute(gemm_bf16o, cudaFuncAttributeMaxDynamicSharedMemorySize, GEMM_SMEM);
    cudaFuncSetAttribute(gemm_qkv, cudaFuncAttributeMaxDynamicSharedMemorySize, GEMM_SMEM);
    cudaFuncSetAttribute(adafm_gemm, cudaFuncAttributeMaxDynamicSharedMemorySize, GEMM_SMEM);
    cudaFuncSetAttribute(gemm_ffn13f8, cudaFuncAttributeMaxDynamicSharedMemorySize, FFN8_SMEM);
    cudaFuncSetAttribute(gemm_w2f8, cudaFuncAttributeMaxDynamicSharedMemorySize, W2F8_SMEM);
    cudaFuncSetAttribute(flash_attn, cudaFuncAttributeMaxDynamicSharedMemorySize, FLASH_SMEM);

    // 0) weight conversions
    cvt_all<<<dim3(256, 4), 256>>>(wq, wk, wv, wo);
    cvt_w13t<<<dim3(2816, 2), 256>>>(w1, w3);
    cvt_w2t<<<2816, 256>>>(w2);

    // 1) time-modulation
    proj_t_kernel<<<dim3(BATCH, 8), 256>>>(adafm, pw, pb, pt);
    make_g_kernel<<<dim3(4, 8), 256>>>(pt);

    // 2) attention branch
    patchify<<<2048, 256>>>(x);
    adafm_gemm<<<dim3(1, 64, 2), 256, GEMM_SMEM>>>(pbgm, pbxa, (unsigned char*)0);
    gemm_qkv<<<dim3(12, 32), 256, GEMM_SMEM>>>(pbxa, fcos, fsin, sqk);
    flash_attn<<<dim3(SEQL/128, NHEAD, BATCH), 256, FLASH_SMEM>>>(pbq, pbk, pbv, pbao);
    gemm_bf16o<<<dim3(DIMN/256, TOK/128), 256, GEMM_SMEM>>>(pbao, pbwo, pbq, TOK, DIMN, DIMN);
    residual_norm<<<TOK, 256>>>(x, pbq, aalpha, pf0, pbxp);

    // 3) FFN branch (fp8)
    adafm_gemm<<<dim3(1, 64, 2), 256, GEMM_SMEM>>>(pbgf, (bf16*)0, pxm8);
    gemm_ffn13f8<<<dim3(HIDDEN/128, TOK/128), 256, FFN8_SMEM>>>(su, sv);
    gemm_w2f8<<<dim3(DIMN/256, TOK/128), 256, W2F8_SMEM>>>(pbk);
    residual_norm<<<TOK, 256>>>(pf0, pbk, malpha, out, (bf16*)0);
}

// round 15
// speedup vs baseline: 7.4593x; 1.0314x over previous
#include <cuda_runtime.h>
#include <cuda_bf16.h>
#include <cuda_fp8.h>
#include <math.h>

typedef __nv_bfloat16 bf16;

#define DIMN   1024
#define NHEAD  16
#define HDIM   64
#define SEQL   2048
#define BATCH  2
#define TOK    4096
#define HIDDEN 2816

// ---------------- scratch ----------------
__device__ float d_t [BATCH*512];
__device__ float d_f0[TOK*DIMN];

__device__ bf16 b_wq[DIMN*DIMN], b_wk[DIMN*DIMN], b_wv[DIMN*DIMN], b_wo[DIMN*DIMN];
__device__ unsigned char b_w13t[(size_t)2*HIDDEN*DIMN];   // fp8 [N][K] w1|w3, x256
__device__ unsigned char b_w2t[(size_t)DIMN*HIDDEN];      // fp8 [N][K], x64
__device__ bf16 b_xp[BATCH*8192*256];
__device__ bf16 b_gm[BATCH*256*256];
__device__ bf16 b_gf[BATCH*256*256];
__device__ bf16 b_xa[TOK*DIMN];
__device__ unsigned char b_xm8[TOK*DIMN];                 // fp8 xm, x16
__device__ bf16 b_q [TOK*DIMN], b_k[TOK*DIMN], b_v[TOK*DIMN], b_ao[TOK*DIMN];
__device__ unsigned char b_h8[(size_t)TOK*HIDDEN];        // fp8 gated h, x256

// ---------------- helpers ----------------
__device__ __forceinline__ float blockSum256(float v) {
    __shared__ float red[8];
    int lane = threadIdx.x & 31, wid = threadIdx.x >> 5;
    #pragma unroll
    for (int o = 16; o > 0; o >>= 1) v += __shfl_xor_sync(0xffffffffu, v, o);
    __syncthreads();
    if (lane == 0) red[wid] = v;
    __syncthreads();
    float s = red[0];
    #pragma unroll
    for (int w = 1; w < 8; w++) s += red[w];
    return s;
}
__device__ __forceinline__ void mma16(float* c, unsigned a0, unsigned a1, unsigned a2, unsigned a3,
                                      unsigned b0, unsigned b1) {
    asm volatile("mma.sync.aligned.m16n8k16.row.col.f32.bf16.bf16.f32 "
        "{%0,%1,%2,%3}, {%4,%5,%6,%7}, {%8,%9}, {%0,%1,%2,%3};"
        : "+f"(c[0]), "+f"(c[1]), "+f"(c[2]), "+f"(c[3])
        : "r"(a0), "r"(a1), "r"(a2), "r"(a3), "r"(b0), "r"(b1));
}
__device__ __forceinline__ void mma8f8(float* c, unsigned a0, unsigned a1, unsigned a2, unsigned a3,
                                       unsigned b0, unsigned b1) {
    asm volatile("mma.sync.aligned.m16n8k32.row.col.f32.e4m3.e4m3.f32 "
        "{%0,%1,%2,%3}, {%4,%5,%6,%7}, {%8,%9}, {%0,%1,%2,%3};"
        : "+f"(c[0]), "+f"(c[1]), "+f"(c[2]), "+f"(c[3])
        : "r"(a0), "r"(a1), "r"(a2), "r"(a3), "r"(b0), "r"(b1));
}
__device__ __forceinline__ void ldmx4(unsigned& r0, unsigned& r1, unsigned& r2, unsigned& r3, unsigned a) {
    asm volatile("ldmatrix.sync.aligned.m8n8.x4.shared.b16 {%0,%1,%2,%3}, [%4];"
                 : "=r"(r0), "=r"(r1), "=r"(r2), "=r"(r3) : "r"(a));
}
__device__ __forceinline__ void ldmx4t(unsigned& r0, unsigned& r1, unsigned& r2, unsigned& r3, unsigned a) {
    asm volatile("ldmatrix.sync.aligned.m8n8.x4.trans.shared.b16 {%0,%1,%2,%3}, [%4];"
                 : "=r"(r0), "=r"(r1), "=r"(r2), "=r"(r3) : "r"(a));
}
__device__ __forceinline__ void cpa16(unsigned s, const void* g) {
    asm volatile("cp.async.cg.shared.global [%0], [%1], 16;" :: "r"(s), "l"(g));
}
__device__ __forceinline__ unsigned pack_bf(float a, float b) {
    __nv_bfloat162 t; t.x = __float2bfloat16_rn(a); t.y = __float2bfloat16_rn(b);
    return *(unsigned*)&t;
}
__device__ __forceinline__ float2 unpack_bf(unsigned u) {
    __nv_bfloat162 t = *(__nv_bfloat162*)&u;
    return make_float2(__bfloat162float(t.x), __bfloat162float(t.y));
}
__device__ __forceinline__ unsigned short pack_f8(float lo, float hi) {
    unsigned short r;
    asm("cvt.rn.satfinite.e4m3x2.f32 %0, %1, %2;" : "=h"(r) : "f"(hi), "f"(lo));
    return r;
}

// ---------------- weight conversions (4 bf16 weights) ----------------
__global__ void cvt_all(const float* __restrict__ s0, const float* __restrict__ s1,
                        const float* __restrict__ s2, const float* __restrict__ s3) {
    int w = blockIdx.y;
    const float* src = (w == 0) ? s0 : (w == 1 ? s1 : (w == 2 ? s2 : s3));
    bf16* dst = (w == 0) ? b_wq : (w == 1 ? b_wk : (w == 2 ? b_wv : b_wo));
    int i = (blockIdx.x * 256 + threadIdx.x) * 16;
    float4 a = *(const float4*)(src + i);
    float4 b = *(const float4*)(src + i + 4);
    float4 c = *(const float4*)(src + i + 8);
    float4 d = *(const float4*)(src + i + 12);
    uint4 o1, o2;
    o1.x = pack_bf(a.x, a.y); o1.y = pack_bf(a.z, a.w);
    o1.z = pack_bf(b.x, b.y); o1.w = pack_bf(b.z, b.w);
    o2.x = pack_bf(c.x, c.y); o2.y = pack_bf(c.z, c.w);
    o2.z = pack_bf(d.x, d.y); o2.w = pack_bf(d.z, d.w);
    *(uint4*)(dst + i) = o1;
    *(uint4*)(dst + i + 8) = o2;
}

// ---- w1/w3 [K=1024][N=2816] fp32 -> w13t [N][K] e4m3 x256 ----
__global__ void cvt_w13t(const float* __restrict__ s1, const float* __restrict__ s3) {
    const float* src = blockIdx.y ? s3 : s1;
    unsigned char* dst = b_w13t + (blockIdx.y ? (size_t)HIDDEN*DIMN : 0);
    const int ntN = HIDDEN / 32;   // 88
    int kt = blockIdx.x / ntN, nt = blockIdx.x % ntN;
    __shared__ float sT[32][33];
    int tx = threadIdx.x & 31, ty0 = threadIdx.x >> 5;
    #pragma unroll
    for (int it = 0; it < 4; it++)
        sT[ty0 + 8*it][tx] = src[(size_t)(kt*32 + ty0 + 8*it) * HIDDEN + nt*32 + tx];
    __syncthreads();
    #pragma unroll
    for (int it = 0; it < 4; it++) {
        int row = ty0 + 8*it;
        __nv_fp8_e4m3 v(sT[tx][row] * 256.f);
        dst[(size_t)(nt*32 + row) * DIMN + kt*32 + tx] = *(unsigned char*)&v;
    }
}

// ---- w2 [K=2816][N=1024] fp32 -> w2t [N][K] e4m3 x64 ----
__global__ void cvt_w2t(const float* __restrict__ src) {
    int kt = blockIdx.x >> 5, nt = blockIdx.x & 31;
    __shared__ float sT[32][33];
    int tx = threadIdx.x & 31, ty0 = threadIdx.x >> 5;
    #pragma unroll
    for (int it = 0; it < 4; it++)
        sT[ty0 + 8*it][tx] = src[(size_t)(kt*32 + ty0 + 8*it) * DIMN + nt*32 + tx];
    __syncthreads();
    #pragma unroll
    for (int it = 0; it < 4; it++) {
        int row = ty0 + 8*it;
        __nv_fp8_e4m3 v(sT[tx][row] * 64.f);
        b_w2t[(size_t)(nt*32 + row) * HIDDEN + kt*32 + tx] = *(unsigned char*)&v;
    }
}

// -------- t = silu(adafm_input) @ proj_w + proj_b --------
// grid (BATCH, 16): block owns 32 outputs; warp w reduces i in [w*128, w*128+128),
// lanes span 32 consecutive outputs -> fully coalesced pw loads.
__global__ void proj_t_kernel(const float* __restrict__ ad, const float* __restrict__ pw,
                              const float* __restrict__ pb, float* __restrict__ t) {
    int b = blockIdx.x, o0 = blockIdx.y * 32;
    __shared__ float s[DIMN];
    __shared__ float red[8][32];
    int tid = threadIdx.x;
    for (int i = tid; i < DIMN; i += 256) {
        float z = ad[b*DIMN + i];
        s[i] = z / (1.f + expf(-z));
    }
    __syncthreads();
    int warp = tid >> 5, lane = tid & 31;
    const float* pwc = pw + o0 + lane;
    float acc = 0.f;
    #pragma unroll 8
    for (int i = warp*128; i < warp*128 + 128; i++)
        acc += s[i] * pwc[i*512];
    red[warp][lane] = acc;
    __syncthreads();
    if (tid < 32) {
        float r = pb[o0 + tid];
        #pragma unroll
        for (int w = 0; w < 8; w++) r += red[w][tid];
        t[b*512 + o0 + tid] = r;
    }
}

// grid (4, 32): block covers 8 q-rows
__global__ void make_g_kernel(const float* __restrict__ t) {
    int b = blockIdx.x >> 1, which = blockIdx.x & 1;
    int q0 = blockIdx.y * 8;
    const float* m = t + b*512 + which*256;
    __shared__ float cs[256], ms[256];
    __shared__ bf16 gd[512];
    int d = threadIdx.x;
    cs[d] = cosf((6.283185307179586f / 256.0f) * (float)d);
    ms[d] = m[d];
    __syncthreads();
    float acc = 0.f;
    #pragma unroll 4
    for (int k = 0; k < 256; k++) acc += ms[k] * cs[(k*d) & 255];
    bf16 gv = __float2bfloat16_rn(acc * (1.0f / 256.0f));
    gd[d] = gv; gd[d + 256] = gv;
    __syncthreads();
    bf16* Bg = (which ? b_gf : b_gm) + b * 65536;
    #pragma unroll
    for (int q = q0; q < q0 + 8; q++)
        Bg[q*256 + d] = gd[d - q + 256];
}

__global__ void patchify(const float* __restrict__ x) {
    int c = blockIdx.x * 256 + threadIdx.x;
    int q  = (c & 31) * 8;
    int pi = (c >> 5) & 8191;
    int b  = c >> 18;
    int p = q >> 4, qq = q & 15;
    const float* src = x + ((size_t)(b*2048 + (pi >> 6)*16 + p)) * DIMN + (pi & 63)*16 + qq;
    float4 a = *(const float4*)src;
    float4 v = *(const float4*)(src + 4);
    uint4 o;
    o.x = pack_bf(a.x, a.y); o.y = pack_bf(a.z, a.w);
    o.z = pack_bf(v.x, v.y); o.w = pack_bf(v.z, v.w);
    *(uint4*)(b_xp + (size_t)c * 8) = o;
}

// ================= bf16 GEMM core (4-stage cp.async) =================
#define AKE 40
#define BNE 264
#define A_ELT (128*AKE)
#define B_ELT (32*BNE)
#define STG_ELT (A_ELT + B_ELT)
#define GEMM_SMEM (4 * STG_ELT * 2)

#define GEMM_PROLOG(Aptr, Bptr, Kdim, Ndim, bmv, bnv)                                    \
    extern __shared__ bf16 smb[];                                                        \
    const unsigned sbase = (unsigned)__cvta_generic_to_shared(smb);                      \
    const int tid  = threadIdx.x;                                                        \
    const int lane = tid & 31;                                                           \
    const int warp = tid >> 5;                                                           \
    const int g    = lane >> 2;                                                          \
    const int t4   = lane & 3;                                                           \
    const int lm   = lane & 15;                                                          \
    const int lh   = lane >> 4;                                                          \
    const int wm = (warp >> 2) * 64;                                                     \
    const int wn = (warp & 3) * 64;                                                      \
    float acc[4][8][4];                                                                  \
    _Pragma("unroll") for (int i = 0; i < 4; i++)                                        \
        _Pragma("unroll") for (int j = 0; j < 8; j++)                                    \
            _Pragma("unroll") for (int r = 0; r < 4; r++) acc[i][j][r] = 0.f;            \
    const int ktiles = (Kdim) >> 5;                                                      \
    auto load_stage = [&](int st, int k0) {                                              \
        unsigned sa = sbase + (unsigned)(st * STG_ELT) * 2u;                             \
        unsigned sb = sa + A_ELT * 2u;                                                   \
        _Pragma("unroll") for (int u = 0; u < 2; u++) {                                  \
            int c = tid + 256*u;                                                         \
            int r = c >> 2, o = (c & 3) * 8;                                             \
            cpa16(sa + (unsigned)(r*AKE + o)*2u, (Aptr) + (size_t)((bmv) + r) * (Kdim) + k0 + o); \
        }                                                                                \
        _Pragma("unroll") for (int u = 0; u < 4; u++) {                                  \
            int c = tid + 256*u;                                                         \
            int r = c >> 5, o = (c & 31) * 8;                                            \
            cpa16(sb + (unsigned)(r*BNE + o)*2u, (Bptr) + (size_t)(k0 + r) * (Ndim) + (bnv) + o); \
        }                                                                                \
    };                                                                                   \
    load_stage(0, 0);                                                                    \
    asm volatile("cp.async.commit_group;");                                              \
    load_stage(1, 32);                                                                   \
    asm volatile("cp.async.commit_group;");                                              \
    load_stage(2, 64);                                                                   \
    asm volatile("cp.async.commit_group;");                                              \
    for (int t = 0; t < ktiles; t++) {                                                   \
        asm volatile("cp.async.wait_group 2;");                                          \
        __syncthreads();                                                                 \
        int nt = t + 3;                                                                  \
        if (nt < ktiles) load_stage(nt & 3, nt * 32);                                    \
        asm volatile("cp.async.commit_group;");                                          \
        unsigned sa = sbase + (unsigned)((t & 3) * STG_ELT) * 2u;                        \
        unsigned sb = sa + A_ELT * 2u;                                                   \
        _Pragma("unroll") for (int kk = 0; kk < 32; kk += 16) {                          \
            unsigned af[4][4], bfr[8][2];                                                \
            _Pragma("unroll") for (int i = 0; i < 4; i++)                                \
                ldmx4(af[i][0], af[i][1], af[i][2], af[i][3],                            \
                      sa + (unsigned)((wm + 16*i + lm)*AKE + kk + lh*8)*2u);             \
            _Pragma("unroll") for (int j2 = 0; j2 < 4; j2++)                             \
                ldmx4t(bfr[2*j2][0], bfr[2*j2][1], bfr[2*j2+1][0], bfr[2*j2+1][1],       \
                       sb + (unsigned)((kk + lm)*BNE + wn + 16*j2 + lh*8)*2u);           \
            _Pragma("unroll") for (int i = 0; i < 4; i++)                                \
                _Pragma("unroll") for (int j = 0; j < 8; j++)                            \
                    mma16(acc[i][j], af[i][0], af[i][1], af[i][2], af[i][3],             \
                          bfr[j][0], bfr[j][1]);                                         \
        }                                                                                \
    }

// ---- generic gemm, bf16 out ----
__global__ __launch_bounds__(256, 1) void gemm_bf16o(const bf16* __restrict__ A,
                                                     const bf16* __restrict__ B,
                                                     bf16* __restrict__ Cb,
                                                     int M, int N, int K) {
    const int bm = blockIdx.y * 128;
    const int bn = blockIdx.x * 256;
    GEMM_PROLOG(A, B, K, N, bm, bn)
    #pragma unroll
    for (int i = 0; i < 4; i++) {
        int row0 = bm + wm + 16*i + g;
        #pragma unroll
        for (int j = 0; j < 8; j++) {
            int col = bn + wn + 8*j + 2*t4;
            *(unsigned*)(Cb + (size_t)row0 * N + col)       = pack_bf(acc[i][j][0], acc[i][j][1]);
            *(unsigned*)(Cb + (size_t)(row0 + 8) * N + col) = pack_bf(acc[i][j][2], acc[i][j][3]);
        }
    }
}

// ---- fused QKV gemm + RoPE + head-norm + sqk_eff ----
__global__ __launch_bounds__(256, 1) void gemm_qkv(const bf16* __restrict__ A,
                                                   const float* __restrict__ fcos,
                                                   const float* __restrict__ fsin,
                                                   const float* __restrict__ sqk) {
    const int wsel = blockIdx.x >> 2;
    const int bn = (blockIdx.x & 3) * 256;
    const int bm = blockIdx.y * 128;
    const bf16* B = (wsel == 0) ? b_wq : ((wsel == 1) ? b_wk : b_wv);
    bf16* C = (wsel == 0) ? b_q : ((wsel == 1) ? b_k : b_v);
    GEMM_PROLOG(A, B, DIMN, DIMN, bm, bn)
    if (wsel == 2) {
        #pragma unroll
        for (int i = 0; i < 4; i++) {
            int row0 = bm + wm + 16*i + g;
            #pragma unroll
            for (int j = 0; j < 8; j++) {
                int col = bn + wn + 8*j + 2*t4;
                *(unsigned*)(C + (size_t)row0 * DIMN + col)       = pack_bf(acc[i][j][0], acc[i][j][1]);
                *(unsigned*)(C + (size_t)(row0 + 8) * DIMN + col) = pack_bf(acc[i][j][2], acc[i][j][3]);
            }
        }
    } else {
        const int h = (bn + wn) >> 6;
        const float qscale = (wsel == 0) ? 8.f * 1.4426950408889634f : 1.f;
        #pragma unroll
        for (int i = 0; i < 4; i++) {
            int row0 = bm + wm + 16*i + g;
            int row1 = row0 + 8;
            float ss0 = 0.f, ss1 = 0.f;
            #pragma unroll
            for (int j = 0; j < 8; j++) {
                ss0 += acc[i][j][0]*acc[i][j][0] + acc[i][j][1]*acc[i][j][1];
                ss1 += acc[i][j][2]*acc[i][j][2] + acc[i][j][3]*acc[i][j][3];
            }
            ss0 += __shfl_xor_sync(0xffffffffu, ss0, 1);
            ss0 += __shfl_xor_sync(0xffffffffu, ss0, 2);
            ss1 += __shfl_xor_sync(0xffffffffu, ss1, 1);
            ss1 += __shfl_xor_sync(0xffffffffu, ss1, 2);
            float inv0 = qscale / fmaxf(sqrtf(ss0), 1e-12f);
            float inv1 = qscale / fmaxf(sqrtf(ss1), 1e-12f);
            int s0 = row0 & (SEQL - 1), s1 = row1 & (SEQL - 1);
            #pragma unroll
            for (int j = 0; j < 8; j++) {
                int pidx = 4*j + t4;
                int d = 8*j + 2*t4;
                float se0 = sqk[h*HDIM + d]     * 32.f;
                float se1 = sqk[h*HDIM + d + 1] * 32.f;
                float c0 = fcos[s0*32 + pidx], sn0 = fsin[s0*32 + pidx];
                float c1 = fcos[s1*32 + pidx], sn1 = fsin[s1*32 + pidx];
                float a0 = acc[i][j][0], a1 = acc[i][j][1];
                float b0 = acc[i][j][2], b1 = acc[i][j][3];
                int col = bn + wn + d;
                *(unsigned*)(C + (size_t)row0 * DIMN + col) =
                    pack_bf((a0*c0 - a1*sn0) * inv0 * se0, (a0*sn0 + a1*c0) * inv0 * se1);
                *(unsigned*)(C + (size_t)row1 * DIMN + col) =
                    pack_bf((b0*c1 - b1*sn1) * inv1 * se0, (b0*sn1 + b1*c1) * inv1 * se1);
            }
        }
    }
}

// ---- adafm gemm: Y = Xp @ Bg, scatter; bf16 out (attn) or fp8 x16 out (ffn) ----
__global__ __launch_bounds__(256, 1) void adafm_gemm(const bf16* __restrict__ Bg0,
                                                     bf16* __restrict__ Y,
                                                     unsigned char* __restrict__ Y8) {
    const int z  = blockIdx.z;
    const int bm = blockIdx.y * 128;
    const int bn = 0;
    const bf16* A = b_xp + (size_t)z * 8192 * 256;
    const bf16* B = Bg0 + (size_t)z * 65536;
    GEMM_PROLOG(A, B, 256, 256, bm, bn)
    #pragma unroll
    for (int i = 0; i < 4; i++) {
        int pi0 = bm + wm + 16*i + g;
        #pragma unroll
        for (int j = 0; j < 8; j++) {
            int col = wn + 8*j + 2*t4;
            int p = col >> 4, qq = col & 15;
            int pi1 = pi0 + 8;
            size_t off0 = (size_t)(z*2048 + (pi0 >> 6)*16 + p) * DIMN + (pi0 & 63)*16 + qq;
            size_t off1 = (size_t)(z*2048 + (pi1 >> 6)*16 + p) * DIMN + (pi1 & 63)*16 + qq;
            if (Y8) {
                *(unsigned short*)(Y8 + off0) = pack_f8(acc[i][j][0]*16.f, acc[i][j][1]*16.f);
                *(unsigned short*)(Y8 + off1) = pack_f8(acc[i][j][2]*16.f, acc[i][j][3]*16.f);
            } else {
                *(unsigned*)(Y + off0) = pack_bf(acc[i][j][0], acc[i][j][1]);
                *(unsigned*)(Y + off1) = pack_bf(acc[i][j][2], acc[i][j][3]);
            }
        }
    }
}

// ================= fp8 FFN w1/w3 GEMM + silu gate =================
#define F8AS 80
#define F8STG (128*F8AS + 256*F8AS)
#define FFN8_SMEM (4 * F8STG)

__global__ __launch_bounds__(256, 1) void gemm_ffn13f8(const float* __restrict__ su,
                                                       const float* __restrict__ sv) {
    const int bnb = blockIdx.x * 128;
    const int bm  = blockIdx.y * 128;
    extern __shared__ __align__(16) unsigned char sm8[];
    const unsigned sbase = (unsigned)__cvta_generic_to_shared(sm8);
    const int tid  = threadIdx.x;
    const int lane = tid & 31;
    const int warp = tid >> 5;
    const int g    = lane >> 2;
    const int t4   = lane & 3;
    const int lm   = lane & 15;
    const int lh   = lane >> 4;
    const int wm = (warp >> 2) * 64;
    const int wn = (warp & 3) * 32;
    const int q8 = lane >> 3, r8 = lane & 7;

    float acc1[4][4][4], acc3[4][4][4];
    #pragma unroll
    for (int i = 0; i < 4; i++)
        #pragma unroll
        for (int j = 0; j < 4; j++)
            #pragma unroll
            for (int r = 0; r < 4; r++) { acc1[i][j][r] = 0.f; acc3[i][j][r] = 0.f; }

    const int ktiles = DIMN >> 6;
    auto load_stage = [&](int st, int k0) {
        unsigned sa = sbase + (unsigned)(st * F8STG);
        unsigned sb = sa + 128*F8AS;
        #pragma unroll
        for (int u = 0; u < 2; u++) {
            int c = tid + 256*u;
            int r = c >> 2, o = (c & 3) * 16;
            cpa16(sa + (unsigned)(r*F8AS + o), b_xm8 + (size_t)(bm + r) * DIMN + k0 + o);
        }
        #pragma unroll
        for (int u = 0; u < 4; u++) {
            int c = tid + 256*u;
            int r = c >> 2, o = (c & 3) * 16;
            const unsigned char* src = (r < 128)
                ? (b_w13t + (size_t)(bnb + r) * DIMN)
                : (b_w13t + (size_t)HIDDEN*DIMN + (size_t)(bnb + r - 128) * DIMN);
            cpa16(sb + (unsigned)(r*F8AS + o), src + k0 + o);
        }
    };
    load_stage(0, 0);
    asm volatile("cp.async.commit_group;");
    load_stage(1, 64);
    asm volatile("cp.async.commit_group;");
    load_stage(2, 128);
    asm volatile("cp.async.commit_group;");

    for (int t = 0; t < ktiles; t++) {
        asm volatile("cp.async.wait_group 2;");
        __syncthreads();
        int nt = t + 3;
        if (nt < ktiles) load_stage(nt & 3, nt * 64);
        asm volatile("cp.async.commit_group;");
        unsigned sa = sbase + (unsigned)((t & 3) * F8STG);
        unsigned sb = sa + 128*F8AS;
        #pragma unroll
        for (int ks = 0; ks < 2; ks++) {
            int k0 = ks * 32;
            unsigned af[4][4], b1f[4][2], b3f[4][2];
            #pragma unroll
            for (int i = 0; i < 4; i++)
                ldmx4(af[i][0], af[i][1], af[i][2], af[i][3],
                      sa + (unsigned)((wm + 16*i + lm)*F8AS + k0 + lh*16));
            #pragma unroll
            for (int jp = 0; jp < 2; jp++) {
                int n0 = wn + 16*jp;
                unsigned ra = (unsigned)((n0 + ((q8 >> 1) << 3) + r8)*F8AS + k0 + ((q8 & 1) << 4));
                ldmx4(b1f[2*jp][0], b1f[2*jp][1], b1f[2*jp+1][0], b1f[2*jp+1][1], sb + ra);
                ldmx4(b3f[2*jp][0], b3f[2*jp][1], b3f[2*jp+1][0], b3f[2*jp+1][1],
                      sb + 128u*F8AS + ra);
            }
            #pragma unroll
            for (int i = 0; i < 4; i++)
                #pragma unroll
                for (int j = 0; j < 4; j++) {
                    mma8f8(acc1[i][j], af[i][0], af[i][1], af[i][2], af[i][3], b1f[j][0], b1f[j][1]);
                    mma8f8(acc3[i][j], af[i][0], af[i][1], af[i][2], af[i][3], b3f[j][0], b3f[j][1]);
                }
        }
    }

    const float SC = 53.06599664568481f;
    const float OS13 = 1.f / 4096.f;
    #pragma unroll
    for (int i = 0; i < 4; i++) {
        int row0 = bm + wm + 16*i + g;
        #pragma unroll
        for (int j = 0; j < 4; j++) {
            int col = bnb + wn + 8*j + 2*t4;
            float sv0 = sv[col] * SC * OS13, sv1 = sv[col+1] * SC * OS13;
            float su0 = su[col] * OS13,      su1 = su[col+1] * OS13;
            float z, sgl, outv[4];
            z = acc1[i][j][0] * sv0; sgl = z / (1.f + __expf(-z)); outv[0] = sgl * (acc3[i][j][0] * su0);
            z = acc1[i][j][1] * sv1; sgl = z / (1.f + __expf(-z)); outv[1] = sgl * (acc3[i][j][1] * su1);
            z = acc1[i][j][2] * sv0; sgl = z / (1.f + __expf(-z)); outv[2] = sgl * (acc3[i][j][2] * su0);
            z = acc1[i][j][3] * sv1; sgl = z / (1.f + __expf(-z)); outv[3] = sgl * (acc3[i][j][3] * su1);
            *(unsigned short*)(b_h8 + (size_t)row0 * HIDDEN + col)
                = pack_f8(outv[0]*256.f, outv[1]*256.f);
            *(unsigned short*)(b_h8 + (size_t)(row0 + 8) * HIDDEN + col)
                = pack_f8(outv[2]*256.f, outv[3]*256.f);
        }
    }
}

// ---- w2 fp8 GEMM: Cb bf16 = (h8/256) @ (w2t/64)^T ----
#define A8S 80
#define STG8 (128*A8S + 256*A8S)
#define W2F8_SMEM (4 * STG8)

__global__ __launch_bounds__(256, 1) void gemm_w2f8(bf16* __restrict__ Cb) {
    const int bm = blockIdx.y * 128;
    const int bn = blockIdx.x * 256;
    extern __shared__ __align__(16) unsigned char sm8[];
    const unsigned sbase = (unsigned)__cvta_generic_to_shared(sm8);
    const int tid  = threadIdx.x;
    const int lane = tid & 31;
    const int warp = tid >> 5;
    const int g    = lane >> 2;
    const int t4   = lane & 3;
    const int lm   = lane & 15;
    const int lh   = lane >> 4;
    const int wm = (warp >> 2) * 64;
    const int wn = (warp & 3) * 64;
    const int q8 = lane >> 3, r8 = lane & 7;

    float acc[4][8][4];
    #pragma unroll
    for (int i = 0; i < 4; i++)
        #pragma unroll
        for (int j = 0; j < 8; j++)
            #pragma unroll
            for (int r = 0; r < 4; r++) acc[i][j][r] = 0.f;

    const int ktiles = HIDDEN >> 6;
    auto load_stage = [&](int st, int k0) {
        unsigned sa = sbase + (unsigned)(st * STG8);
        unsigned sb = sa + 128*A8S;
        #pragma unroll
        for (int u = 0; u < 2; u++) {
            int c = tid + 256*u;
            int r = c >> 2, o = (c & 3) * 16;
            cpa16(sa + (unsigned)(r*A8S + o), b_h8 + (size_t)(bm + r) * HIDDEN + k0 + o);
        }
        #pragma unroll
        for (int u = 0; u < 4; u++) {
            int c = tid + 256*u;
            int r = c >> 2, o = (c & 3) * 16;
            cpa16(sb + (unsigned)(r*A8S + o), b_w2t + (size_t)(bn + r) * HIDDEN + k0 + o);
        }
    };
    load_stage(0, 0);
    asm volatile("cp.async.commit_group;");
    load_stage(1, 64);
    asm volatile("cp.async.commit_group;");
    load_stage(2, 128);
    asm volatile("cp.async.commit_group;");

    for (int t = 0; t < ktiles; t++) {
        asm volatile("cp.async.wait_group 2;");
        __syncthreads();
        int nt = t + 3;
        if (nt < ktiles) load_stage(nt & 3, nt * 64);
        asm volatile("cp.async.commit_group;");
        unsigned sa = sbase + (unsigned)((t & 3) * STG8);
        unsigned sb = sa + 128*A8S;
        #pragma unroll
        for (int ks = 0; ks < 2; ks++) {
            int k0 = ks * 32;
            unsigned af[4][4], bfr[8][2];
            #pragma unroll
            for (int i = 0; i < 4; i++)
                ldmx4(af[i][0], af[i][1], af[i][2], af[i][3],
                      sa + (unsigned)((wm + 16*i + lm)*A8S + k0 + lh*16));
            #pragma unroll
            for (int jp = 0; jp < 4; jp++) {
                int n0 = wn + 16*jp;
                unsigned addr = sb + (unsigned)((n0 + ((q8 >> 1) << 3) + r8)*A8S + k0 + ((q8 & 1) << 4));
                ldmx4(bfr[2*jp][0], bfr[2*jp][1], bfr[2*jp+1][0], bfr[2*jp+1][1], addr);
            }
            #pragma unroll
            for (int i = 0; i < 4; i++)
                #pragma unroll
                for (int j = 0; j < 8; j++)
                    mma8f8(acc[i][j], af[i][0], af[i][1], af[i][2], af[i][3],
                           bfr[j][0], bfr[j][1]);
        }
    }

    const float OS = 1.f / 16384.f;
    #pragma unroll
    for (int i = 0; i < 4; i++) {
        int row0 = bm + wm + 16*i + g;
        #pragma unroll
        for (int j = 0; j < 8; j++) {
            int col = bn + wn + 8*j + 2*t4;
            *(unsigned*)(Cb + (size_t)row0 * DIMN + col)       = pack_bf(acc[i][j][0]*OS, acc[i][j][1]*OS);
            *(unsigned*)(Cb + (size_t)(row0 + 8) * DIMN + col) = pack_bf(acc[i][j][2]*OS, acc[i][j][3]*OS);
        }
    }
}

// --------- FA2 flash attention, cp.async 3-stage ring ---------
#define FAE 72
#define FLASH_SMEM ((128 + 6*64) * FAE * 2)

__global__ __launch_bounds__(256, 2) void flash_attn(const bf16* __restrict__ Q,
                                                     const bf16* __restrict__ K,
                                                     const bf16* __restrict__ V,
                                                     bf16* __restrict__ O) {
    extern __shared__ bf16 fsm[];
    bf16* Qs = fsm;
    const unsigned sQ  = (unsigned)__cvta_generic_to_shared(Qs);
    const unsigned sK0 = sQ + 128*FAE*2u;
    const unsigned sV0 = sK0 + 3*64*FAE*2u;

    const int q0 = blockIdx.x * 128;
    const int h  = blockIdx.y;
    const int b  = blockIdx.z;
    const bf16* Qb = Q + (size_t)b*SEQL*DIMN + h*HDIM;
    const bf16* Kb = K + (size_t)b*SEQL*DIMN + h*HDIM;
    const bf16* Vb = V + (size_t)b*SEQL*DIMN + h*HDIM;
    bf16*       Ob = O + (size_t)b*SEQL*DIMN + h*HDIM;

    const int tid  = threadIdx.x;
    const int lane = tid & 31;
    const int warp = tid >> 5;
    const int g  = lane >> 2;
    const int t4 = lane & 3;
    const int lm = lane & 15;
    const int lh = lane >> 4;
    const int wm = warp * 16;

    auto loadKV = [&](int st, int k0) {
        unsigned sk = sK0 + (unsigned)st * 64*FAE*2u;
        unsigned sv = sV0 + (unsigned)st * 64*FAE*2u;
        #pragma unroll
        for (int u = 0; u < 2; u++) {
            int c = tid + 256*u;
            int r = c >> 3, ofs = (c & 7) * 8;
            cpa16(sk + (unsigned)(r*FAE + ofs)*2u, Kb + (size_t)(k0 + r)*DIMN + ofs);
            cpa16(sv + (unsigned)(r*FAE + ofs)*2u, Vb + (size_t)(k0 + r)*DIMN + ofs);
        }
    };

    #pragma unroll
    for (int u = 0; u < 4; u++) {
        int c = tid + 256*u;
        int r = c >> 3, ofs = (c & 7) * 8;
        *(uint4*)&Qs[r*FAE + ofs] = *(const uint4*)(Qb + (size_t)(q0 + r)*DIMN + ofs);
    }

    loadKV(0, 0);
    asm volatile("cp.async.commit_group;");
    loadKV(1, 64);
    asm volatile("cp.async.commit_group;");

    float o[8][4];
    #pragma unroll
    for (int j = 0; j < 8; j++)
        #pragma unroll
        for (int r = 0; r < 4; r++) o[j][r] = 0.f;
    float m0 = -1e30f, m1 = -1e30f, l0 = 0.f, l1 = 0.f;

    const int NT = SEQL / 64;
    for (int t = 0; t < NT; t++) {
        if (t + 1 < NT) asm volatile("cp.async.wait_group 1;");
        else            asm volatile("cp.async.wait_group 0;");
        __syncthreads();
        if (t + 2 < NT) {
            loadKV((t + 2) % 3, (t + 2) * 64);
            asm volatile("cp.async.commit_group;");
        }

        const unsigned sK = sK0 + (unsigned)(t % 3) * 64*FAE*2u;
        const unsigned sV = sV0 + (unsigned)(t % 3) * 64*FAE*2u;

        float s[8][4];
        #pragma unroll
        for (int j = 0; j < 8; j++)
            #pragma unroll
            for (int r = 0; r < 4; r++) s[j][r] = 0.f;

        #pragma unroll
        for (int kc = 0; kc < 4; kc++) {
            int kk = 16*kc;
            unsigned a0, a1, a2, a3;
            ldmx4(a0, a1, a2, a3, sQ + (unsigned)((wm + lm)*FAE + kk + lh*8)*2u);
            #pragma unroll
            for (int j2 = 0; j2 < 4; j2++) {
                unsigned r0, r1, r2, r3;
                ldmx4(r0, r1, r2, r3,
                      sK + (unsigned)((16*j2 + (lane & 7) + ((lane >> 4) << 3))*FAE
                                       + kk + (((lane >> 3) & 1) << 3))*2u);
                mma16(s[2*j2],     a0, a1, a2, a3, r0, r1);
                mma16(s[2*j2 + 1], a0, a1, a2, a3, r2, r3);
            }
        }

        float tm0 = -1e30f, tm1 = -1e30f;
        #pragma unroll
        for (int j = 0; j < 8; j++) {
            tm0 = fmaxf(tm0, fmaxf(s[j][0], s[j][1]));
            tm1 = fmaxf(tm1, fmaxf(s[j][2], s[j][3]));
        }
        tm0 = fmaxf(tm0, __shfl_xor_sync(0xffffffffu, tm0, 1));
        tm0 = fmaxf(tm0, __shfl_xor_sync(0xffffffffu, tm0, 2));
        tm1 = fmaxf(tm1, __shfl_xor_sync(0xffffffffu, tm1, 1));
        tm1 = fmaxf(tm1, __shfl_xor_sync(0xffffffffu, tm1, 2));
        float mn0 = fmaxf(m0, tm0), mn1 = fmaxf(m1, tm1);
        float c0 = exp2f(m0 - mn0), c1 = exp2f(m1 - mn1);
        float ps0 = 0.f, ps1 = 0.f;
        #pragma unroll
        for (int j = 0; j < 8; j++) {
            s[j][0] = exp2f(s[j][0] - mn0);
            s[j][1] = exp2f(s[j][1] - mn0);
            s[j][2] = exp2f(s[j][2] - mn1);
            s[j][3] = exp2f(s[j][3] - mn1);
            ps0 += s[j][0] + s[j][1];
            ps1 += s[j][2] + s[j][3];
        }
        ps0 += __shfl_xor_sync(0xffffffffu, ps0, 1);
        ps0 += __shfl_xor_sync(0xffffffffu, ps0, 2);
        ps1 += __shfl_xor_sync(0xffffffffu, ps1, 1);
        ps1 += __shfl_xor_sync(0xffffffffu, ps1, 2);
        l0 = l0 * c0 + ps0;  l1 = l1 * c1 + ps1;
        m0 = mn0;            m1 = mn1;
        #pragma unroll
        for (int j = 0; j < 8; j++) {
            o[j][0] *= c0; o[j][1] *= c0; o[j][2] *= c1; o[j][3] *= c1;
        }

        #pragma unroll
        for (int c = 0; c < 4; c++) {
            unsigned pa0 = pack_bf(s[2*c][0],   s[2*c][1]);
            unsigned pa1 = pack_bf(s[2*c][2],   s[2*c][3]);
            unsigned pa2 = pack_bf(s[2*c+1][0], s[2*c+1][1]);
            unsigned pa3 = pack_bf(s[2*c+1][2], s[2*c+1][3]);
            #pragma unroll
            for (int j2 = 0; j2 < 4; j2++) {
                unsigned r0, r1, r2, r3;
                ldmx4t(r0, r1, r2, r3,
                       sV + (unsigned)((16*c + lm)*FAE + 16*j2 + lh*8)*2u);
                mma16(o[2*j2],     pa0, pa1, pa2, pa3, r0, r1);
                mma16(o[2*j2 + 1], pa0, pa1, pa2, pa3, r2, r3);
            }
        }
    }

    float inv0 = 1.f / l0, inv1 = 1.f / l1;
    #pragma unroll
    for (int j = 0; j < 8; j++) {
        int col = 8*j + 2*t4;
        *(unsigned*)(Ob + (size_t)(q0 + wm + g    )*DIMN + col) = pack_bf(o[j][0]*inv0, o[j][1]*inv0);
        *(unsigned*)(Ob + (size_t)(q0 + wm + g + 8)*DIMN + col) = pack_bf(o[j][2]*inv1, o[j][3]*inv1);
    }
}

// ------- fused residual + norms; branch input bf16; optional patchified output -------
__global__ __launch_bounds__(256) void residual_norm(const float* __restrict__ xb,
                                                     const bf16* __restrict__ br,
                                                     const float* __restrict__ alpha,
                                                     float* __restrict__ out,
                                                     bf16* __restrict__ xp) {
    int t = blockIdx.x;
    int tid = threadIdx.x;
    const float* xr = xb + (size_t)t * DIMN;
    const bf16*  rr = br + (size_t)t * DIMN;
    float xv[4], bv[4];
    float ssx = 0.f, ssb = 0.f;
    #pragma unroll
    for (int u = 0; u < 2; u++) {
        int d = tid*2 + u * 512;
        float2 xx = *(const float2*)(xr + d);
        float2 bb = unpack_bf(*(const unsigned*)(rr + d));
        xv[2*u] = xx.x; xv[2*u+1] = xx.y;
        bv[2*u] = bb.x; bv[2*u+1] = bb.y;
        ssx += xx.x*xx.x + xx.y*xx.y;
        ssb += bb.x*bb.x + bb.y*bb.y;
    }
    ssx = blockSum256(ssx);
    ssb = blockSum256(ssb);
    float rx = 1.f / fmaxf(sqrtf(ssx), 1e-12f);
    float rb = 1.f / fmaxf(sqrtf(ssb), 1e-12f);
    float yv[4]; float ssy = 0.f;
    #pragma unroll
    for (int u = 0; u < 4; u++) {
        int d = tid*2 + (u >> 1) * 512 + (u & 1);
        float hh = xv[u] * rx;
        float ha = bv[u] * rb;
        float lr = fabsf(alpha[d] * 1.6f);
        float y = hh + lr * (ha - hh);
        yv[u] = y; ssy += y * y;
    }
    ssy = blockSum256(ssy);
    float ry = 1.f / fmaxf(sqrtf(ssy), 1e-12f);
    int b = t >> 11, se = t & 2047;
    int ip = se >> 4, p = se & 15;
    #pragma unroll
    for (int u = 0; u < 4; u++) {
        int d = tid*2 + (u >> 1) * 512 + (u & 1);
        float y = yv[u] * ry;
        out[(size_t)t * DIMN + d] = y;
        if (xp) {
            int jj = d >> 4, qq = d & 15;
            xp[((size_t)b*8192 + ip*64 + jj)*256 + p*16 + qq] = __float2bfloat16_rn(y);
        }
    }
}

// ---------------- launch ----------------
extern "C" void kernel_launch(void* const* d_in, const int* in_sizes, int n_in,
                              void* d_out, int out_size) {
    const float* x      = (const float*)d_in[0];
    const float* fcos   = (const float*)d_in[1];
    const float* fsin   = (const float*)d_in[2];
    const float* adafm  = (const float*)d_in[3];
    const float* wq     = (const float*)d_in[4];
    const float* wk     = (const float*)d_in[5];
    const float* wv     = (const float*)d_in[6];
    const float* wo     = (const float*)d_in[7];
    const float* sqk    = (const float*)d_in[8];
    const float* w1     = (const float*)d_in[9];
    const float* w2     = (const float*)d_in[10];
    const float* w3     = (const float*)d_in[11];
    const float* su     = (const float*)d_in[12];
    const float* sv     = (const float*)d_in[13];
    const float* pw     = (const float*)d_in[14];
    const float* pb     = (const float*)d_in[15];
    const float* aalpha = (const float*)d_in[16];
    const float* malpha = (const float*)d_in[17];
    float* out = (float*)d_out;

    float *pt, *pf0;
    bf16 *pbgm, *pbgf, *pbxa, *pbq, *pbk, *pbv, *pbao, *pbwo, *pbxp;
    unsigned char *pxm8;
    cudaGetSymbolAddress((void**)&pt,  d_t);
    cudaGetSymbolAddress((void**)&pf0, d_f0);
    cudaGetSymbolAddress((void**)&pbgm, b_gm);
    cudaGetSymbolAddress((void**)&pbgf, b_gf);
    cudaGetSymbolAddress((void**)&pbxa, b_xa);
    cudaGetSymbolAddress((void**)&pbq,  b_q);
    cudaGetSymbolAddress((void**)&pbk,  b_k);
    cudaGetSymbolAddress((void**)&pbv,  b_v);
    cudaGetSymbolAddress((void**)&pbao, b_ao);
    cudaGetSymbolAddress((void**)&pbwo, b_wo);
    cudaGetSymbolAddress((void**)&pbxp, b_xp);
    cudaGetSymbolAddress((void**)&pxm8, b_xm8);

    cudaFuncSetAttribute(gemm_bf16o, cudaFuncAttributeMaxDynamicSharedMemorySize, GEMM_SMEM);
    cudaFuncSetAttribute(gemm_qkv, cudaFuncAttributeMaxDynamicSharedMemorySize, GEMM_SMEM);
    cudaFuncSetAttribute(adafm_gemm, cudaFuncAttributeMaxDynamicSharedMemorySize, GEMM_SMEM);
    cudaFuncSetAttribute(gemm_ffn13f8, cudaFuncAttributeMaxDynamicSharedMemorySize, FFN8_SMEM);
    cudaFuncSetAttribute(gemm_w2f8, cudaFuncAttributeMaxDynamicSharedMemorySize, W2F8_SMEM);
    cudaFuncSetAttribute(flash_attn, cudaFuncAttributeMaxDynamicSharedMemorySize, FLASH_SMEM);

    // 0) weight conversions
    cvt_all<<<dim3(256, 4), 256>>>(wq, wk, wv, wo);
    cvt_w13t<<<dim3(2816, 2), 256>>>(w1, w3);
    cvt_w2t<<<2816, 256>>>(w2);

    // 1) time-modulation
    proj_t_kernel<<<dim3(BATCH, 16), 256>>>(adafm, pw, pb, pt);
    make_g_kernel<<<dim3(4, 32), 256>>>(pt);

    // 2) attention branch
    patchify<<<2048, 256>>>(x);
    adafm_gemm<<<dim3(1, 64, 2), 256, GEMM_SMEM>>>(pbgm, pbxa, (unsigned char*)0);
    gemm_qkv<<<dim3(12, 32), 256, GEMM_SMEM>>>(pbxa, fcos, fsin, sqk);
    flash_attn<<<dim3(SEQL/128, NHEAD, BATCH), 256, FLASH_SMEM>>>(pbq, pbk, pbv, pbao);
    gemm_bf16o<<<dim3(DIMN/256, TOK/128), 256, GEMM_SMEM>>>(pbao, pbwo, pbq, TOK, DIMN, DIMN);
    residual_norm<<<TOK, 256>>>(x, pbq, aalpha, pf0, pbxp);

    // 3) FFN branch (fp8)
    adafm_gemm<<<dim3(1, 64, 2), 256, GEMM_SMEM>>>(pbgf, (bf16*)0, pxm8);
    gemm_ffn13f8<<<dim3(HIDDEN/128, TOK/128), 256, FFN8_SMEM>>>(su, sv);
    gemm_w2f8<<<dim3(DIMN/256, TOK/128), 256, W2F8_SMEM>>>(pbk);
    residual_norm<<<TOK, 256>>>(pf0, pbk, malpha, out, (bf16*)0);
}